// round 1
// baseline (speedup 1.0000x reference)
#include <cuda_runtime.h>
#include <math.h>

// ---------------- problem constants ----------------
#define DIMC   1024
#define DEPTHL 6
#define HEADS  16
#define DHEAD  64
#define NKV    2048
#define FFD    4096
#define BTOT   32                    // B*T = 4*8
#define MEDIA  1024                  // F*V = 4*256 media tokens per (b,t)
#define NMEDIA (BTOT*MEDIA)          // 32768
#define NLAT   64
#define LROWS  (BTOT*NLAT)           // 2048

// ---------------- scratch (static device globals; no allocs) ----------------
__device__ float g_xhat[NMEDIA*DIMC];   // normalized x (no affine), computed once
__device__ float g_kvm [(size_t)NMEDIA*NKV]; // media K|V for current layer
__device__ float g_lat [LROWS*DIMC];    // latent residual stream
__device__ float g_latn[LROWS*DIMC];    // LN(lat) scratch
__device__ float g_q   [LROWS*DIMC];
__device__ float g_kvl [LROWS*NKV];
__device__ float g_attn[LROWS*DIMC];
__device__ float g_h1  [(size_t)LROWS*FFD];
__device__ float g_bias[NKV];           // b_i @ wkv_i

// ---------------- LayerNorm (one block per row, 1024 cols) ----------------
__global__ void ln_kernel(const float* __restrict__ in, float* __restrict__ out,
                          const float* __restrict__ g, const float* __restrict__ b)
{
    const int row = blockIdx.x;
    const float* x = in + (size_t)row * DIMC;
    float s = 0.f, sq = 0.f;
    for (int c = threadIdx.x; c < DIMC; c += blockDim.x) {
        float v = x[c]; s += v; sq += v * v;
    }
    __shared__ float sh[64];
    #pragma unroll
    for (int o = 16; o > 0; o >>= 1) {
        s  += __shfl_down_sync(0xffffffffu, s,  o);
        sq += __shfl_down_sync(0xffffffffu, sq, o);
    }
    const int wid = threadIdx.x >> 5, lid = threadIdx.x & 31;
    if (lid == 0) { sh[wid] = s; sh[wid + 32] = sq; }
    __syncthreads();
    if (threadIdx.x == 0) {
        float ts = 0.f, tsq = 0.f;
        const int nw = blockDim.x >> 5;
        for (int i = 0; i < nw; i++) { ts += sh[i]; tsq += sh[i + 32]; }
        const float mean = ts * (1.0f / DIMC);
        const float var  = tsq * (1.0f / DIMC) - mean * mean;
        sh[0] = mean; sh[1] = rsqrtf(var + 1e-5f);
    }
    __syncthreads();
    const float mean = sh[0], rstd = sh[1];
    float* o = out + (size_t)row * DIMC;
    for (int c = threadIdx.x; c < DIMC; c += blockDim.x) {
        float v = (x[c] - mean) * rstd;
        if (g) v = v * g[c] + b[c];
        o[c] = v;
    }
}

// ---------------- bias row: c[n] = sum_k bvec[k] * W[k][n]  (N=2048, K=1024) ----
__global__ void bias_kernel(const float* __restrict__ bvec,
                            const float* __restrict__ W,
                            float* __restrict__ c)
{
    const int n = blockIdx.x * blockDim.x + threadIdx.x;
    float s = 0.f;
    for (int k = 0; k < DIMC; k++) s += bvec[k] * W[(size_t)k * NKV + n];
    c[n] = s;
}

// ---------------- broadcast latents into lat buffer ----------------
__global__ void init_lat_kernel(const float* __restrict__ latents, float* __restrict__ lat)
{
    const int idx = blockIdx.x * blockDim.x + threadIdx.x;
    lat[idx] = latents[idx & (NLAT * DIMC - 1)];
}

// ---------------- generic tiled fp32 GEMM: C = epi(A[M,K] @ B[K,N]) -------------
// optional: kscale[k] applied to B rows (folds LN gamma), bias[n], GELU, residual.
// All of M,N multiples of 128; K multiple of 16 (true for every call here).
__global__ void __launch_bounds__(256)
gemm_kernel(const float* __restrict__ A, const float* __restrict__ B,
            float* __restrict__ C, int M, int N, int K,
            const float* __restrict__ kscale, const float* __restrict__ bias,
            const float* __restrict__ resid, int dogelu)
{
    __shared__ float As[16][128];
    __shared__ float Bs[16][128];
    const int bm = blockIdx.y * 128;
    const int bn = blockIdx.x * 128;
    const int tid = threadIdx.x;
    const int tx = tid & 15, ty = tid >> 4;

    float acc[8][8] = {};
    for (int k0 = 0; k0 < K; k0 += 16) {
        // A tile: 128 rows x 16 k  (512 float4 / 256 threads)
        #pragma unroll
        for (int i = 0; i < 2; i++) {
            const int idx = tid + i * 256;
            const int r  = idx >> 2;
            const int kq = (idx & 3) << 2;
            const float4 v = *reinterpret_cast<const float4*>(
                &A[(size_t)(bm + r) * K + k0 + kq]);
            As[kq + 0][r] = v.x; As[kq + 1][r] = v.y;
            As[kq + 2][r] = v.z; As[kq + 3][r] = v.w;
        }
        // B tile: 16 k x 128 n
        #pragma unroll
        for (int i = 0; i < 2; i++) {
            const int idx = tid + i * 256;
            const int kr = idx >> 5;
            const int nc = (idx & 31) << 2;
            float4 v = *reinterpret_cast<const float4*>(
                &B[(size_t)(k0 + kr) * N + bn + nc]);
            if (kscale) {
                const float sc = kscale[k0 + kr];
                v.x *= sc; v.y *= sc; v.z *= sc; v.w *= sc;
            }
            *reinterpret_cast<float4*>(&Bs[kr][nc]) = v;
        }
        __syncthreads();
        #pragma unroll
        for (int kk = 0; kk < 16; kk++) {
            const float4 a0 = *reinterpret_cast<const float4*>(&As[kk][ty * 8]);
            const float4 a1 = *reinterpret_cast<const float4*>(&As[kk][ty * 8 + 4]);
            const float4 b0 = *reinterpret_cast<const float4*>(&Bs[kk][tx * 8]);
            const float4 b1 = *reinterpret_cast<const float4*>(&Bs[kk][tx * 8 + 4]);
            const float a[8] = {a0.x, a0.y, a0.z, a0.w, a1.x, a1.y, a1.z, a1.w};
            const float bb[8] = {b0.x, b0.y, b0.z, b0.w, b1.x, b1.y, b1.z, b1.w};
            #pragma unroll
            for (int i = 0; i < 8; i++)
                #pragma unroll
                for (int j = 0; j < 8; j++)
                    acc[i][j] += a[i] * bb[j];
        }
        __syncthreads();
    }
    #pragma unroll
    for (int i = 0; i < 8; i++) {
        const int row = bm + ty * 8 + i;
        #pragma unroll
        for (int j = 0; j < 8; j++) {
            const int col = bn + tx * 8 + j;
            float v = acc[i][j];
            if (bias)   v += bias[col];
            if (dogelu) v = 0.5f * v * (1.f + erff(v * 0.70710678118654752f));
            if (resid)  v += resid[(size_t)row * N + col];
            C[(size_t)row * N + col] = v;
        }
    }
}

// ---------------- flash attention: 64 queries x (1024 media + 64 lat) keys ------
// grid = BTOT*HEADS blocks; block = 256 threads; dynamic smem ~66 KB.
#define SPAD 65
__global__ void __launch_bounds__(256)
attn_kernel(const float* __restrict__ Q,    // [LROWS, DIMC]
            const float* __restrict__ KVm,  // [NMEDIA, NKV]  (k | v)
            const float* __restrict__ KVl,  // [LROWS, NKV]
            float* __restrict__ O)          // [LROWS, DIMC]
{
    extern __shared__ float sm[];
    float* Qs   = sm;
    float* Ks   = Qs + 64 * SPAD;
    float* Vs   = Ks + 64 * SPAD;
    float* Ss   = Vs + 64 * SPAD;
    float* mrow = Ss + 64 * SPAD;
    float* lrow = mrow + 64;
    float* frow = lrow + 64;

    const int bt  = blockIdx.x >> 4;
    const int h   = blockIdx.x & 15;
    const int tid = threadIdx.x;
    const int tx  = tid & 15, ty = tid >> 4;

    for (int idx = tid; idx < 64 * 64; idx += 256) {
        const int r = idx >> 6, d = idx & 63;
        Qs[r * SPAD + d] = Q[(size_t)(bt * 64 + r) * DIMC + h * 64 + d] * 0.125f;
    }
    if (tid < 64) { mrow[tid] = -INFINITY; lrow[tid] = 0.f; }
    float acc[4][4] = {};
    __syncthreads();

    for (int tile = 0; tile < 17; tile++) {
        for (int idx = tid; idx < 64 * 64; idx += 256) {
            const int r = idx >> 6, d = idx & 63;
            const float* KV;
            size_t base;
            if (tile < 16) { KV = KVm; base = (size_t)(bt * 1024 + tile * 64 + r) * NKV; }
            else           { KV = KVl; base = (size_t)(bt * 64 + r) * NKV; }
            Ks[r * SPAD + d] = KV[base + h * 64 + d];
            Vs[r * SPAD + d] = KV[base + 1024 + h * 64 + d];
        }
        __syncthreads();

        // S = Q @ K^T : thread covers q = ty*4+i, k = tx + 16*j (bank-conflict-free)
        float s4[4][4] = {};
        for (int kk = 0; kk < 64; kk++) {
            float a[4], b[4];
            #pragma unroll
            for (int i = 0; i < 4; i++) a[i] = Qs[(ty * 4 + i) * SPAD + kk];
            #pragma unroll
            for (int j = 0; j < 4; j++) b[j] = Ks[(tx + 16 * j) * SPAD + kk];
            #pragma unroll
            for (int i = 0; i < 4; i++)
                #pragma unroll
                for (int j = 0; j < 4; j++)
                    s4[i][j] += a[i] * b[j];
        }
        #pragma unroll
        for (int i = 0; i < 4; i++)
            #pragma unroll
            for (int j = 0; j < 4; j++)
                Ss[(ty * 4 + i) * SPAD + tx + 16 * j] = s4[i][j];
        __syncthreads();

        // online softmax row update (one thread per query row)
        if (tid < 64) {
            const int q = tid;
            const float mold = mrow[q];
            float tmax = -INFINITY;
            for (int k = 0; k < 64; k++) tmax = fmaxf(tmax, Ss[q * SPAD + k]);
            const float mnew = fmaxf(mold, tmax);
            const float fac = __expf(mold - mnew);
            float s = 0.f;
            for (int k = 0; k < 64; k++) {
                const float p = __expf(Ss[q * SPAD + k] - mnew);
                Ss[q * SPAD + k] = p;
                s += p;
            }
            lrow[q] = lrow[q] * fac + s;
            mrow[q] = mnew;
            frow[q] = fac;
        }
        __syncthreads();

        // acc = acc*fac + P @ V : thread covers q = ty*4+i, d = tx + 16*j
        #pragma unroll
        for (int i = 0; i < 4; i++) {
            const float fac = frow[ty * 4 + i];
            #pragma unroll
            for (int j = 0; j < 4; j++) acc[i][j] *= fac;
        }
        for (int kk = 0; kk < 64; kk++) {
            float p[4], v[4];
            #pragma unroll
            for (int i = 0; i < 4; i++) p[i] = Ss[(ty * 4 + i) * SPAD + kk];
            #pragma unroll
            for (int j = 0; j < 4; j++) v[j] = Vs[kk * SPAD + tx + 16 * j];
            #pragma unroll
            for (int i = 0; i < 4; i++)
                #pragma unroll
                for (int j = 0; j < 4; j++)
                    acc[i][j] += p[i] * v[j];
        }
        __syncthreads();
    }

    #pragma unroll
    for (int i = 0; i < 4; i++) {
        const int q = ty * 4 + i;
        const float inv_l = 1.0f / lrow[q];
        #pragma unroll
        for (int j = 0; j < 4; j++) {
            const int d = tx + 16 * j;
            O[(size_t)(bt * 64 + q) * DIMC + h * 64 + d] = acc[i][j] * inv_l;
        }
    }
}

// ---------------- orchestration ----------------
extern "C" void kernel_launch(void* const* d_in, const int* in_sizes, int n_in,
                              void* d_out, int out_size)
{
    (void)in_sizes; (void)n_in; (void)out_size;
    const float* x       = (const float*)d_in[0];
    const float* latents = (const float*)d_in[1];
    const float* nm_g    = (const float*)d_in[2];
    const float* nm_b    = (const float*)d_in[3];
    const float* nl_g    = (const float*)d_in[4];
    const float* nl_b    = (const float*)d_in[5];
    const float* wq      = (const float*)d_in[6];
    const float* wkv     = (const float*)d_in[7];
    const float* wo      = (const float*)d_in[8];
    const float* ff_g    = (const float*)d_in[9];
    const float* ff_b    = (const float*)d_in[10];
    const float* w1      = (const float*)d_in[11];
    const float* w2      = (const float*)d_in[12];
    const float* fin_g   = (const float*)d_in[13];
    const float* fin_b   = (const float*)d_in[14];
    float* out = (float*)d_out;

    float *xhat, *kvm, *lat, *latn, *q, *kvl, *attn, *h1, *bias;
    cudaGetSymbolAddress((void**)&xhat, g_xhat);
    cudaGetSymbolAddress((void**)&kvm,  g_kvm);
    cudaGetSymbolAddress((void**)&lat,  g_lat);
    cudaGetSymbolAddress((void**)&latn, g_latn);
    cudaGetSymbolAddress((void**)&q,    g_q);
    cudaGetSymbolAddress((void**)&kvl,  g_kvl);
    cudaGetSymbolAddress((void**)&attn, g_attn);
    cudaGetSymbolAddress((void**)&h1,   g_h1);
    cudaGetSymbolAddress((void**)&bias, g_bias);

    cudaFuncSetAttribute(attn_kernel, cudaFuncAttributeMaxDynamicSharedMemorySize, 69632);
    const int ATTN_SMEM = (4 * 64 * SPAD + 3 * 64) * (int)sizeof(float);

    // once: xhat = normalize(x) (LN affine folded into per-layer GEMMs)
    ln_kernel<<<NMEDIA, 128>>>(x, xhat, nullptr, nullptr);
    // init latent stream
    init_lat_kernel<<<(LROWS * DIMC) / 256, 256>>>(latents, lat);

    for (int i = 0; i < DEPTHL; i++) {
        const float* wq_i  = wq  + (size_t)i * DIMC * DIMC;
        const float* wkv_i = wkv + (size_t)i * DIMC * NKV;
        const float* wo_i  = wo  + (size_t)i * DIMC * DIMC;
        const float* w1_i  = w1  + (size_t)i * DIMC * FFD;
        const float* w2_i  = w2  + (size_t)i * FFD  * DIMC;

        // c_i = nm_b[i] @ wkv[i]
        bias_kernel<<<NKV / 256, 256>>>(nm_b + (size_t)i * DIMC, wkv_i, bias);
        // KV_media = (xhat * g + b) @ wkv  via k-scale + bias epilogue   [32768x2048]
        gemm_kernel<<<dim3(NKV / 128, NMEDIA / 128), 256>>>(
            xhat, wkv_i, kvm, NMEDIA, NKV, DIMC,
            nm_g + (size_t)i * DIMC, bias, nullptr, 0);
        // latn = LN(lat; nl)
        ln_kernel<<<LROWS, 128>>>(lat, latn, nl_g + (size_t)i * DIMC, nl_b + (size_t)i * DIMC);
        // Q = latn @ wq ; KV_lat = latn @ wkv
        gemm_kernel<<<dim3(DIMC / 128, LROWS / 128), 256>>>(
            latn, wq_i, q, LROWS, DIMC, DIMC, nullptr, nullptr, nullptr, 0);
        gemm_kernel<<<dim3(NKV / 128, LROWS / 128), 256>>>(
            latn, wkv_i, kvl, LROWS, NKV, DIMC, nullptr, nullptr, nullptr, 0);
        // attention
        attn_kernel<<<BTOT * HEADS, 256, ATTN_SMEM>>>(q, kvm, kvl, attn);
        // lat += attn_out @ wo
        gemm_kernel<<<dim3(DIMC / 128, LROWS / 128), 256>>>(
            attn, wo_i, lat, LROWS, DIMC, DIMC, nullptr, nullptr, lat, 0);
        // FFN
        ln_kernel<<<LROWS, 128>>>(lat, latn, ff_g + (size_t)i * DIMC, ff_b + (size_t)i * DIMC);
        gemm_kernel<<<dim3(FFD / 128, LROWS / 128), 256>>>(
            latn, w1_i, h1, LROWS, FFD, DIMC, nullptr, nullptr, nullptr, 1);
        gemm_kernel<<<dim3(DIMC / 128, LROWS / 128), 256>>>(
            h1, w2_i, lat, LROWS, DIMC, FFD, nullptr, nullptr, lat, 0);
    }
    // final LN -> output
    ln_kernel<<<LROWS, 128>>>(lat, out, fin_g, fin_b);
}

// round 2
// speedup vs baseline: 1.8806x; 1.8806x over previous
#include <cuda_runtime.h>
#include <cuda_bf16.h>
#include <math.h>
#include <stdint.h>

// ---------------- problem constants ----------------
#define DIMC   1024
#define DEPTHL 6
#define HEADS  16
#define DHEAD  64
#define NKV    2048
#define FFD    4096
#define BTOT   32                    // B*T = 4*8
#define MEDIA  1024                  // F*V media tokens per (b,t)
#define NMEDIA (BTOT*MEDIA)          // 32768
#define NLAT   64
#define LROWS  (BTOT*NLAT)           // 2048

// ---------------- scratch (static device globals; no allocs) ----------------
__device__ float g_xhat[NMEDIA*DIMC];
__device__ float g_kvm [(size_t)NMEDIA*NKV];
__device__ float g_lat [LROWS*DIMC];
__device__ float g_latn[LROWS*DIMC];
__device__ float g_q   [LROWS*DIMC];
__device__ float g_kvl [LROWS*NKV];
__device__ float g_attn[LROWS*DIMC];
__device__ float g_h1  [(size_t)LROWS*FFD];
__device__ float g_bias[NKV];

// ---------------- LayerNorm ----------------
__global__ void ln_kernel(const float* __restrict__ in, float* __restrict__ out,
                          const float* __restrict__ g, const float* __restrict__ b)
{
    const int row = blockIdx.x;
    const float* x = in + (size_t)row * DIMC;
    float s = 0.f, sq = 0.f;
    for (int c = threadIdx.x; c < DIMC; c += blockDim.x) {
        float v = x[c]; s += v; sq += v * v;
    }
    __shared__ float sh[64];
    #pragma unroll
    for (int o = 16; o > 0; o >>= 1) {
        s  += __shfl_down_sync(0xffffffffu, s,  o);
        sq += __shfl_down_sync(0xffffffffu, sq, o);
    }
    const int wid = threadIdx.x >> 5, lid = threadIdx.x & 31;
    if (lid == 0) { sh[wid] = s; sh[wid + 32] = sq; }
    __syncthreads();
    if (threadIdx.x == 0) {
        float ts = 0.f, tsq = 0.f;
        const int nw = blockDim.x >> 5;
        for (int i = 0; i < nw; i++) { ts += sh[i]; tsq += sh[i + 32]; }
        const float mean = ts * (1.0f / DIMC);
        const float var  = tsq * (1.0f / DIMC) - mean * mean;
        sh[0] = mean; sh[1] = rsqrtf(var + 1e-5f);
    }
    __syncthreads();
    const float mean = sh[0], rstd = sh[1];
    float* o = out + (size_t)row * DIMC;
    for (int c = threadIdx.x; c < DIMC; c += blockDim.x) {
        float v = (x[c] - mean) * rstd;
        if (g) v = v * g[c] + b[c];
        o[c] = v;
    }
}

// ---------------- bias row: c[n] = sum_k bvec[k] * W[k][n] ----------------
__global__ void bias_kernel(const float* __restrict__ bvec,
                            const float* __restrict__ W,
                            float* __restrict__ c)
{
    const int n = blockIdx.x * blockDim.x + threadIdx.x;
    float s = 0.f;
    for (int k = 0; k < DIMC; k++) s += bvec[k] * W[(size_t)k * NKV + n];
    c[n] = s;
}

__global__ void init_lat_kernel(const float* __restrict__ latents, float* __restrict__ lat)
{
    const int idx = blockIdx.x * blockDim.x + threadIdx.x;
    lat[idx] = latents[idx & (NLAT * DIMC - 1)];
}

// =====================================================================
// bf16x3 tensor-core GEMM: C = epi(A[M,K] @ B[K,N]) in ~fp32 precision.
// A,B fp32 in gmem; split into bf16 hi/lo planes at STS time.
// Block 128x128, 8 warps (2m x 4n), warp tile 64x32, K-chunk 32.
// =====================================================================
#define BMT 128
#define BNT 128
#define BKT 32
#define APITCH 80                     // bytes/row: 32 bf16 (64B) + 16 pad
#define BPITCH 272                    // bytes/row: 128 bf16 (256B) + 16 pad
#define A_PLANE (128*APITCH)          // 10240
#define B_PLANE (32*BPITCH)           // 8704
#define BUF_BYTES (2*A_PLANE + 2*B_PLANE)   // 37888
#define GEMM_SMEM (2*BUF_BYTES)             // 75776

__device__ __forceinline__ uint32_t b2u(__nv_bfloat162 h) {
    return *reinterpret_cast<uint32_t*>(&h);
}
__device__ __forceinline__ void ldmx4(uint32_t* r, uint32_t a) {
    asm volatile("ldmatrix.sync.aligned.m8n8.x4.shared.b16 {%0,%1,%2,%3}, [%4];"
                 : "=r"(r[0]), "=r"(r[1]), "=r"(r[2]), "=r"(r[3]) : "r"(a));
}
__device__ __forceinline__ void ldmx4t(uint32_t* r, uint32_t a) {
    asm volatile("ldmatrix.sync.aligned.m8n8.x4.trans.shared.b16 {%0,%1,%2,%3}, [%4];"
                 : "=r"(r[0]), "=r"(r[1]), "=r"(r[2]), "=r"(r[3]) : "r"(a));
}
__device__ __forceinline__ void mma16816(float* d, const uint32_t* a, const uint32_t* b) {
    asm volatile("mma.sync.aligned.m16n8k16.row.col.f32.bf16.bf16.f32 "
                 "{%0,%1,%2,%3},{%4,%5,%6,%7},{%8,%9},{%0,%1,%2,%3};"
                 : "+f"(d[0]), "+f"(d[1]), "+f"(d[2]), "+f"(d[3])
                 : "r"(a[0]), "r"(a[1]), "r"(a[2]), "r"(a[3]),
                   "r"(b[0]), "r"(b[1]));
}

__global__ void __launch_bounds__(256, 1)
gemm_kernel(const float* __restrict__ A, const float* __restrict__ B,
            float* __restrict__ C, int M, int N, int K,
            const float* __restrict__ kscale, const float* __restrict__ bias,
            const float* __restrict__ resid, int dogelu)
{
    extern __shared__ char smem[];
    const int tid  = threadIdx.x;
    const int lane = tid & 31;
    const int wid  = tid >> 5;
    const int wm   = wid & 1;          // 2 warp-rows of 64
    const int wn   = wid >> 1;         // 4 warp-cols of 32
    const int bm   = blockIdx.y * BMT;
    const int bn   = blockIdx.x * BNT;

    float acc[4][4][4];
    #pragma unroll
    for (int i = 0; i < 4; i++)
        #pragma unroll
        for (int j = 0; j < 4; j++)
            #pragma unroll
            for (int c = 0; c < 4; c++) acc[i][j][c] = 0.f;

    float4 rA[4], rB[4];
    const int nc = K / BKT;

    // per-thread gmem slot mapping (constant across chunks)
    const int arow = tid >> 3, akq = (tid & 7) << 2;     // +i*256: arow+32*i
    const int brow = tid >> 5, bnq = (tid & 31) << 2;    // +i*256: brow+8*i

    // ---- prologue: load chunk 0 ----
    #pragma unroll
    for (int i = 0; i < 4; i++)
        rA[i] = *reinterpret_cast<const float4*>(&A[(size_t)(bm + arow + 32 * i) * K + akq]);
    #pragma unroll
    for (int i = 0; i < 4; i++) {
        float4 v = *reinterpret_cast<const float4*>(&B[(size_t)(brow + 8 * i) * N + bn + bnq]);
        if (kscale) { const float sc = kscale[brow + 8 * i]; v.x *= sc; v.y *= sc; v.z *= sc; v.w *= sc; }
        rB[i] = v;
    }

    for (int c = 0; c < nc; c++) {
        // ---- STS: split fp32 -> bf16 hi/lo planes, buffer c&1 ----
        {
            char* base = smem + (c & 1) * BUF_BYTES;
            #pragma unroll
            for (int i = 0; i < 4; i++) {
                const float4 v = rA[i];
                __nv_bfloat162 h0 = __floats2bfloat162_rn(v.x, v.y);
                __nv_bfloat162 h1 = __floats2bfloat162_rn(v.z, v.w);
                __nv_bfloat162 l0 = __floats2bfloat162_rn(v.x - __low2float(h0), v.y - __high2float(h0));
                __nv_bfloat162 l1 = __floats2bfloat162_rn(v.z - __low2float(h1), v.w - __high2float(h1));
                const int off = (arow + 32 * i) * APITCH + akq * 2;
                *reinterpret_cast<uint2*>(base + off)           = make_uint2(b2u(h0), b2u(h1));
                *reinterpret_cast<uint2*>(base + A_PLANE + off) = make_uint2(b2u(l0), b2u(l1));
            }
            #pragma unroll
            for (int i = 0; i < 4; i++) {
                const float4 v = rB[i];
                __nv_bfloat162 h0 = __floats2bfloat162_rn(v.x, v.y);
                __nv_bfloat162 h1 = __floats2bfloat162_rn(v.z, v.w);
                __nv_bfloat162 l0 = __floats2bfloat162_rn(v.x - __low2float(h0), v.y - __high2float(h0));
                __nv_bfloat162 l1 = __floats2bfloat162_rn(v.z - __low2float(h1), v.w - __high2float(h1));
                const int off = (brow + 8 * i) * BPITCH + bnq * 2;
                char* bb = base + 2 * A_PLANE;
                *reinterpret_cast<uint2*>(bb + off)           = make_uint2(b2u(h0), b2u(h1));
                *reinterpret_cast<uint2*>(bb + B_PLANE + off) = make_uint2(b2u(l0), b2u(l1));
            }
        }
        __syncthreads();

        // ---- prefetch next chunk into regs (overlaps MMA) ----
        if (c + 1 < nc) {
            const int k0 = (c + 1) * BKT;
            #pragma unroll
            for (int i = 0; i < 4; i++)
                rA[i] = *reinterpret_cast<const float4*>(&A[(size_t)(bm + arow + 32 * i) * K + k0 + akq]);
            #pragma unroll
            for (int i = 0; i < 4; i++) {
                float4 v = *reinterpret_cast<const float4*>(&B[(size_t)(k0 + brow + 8 * i) * N + bn + bnq]);
                if (kscale) { const float sc = kscale[k0 + brow + 8 * i]; v.x *= sc; v.y *= sc; v.z *= sc; v.w *= sc; }
                rB[i] = v;
            }
        }

        // ---- MMA over the 2 k16 halves of this chunk ----
        {
            char* base = smem + (c & 1) * BUF_BYTES;
            const uint32_t sA = (uint32_t)__cvta_generic_to_shared(base);
            const uint32_t sB = sA + 2 * A_PLANE;
            #pragma unroll
            for (int s16 = 0; s16 < 2; s16++) {
                uint32_t aH[4][4], aL[4][4], bH[4][2], bL[4][2];
                #pragma unroll
                for (int mi = 0; mi < 4; mi++) {
                    const uint32_t addr = sA + (wm * 64 + mi * 16 + (lane & 15)) * APITCH
                                        + ((lane >> 4) * 16) + s16 * 32;
                    ldmx4(aH[mi], addr);
                    ldmx4(aL[mi], addr + A_PLANE);
                }
                #pragma unroll
                for (int ni = 0; ni < 2; ni++) {
                    const uint32_t addr = sB + (s16 * 16 + (lane & 15)) * BPITCH
                                        + (wn * 32 + ni * 16 + (lane >> 4) * 8) * 2;
                    uint32_t t[4];
                    ldmx4t(t, addr);
                    bH[ni * 2][0] = t[0]; bH[ni * 2][1] = t[1];
                    bH[ni * 2 + 1][0] = t[2]; bH[ni * 2 + 1][1] = t[3];
                    ldmx4t(t, addr + B_PLANE);
                    bL[ni * 2][0] = t[0]; bL[ni * 2][1] = t[1];
                    bL[ni * 2 + 1][0] = t[2]; bL[ni * 2 + 1][1] = t[3];
                }
                #pragma unroll
                for (int mi = 0; mi < 4; mi++)
                    #pragma unroll
                    for (int j = 0; j < 4; j++) {
                        mma16816(acc[mi][j], aH[mi], bH[j]);
                        mma16816(acc[mi][j], aH[mi], bL[j]);
                        mma16816(acc[mi][j], aL[mi], bH[j]);
                    }
            }
        }
        __syncthreads();
    }

    // ---- epilogue ----
    #pragma unroll
    for (int mi = 0; mi < 4; mi++) {
        #pragma unroll
        for (int j = 0; j < 4; j++) {
            const int col = bn + wn * 32 + j * 8 + (lane & 3) * 2;
            #pragma unroll
            for (int p = 0; p < 2; p++) {          // p=0: row, p=1: row+8
                const int row = bm + wm * 64 + mi * 16 + (lane >> 2) + 8 * p;
                #pragma unroll
                for (int q = 0; q < 2; q++) {
                    float v = acc[mi][j][p * 2 + q];
                    const int cc = col + q;
                    if (bias)   v += bias[cc];
                    if (dogelu) v = 0.5f * v * (1.f + erff(v * 0.70710678118654752f));
                    if (resid)  v += resid[(size_t)row * N + cc];
                    C[(size_t)row * N + cc] = v;
                }
            }
        }
    }
}

// ---------------- flash attention (unchanged from R1) ----------------
#define SPAD 65
__global__ void __launch_bounds__(256)
attn_kernel(const float* __restrict__ Q,
            const float* __restrict__ KVm,
            const float* __restrict__ KVl,
            float* __restrict__ O)
{
    extern __shared__ float sm[];
    float* Qs   = sm;
    float* Ks   = Qs + 64 * SPAD;
    float* Vs   = Ks + 64 * SPAD;
    float* Ss   = Vs + 64 * SPAD;
    float* mrow = Ss + 64 * SPAD;
    float* lrow = mrow + 64;
    float* frow = lrow + 64;

    const int bt  = blockIdx.x >> 4;
    const int h   = blockIdx.x & 15;
    const int tid = threadIdx.x;
    const int tx  = tid & 15, ty = tid >> 4;

    for (int idx = tid; idx < 64 * 64; idx += 256) {
        const int r = idx >> 6, d = idx & 63;
        Qs[r * SPAD + d] = Q[(size_t)(bt * 64 + r) * DIMC + h * 64 + d] * 0.125f;
    }
    if (tid < 64) { mrow[tid] = -INFINITY; lrow[tid] = 0.f; }
    float acc[4][4] = {};
    __syncthreads();

    for (int tile = 0; tile < 17; tile++) {
        for (int idx = tid; idx < 64 * 64; idx += 256) {
            const int r = idx >> 6, d = idx & 63;
            const float* KV;
            size_t base;
            if (tile < 16) { KV = KVm; base = (size_t)(bt * 1024 + tile * 64 + r) * NKV; }
            else           { KV = KVl; base = (size_t)(bt * 64 + r) * NKV; }
            Ks[r * SPAD + d] = KV[base + h * 64 + d];
            Vs[r * SPAD + d] = KV[base + 1024 + h * 64 + d];
        }
        __syncthreads();

        float s4[4][4] = {};
        for (int kk = 0; kk < 64; kk++) {
            float a[4], b[4];
            #pragma unroll
            for (int i = 0; i < 4; i++) a[i] = Qs[(ty * 4 + i) * SPAD + kk];
            #pragma unroll
            for (int j = 0; j < 4; j++) b[j] = Ks[(tx + 16 * j) * SPAD + kk];
            #pragma unroll
            for (int i = 0; i < 4; i++)
                #pragma unroll
                for (int j = 0; j < 4; j++)
                    s4[i][j] += a[i] * b[j];
        }
        #pragma unroll
        for (int i = 0; i < 4; i++)
            #pragma unroll
            for (int j = 0; j < 4; j++)
                Ss[(ty * 4 + i) * SPAD + tx + 16 * j] = s4[i][j];
        __syncthreads();

        if (tid < 64) {
            const int q = tid;
            const float mold = mrow[q];
            float tmax = -INFINITY;
            for (int k = 0; k < 64; k++) tmax = fmaxf(tmax, Ss[q * SPAD + k]);
            const float mnew = fmaxf(mold, tmax);
            const float fac = __expf(mold - mnew);
            float s = 0.f;
            for (int k = 0; k < 64; k++) {
                const float p = __expf(Ss[q * SPAD + k] - mnew);
                Ss[q * SPAD + k] = p;
                s += p;
            }
            lrow[q] = lrow[q] * fac + s;
            mrow[q] = mnew;
            frow[q] = fac;
        }
        __syncthreads();

        #pragma unroll
        for (int i = 0; i < 4; i++) {
            const float fac = frow[ty * 4 + i];
            #pragma unroll
            for (int j = 0; j < 4; j++) acc[i][j] *= fac;
        }
        for (int kk = 0; kk < 64; kk++) {
            float p[4], v[4];
            #pragma unroll
            for (int i = 0; i < 4; i++) p[i] = Ss[(ty * 4 + i) * SPAD + kk];
            #pragma unroll
            for (int j = 0; j < 4; j++) v[j] = Vs[kk * SPAD + tx + 16 * j];
            #pragma unroll
            for (int i = 0; i < 4; i++)
                #pragma unroll
                for (int j = 0; j < 4; j++)
                    acc[i][j] += p[i] * v[j];
        }
        __syncthreads();
    }

    #pragma unroll
    for (int i = 0; i < 4; i++) {
        const int q = ty * 4 + i;
        const float inv_l = 1.0f / lrow[q];
        #pragma unroll
        for (int j = 0; j < 4; j++) {
            const int d = tx + 16 * j;
            O[(size_t)(bt * 64 + q) * DIMC + h * 64 + d] = acc[i][j] * inv_l;
        }
    }
}

// ---------------- orchestration ----------------
extern "C" void kernel_launch(void* const* d_in, const int* in_sizes, int n_in,
                              void* d_out, int out_size)
{
    (void)in_sizes; (void)n_in; (void)out_size;
    const float* x       = (const float*)d_in[0];
    const float* latents = (const float*)d_in[1];
    const float* nm_g    = (const float*)d_in[2];
    const float* nm_b    = (const float*)d_in[3];
    const float* nl_g    = (const float*)d_in[4];
    const float* nl_b    = (const float*)d_in[5];
    const float* wq      = (const float*)d_in[6];
    const float* wkv     = (const float*)d_in[7];
    const float* wo      = (const float*)d_in[8];
    const float* ff_g    = (const float*)d_in[9];
    const float* ff_b    = (const float*)d_in[10];
    const float* w1      = (const float*)d_in[11];
    const float* w2      = (const float*)d_in[12];
    const float* fin_g   = (const float*)d_in[13];
    const float* fin_b   = (const float*)d_in[14];
    float* out = (float*)d_out;

    float *xhat, *kvm, *lat, *latn, *q, *kvl, *attn, *h1, *bias;
    cudaGetSymbolAddress((void**)&xhat, g_xhat);
    cudaGetSymbolAddress((void**)&kvm,  g_kvm);
    cudaGetSymbolAddress((void**)&lat,  g_lat);
    cudaGetSymbolAddress((void**)&latn, g_latn);
    cudaGetSymbolAddress((void**)&q,    g_q);
    cudaGetSymbolAddress((void**)&kvl,  g_kvl);
    cudaGetSymbolAddress((void**)&attn, g_attn);
    cudaGetSymbolAddress((void**)&h1,   g_h1);
    cudaGetSymbolAddress((void**)&bias, g_bias);

    cudaFuncSetAttribute(gemm_kernel, cudaFuncAttributeMaxDynamicSharedMemorySize, GEMM_SMEM);
    cudaFuncSetAttribute(attn_kernel, cudaFuncAttributeMaxDynamicSharedMemorySize, 69632);
    const int ATTN_SMEM = (4 * 64 * SPAD + 3 * 64) * (int)sizeof(float);

    ln_kernel<<<NMEDIA, 128>>>(x, xhat, nullptr, nullptr);
    init_lat_kernel<<<(LROWS * DIMC) / 256, 256>>>(latents, lat);

    for (int i = 0; i < DEPTHL; i++) {
        const float* wq_i  = wq  + (size_t)i * DIMC * DIMC;
        const float* wkv_i = wkv + (size_t)i * DIMC * NKV;
        const float* wo_i  = wo  + (size_t)i * DIMC * DIMC;
        const float* w1_i  = w1  + (size_t)i * DIMC * FFD;
        const float* w2_i  = w2  + (size_t)i * FFD  * DIMC;

        bias_kernel<<<NKV / 256, 256>>>(nm_b + (size_t)i * DIMC, wkv_i, bias);
        gemm_kernel<<<dim3(NKV / 128, NMEDIA / 128), 256, GEMM_SMEM>>>(
            xhat, wkv_i, kvm, NMEDIA, NKV, DIMC,
            nm_g + (size_t)i * DIMC, bias, nullptr, 0);
        ln_kernel<<<LROWS, 128>>>(lat, latn, nl_g + (size_t)i * DIMC, nl_b + (size_t)i * DIMC);
        gemm_kernel<<<dim3(DIMC / 128, LROWS / 128), 256, GEMM_SMEM>>>(
            latn, wq_i, q, LROWS, DIMC, DIMC, nullptr, nullptr, nullptr, 0);
        gemm_kernel<<<dim3(NKV / 128, LROWS / 128), 256, GEMM_SMEM>>>(
            latn, wkv_i, kvl, LROWS, NKV, DIMC, nullptr, nullptr, nullptr, 0);
        attn_kernel<<<BTOT * HEADS, 256, ATTN_SMEM>>>(q, kvm, kvl, attn);
        gemm_kernel<<<dim3(DIMC / 128, LROWS / 128), 256, GEMM_SMEM>>>(
            attn, wo_i, lat, LROWS, DIMC, DIMC, nullptr, nullptr, lat, 0);
        ln_kernel<<<LROWS, 128>>>(lat, latn, ff_g + (size_t)i * DIMC, ff_b + (size_t)i * DIMC);
        gemm_kernel<<<dim3(FFD / 128, LROWS / 128), 256, GEMM_SMEM>>>(
            latn, w1_i, h1, LROWS, FFD, DIMC, nullptr, nullptr, nullptr, 1);
        gemm_kernel<<<dim3(DIMC / 128, LROWS / 128), 256, GEMM_SMEM>>>(
            h1, w2_i, lat, LROWS, DIMC, FFD, nullptr, nullptr, lat, 0);
    }
    ln_kernel<<<LROWS, 128>>>(lat, out, fin_g, fin_b);
}

// round 4
// speedup vs baseline: 2.2595x; 1.2014x over previous
#include <cuda_runtime.h>
#include <cuda_bf16.h>
#include <math.h>
#include <stdint.h>

// ---------------- problem constants ----------------
#define DIMC   1024
#define DEPTHL 6
#define HEADS  16
#define DHEAD  64
#define NKV    2048
#define FFD    4096
#define BTOT   32
#define MEDIA  1024
#define NMEDIA (BTOT*MEDIA)          // 32768
#define NLAT   64
#define LROWS  (BTOT*NLAT)           // 2048

typedef __nv_bfloat16 bf16;

// ---------------- scratch (static device globals) ----------------
__device__ bf16  g_xh  [(size_t)NMEDIA*DIMC];   // xhat hi plane (no affine)
__device__ bf16  g_xl  [(size_t)NMEDIA*DIMC];   // xhat lo plane
__device__ float g_kvm [(size_t)NMEDIA*NKV];
__device__ float g_lat [LROWS*DIMC];
__device__ bf16  g_lnh [LROWS*DIMC];            // LN(lat) planes
__device__ bf16  g_lnl [LROWS*DIMC];
__device__ float g_q   [LROWS*DIMC];
__device__ float g_kvl [LROWS*NKV];
__device__ bf16  g_ath [LROWS*DIMC];            // attention out planes
__device__ bf16  g_atl [LROWS*DIMC];
__device__ bf16  g_h1h [(size_t)LROWS*FFD];     // gelu(h) planes
__device__ bf16  g_h1l [(size_t)LROWS*FFD];
__device__ float g_bias[NKV];

// pre-transposed, bf16-split weights: [N,K] K-major, hi & lo planes
__device__ bf16 g_wqTh [(size_t)DEPTHL*DIMC*DIMC];
__device__ bf16 g_wqTl [(size_t)DEPTHL*DIMC*DIMC];
__device__ bf16 g_wkvTh[(size_t)DEPTHL*NKV*DIMC];    // plain (for kv_lat)
__device__ bf16 g_wkvTl[(size_t)DEPTHL*NKV*DIMC];
__device__ bf16 g_wkvGh[(size_t)DEPTHL*NKV*DIMC];    // nm_g-folded (for kv_media)
__device__ bf16 g_wkvGl[(size_t)DEPTHL*NKV*DIMC];
__device__ bf16 g_woTh [(size_t)DEPTHL*DIMC*DIMC];
__device__ bf16 g_woTl [(size_t)DEPTHL*DIMC*DIMC];
__device__ bf16 g_w1Th [(size_t)DEPTHL*FFD*DIMC];
__device__ bf16 g_w1Tl [(size_t)DEPTHL*FFD*DIMC];
__device__ bf16 g_w2Th [(size_t)DEPTHL*DIMC*FFD];
__device__ bf16 g_w2Tl [(size_t)DEPTHL*DIMC*FFD];

// ---------------- helpers ----------------
__device__ __forceinline__ uint32_t smem_u32(const void* p) {
    return (uint32_t)__cvta_generic_to_shared(p);
}
__device__ __forceinline__ void cp_async16(uint32_t dst, const void* src) {
    asm volatile("cp.async.cg.shared.global [%0], [%1], 16;" :: "r"(dst), "l"(src));
}
#define CP_COMMIT() asm volatile("cp.async.commit_group;" ::: "memory")
#define CP_WAIT2()  asm volatile("cp.async.wait_group 2;" ::: "memory")

__device__ __forceinline__ void ldmx4(uint32_t* r, uint32_t a) {
    asm volatile("ldmatrix.sync.aligned.m8n8.x4.shared.b16 {%0,%1,%2,%3}, [%4];"
                 : "=r"(r[0]), "=r"(r[1]), "=r"(r[2]), "=r"(r[3]) : "r"(a));
}
__device__ __forceinline__ void mma16816(float* d, const uint32_t* a, const uint32_t* b) {
    asm volatile("mma.sync.aligned.m16n8k16.row.col.f32.bf16.bf16.f32 "
                 "{%0,%1,%2,%3},{%4,%5,%6,%7},{%8,%9},{%0,%1,%2,%3};"
                 : "+f"(d[0]), "+f"(d[1]), "+f"(d[2]), "+f"(d[3])
                 : "r"(a[0]), "r"(a[1]), "r"(a[2]), "r"(a[3]),
                   "r"(b[0]), "r"(b[1]));
}
__device__ __forceinline__ uint32_t bits(__nv_bfloat162 h) {
    return *reinterpret_cast<uint32_t*>(&h);
}

// ---------------- LayerNorm: fp32 in -> optional fp32 out + optional bf16 planes ----
__global__ void ln_kernel(const float* __restrict__ in,
                          float* __restrict__ outF,
                          bf16* __restrict__ outH, bf16* __restrict__ outL,
                          const float* __restrict__ g, const float* __restrict__ b)
{
    const int row = blockIdx.x;
    const float* x = in + (size_t)row * DIMC;
    float s = 0.f, sq = 0.f;
    for (int c = threadIdx.x; c < DIMC; c += blockDim.x) {
        float v = x[c]; s += v; sq += v * v;
    }
    __shared__ float sh[64];
    #pragma unroll
    for (int o = 16; o > 0; o >>= 1) {
        s  += __shfl_down_sync(0xffffffffu, s,  o);
        sq += __shfl_down_sync(0xffffffffu, sq, o);
    }
    const int wid = threadIdx.x >> 5, lid = threadIdx.x & 31;
    if (lid == 0) { sh[wid] = s; sh[wid + 32] = sq; }
    __syncthreads();
    if (threadIdx.x == 0) {
        float ts = 0.f, tsq = 0.f;
        const int nw = blockDim.x >> 5;
        for (int i = 0; i < nw; i++) { ts += sh[i]; tsq += sh[i + 32]; }
        const float mean = ts * (1.0f / DIMC);
        const float var  = tsq * (1.0f / DIMC) - mean * mean;
        sh[0] = mean; sh[1] = rsqrtf(var + 1e-5f);
    }
    __syncthreads();
    const float mean = sh[0], rstd = sh[1];
    for (int c = threadIdx.x; c < DIMC; c += blockDim.x) {
        float v = (x[c] - mean) * rstd;
        if (g) v = v * g[c] + b[c];
        if (outF) outF[(size_t)row * DIMC + c] = v;
        if (outH) {
            const bf16 h = __float2bfloat16_rn(v);
            outH[(size_t)row * DIMC + c] = h;
            outL[(size_t)row * DIMC + c] = __float2bfloat16_rn(v - __bfloat162float(h));
        }
    }
}

__global__ void bias_kernel(const float* __restrict__ bvec,
                            const float* __restrict__ W, float* __restrict__ c)
{
    const int n = blockIdx.x * blockDim.x + threadIdx.x;
    float s = 0.f;
    #pragma unroll 8
    for (int k = 0; k < DIMC; k++) s += bvec[k] * __ldg(&W[(size_t)k * NKV + n]);
    c[n] = s;
}

__global__ void init_lat_kernel(const float* __restrict__ latents, float* __restrict__ lat)
{
    const int idx = blockIdx.x * blockDim.x + threadIdx.x;
    lat[idx] = latents[idx & (NLAT * DIMC - 1)];
}

// ---------------- weight transpose + optional gamma + bf16 split ----------------
// W[K,N] fp32 -> Th/Tl[N,K] bf16 (optionally W[k][n]*g[k])
__global__ void wsplit_kernel(const float* __restrict__ W, const float* __restrict__ g,
                              bf16* __restrict__ Th, bf16* __restrict__ Tl, int K, int N)
{
    __shared__ float t[32][33];
    const int n0 = blockIdx.x * 32, k0 = blockIdx.y * 32;
    const int tx = threadIdx.x, ty = threadIdx.y;
    #pragma unroll
    for (int i = 0; i < 4; i++) {
        float v = W[(size_t)(k0 + ty + 8 * i) * N + n0 + tx];
        if (g) v *= g[k0 + ty + 8 * i];
        t[ty + 8 * i][tx] = v;
    }
    __syncthreads();
    #pragma unroll
    for (int i = 0; i < 4; i++) {
        const int n = n0 + ty + 8 * i, k = k0 + tx;
        const float v = t[tx][ty + 8 * i];
        const bf16 h = __float2bfloat16_rn(v);
        Th[(size_t)n * K + k] = h;
        Tl[(size_t)n * K + k] = __float2bfloat16_rn(v - __bfloat162float(h));
    }
}

// =====================================================================
// Pure-bf16 multistage HMMA GEMM (bf16x3): C = epi(A @ B^T)
// A planes [M,K] K-major, B planes [N,K] K-major. Block 128x128, 8 warps.
// cp.async 4-stage pipeline, K-chunk 32. Pad-pitch 80B smem rows.
// =====================================================================
#define NSTAGE 4
#define PITCH  80
#define PLANE  (128*PITCH)           // 10240
#define STAGE  (4*PLANE)             // 40960: Ah | Al | Bh | Bl
#define GEMM_SMEM (NSTAGE*STAGE)     // 163840

__global__ void __launch_bounds__(256, 1)
gemm_tc(const bf16* __restrict__ Ah, const bf16* __restrict__ Al,
        const bf16* __restrict__ Bh, const bf16* __restrict__ Bl,
        float* __restrict__ Cf, bf16* __restrict__ Ch, bf16* __restrict__ Cl,
        int M, int N, int K,
        const float* __restrict__ bias, const float* __restrict__ resid, int dogelu)
{
    extern __shared__ char smem[];
    const uint32_t sb = smem_u32(smem);
    const int tid  = threadIdx.x;
    const int lane = tid & 31;
    const int wid  = tid >> 5;
    const int wm   = wid & 1;          // 2 warp-rows of 64
    const int wn   = wid >> 1;         // 4 warp-cols of 32
    const int bm   = blockIdx.y * 128;
    const int bn   = blockIdx.x * 128;
    const int nc   = K >> 5;

    float acc[4][4][4];
    #pragma unroll
    for (int i = 0; i < 4; i++)
        #pragma unroll
        for (int j = 0; j < 4; j++)
            #pragma unroll
            for (int q = 0; q < 4; q++) acc[i][j][q] = 0.f;

    // ---- stage loader: 8 x 16B cp.async per thread ----
    auto load_stage = [&](int slot, int c) {
        const int k0 = c << 5;
        const uint32_t st = sb + slot * STAGE;
        #pragma unroll
        for (int i = 0; i < 8; i++) {
            const int idx   = tid + i * 256;
            const int part  = idx >> 10;            // 0:A 1:B (const per i)
            const int rest  = idx & 1023;
            const int plane = rest >> 9;            // const per i
            const int r     = (rest >> 2) & 127;
            const int c16   = rest & 3;
            const bf16* src = part == 0 ? (plane ? Al : Ah) : (plane ? Bl : Bh);
            const int rowg  = (part == 0 ? bm : bn) + r;
            cp_async16(st + part * (2 * PLANE) + plane * PLANE + r * PITCH + c16 * 16,
                       src + (size_t)rowg * K + k0 + c16 * 8);
        }
    };

    // ---- prologue ----
    #pragma unroll
    for (int s = 0; s < NSTAGE - 1; s++) { load_stage(s, s); CP_COMMIT(); }

    for (int c = 0; c < nc; c++) {
        CP_WAIT2();
        __syncthreads();
        if (c + NSTAGE - 1 < nc) load_stage((c + NSTAGE - 1) & (NSTAGE - 1), c + NSTAGE - 1);
        CP_COMMIT();

        const uint32_t st = sb + (c & (NSTAGE - 1)) * STAGE;
        #pragma unroll
        for (int s16 = 0; s16 < 2; s16++) {
            uint32_t aH[4][4], aL[4][4], bH[4][2], bL[4][2];
            #pragma unroll
            for (int mi = 0; mi < 4; mi++) {
                const uint32_t ad = st + (wm * 64 + mi * 16 + (lane & 15)) * PITCH
                                  + s16 * 32 + ((lane >> 4) << 4);
                ldmx4(aH[mi], ad);
                ldmx4(aL[mi], ad + PLANE);
            }
            #pragma unroll
            for (int ni = 0; ni < 2; ni++) {
                const uint32_t bd = st + 2 * PLANE
                                  + (wn * 32 + ni * 16 + (lane & 7) + ((lane >> 4) << 3)) * PITCH
                                  + s16 * 32 + (((lane >> 3) & 1) << 4);
                uint32_t t[4];
                ldmx4(t, bd);
                bH[ni * 2][0] = t[0]; bH[ni * 2][1] = t[1];
                bH[ni * 2 + 1][0] = t[2]; bH[ni * 2 + 1][1] = t[3];
                ldmx4(t, bd + PLANE);
                bL[ni * 2][0] = t[0]; bL[ni * 2][1] = t[1];
                bL[ni * 2 + 1][0] = t[2]; bL[ni * 2 + 1][1] = t[3];
            }
            #pragma unroll
            for (int mi = 0; mi < 4; mi++)
                #pragma unroll
                for (int j = 0; j < 4; j++) {
                    mma16816(acc[mi][j], aH[mi], bH[j]);
                    mma16816(acc[mi][j], aH[mi], bL[j]);
                    mma16816(acc[mi][j], aL[mi], bH[j]);
                }
        }
    }

    // ---- epilogue ----
    #pragma unroll
    for (int mi = 0; mi < 4; mi++) {
        #pragma unroll
        for (int j = 0; j < 4; j++) {
            const int colb = bn + wn * 32 + j * 8 + (lane & 3) * 2;
            #pragma unroll
            for (int p = 0; p < 2; p++) {
                const int row = bm + wm * 64 + mi * 16 + (lane >> 2) + 8 * p;
                float v0 = acc[mi][j][p * 2], v1 = acc[mi][j][p * 2 + 1];
                if (bias) { v0 += bias[colb]; v1 += bias[colb + 1]; }
                if (dogelu) {
                    v0 = 0.5f * v0 * (1.f + erff(v0 * 0.70710678118654752f));
                    v1 = 0.5f * v1 * (1.f + erff(v1 * 0.70710678118654752f));
                }
                if (resid) {
                    const float2 r = *reinterpret_cast<const float2*>(&resid[(size_t)row * N + colb]);
                    v0 += r.x; v1 += r.y;
                }
                if (Cf) *reinterpret_cast<float2*>(&Cf[(size_t)row * N + colb]) = make_float2(v0, v1);
                if (Ch) {
                    const __nv_bfloat162 h = __floats2bfloat162_rn(v0, v1);
                    const __nv_bfloat162 l = __floats2bfloat162_rn(v0 - __low2float(h),
                                                                   v1 - __high2float(h));
                    *reinterpret_cast<uint32_t*>(&Ch[(size_t)row * N + colb]) = bits(h);
                    *reinterpret_cast<uint32_t*>(&Cl[(size_t)row * N + colb]) = bits(l);
                }
            }
        }
    }
}

// ---------------- flash attention: fp32 in, bf16-plane out ----------------
#define SPAD 65
__global__ void __launch_bounds__(256)
attn_kernel(const float* __restrict__ Q,
            const float* __restrict__ KVm,
            const float* __restrict__ KVl,
            bf16* __restrict__ OH, bf16* __restrict__ OL)
{
    extern __shared__ float sm[];
    float* Qs   = sm;
    float* Ks   = Qs + 64 * SPAD;
    float* Vs   = Ks + 64 * SPAD;
    float* Ss   = Vs + 64 * SPAD;
    float* mrow = Ss + 64 * SPAD;
    float* lrow = mrow + 64;
    float* frow = lrow + 64;

    const int bt  = blockIdx.x >> 4;
    const int h   = blockIdx.x & 15;
    const int tid = threadIdx.x;
    const int tx  = tid & 15, ty = tid >> 4;

    for (int idx = tid; idx < 64 * 64; idx += 256) {
        const int r = idx >> 6, d = idx & 63;
        Qs[r * SPAD + d] = Q[(size_t)(bt * 64 + r) * DIMC + h * 64 + d] * 0.125f;
    }
    if (tid < 64) { mrow[tid] = -INFINITY; lrow[tid] = 0.f; }
    float acc[4][4] = {};
    __syncthreads();

    for (int tile = 0; tile < 17; tile++) {
        for (int idx = tid; idx < 64 * 64; idx += 256) {
            const int r = idx >> 6, d = idx & 63;
            const float* KV;
            size_t base;
            if (tile < 16) { KV = KVm; base = (size_t)(bt * 1024 + tile * 64 + r) * NKV; }
            else           { KV = KVl; base = (size_t)(bt * 64 + r) * NKV; }
            Ks[r * SPAD + d] = KV[base + h * 64 + d];
            Vs[r * SPAD + d] = KV[base + 1024 + h * 64 + d];
        }
        __syncthreads();

        float s4[4][4] = {};
        for (int kk = 0; kk < 64; kk++) {
            float a[4], b[4];
            #pragma unroll
            for (int i = 0; i < 4; i++) a[i] = Qs[(ty * 4 + i) * SPAD + kk];
            #pragma unroll
            for (int j = 0; j < 4; j++) b[j] = Ks[(tx + 16 * j) * SPAD + kk];
            #pragma unroll
            for (int i = 0; i < 4; i++)
                #pragma unroll
                for (int j = 0; j < 4; j++)
                    s4[i][j] += a[i] * b[j];
        }
        #pragma unroll
        for (int i = 0; i < 4; i++)
            #pragma unroll
            for (int j = 0; j < 4; j++)
                Ss[(ty * 4 + i) * SPAD + tx + 16 * j] = s4[i][j];
        __syncthreads();

        if (tid < 64) {
            const int q = tid;
            const float mold = mrow[q];
            float tmax = -INFINITY;
            for (int k = 0; k < 64; k++) tmax = fmaxf(tmax, Ss[q * SPAD + k]);
            const float mnew = fmaxf(mold, tmax);
            const float fac = __expf(mold - mnew);
            float s = 0.f;
            for (int k = 0; k < 64; k++) {
                const float p = __expf(Ss[q * SPAD + k] - mnew);
                Ss[q * SPAD + k] = p;
                s += p;
            }
            lrow[q] = lrow[q] * fac + s;
            mrow[q] = mnew;
            frow[q] = fac;
        }
        __syncthreads();

        #pragma unroll
        for (int i = 0; i < 4; i++) {
            const float fac = frow[ty * 4 + i];
            #pragma unroll
            for (int j = 0; j < 4; j++) acc[i][j] *= fac;
        }
        for (int kk = 0; kk < 64; kk++) {
            float p[4], v[4];
            #pragma unroll
            for (int i = 0; i < 4; i++) p[i] = Ss[(ty * 4 + i) * SPAD + kk];
            #pragma unroll
            for (int j = 0; j < 4; j++) v[j] = Vs[kk * SPAD + tx + 16 * j];
            #pragma unroll
            for (int i = 0; i < 4; i++)
                #pragma unroll
                for (int j = 0; j < 4; j++)
                    acc[i][j] += p[i] * v[j];
        }
        __syncthreads();
    }

    #pragma unroll
    for (int i = 0; i < 4; i++) {
        const int q = ty * 4 + i;
        const float inv_l = 1.0f / lrow[q];
        #pragma unroll
        for (int j = 0; j < 4; j++) {
            const int d = tx + 16 * j;
            const float v = acc[i][j] * inv_l;
            const bf16 hb = __float2bfloat16_rn(v);
            const size_t o = (size_t)(bt * 64 + q) * DIMC + h * 64 + d;
            OH[o] = hb;
            OL[o] = __float2bfloat16_rn(v - __bfloat162float(hb));
        }
    }
}

// ---------------- orchestration ----------------
extern "C" void kernel_launch(void* const* d_in, const int* in_sizes, int n_in,
                              void* d_out, int out_size)
{
    (void)in_sizes; (void)n_in; (void)out_size;
    const float* x       = (const float*)d_in[0];
    const float* latents = (const float*)d_in[1];
    const float* nm_g    = (const float*)d_in[2];
    const float* nm_b    = (const float*)d_in[3];
    const float* nl_g    = (const float*)d_in[4];
    const float* nl_b    = (const float*)d_in[5];
    const float* wq      = (const float*)d_in[6];
    const float* wkv     = (const float*)d_in[7];
    const float* wo      = (const float*)d_in[8];
    const float* ff_g    = (const float*)d_in[9];
    const float* ff_b    = (const float*)d_in[10];
    const float* w1      = (const float*)d_in[11];
    const float* w2      = (const float*)d_in[12];
    const float* fin_g   = (const float*)d_in[13];
    const float* fin_b   = (const float*)d_in[14];
    float* out = (float*)d_out;

    bf16 *xh, *xl, *lnh, *lnl, *ath, *atl, *h1h, *h1l;
    float *kvm, *lat, *q, *kvl, *bias;
    cudaGetSymbolAddress((void**)&xh,  g_xh);   cudaGetSymbolAddress((void**)&xl,  g_xl);
    cudaGetSymbolAddress((void**)&kvm, g_kvm);  cudaGetSymbolAddress((void**)&lat, g_lat);
    cudaGetSymbolAddress((void**)&lnh, g_lnh);  cudaGetSymbolAddress((void**)&lnl, g_lnl);
    cudaGetSymbolAddress((void**)&q,   g_q);    cudaGetSymbolAddress((void**)&kvl, g_kvl);
    cudaGetSymbolAddress((void**)&ath, g_ath);  cudaGetSymbolAddress((void**)&atl, g_atl);
    cudaGetSymbolAddress((void**)&h1h, g_h1h);  cudaGetSymbolAddress((void**)&h1l, g_h1l);
    cudaGetSymbolAddress((void**)&bias, g_bias);

    bf16 *wqTh, *wqTl, *wkvTh, *wkvTl, *wkvGh, *wkvGl, *woTh, *woTl, *w1Th, *w1Tl, *w2Th, *w2Tl;
    cudaGetSymbolAddress((void**)&wqTh,  g_wqTh);  cudaGetSymbolAddress((void**)&wqTl,  g_wqTl);
    cudaGetSymbolAddress((void**)&wkvTh, g_wkvTh); cudaGetSymbolAddress((void**)&wkvTl, g_wkvTl);
    cudaGetSymbolAddress((void**)&wkvGh, g_wkvGh); cudaGetSymbolAddress((void**)&wkvGl, g_wkvGl);
    cudaGetSymbolAddress((void**)&woTh,  g_woTh);  cudaGetSymbolAddress((void**)&woTl,  g_woTl);
    cudaGetSymbolAddress((void**)&w1Th,  g_w1Th);  cudaGetSymbolAddress((void**)&w1Tl,  g_w1Tl);
    cudaGetSymbolAddress((void**)&w2Th,  g_w2Th);  cudaGetSymbolAddress((void**)&w2Tl,  g_w2Tl);

    cudaFuncSetAttribute(gemm_tc,     cudaFuncAttributeMaxDynamicSharedMemorySize, GEMM_SMEM);
    cudaFuncSetAttribute(attn_kernel, cudaFuncAttributeMaxDynamicSharedMemorySize, 69632);
    const int ATTN_SMEM = (4 * 64 * SPAD + 3 * 64) * (int)sizeof(float);
    const dim3 tb(32, 8);

    // ---- weight prep ----
    for (int i = 0; i < DEPTHL; i++) {
        wsplit_kernel<<<dim3(DIMC/32, DIMC/32), tb>>>(wq + (size_t)i*DIMC*DIMC, nullptr,
            wqTh + (size_t)i*DIMC*DIMC, wqTl + (size_t)i*DIMC*DIMC, DIMC, DIMC);
        wsplit_kernel<<<dim3(NKV/32, DIMC/32), tb>>>(wkv + (size_t)i*DIMC*NKV, nullptr,
            wkvTh + (size_t)i*NKV*DIMC, wkvTl + (size_t)i*NKV*DIMC, DIMC, NKV);
        wsplit_kernel<<<dim3(NKV/32, DIMC/32), tb>>>(wkv + (size_t)i*DIMC*NKV, nm_g + (size_t)i*DIMC,
            wkvGh + (size_t)i*NKV*DIMC, wkvGl + (size_t)i*NKV*DIMC, DIMC, NKV);
        wsplit_kernel<<<dim3(DIMC/32, DIMC/32), tb>>>(wo + (size_t)i*DIMC*DIMC, nullptr,
            woTh + (size_t)i*DIMC*DIMC, woTl + (size_t)i*DIMC*DIMC, DIMC, DIMC);
        wsplit_kernel<<<dim3(FFD/32, DIMC/32), tb>>>(w1 + (size_t)i*DIMC*FFD, nullptr,
            w1Th + (size_t)i*FFD*DIMC, w1Tl + (size_t)i*FFD*DIMC, DIMC, FFD);
        wsplit_kernel<<<dim3(DIMC/32, FFD/32), tb>>>(w2 + (size_t)i*FFD*DIMC, nullptr,
            w2Th + (size_t)i*DIMC*FFD, w2Tl + (size_t)i*DIMC*FFD, FFD, DIMC);
    }

    // xhat planes (no affine; nm gamma folded into wkvG, beta via bias vector)
    ln_kernel<<<NMEDIA, 128>>>(x, nullptr, xh, xl, nullptr, nullptr);
    init_lat_kernel<<<(LROWS * DIMC) / 256, 256>>>(latents, lat);

    for (int i = 0; i < DEPTHL; i++) {
        bias_kernel<<<NKV / 256, 256>>>(nm_b + (size_t)i*DIMC, wkv + (size_t)i*DIMC*NKV, bias);
        // KV_media = LN_nm(x) @ wkv
        gemm_tc<<<dim3(NKV/128, NMEDIA/128), 256, GEMM_SMEM>>>(
            xh, xl, wkvGh + (size_t)i*NKV*DIMC, wkvGl + (size_t)i*NKV*DIMC,
            kvm, nullptr, nullptr, NMEDIA, NKV, DIMC, bias, nullptr, 0);
        // LN_nl(lat) planes
        ln_kernel<<<LROWS, 128>>>(lat, nullptr, lnh, lnl,
                                  nl_g + (size_t)i*DIMC, nl_b + (size_t)i*DIMC);
        // Q / KV_lat
        gemm_tc<<<dim3(DIMC/128, LROWS/128), 256, GEMM_SMEM>>>(
            lnh, lnl, wqTh + (size_t)i*DIMC*DIMC, wqTl + (size_t)i*DIMC*DIMC,
            q, nullptr, nullptr, LROWS, DIMC, DIMC, nullptr, nullptr, 0);
        gemm_tc<<<dim3(NKV/128, LROWS/128), 256, GEMM_SMEM>>>(
            lnh, lnl, wkvTh + (size_t)i*NKV*DIMC, wkvTl + (size_t)i*NKV*DIMC,
            kvl, nullptr, nullptr, LROWS, NKV, DIMC, nullptr, nullptr, 0);
        // attention -> planes
        attn_kernel<<<BTOT * HEADS, 256, ATTN_SMEM>>>(q, kvm, kvl, ath, atl);
        // lat += attn @ wo
        gemm_tc<<<dim3(DIMC/128, LROWS/128), 256, GEMM_SMEM>>>(
            ath, atl, woTh + (size_t)i*DIMC*DIMC, woTl + (size_t)i*DIMC*DIMC,
            lat, nullptr, nullptr, LROWS, DIMC, DIMC, nullptr, lat, 0);
        // FFN
        ln_kernel<<<LROWS, 128>>>(lat, nullptr, lnh, lnl,
                                  ff_g + (size_t)i*DIMC, ff_b + (size_t)i*DIMC);
        gemm_tc<<<dim3(FFD/128, LROWS/128), 256, GEMM_SMEM>>>(
            lnh, lnl, w1Th + (size_t)i*FFD*DIMC, w1Tl + (size_t)i*FFD*DIMC,
            nullptr, h1h, h1l, LROWS, FFD, DIMC, nullptr, nullptr, 1);
        gemm_tc<<<dim3(DIMC/128, LROWS/128), 256, GEMM_SMEM>>>(
            h1h, h1l, w2Th + (size_t)i*DIMC*FFD, w2Tl + (size_t)i*DIMC*FFD,
            lat, nullptr, nullptr, LROWS, DIMC, FFD, nullptr, lat, 0);
    }
    ln_kernel<<<LROWS, 128>>>(lat, out, nullptr, nullptr, fin_g, fin_b);
}

// round 5
// speedup vs baseline: 2.8249x; 1.2502x over previous
#include <cuda_runtime.h>
#include <cuda_bf16.h>
#include <math.h>
#include <stdint.h>

// ---------------- problem constants ----------------
#define DIMC   1024
#define DEPTHL 6
#define HEADS  16
#define DHEAD  64
#define NKV    2048
#define FFD    4096
#define BTOT   32
#define MEDIA  1024
#define NMEDIA (BTOT*MEDIA)          // 32768
#define NLAT   64
#define LROWS  (BTOT*NLAT)           // 2048

typedef __nv_bfloat16 bf16;

// ---------------- scratch (static device globals; bulk-copy sources => aligned) ----
__device__ __align__(1024) bf16  g_xh  [(size_t)NMEDIA*DIMC];
__device__ __align__(1024) bf16  g_xl  [(size_t)NMEDIA*DIMC];
__device__ float g_kvm [(size_t)NMEDIA*NKV];
__device__ float g_lat [LROWS*DIMC];
__device__ __align__(1024) bf16  g_lnh [LROWS*DIMC];
__device__ __align__(1024) bf16  g_lnl [LROWS*DIMC];
__device__ float g_q   [LROWS*DIMC];
__device__ float g_kvl [LROWS*NKV];
__device__ __align__(1024) bf16  g_ath [LROWS*DIMC];
__device__ __align__(1024) bf16  g_atl [LROWS*DIMC];
__device__ __align__(1024) bf16  g_h1h [(size_t)LROWS*FFD];
__device__ __align__(1024) bf16  g_h1l [(size_t)LROWS*FFD];
__device__ float g_bias[NKV];

// weight planes, chunk-tiled [K/32][N][32]
__device__ __align__(1024) bf16 g_wqTh [(size_t)DEPTHL*DIMC*DIMC];
__device__ __align__(1024) bf16 g_wqTl [(size_t)DEPTHL*DIMC*DIMC];
__device__ __align__(1024) bf16 g_wkvTh[(size_t)DEPTHL*NKV*DIMC];
__device__ __align__(1024) bf16 g_wkvTl[(size_t)DEPTHL*NKV*DIMC];
__device__ __align__(1024) bf16 g_wkvGh[(size_t)DEPTHL*NKV*DIMC];
__device__ __align__(1024) bf16 g_wkvGl[(size_t)DEPTHL*NKV*DIMC];
__device__ __align__(1024) bf16 g_woTh [(size_t)DEPTHL*DIMC*DIMC];
__device__ __align__(1024) bf16 g_woTl [(size_t)DEPTHL*DIMC*DIMC];
__device__ __align__(1024) bf16 g_w1Th [(size_t)DEPTHL*FFD*DIMC];
__device__ __align__(1024) bf16 g_w1Tl [(size_t)DEPTHL*FFD*DIMC];
__device__ __align__(1024) bf16 g_w2Th [(size_t)DEPTHL*DIMC*FFD];
__device__ __align__(1024) bf16 g_w2Tl [(size_t)DEPTHL*DIMC*FFD];

// ---------------- helpers ----------------
__device__ __forceinline__ uint32_t smem_u32(const void* p) {
    return (uint32_t)__cvta_generic_to_shared(p);
}
// chunk-tiled element index: plane[k/32][row][swizzled 32], quad swizzle for ldmatrix
__device__ __forceinline__ size_t tiled_idx(int row, int k, int nrows) {
    const int kc = k >> 5, kin = k & 31;
    const int q = kin >> 3, b = kin & 7;
    const int qs = q ^ ((row >> 1) & 3);
    return ((size_t)kc * nrows + row) * 32 + qs * 8 + b;
}
__device__ __forceinline__ void bulk_g2s(uint32_t dst, const void* src, uint32_t bytes, uint32_t mbar) {
    asm volatile("cp.async.bulk.shared::cluster.global.mbarrier::complete_tx::bytes [%0], [%1], %2, [%3];"
                 :: "r"(dst), "l"(src), "r"(bytes), "r"(mbar) : "memory");
}
#define MBARRIER_INIT(addr, cnt) \
    asm volatile("mbarrier.init.shared.b64 [%0], %1;" :: "r"(addr), "r"(cnt) : "memory")
#define MBARRIER_EXPECT_TX(addr, tx) \
    asm volatile("mbarrier.arrive.expect_tx.shared.b64 _, [%0], %1;" :: "r"(addr), "r"(tx) : "memory")
#define MBARRIER_WAIT_PARITY(addr, par) do { \
    uint32_t _m = (addr), _p = (par), _d; \
    asm volatile("{\n\t.reg .pred p;\n\t" \
        "mbarrier.try_wait.parity.acquire.cta.shared::cta.b64 p, [%1], %2;\n\t" \
        "selp.b32 %0, 1, 0, p;\n\t}" : "=r"(_d) : "r"(_m), "r"(_p) : "memory"); \
    if (!_d) { \
        asm volatile("{\n\t.reg .pred P1;\n\t" \
            "WL_%=:\n\t" \
            "mbarrier.try_wait.parity.acquire.cta.shared::cta.b64 P1, [%0], %1, 0x989680;\n\t" \
            "@P1 bra.uni WD_%=;\n\tbra.uni WL_%=;\n\tWD_%=:\n\t}" \
            :: "r"(_m), "r"(_p) : "memory"); \
    } } while (0)

__device__ __forceinline__ void ldmx4(uint32_t* r, uint32_t a) {
    asm volatile("ldmatrix.sync.aligned.m8n8.x4.shared.b16 {%0,%1,%2,%3}, [%4];"
                 : "=r"(r[0]), "=r"(r[1]), "=r"(r[2]), "=r"(r[3]) : "r"(a));
}
__device__ __forceinline__ void mma16816(float* d, const uint32_t* a, const uint32_t* b) {
    asm volatile("mma.sync.aligned.m16n8k16.row.col.f32.bf16.bf16.f32 "
                 "{%0,%1,%2,%3},{%4,%5,%6,%7},{%8,%9},{%0,%1,%2,%3};"
                 : "+f"(d[0]), "+f"(d[1]), "+f"(d[2]), "+f"(d[3])
                 : "r"(a[0]), "r"(a[1]), "r"(a[2]), "r"(a[3]),
                   "r"(b[0]), "r"(b[1]));
}
__device__ __forceinline__ uint32_t bits(__nv_bfloat162 h) {
    return *reinterpret_cast<uint32_t*>(&h);
}

// ---------------- LayerNorm: fp32 in -> fp32 out and/or tiled bf16 planes ---------
__global__ void ln_kernel(const float* __restrict__ in,
                          float* __restrict__ outF,
                          bf16* __restrict__ outH, bf16* __restrict__ outL,
                          const float* __restrict__ g, const float* __restrict__ b,
                          int nrows)
{
    const int row = blockIdx.x;
    const float* x = in + (size_t)row * DIMC;
    float s = 0.f, sq = 0.f;
    for (int c = threadIdx.x; c < DIMC; c += blockDim.x) {
        float v = x[c]; s += v; sq += v * v;
    }
    __shared__ float sh[64];
    #pragma unroll
    for (int o = 16; o > 0; o >>= 1) {
        s  += __shfl_down_sync(0xffffffffu, s,  o);
        sq += __shfl_down_sync(0xffffffffu, sq, o);
    }
    const int wid = threadIdx.x >> 5, lid = threadIdx.x & 31;
    if (lid == 0) { sh[wid] = s; sh[wid + 32] = sq; }
    __syncthreads();
    if (threadIdx.x == 0) {
        float ts = 0.f, tsq = 0.f;
        const int nw = blockDim.x >> 5;
        for (int i = 0; i < nw; i++) { ts += sh[i]; tsq += sh[i + 32]; }
        const float mean = ts * (1.0f / DIMC);
        const float var  = tsq * (1.0f / DIMC) - mean * mean;
        sh[0] = mean; sh[1] = rsqrtf(var + 1e-5f);
    }
    __syncthreads();
    const float mean = sh[0], rstd = sh[1];

    for (int k0 = threadIdx.x * 8; k0 < DIMC; k0 += blockDim.x * 8) {
        float v[8];
        #pragma unroll
        for (int e = 0; e < 8; e++) {
            float t = (x[k0 + e] - mean) * rstd;
            if (g) t = t * g[k0 + e] + b[k0 + e];
            v[e] = t;
        }
        if (outF) {
            float* o = outF + (size_t)row * DIMC + k0;
            #pragma unroll
            for (int e = 0; e < 8; e++) o[e] = v[e];
        }
        if (outH) {
            uint32_t hq[4], lq[4];
            #pragma unroll
            for (int e = 0; e < 4; e++) {
                const __nv_bfloat162 h = __floats2bfloat162_rn(v[2*e], v[2*e+1]);
                const __nv_bfloat162 l = __floats2bfloat162_rn(v[2*e]   - __low2float(h),
                                                               v[2*e+1] - __high2float(h));
                hq[e] = bits(h); lq[e] = bits(l);
            }
            const size_t ti = tiled_idx(row, k0, nrows);
            *reinterpret_cast<uint4*>(&outH[ti]) = make_uint4(hq[0], hq[1], hq[2], hq[3]);
            *reinterpret_cast<uint4*>(&outL[ti]) = make_uint4(lq[0], lq[1], lq[2], lq[3]);
        }
    }
}

__global__ void bias_kernel(const float* __restrict__ bvec,
                            const float* __restrict__ W, float* __restrict__ c)
{
    const int n = blockIdx.x * blockDim.x + threadIdx.x;
    float s = 0.f;
    #pragma unroll 8
    for (int k = 0; k < DIMC; k++) s += bvec[k] * __ldg(&W[(size_t)k * NKV + n]);
    c[n] = s;
}

__global__ void init_lat_kernel(const float* __restrict__ latents, float* __restrict__ lat)
{
    const int idx = blockIdx.x * blockDim.x + threadIdx.x;
    lat[idx] = latents[idx & (NLAT * DIMC - 1)];
}

// ---------------- weight transpose + gamma + bf16 split -> chunk-tiled [K/32][N][32] ----
__global__ void wsplit_kernel(const float* __restrict__ W, const float* __restrict__ g,
                              bf16* __restrict__ Th, bf16* __restrict__ Tl, int K, int N)
{
    __shared__ float t[32][33];
    const int n0 = blockIdx.x * 32, k0 = blockIdx.y * 32;
    const int tx = threadIdx.x, ty = threadIdx.y;
    #pragma unroll
    for (int i = 0; i < 4; i++) {
        float v = W[(size_t)(k0 + ty + 8 * i) * N + n0 + tx];
        if (g) v *= g[k0 + ty + 8 * i];
        t[ty + 8 * i][tx] = v;
    }
    __syncthreads();
    #pragma unroll
    for (int i = 0; i < 4; i++) {
        const int n = n0 + ty + 8 * i, k = k0 + tx;
        const float v = t[tx][ty + 8 * i];
        const bf16 h = __float2bfloat16_rn(v);
        const size_t ti = tiled_idx(n, k, N);
        Th[ti] = h;
        Tl[ti] = __float2bfloat16_rn(v - __bfloat162float(h));
    }
}

// =====================================================================
// bf16x3 HMMA GEMM with cp.async.bulk staged loads.
// Operands chunk-tiled [K/32][rows][32](swizzled). Block 128x128, 8 warps.
// =====================================================================
#define NSTG 4
#define STG_BYTES 32768            // Ah | Al | Bh | Bl, 8KB each
#define TILEOFF 1024
#define GEMM_SMEM (TILEOFF + NSTG*STG_BYTES)   // 132096

__global__ void __launch_bounds__(256, 1)
gemm_tc(const bf16* __restrict__ Ah, const bf16* __restrict__ Al,
        const bf16* __restrict__ Bh, const bf16* __restrict__ Bl,
        float* __restrict__ Cf, bf16* __restrict__ Ch, bf16* __restrict__ Cl,
        int M, int N, int K,
        const float* __restrict__ bias, const float* __restrict__ resid, int dogelu)
{
    extern __shared__ char smem[];
    const uint32_t sb = smem_u32(smem);
    const int tid  = threadIdx.x;
    const int lane = tid & 31;
    const int wid  = tid >> 5;
    const int wm   = wid & 1;
    const int wn   = wid >> 1;
    const int bm   = blockIdx.y * 128;
    const int bn   = blockIdx.x * 128;
    const int nc   = K >> 5;

    if (tid == 0) {
        #pragma unroll
        for (int s = 0; s < NSTG; s++) MBARRIER_INIT(sb + 8 * s, 1);
    }
    __syncthreads();

    float acc[4][4][4];
    #pragma unroll
    for (int i = 0; i < 4; i++)
        #pragma unroll
        for (int j = 0; j < 4; j++)
            #pragma unroll
            for (int q = 0; q < 4; q++) acc[i][j][q] = 0.f;

    auto issue = [&](int s, int c) {
        const uint32_t mb  = sb + 8 * s;
        const uint32_t dst = sb + TILEOFF + s * STG_BYTES;
        MBARRIER_EXPECT_TX(mb, 32768u);
        bulk_g2s(dst,         Ah + ((size_t)c * M + bm) * 32, 8192, mb);
        bulk_g2s(dst +  8192, Al + ((size_t)c * M + bm) * 32, 8192, mb);
        bulk_g2s(dst + 16384, Bh + ((size_t)c * N + bn) * 32, 8192, mb);
        bulk_g2s(dst + 24576, Bl + ((size_t)c * N + bn) * 32, 8192, mb);
    };
    if (tid == 0) {
        #pragma unroll
        for (int s = 0; s < NSTG; s++) issue(s, s);   // nc >= 32 always
    }

    for (int c = 0; c < nc; c++) {
        const int s = c & (NSTG - 1);
        MBARRIER_WAIT_PARITY(sb + 8 * s, (c >> 2) & 1);
        const uint32_t stA = sb + TILEOFF + s * STG_BYTES;
        const uint32_t stB = stA + 16384;

        #pragma unroll
        for (int s16 = 0; s16 < 2; s16++) {
            uint32_t aH[4][4], aL[4][4], bH[4][2], bL[4][2];
            #pragma unroll
            for (int mi = 0; mi < 4; mi++) {
                const int row = wm * 64 + mi * 16 + (lane & 15);
                const int q   = s16 * 2 + (lane >> 4);
                const uint32_t ad = stA + row * 64 + ((q ^ ((row >> 1) & 3)) << 4);
                ldmx4(aH[mi], ad);
                ldmx4(aL[mi], ad + 8192);
            }
            #pragma unroll
            for (int ni = 0; ni < 2; ni++) {
                const int row = wn * 32 + ni * 16 + (lane & 7) + ((lane >> 4) << 3);
                const int q   = s16 * 2 + ((lane >> 3) & 1);
                const uint32_t bd = stB + row * 64 + ((q ^ ((row >> 1) & 3)) << 4);
                uint32_t t[4];
                ldmx4(t, bd);
                bH[ni * 2][0] = t[0]; bH[ni * 2][1] = t[1];
                bH[ni * 2 + 1][0] = t[2]; bH[ni * 2 + 1][1] = t[3];
                ldmx4(t, bd + 8192);
                bL[ni * 2][0] = t[0]; bL[ni * 2][1] = t[1];
                bL[ni * 2 + 1][0] = t[2]; bL[ni * 2 + 1][1] = t[3];
            }
            #pragma unroll
            for (int mi = 0; mi < 4; mi++)
                #pragma unroll
                for (int j = 0; j < 4; j++) {
                    mma16816(acc[mi][j], aH[mi], bH[j]);
                    mma16816(acc[mi][j], aH[mi], bL[j]);
                    mma16816(acc[mi][j], aL[mi], bH[j]);
                }
        }
        __syncthreads();                 // all warps done with buffer s
        if (tid == 0 && c + NSTG < nc) issue(s, c + NSTG);
    }

    // ---- epilogue ----
    #pragma unroll
    for (int mi = 0; mi < 4; mi++) {
        #pragma unroll
        for (int j = 0; j < 4; j++) {
            const int colb = bn + wn * 32 + j * 8 + (lane & 3) * 2;
            #pragma unroll
            for (int p = 0; p < 2; p++) {
                const int row = bm + wm * 64 + mi * 16 + (lane >> 2) + 8 * p;
                float v0 = acc[mi][j][p * 2], v1 = acc[mi][j][p * 2 + 1];
                if (bias) { v0 += bias[colb]; v1 += bias[colb + 1]; }
                if (dogelu) {
                    v0 = 0.5f * v0 * (1.f + erff(v0 * 0.70710678118654752f));
                    v1 = 0.5f * v1 * (1.f + erff(v1 * 0.70710678118654752f));
                }
                if (resid) {
                    const float2 r = *reinterpret_cast<const float2*>(&resid[(size_t)row * N + colb]);
                    v0 += r.x; v1 += r.y;
                }
                if (Cf) *reinterpret_cast<float2*>(&Cf[(size_t)row * N + colb]) = make_float2(v0, v1);
                if (Ch) {
                    const __nv_bfloat162 h = __floats2bfloat162_rn(v0, v1);
                    const __nv_bfloat162 l = __floats2bfloat162_rn(v0 - __low2float(h),
                                                                   v1 - __high2float(h));
                    const size_t ti = tiled_idx(row, colb, M);  // pairs stay in-quad (colb%8 even)
                    *reinterpret_cast<uint32_t*>(&Ch[ti]) = bits(h);
                    *reinterpret_cast<uint32_t*>(&Cl[ti]) = bits(l);
                }
            }
        }
    }
}

// ---------------- flash attention: fp32 in, tiled bf16-plane out ----------------
#define SPAD 65
__global__ void __launch_bounds__(256)
attn_kernel(const float* __restrict__ Q,
            const float* __restrict__ KVm,
            const float* __restrict__ KVl,
            bf16* __restrict__ OH, bf16* __restrict__ OL)
{
    extern __shared__ float sm[];
    float* Qs   = sm;
    float* Ks   = Qs + 64 * SPAD;
    float* Vs   = Ks + 64 * SPAD;
    float* Ss   = Vs + 64 * SPAD;
    float* mrow = Ss + 64 * SPAD;
    float* lrow = mrow + 64;
    float* frow = lrow + 64;

    const int bt  = blockIdx.x >> 4;
    const int h   = blockIdx.x & 15;
    const int tid = threadIdx.x;
    const int tx  = tid & 15, ty = tid >> 4;

    for (int idx = tid; idx < 64 * 64; idx += 256) {
        const int r = idx >> 6, d = idx & 63;
        Qs[r * SPAD + d] = Q[(size_t)(bt * 64 + r) * DIMC + h * 64 + d] * 0.125f;
    }
    if (tid < 64) { mrow[tid] = -INFINITY; lrow[tid] = 0.f; }
    float acc[4][4] = {};
    __syncthreads();

    for (int tile = 0; tile < 17; tile++) {
        for (int idx = tid; idx < 64 * 64; idx += 256) {
            const int r = idx >> 6, d = idx & 63;
            const float* KV;
            size_t base;
            if (tile < 16) { KV = KVm; base = (size_t)(bt * 1024 + tile * 64 + r) * NKV; }
            else           { KV = KVl; base = (size_t)(bt * 64 + r) * NKV; }
            Ks[r * SPAD + d] = KV[base + h * 64 + d];
            Vs[r * SPAD + d] = KV[base + 1024 + h * 64 + d];
        }
        __syncthreads();

        float s4[4][4] = {};
        for (int kk = 0; kk < 64; kk++) {
            float a[4], b[4];
            #pragma unroll
            for (int i = 0; i < 4; i++) a[i] = Qs[(ty * 4 + i) * SPAD + kk];
            #pragma unroll
            for (int j = 0; j < 4; j++) b[j] = Ks[(tx + 16 * j) * SPAD + kk];
            #pragma unroll
            for (int i = 0; i < 4; i++)
                #pragma unroll
                for (int j = 0; j < 4; j++)
                    s4[i][j] += a[i] * b[j];
        }
        #pragma unroll
        for (int i = 0; i < 4; i++)
            #pragma unroll
            for (int j = 0; j < 4; j++)
                Ss[(ty * 4 + i) * SPAD + tx + 16 * j] = s4[i][j];
        __syncthreads();

        // online softmax: 4 threads per row (r = tid>>2, quarter = tid&3)
        {
            const int r = tid >> 2, qd = tid & 3;
            const int kb = qd * 16;
            float tmax = -INFINITY;
            #pragma unroll
            for (int k = 0; k < 16; k++) tmax = fmaxf(tmax, Ss[r * SPAD + kb + k]);
            tmax = fmaxf(tmax, __shfl_xor_sync(0xffffffffu, tmax, 1));
            tmax = fmaxf(tmax, __shfl_xor_sync(0xffffffffu, tmax, 2));
            const float mold = mrow[r];
            const float mnew = fmaxf(mold, tmax);
            float s = 0.f;
            #pragma unroll
            for (int k = 0; k < 16; k++) {
                const float p = __expf(Ss[r * SPAD + kb + k] - mnew);
                Ss[r * SPAD + kb + k] = p;
                s += p;
            }
            s += __shfl_xor_sync(0xffffffffu, s, 1);
            s += __shfl_xor_sync(0xffffffffu, s, 2);
            if (qd == 0) {
                const float fac = __expf(mold - mnew);
                lrow[r] = lrow[r] * fac + s;
                mrow[r] = mnew;
                frow[r] = fac;
            }
        }
        __syncthreads();

        #pragma unroll
        for (int i = 0; i < 4; i++) {
            const float fac = frow[ty * 4 + i];
            #pragma unroll
            for (int j = 0; j < 4; j++) acc[i][j] *= fac;
        }
        for (int kk = 0; kk < 64; kk++) {
            float p[4], v[4];
            #pragma unroll
            for (int i = 0; i < 4; i++) p[i] = Ss[(ty * 4 + i) * SPAD + kk];
            #pragma unroll
            for (int j = 0; j < 4; j++) v[j] = Vs[kk * SPAD + tx + 16 * j];
            #pragma unroll
            for (int i = 0; i < 4; i++)
                #pragma unroll
                for (int j = 0; j < 4; j++)
                    acc[i][j] += p[i] * v[j];
        }
        __syncthreads();
    }

    #pragma unroll
    for (int i = 0; i < 4; i++) {
        const int q = ty * 4 + i;
        const float inv_l = 1.0f / lrow[q];
        #pragma unroll
        for (int j = 0; j < 4; j++) {
            const int d = tx + 16 * j;
            const float v = acc[i][j] * inv_l;
            const bf16 hb = __float2bfloat16_rn(v);
            const size_t ti = tiled_idx(bt * 64 + q, h * 64 + d, LROWS);
            OH[ti] = hb;
            OL[ti] = __float2bfloat16_rn(v - __bfloat162float(hb));
        }
    }
}

// ---------------- orchestration ----------------
extern "C" void kernel_launch(void* const* d_in, const int* in_sizes, int n_in,
                              void* d_out, int out_size)
{
    (void)in_sizes; (void)n_in; (void)out_size;
    const float* x       = (const float*)d_in[0];
    const float* latents = (const float*)d_in[1];
    const float* nm_g    = (const float*)d_in[2];
    const float* nm_b    = (const float*)d_in[3];
    const float* nl_g    = (const float*)d_in[4];
    const float* nl_b    = (const float*)d_in[5];
    const float* wq      = (const float*)d_in[6];
    const float* wkv     = (const float*)d_in[7];
    const float* wo      = (const float*)d_in[8];
    const float* ff_g    = (const float*)d_in[9];
    const float* ff_b    = (const float*)d_in[10];
    const float* w1      = (const float*)d_in[11];
    const float* w2      = (const float*)d_in[12];
    const float* fin_g   = (const float*)d_in[13];
    const float* fin_b   = (const float*)d_in[14];
    float* out = (float*)d_out;

    bf16 *xh, *xl, *lnh, *lnl, *ath, *atl, *h1h, *h1l;
    float *kvm, *lat, *q, *kvl, *bias;
    cudaGetSymbolAddress((void**)&xh,  g_xh);   cudaGetSymbolAddress((void**)&xl,  g_xl);
    cudaGetSymbolAddress((void**)&kvm, g_kvm);  cudaGetSymbolAddress((void**)&lat, g_lat);
    cudaGetSymbolAddress((void**)&lnh, g_lnh);  cudaGetSymbolAddress((void**)&lnl, g_lnl);
    cudaGetSymbolAddress((void**)&q,   g_q);    cudaGetSymbolAddress((void**)&kvl, g_kvl);
    cudaGetSymbolAddress((void**)&ath, g_ath);  cudaGetSymbolAddress((void**)&atl, g_atl);
    cudaGetSymbolAddress((void**)&h1h, g_h1h);  cudaGetSymbolAddress((void**)&h1l, g_h1l);
    cudaGetSymbolAddress((void**)&bias, g_bias);

    bf16 *wqTh, *wqTl, *wkvTh, *wkvTl, *wkvGh, *wkvGl, *woTh, *woTl, *w1Th, *w1Tl, *w2Th, *w2Tl;
    cudaGetSymbolAddress((void**)&wqTh,  g_wqTh);  cudaGetSymbolAddress((void**)&wqTl,  g_wqTl);
    cudaGetSymbolAddress((void**)&wkvTh, g_wkvTh); cudaGetSymbolAddress((void**)&wkvTl, g_wkvTl);
    cudaGetSymbolAddress((void**)&wkvGh, g_wkvGh); cudaGetSymbolAddress((void**)&wkvGl, g_wkvGl);
    cudaGetSymbolAddress((void**)&woTh,  g_woTh);  cudaGetSymbolAddress((void**)&woTl,  g_woTl);
    cudaGetSymbolAddress((void**)&w1Th,  g_w1Th);  cudaGetSymbolAddress((void**)&w1Tl,  g_w1Tl);
    cudaGetSymbolAddress((void**)&w2Th,  g_w2Th);  cudaGetSymbolAddress((void**)&w2Tl,  g_w2Tl);

    cudaFuncSetAttribute(gemm_tc,     cudaFuncAttributeMaxDynamicSharedMemorySize, GEMM_SMEM);
    cudaFuncSetAttribute(attn_kernel, cudaFuncAttributeMaxDynamicSharedMemorySize, 69632);
    const int ATTN_SMEM = (4 * 64 * SPAD + 3 * 64) * (int)sizeof(float);
    const dim3 tb(32, 8);

    // ---- weight prep (chunk-tiled planes) ----
    for (int i = 0; i < DEPTHL; i++) {
        wsplit_kernel<<<dim3(DIMC/32, DIMC/32), tb>>>(wq + (size_t)i*DIMC*DIMC, nullptr,
            wqTh + (size_t)i*DIMC*DIMC, wqTl + (size_t)i*DIMC*DIMC, DIMC, DIMC);
        wsplit_kernel<<<dim3(NKV/32, DIMC/32), tb>>>(wkv + (size_t)i*DIMC*NKV, nullptr,
            wkvTh + (size_t)i*NKV*DIMC, wkvTl + (size_t)i*NKV*DIMC, DIMC, NKV);
        wsplit_kernel<<<dim3(NKV/32, DIMC/32), tb>>>(wkv + (size_t)i*DIMC*NKV, nm_g + (size_t)i*DIMC,
            wkvGh + (size_t)i*NKV*DIMC, wkvGl + (size_t)i*NKV*DIMC, DIMC, NKV);
        wsplit_kernel<<<dim3(DIMC/32, DIMC/32), tb>>>(wo + (size_t)i*DIMC*DIMC, nullptr,
            woTh + (size_t)i*DIMC*DIMC, woTl + (size_t)i*DIMC*DIMC, DIMC, DIMC);
        wsplit_kernel<<<dim3(FFD/32, DIMC/32), tb>>>(w1 + (size_t)i*DIMC*FFD, nullptr,
            w1Th + (size_t)i*FFD*DIMC, w1Tl + (size_t)i*FFD*DIMC, DIMC, FFD);
        wsplit_kernel<<<dim3(DIMC/32, FFD/32), tb>>>(w2 + (size_t)i*FFD*DIMC, nullptr,
            w2Th + (size_t)i*DIMC*FFD, w2Tl + (size_t)i*DIMC*FFD, FFD, DIMC);
    }

    ln_kernel<<<NMEDIA, 128>>>(x, nullptr, xh, xl, nullptr, nullptr, NMEDIA);
    init_lat_kernel<<<(LROWS * DIMC) / 256, 256>>>(latents, lat);

    for (int i = 0; i < DEPTHL; i++) {
        bias_kernel<<<NKV / 256, 256>>>(nm_b + (size_t)i*DIMC, wkv + (size_t)i*DIMC*NKV, bias);
        gemm_tc<<<dim3(NKV/128, NMEDIA/128), 256, GEMM_SMEM>>>(
            xh, xl, wkvGh + (size_t)i*NKV*DIMC, wkvGl + (size_t)i*NKV*DIMC,
            kvm, nullptr, nullptr, NMEDIA, NKV, DIMC, bias, nullptr, 0);
        ln_kernel<<<LROWS, 128>>>(lat, nullptr, lnh, lnl,
                                  nl_g + (size_t)i*DIMC, nl_b + (size_t)i*DIMC, LROWS);
        gemm_tc<<<dim3(DIMC/128, LROWS/128), 256, GEMM_SMEM>>>(
            lnh, lnl, wqTh + (size_t)i*DIMC*DIMC, wqTl + (size_t)i*DIMC*DIMC,
            q, nullptr, nullptr, LROWS, DIMC, DIMC, nullptr, nullptr, 0);
        gemm_tc<<<dim3(NKV/128, LROWS/128), 256, GEMM_SMEM>>>(
            lnh, lnl, wkvTh + (size_t)i*NKV*DIMC, wkvTl + (size_t)i*NKV*DIMC,
            kvl, nullptr, nullptr, LROWS, NKV, DIMC, nullptr, nullptr, 0);
        attn_kernel<<<BTOT * HEADS, 256, ATTN_SMEM>>>(q, kvm, kvl, ath, atl);
        gemm_tc<<<dim3(DIMC/128, LROWS/128), 256, GEMM_SMEM>>>(
            ath, atl, woTh + (size_t)i*DIMC*DIMC, woTl + (size_t)i*DIMC*DIMC,
            lat, nullptr, nullptr, LROWS, DIMC, DIMC, nullptr, lat, 0);
        ln_kernel<<<LROWS, 128>>>(lat, nullptr, lnh, lnl,
                                  ff_g + (size_t)i*DIMC, ff_b + (size_t)i*DIMC, LROWS);
        gemm_tc<<<dim3(FFD/128, LROWS/128), 256, GEMM_SMEM>>>(
            lnh, lnl, w1Th + (size_t)i*FFD*DIMC, w1Tl + (size_t)i*FFD*DIMC,
            nullptr, h1h, h1l, LROWS, FFD, DIMC, nullptr, nullptr, 1);
        gemm_tc<<<dim3(DIMC/128, LROWS/128), 256, GEMM_SMEM>>>(
            h1h, h1l, w2Th + (size_t)i*DIMC*FFD, w2Tl + (size_t)i*DIMC*FFD,
            lat, nullptr, nullptr, LROWS, DIMC, FFD, nullptr, lat, 0);
    }
    ln_kernel<<<LROWS, 128>>>(lat, out, nullptr, nullptr, fin_g, fin_b, LROWS);
}

// round 6
// speedup vs baseline: 3.2273x; 1.1425x over previous
#include <cuda_runtime.h>
#include <cuda_bf16.h>
#include <math.h>
#include <stdint.h>

// ---------------- problem constants ----------------
#define DIMC   1024
#define DEPTHL 6
#define HEADS  16
#define DHEAD  64
#define NKV    2048
#define FFD    4096
#define BTOT   32
#define MEDIA  1024
#define NMEDIA (BTOT*MEDIA)          // 32768
#define NLAT   64
#define LROWS  (BTOT*NLAT)           // 2048

typedef __nv_bfloat16 bf16;

// ---------------- scratch ----------------
__device__ __align__(1024) bf16  g_xh  [(size_t)NMEDIA*DIMC];
__device__ __align__(1024) bf16  g_xl  [(size_t)NMEDIA*DIMC];
__device__ __align__(1024) bf16  g_kvmh[(size_t)NMEDIA*NKV];   // media K|V hi plane (tiled)
__device__ __align__(1024) bf16  g_kvml[(size_t)NMEDIA*NKV];
__device__ float g_lat [LROWS*DIMC];
__device__ __align__(1024) bf16  g_lnh [LROWS*DIMC];
__device__ __align__(1024) bf16  g_lnl [LROWS*DIMC];
__device__ __align__(1024) bf16  g_qh  [LROWS*DIMC];
__device__ __align__(1024) bf16  g_ql  [LROWS*DIMC];
__device__ __align__(1024) bf16  g_kvlh[LROWS*NKV];
__device__ __align__(1024) bf16  g_kvll[LROWS*NKV];
__device__ __align__(1024) bf16  g_ath [LROWS*DIMC];
__device__ __align__(1024) bf16  g_atl [LROWS*DIMC];
__device__ __align__(1024) bf16  g_h1h [(size_t)LROWS*FFD];
__device__ __align__(1024) bf16  g_h1l [(size_t)LROWS*FFD];
__device__ float g_bias[DEPTHL*NKV];

// weight planes, chunk-tiled [K/32][N][32]
__device__ __align__(1024) bf16 g_wqTh [(size_t)DEPTHL*DIMC*DIMC];
__device__ __align__(1024) bf16 g_wqTl [(size_t)DEPTHL*DIMC*DIMC];
__device__ __align__(1024) bf16 g_wkvTh[(size_t)DEPTHL*NKV*DIMC];
__device__ __align__(1024) bf16 g_wkvTl[(size_t)DEPTHL*NKV*DIMC];
__device__ __align__(1024) bf16 g_wkvGh[(size_t)DEPTHL*NKV*DIMC];
__device__ __align__(1024) bf16 g_wkvGl[(size_t)DEPTHL*NKV*DIMC];
__device__ __align__(1024) bf16 g_woTh [(size_t)DEPTHL*DIMC*DIMC];
__device__ __align__(1024) bf16 g_woTl [(size_t)DEPTHL*DIMC*DIMC];
__device__ __align__(1024) bf16 g_w1Th [(size_t)DEPTHL*FFD*DIMC];
__device__ __align__(1024) bf16 g_w1Tl [(size_t)DEPTHL*FFD*DIMC];
__device__ __align__(1024) bf16 g_w2Th [(size_t)DEPTHL*DIMC*FFD];
__device__ __align__(1024) bf16 g_w2Tl [(size_t)DEPTHL*DIMC*FFD];

// ---------------- helpers ----------------
__device__ __forceinline__ uint32_t smem_u32(const void* p) {
    return (uint32_t)__cvta_generic_to_shared(p);
}
__device__ __forceinline__ size_t tiled_idx(int row, int k, int nrows) {
    const int kc = k >> 5, kin = k & 31;
    const int q = kin >> 3, b = kin & 7;
    const int qs = q ^ ((row >> 1) & 3);
    return ((size_t)kc * nrows + row) * 32 + qs * 8 + b;
}
__device__ __forceinline__ void bulk_g2s(uint32_t dst, const void* src, uint32_t bytes, uint32_t mbar) {
    asm volatile("cp.async.bulk.shared::cluster.global.mbarrier::complete_tx::bytes [%0], [%1], %2, [%3];"
                 :: "r"(dst), "l"(src), "r"(bytes), "r"(mbar) : "memory");
}
#define MBARRIER_INIT(addr, cnt) \
    asm volatile("mbarrier.init.shared.b64 [%0], %1;" :: "r"(addr), "r"(cnt) : "memory")
#define MBARRIER_EXPECT_TX(addr, tx) \
    asm volatile("mbarrier.arrive.expect_tx.shared.b64 _, [%0], %1;" :: "r"(addr), "r"(tx) : "memory")
#define MBARRIER_WAIT_PARITY(addr, par) do { \
    uint32_t _m = (addr), _p = (par), _d; \
    asm volatile("{\n\t.reg .pred p;\n\t" \
        "mbarrier.try_wait.parity.acquire.cta.shared::cta.b64 p, [%1], %2;\n\t" \
        "selp.b32 %0, 1, 0, p;\n\t}" : "=r"(_d) : "r"(_m), "r"(_p) : "memory"); \
    if (!_d) { \
        asm volatile("{\n\t.reg .pred P1;\n\t" \
            "WL_%=:\n\t" \
            "mbarrier.try_wait.parity.acquire.cta.shared::cta.b64 P1, [%0], %1, 0x989680;\n\t" \
            "@P1 bra.uni WD_%=;\n\tbra.uni WL_%=;\n\tWD_%=:\n\t}" \
            :: "r"(_m), "r"(_p) : "memory"); \
    } } while (0)

__device__ __forceinline__ void ldmx4(uint32_t* r, uint32_t a) {
    asm volatile("ldmatrix.sync.aligned.m8n8.x4.shared.b16 {%0,%1,%2,%3}, [%4];"
                 : "=r"(r[0]), "=r"(r[1]), "=r"(r[2]), "=r"(r[3]) : "r"(a));
}
__device__ __forceinline__ void ldmx4t(uint32_t* r, uint32_t a) {
    asm volatile("ldmatrix.sync.aligned.m8n8.x4.trans.shared.b16 {%0,%1,%2,%3}, [%4];"
                 : "=r"(r[0]), "=r"(r[1]), "=r"(r[2]), "=r"(r[3]) : "r"(a));
}
__device__ __forceinline__ void mma16816(float* d, const uint32_t* a, const uint32_t* b) {
    asm volatile("mma.sync.aligned.m16n8k16.row.col.f32.bf16.bf16.f32 "
                 "{%0,%1,%2,%3},{%4,%5,%6,%7},{%8,%9},{%0,%1,%2,%3};"
                 : "+f"(d[0]), "+f"(d[1]), "+f"(d[2]), "+f"(d[3])
                 : "r"(a[0]), "r"(a[1]), "r"(a[2]), "r"(a[3]),
                   "r"(b[0]), "r"(b[1]));
}
__device__ __forceinline__ uint32_t bits(__nv_bfloat162 h) {
    return *reinterpret_cast<uint32_t*>(&h);
}

// ---------------- LayerNorm ----------------
__global__ void ln_kernel(const float* __restrict__ in,
                          float* __restrict__ outF,
                          bf16* __restrict__ outH, bf16* __restrict__ outL,
                          const float* __restrict__ g, const float* __restrict__ b,
                          int nrows)
{
    const int row = blockIdx.x;
    const float* x = in + (size_t)row * DIMC;
    float s = 0.f, sq = 0.f;
    for (int c = threadIdx.x; c < DIMC; c += blockDim.x) {
        float v = x[c]; s += v; sq += v * v;
    }
    __shared__ float sh[64];
    #pragma unroll
    for (int o = 16; o > 0; o >>= 1) {
        s  += __shfl_down_sync(0xffffffffu, s,  o);
        sq += __shfl_down_sync(0xffffffffu, sq, o);
    }
    const int wid = threadIdx.x >> 5, lid = threadIdx.x & 31;
    if (lid == 0) { sh[wid] = s; sh[wid + 32] = sq; }
    __syncthreads();
    if (threadIdx.x == 0) {
        float ts = 0.f, tsq = 0.f;
        const int nw = blockDim.x >> 5;
        for (int i = 0; i < nw; i++) { ts += sh[i]; tsq += sh[i + 32]; }
        const float mean = ts * (1.0f / DIMC);
        const float var  = tsq * (1.0f / DIMC) - mean * mean;
        sh[0] = mean; sh[1] = rsqrtf(var + 1e-5f);
    }
    __syncthreads();
    const float mean = sh[0], rstd = sh[1];

    for (int k0 = threadIdx.x * 8; k0 < DIMC; k0 += blockDim.x * 8) {
        float v[8];
        #pragma unroll
        for (int e = 0; e < 8; e++) {
            float t = (x[k0 + e] - mean) * rstd;
            if (g) t = t * g[k0 + e] + b[k0 + e];
            v[e] = t;
        }
        if (outF) {
            float* o = outF + (size_t)row * DIMC + k0;
            #pragma unroll
            for (int e = 0; e < 8; e++) o[e] = v[e];
        }
        if (outH) {
            uint32_t hq[4], lq[4];
            #pragma unroll
            for (int e = 0; e < 4; e++) {
                const __nv_bfloat162 h = __floats2bfloat162_rn(v[2*e], v[2*e+1]);
                const __nv_bfloat162 l = __floats2bfloat162_rn(v[2*e]   - __low2float(h),
                                                               v[2*e+1] - __high2float(h));
                hq[e] = bits(h); lq[e] = bits(l);
            }
            const size_t ti = tiled_idx(row, k0, nrows);
            *reinterpret_cast<uint4*>(&outH[ti]) = make_uint4(hq[0], hq[1], hq[2], hq[3]);
            *reinterpret_cast<uint4*>(&outL[ti]) = make_uint4(lq[0], lq[1], lq[2], lq[3]);
        }
    }
}

// ---------------- bias: all layers, k-parallel ----------------
__global__ void bias_kernel(const float* __restrict__ nm_b,
                            const float* __restrict__ wkv, float* __restrict__ out)
{
    const int layer = blockIdx.y;
    const int tid = threadIdx.x;
    const int n  = blockIdx.x * 32 + (tid & 31);
    const int ks = tid >> 5;
    const float* bv = nm_b + (size_t)layer * DIMC;
    const float* W  = wkv  + (size_t)layer * DIMC * NKV;
    float s = 0.f;
    #pragma unroll 4
    for (int k = ks * 128; k < ks * 128 + 128; k++)
        s += bv[k] * __ldg(&W[(size_t)k * NKV + n]);
    __shared__ float red[8][32];
    red[ks][tid & 31] = s;
    __syncthreads();
    if (ks == 0) {
        float t = 0.f;
        #pragma unroll
        for (int i = 0; i < 8; i++) t += red[i][tid & 31];
        out[(size_t)layer * NKV + n] = t;
    }
}

__global__ void init_lat_kernel(const float* __restrict__ latents, float* __restrict__ lat)
{
    const int idx = blockIdx.x * blockDim.x + threadIdx.x;
    lat[idx] = latents[idx & (NLAT * DIMC - 1)];
}

// ---------------- weight transpose + gamma + split, batched over depth ----------------
__global__ void wsplit_kernel(const float* __restrict__ W0, const float* __restrict__ g0,
                              bf16* __restrict__ Th0, bf16* __restrict__ Tl0, int K, int N)
{
    const size_t loff = (size_t)blockIdx.z * K * N;
    const float* W = W0 + loff;
    const float* g = g0 ? g0 + (size_t)blockIdx.z * K : nullptr;
    bf16* Th = Th0 + loff;
    bf16* Tl = Tl0 + loff;
    __shared__ float t[32][33];
    const int n0 = blockIdx.x * 32, k0 = blockIdx.y * 32;
    const int tx = threadIdx.x, ty = threadIdx.y;
    #pragma unroll
    for (int i = 0; i < 4; i++) {
        float v = W[(size_t)(k0 + ty + 8 * i) * N + n0 + tx];
        if (g) v *= g[k0 + ty + 8 * i];
        t[ty + 8 * i][tx] = v;
    }
    __syncthreads();
    #pragma unroll
    for (int i = 0; i < 4; i++) {
        const int n = n0 + ty + 8 * i, k = k0 + tx;
        const float v = t[tx][ty + 8 * i];
        const bf16 h = __float2bfloat16_rn(v);
        const size_t ti = tiled_idx(n, k, N);
        Th[ti] = h;
        Tl[ti] = __float2bfloat16_rn(v - __bfloat162float(h));
    }
}

// =====================================================================
// bf16x3 HMMA GEMM (unchanged mainloop from R5)
// =====================================================================
#define NSTG 4
#define STG_BYTES 32768
#define TILEOFF 1024
#define GEMM_SMEM (TILEOFF + NSTG*STG_BYTES)

__global__ void __launch_bounds__(256, 1)
gemm_tc(const bf16* __restrict__ Ah, const bf16* __restrict__ Al,
        const bf16* __restrict__ Bh, const bf16* __restrict__ Bl,
        float* __restrict__ Cf, bf16* __restrict__ Ch, bf16* __restrict__ Cl,
        int M, int N, int K,
        const float* __restrict__ bias, const float* __restrict__ resid, int dogelu)
{
    extern __shared__ char smem[];
    const uint32_t sb = smem_u32(smem);
    const int tid  = threadIdx.x;
    const int lane = tid & 31;
    const int wid  = tid >> 5;
    const int wm   = wid & 1;
    const int wn   = wid >> 1;
    const int bm   = blockIdx.y * 128;
    const int bn   = blockIdx.x * 128;
    const int nc   = K >> 5;

    if (tid == 0) {
        #pragma unroll
        for (int s = 0; s < NSTG; s++) MBARRIER_INIT(sb + 8 * s, 1);
    }
    __syncthreads();

    float acc[4][4][4];
    #pragma unroll
    for (int i = 0; i < 4; i++)
        #pragma unroll
        for (int j = 0; j < 4; j++)
            #pragma unroll
            for (int q = 0; q < 4; q++) acc[i][j][q] = 0.f;

    auto issue = [&](int s, int c) {
        const uint32_t mb  = sb + 8 * s;
        const uint32_t dst = sb + TILEOFF + s * STG_BYTES;
        MBARRIER_EXPECT_TX(mb, 32768u);
        bulk_g2s(dst,         Ah + ((size_t)c * M + bm) * 32, 8192, mb);
        bulk_g2s(dst +  8192, Al + ((size_t)c * M + bm) * 32, 8192, mb);
        bulk_g2s(dst + 16384, Bh + ((size_t)c * N + bn) * 32, 8192, mb);
        bulk_g2s(dst + 24576, Bl + ((size_t)c * N + bn) * 32, 8192, mb);
    };
    if (tid == 0) {
        #pragma unroll
        for (int s = 0; s < NSTG; s++) issue(s, s);
    }

    for (int c = 0; c < nc; c++) {
        const int s = c & (NSTG - 1);
        MBARRIER_WAIT_PARITY(sb + 8 * s, (c >> 2) & 1);
        const uint32_t stA = sb + TILEOFF + s * STG_BYTES;
        const uint32_t stB = stA + 16384;

        #pragma unroll
        for (int s16 = 0; s16 < 2; s16++) {
            uint32_t aH[4][4], aL[4][4], bH[4][2], bL[4][2];
            #pragma unroll
            for (int mi = 0; mi < 4; mi++) {
                const int row = wm * 64 + mi * 16 + (lane & 15);
                const int q   = s16 * 2 + (lane >> 4);
                const uint32_t ad = stA + row * 64 + ((q ^ ((row >> 1) & 3)) << 4);
                ldmx4(aH[mi], ad);
                ldmx4(aL[mi], ad + 8192);
            }
            #pragma unroll
            for (int ni = 0; ni < 2; ni++) {
                const int row = wn * 32 + ni * 16 + (lane & 7) + ((lane >> 4) << 3);
                const int q   = s16 * 2 + ((lane >> 3) & 1);
                const uint32_t bd = stB + row * 64 + ((q ^ ((row >> 1) & 3)) << 4);
                uint32_t t[4];
                ldmx4(t, bd);
                bH[ni * 2][0] = t[0]; bH[ni * 2][1] = t[1];
                bH[ni * 2 + 1][0] = t[2]; bH[ni * 2 + 1][1] = t[3];
                ldmx4(t, bd + 8192);
                bL[ni * 2][0] = t[0]; bL[ni * 2][1] = t[1];
                bL[ni * 2 + 1][0] = t[2]; bL[ni * 2 + 1][1] = t[3];
            }
            #pragma unroll
            for (int mi = 0; mi < 4; mi++)
                #pragma unroll
                for (int j = 0; j < 4; j++) {
                    mma16816(acc[mi][j], aH[mi], bH[j]);
                    mma16816(acc[mi][j], aH[mi], bL[j]);
                    mma16816(acc[mi][j], aL[mi], bH[j]);
                }
        }
        __syncthreads();
        if (tid == 0 && c + NSTG < nc) issue(s, c + NSTG);
    }

    #pragma unroll
    for (int mi = 0; mi < 4; mi++) {
        #pragma unroll
        for (int j = 0; j < 4; j++) {
            const int colb = bn + wn * 32 + j * 8 + (lane & 3) * 2;
            #pragma unroll
            for (int p = 0; p < 2; p++) {
                const int row = bm + wm * 64 + mi * 16 + (lane >> 2) + 8 * p;
                float v0 = acc[mi][j][p * 2], v1 = acc[mi][j][p * 2 + 1];
                if (bias) { v0 += bias[colb]; v1 += bias[colb + 1]; }
                if (dogelu) {
                    v0 = 0.5f * v0 * (1.f + erff(v0 * 0.70710678118654752f));
                    v1 = 0.5f * v1 * (1.f + erff(v1 * 0.70710678118654752f));
                }
                if (resid) {
                    const float2 r = *reinterpret_cast<const float2*>(&resid[(size_t)row * N + colb]);
                    v0 += r.x; v1 += r.y;
                }
                if (Cf) *reinterpret_cast<float2*>(&Cf[(size_t)row * N + colb]) = make_float2(v0, v1);
                if (Ch) {
                    const __nv_bfloat162 h = __floats2bfloat162_rn(v0, v1);
                    const __nv_bfloat162 l = __floats2bfloat162_rn(v0 - __low2float(h),
                                                                   v1 - __high2float(h));
                    const size_t ti = tiled_idx(row, colb, M);
                    *reinterpret_cast<uint32_t*>(&Ch[ti]) = bits(h);
                    *reinterpret_cast<uint32_t*>(&Cl[ti]) = bits(l);
                }
            }
        }
    }
}

// =====================================================================
// Tensor-core flash attention (bf16x3), all operands chunk-tiled planes.
// Block = one (bt, head), 256 threads / 8 warps (wm = q-half, wn = 16-col strip).
// =====================================================================
#define OFF_Q   1024
#define OFF_KV  (OFF_Q + 16384)          // 2 stages x 32768
#define OFF_P   (OFF_KV + 65536)
#define OFF_SS  (OFF_P + 16384)
#define OFF_ST  (OFF_SS + 64*65*4)
#define ATT_SMEM (OFF_ST + 768)

__global__ void __launch_bounds__(256, 1)
attn_tc(const bf16* __restrict__ Qh, const bf16* __restrict__ Ql,
        const bf16* __restrict__ Kmh, const bf16* __restrict__ Kml,
        const bf16* __restrict__ Klh, const bf16* __restrict__ Kll,
        bf16* __restrict__ OH, bf16* __restrict__ OL)
{
    extern __shared__ char smem[];
    const uint32_t sb = smem_u32(smem);
    const int bt  = blockIdx.x >> 4;
    const int h   = blockIdx.x & 15;
    const int tid = threadIdx.x;
    const int lane = tid & 31;
    const int wid  = tid >> 5;
    const int wm   = wid & 1;
    const int wn   = wid >> 1;
    float* Ss    = reinterpret_cast<float*>(smem + OFF_SS);
    float* mrow  = reinterpret_cast<float*>(smem + OFF_ST);
    float* lrow  = mrow + 64;
    float* frow  = lrow + 64;

    if (tid == 0) { MBARRIER_INIT(sb, 1); MBARRIER_INIT(sb + 8, 1); }

    // ---- Q tile copy: 4 contiguous 4KB segments (Qh kc0,kc1 ; Ql kc0,kc1) ----
    {
        #pragma unroll
        for (int seg = 0; seg < 4; seg++) {
            const bf16* src = (seg < 2 ? Qh : Ql) + ((size_t)(2 * h + (seg & 1)) * LROWS + bt * 64) * 32;
            const uint4 v = reinterpret_cast<const uint4*>(src)[tid];
            *reinterpret_cast<uint4*>(smem + OFF_Q + (seg >= 2 ? 8192 : 0) + (seg & 1) * 4096 + tid * 16) = v;
        }
    }
    if (tid < 64) { mrow[tid] = -INFINITY; lrow[tid] = 0.f; }
    __syncthreads();

    auto issueKV = [&](int t) {
        const int st = t & 1;
        const uint32_t mb = sb + 8 * st;
        const uint32_t dst = sb + OFF_KV + st * 32768;
        MBARRIER_EXPECT_TX(mb, 32768u);
        const bf16 *PH, *PL; size_t rbase, nr;
        if (t < 16) { PH = Kmh; PL = Kml; rbase = (size_t)bt * 1024 + t * 64; nr = NMEDIA; }
        else        { PH = Klh; PL = Kll; rbase = (size_t)bt * 64;            nr = LROWS; }
        const int kcK = 2 * h, kcV = 32 + 2 * h;
        bulk_g2s(dst,          PH + ((size_t)kcK * nr + rbase) * 32,       4096, mb);
        bulk_g2s(dst +  4096,  PH + ((size_t)(kcK + 1) * nr + rbase) * 32, 4096, mb);
        bulk_g2s(dst +  8192,  PL + ((size_t)kcK * nr + rbase) * 32,       4096, mb);
        bulk_g2s(dst + 12288,  PL + ((size_t)(kcK + 1) * nr + rbase) * 32, 4096, mb);
        bulk_g2s(dst + 16384,  PH + ((size_t)kcV * nr + rbase) * 32,       4096, mb);
        bulk_g2s(dst + 20480,  PH + ((size_t)(kcV + 1) * nr + rbase) * 32, 4096, mb);
        bulk_g2s(dst + 24576,  PL + ((size_t)kcV * nr + rbase) * 32,       4096, mb);
        bulk_g2s(dst + 28672,  PL + ((size_t)(kcV + 1) * nr + rbase) * 32, 4096, mb);
    };
    if (tid == 0) issueKV(0);

    // ---- Q fragments (held in registers) ----
    uint32_t qH[2][4][4], qL[2][4][4];
    #pragma unroll
    for (int mi = 0; mi < 2; mi++)
        #pragma unroll
        for (int s = 0; s < 4; s++) {
            const int row = wm * 32 + mi * 16 + (lane & 15);
            const int qq = (((s & 1) * 2 + (lane >> 4)) ^ ((row >> 1) & 3));
            const uint32_t ad = sb + OFF_Q + (s >> 1) * 4096 + row * 64 + (qq << 4);
            ldmx4(qH[mi][s], ad);
            ldmx4(qL[mi][s], ad + 8192);
        }

    float acc[2][2][4];
    #pragma unroll
    for (int i = 0; i < 2; i++)
        #pragma unroll
        for (int j = 0; j < 2; j++)
            #pragma unroll
            for (int q = 0; q < 4; q++) acc[i][j][q] = 0.f;

    for (int t = 0; t < 17; t++) {
        if (tid == 0 && t + 1 < 17) issueKV(t + 1);
        MBARRIER_WAIT_PARITY(sb + 8 * (t & 1), (t >> 1) & 1);
        const uint32_t kb = sb + OFF_KV + (t & 1) * 32768;

        // ---- sim = Q @ K^T (bf16x3) ----
        float sc[2][2][4] = {};
        #pragma unroll
        for (int s = 0; s < 4; s++) {
            const int row = wn * 16 + (lane & 7) + ((lane >> 4) << 3);
            const int qq = (((s & 1) * 2 + ((lane >> 3) & 1)) ^ ((row >> 1) & 3));
            const uint32_t ad = kb + (s >> 1) * 4096 + row * 64 + (qq << 4);
            uint32_t tH[4], tL[4];
            ldmx4(tH, ad); ldmx4(tL, ad + 8192);
            uint32_t bh0[2] = {tH[0], tH[1]}, bh1[2] = {tH[2], tH[3]};
            uint32_t bl0[2] = {tL[0], tL[1]}, bl1[2] = {tL[2], tL[3]};
            #pragma unroll
            for (int mi = 0; mi < 2; mi++) {
                mma16816(sc[mi][0], qH[mi][s], bh0);
                mma16816(sc[mi][0], qH[mi][s], bl0);
                mma16816(sc[mi][0], qL[mi][s], bh0);
                mma16816(sc[mi][1], qH[mi][s], bh1);
                mma16816(sc[mi][1], qH[mi][s], bl1);
                mma16816(sc[mi][1], qL[mi][s], bh1);
            }
        }
        #pragma unroll
        for (int mi = 0; mi < 2; mi++)
            #pragma unroll
            for (int j = 0; j < 2; j++)
                #pragma unroll
                for (int p = 0; p < 2; p++) {
                    const int r = wm * 32 + mi * 16 + (lane >> 2) + 8 * p;
                    const int col = wn * 16 + j * 8 + (lane & 3) * 2;
                    Ss[r * 65 + col]     = sc[mi][j][p * 2]     * 0.125f;
                    Ss[r * 65 + col + 1] = sc[mi][j][p * 2 + 1] * 0.125f;
                }
        __syncthreads();

        // ---- online softmax (4 threads per row) ----
        {
            const int r = tid >> 2, qd = tid & 3;
            const int kb2 = qd * 16;
            float tmax = -INFINITY;
            #pragma unroll
            for (int k = 0; k < 16; k++) tmax = fmaxf(tmax, Ss[r * 65 + kb2 + k]);
            tmax = fmaxf(tmax, __shfl_xor_sync(0xffffffffu, tmax, 1));
            tmax = fmaxf(tmax, __shfl_xor_sync(0xffffffffu, tmax, 2));
            const float mold = mrow[r];
            const float mnew = fmaxf(mold, tmax);
            float s = 0.f;
            #pragma unroll
            for (int k = 0; k < 16; k++) {
                const float p = __expf(Ss[r * 65 + kb2 + k] - mnew);
                Ss[r * 65 + kb2 + k] = p;
                s += p;
            }
            s += __shfl_xor_sync(0xffffffffu, s, 1);
            s += __shfl_xor_sync(0xffffffffu, s, 2);
            if (qd == 0) {
                const float fac = __expf(mold - mnew);
                lrow[r] = lrow[r] * fac + s;
                mrow[r] = mnew;
                frow[r] = fac;
            }
        }
        __syncthreads();

        // ---- rescale acc, write P planes (bf16 split, chunk-tiled in smem) ----
        #pragma unroll
        for (int mi = 0; mi < 2; mi++)
            #pragma unroll
            for (int p = 0; p < 2; p++) {
                const float fac = frow[wm * 32 + mi * 16 + (lane >> 2) + 8 * p];
                #pragma unroll
                for (int j = 0; j < 2; j++) {
                    acc[mi][j][p * 2]     *= fac;
                    acc[mi][j][p * 2 + 1] *= fac;
                }
            }
        #pragma unroll
        for (int i = 0; i < 8; i++) {
            const int pi = tid * 8 + i;
            const int q = pi >> 5, kp = pi & 31, k = kp * 2;
            const int kc = k >> 5, kin = k & 31;
            const int qq = ((kin >> 3) ^ ((q >> 1) & 3));
            const int off = OFF_P + kc * 4096 + q * 64 + (qq << 4) + (kin & 7) * 2;
            const float v0 = Ss[q * 65 + k], v1 = Ss[q * 65 + k + 1];
            const __nv_bfloat162 hh = __floats2bfloat162_rn(v0, v1);
            const __nv_bfloat162 ll = __floats2bfloat162_rn(v0 - __low2float(hh),
                                                            v1 - __high2float(hh));
            *reinterpret_cast<uint32_t*>(smem + off)        = bits(hh);
            *reinterpret_cast<uint32_t*>(smem + off + 8192) = bits(ll);
        }
        __syncthreads();

        // ---- out += P @ V (bf16x3) ----
        #pragma unroll
        for (int s = 0; s < 4; s++) {
            uint32_t pH[2][4], pL[2][4];
            #pragma unroll
            for (int mi = 0; mi < 2; mi++) {
                const int row = wm * 32 + mi * 16 + (lane & 15);
                const int qq = (((s & 1) * 2 + (lane >> 4)) ^ ((row >> 1) & 3));
                const uint32_t ad = sb + OFF_P + (s >> 1) * 4096 + row * 64 + (qq << 4);
                ldmx4(pH[mi], ad);
                ldmx4(pL[mi], ad + 8192);
            }
            const int key  = s * 16 + (lane & 15);
            const int dinb = wn * 16 + ((lane >> 4) << 3);
            const int kcv  = dinb >> 5, din = dinb & 31;
            const int qq   = ((din >> 3) ^ ((key >> 1) & 3));
            const uint32_t ad = kb + 16384 + kcv * 4096 + key * 64 + (qq << 4);
            uint32_t tH[4], tL[4];
            ldmx4t(tH, ad); ldmx4t(tL, ad + 8192);
            uint32_t vh0[2] = {tH[0], tH[1]}, vh1[2] = {tH[2], tH[3]};
            uint32_t vl0[2] = {tL[0], tL[1]}, vl1[2] = {tL[2], tL[3]};
            #pragma unroll
            for (int mi = 0; mi < 2; mi++) {
                mma16816(acc[mi][0], pH[mi], vh0);
                mma16816(acc[mi][0], pH[mi], vl0);
                mma16816(acc[mi][0], pL[mi], vh0);
                mma16816(acc[mi][1], pH[mi], vh1);
                mma16816(acc[mi][1], pH[mi], vl1);
                mma16816(acc[mi][1], pL[mi], vh1);
            }
        }
        __syncthreads();
    }

    // ---- finalize: /lrow, split, tiled store ----
    #pragma unroll
    for (int mi = 0; mi < 2; mi++)
        #pragma unroll
        for (int p = 0; p < 2; p++) {
            const int r = wm * 32 + mi * 16 + (lane >> 2) + 8 * p;
            const float inv = 1.0f / lrow[r];
            #pragma unroll
            for (int j = 0; j < 2; j++) {
                const int col = h * 64 + wn * 16 + j * 8 + (lane & 3) * 2;
                const float v0 = acc[mi][j][p * 2] * inv;
                const float v1 = acc[mi][j][p * 2 + 1] * inv;
                const __nv_bfloat162 hh = __floats2bfloat162_rn(v0, v1);
                const __nv_bfloat162 ll = __floats2bfloat162_rn(v0 - __low2float(hh),
                                                                v1 - __high2float(hh));
                const size_t ti = tiled_idx(bt * 64 + r, col, LROWS);
                *reinterpret_cast<uint32_t*>(&OH[ti]) = bits(hh);
                *reinterpret_cast<uint32_t*>(&OL[ti]) = bits(ll);
            }
        }
}

// ---------------- orchestration ----------------
extern "C" void kernel_launch(void* const* d_in, const int* in_sizes, int n_in,
                              void* d_out, int out_size)
{
    (void)in_sizes; (void)n_in; (void)out_size;
    const float* x       = (const float*)d_in[0];
    const float* latents = (const float*)d_in[1];
    const float* nm_g    = (const float*)d_in[2];
    const float* nm_b    = (const float*)d_in[3];
    const float* nl_g    = (const float*)d_in[4];
    const float* nl_b    = (const float*)d_in[5];
    const float* wq      = (const float*)d_in[6];
    const float* wkv     = (const float*)d_in[7];
    const float* wo      = (const float*)d_in[8];
    const float* ff_g    = (const float*)d_in[9];
    const float* ff_b    = (const float*)d_in[10];
    const float* w1      = (const float*)d_in[11];
    const float* w2      = (const float*)d_in[12];
    const float* fin_g   = (const float*)d_in[13];
    const float* fin_b   = (const float*)d_in[14];
    float* out = (float*)d_out;

    bf16 *xh, *xl, *kvmh, *kvml, *lnh, *lnl, *qh, *ql, *kvlh, *kvll, *ath, *atl, *h1h, *h1l;
    float *lat, *bias;
    cudaGetSymbolAddress((void**)&xh,   g_xh);   cudaGetSymbolAddress((void**)&xl,   g_xl);
    cudaGetSymbolAddress((void**)&kvmh, g_kvmh); cudaGetSymbolAddress((void**)&kvml, g_kvml);
    cudaGetSymbolAddress((void**)&lat,  g_lat);
    cudaGetSymbolAddress((void**)&lnh,  g_lnh);  cudaGetSymbolAddress((void**)&lnl,  g_lnl);
    cudaGetSymbolAddress((void**)&qh,   g_qh);   cudaGetSymbolAddress((void**)&ql,   g_ql);
    cudaGetSymbolAddress((void**)&kvlh, g_kvlh); cudaGetSymbolAddress((void**)&kvll, g_kvll);
    cudaGetSymbolAddress((void**)&ath,  g_ath);  cudaGetSymbolAddress((void**)&atl,  g_atl);
    cudaGetSymbolAddress((void**)&h1h,  g_h1h);  cudaGetSymbolAddress((void**)&h1l,  g_h1l);
    cudaGetSymbolAddress((void**)&bias, g_bias);

    bf16 *wqTh, *wqTl, *wkvTh, *wkvTl, *wkvGh, *wkvGl, *woTh, *woTl, *w1Th, *w1Tl, *w2Th, *w2Tl;
    cudaGetSymbolAddress((void**)&wqTh,  g_wqTh);  cudaGetSymbolAddress((void**)&wqTl,  g_wqTl);
    cudaGetSymbolAddress((void**)&wkvTh, g_wkvTh); cudaGetSymbolAddress((void**)&wkvTl, g_wkvTl);
    cudaGetSymbolAddress((void**)&wkvGh, g_wkvGh); cudaGetSymbolAddress((void**)&wkvGl, g_wkvGl);
    cudaGetSymbolAddress((void**)&woTh,  g_woTh);  cudaGetSymbolAddress((void**)&woTl,  g_woTl);
    cudaGetSymbolAddress((void**)&w1Th,  g_w1Th);  cudaGetSymbolAddress((void**)&w1Tl,  g_w1Tl);
    cudaGetSymbolAddress((void**)&w2Th,  g_w2Th);  cudaGetSymbolAddress((void**)&w2Tl,  g_w2Tl);

    cudaFuncSetAttribute(gemm_tc, cudaFuncAttributeMaxDynamicSharedMemorySize, GEMM_SMEM);
    cudaFuncSetAttribute(attn_tc, cudaFuncAttributeMaxDynamicSharedMemorySize, ATT_SMEM);
    const dim3 tb(32, 8);

    // ---- weight prep (batched over depth) ----
    wsplit_kernel<<<dim3(DIMC/32, DIMC/32, DEPTHL), tb>>>(wq,  nullptr, wqTh,  wqTl,  DIMC, DIMC);
    wsplit_kernel<<<dim3(NKV/32,  DIMC/32, DEPTHL), tb>>>(wkv, nullptr, wkvTh, wkvTl, DIMC, NKV);
    wsplit_kernel<<<dim3(NKV/32,  DIMC/32, DEPTHL), tb>>>(wkv, nm_g,    wkvGh, wkvGl, DIMC, NKV);
    wsplit_kernel<<<dim3(DIMC/32, DIMC/32, DEPTHL), tb>>>(wo,  nullptr, woTh,  woTl,  DIMC, DIMC);
    wsplit_kernel<<<dim3(FFD/32,  DIMC/32, DEPTHL), tb>>>(w1,  nullptr, w1Th,  w1Tl,  DIMC, FFD);
    wsplit_kernel<<<dim3(DIMC/32, FFD/32,  DEPTHL), tb>>>(w2,  nullptr, w2Th,  w2Tl,  FFD,  DIMC);
    bias_kernel<<<dim3(NKV/32, DEPTHL), 256>>>(nm_b, wkv, bias);

    ln_kernel<<<NMEDIA, 128>>>(x, nullptr, xh, xl, nullptr, nullptr, NMEDIA);
    init_lat_kernel<<<(LROWS * DIMC) / 256, 256>>>(latents, lat);

    for (int i = 0; i < DEPTHL; i++) {
        gemm_tc<<<dim3(NKV/128, NMEDIA/128), 256, GEMM_SMEM>>>(
            xh, xl, wkvGh + (size_t)i*NKV*DIMC, wkvGl + (size_t)i*NKV*DIMC,
            nullptr, kvmh, kvml, NMEDIA, NKV, DIMC, bias + (size_t)i*NKV, nullptr, 0);
        ln_kernel<<<LROWS, 128>>>(lat, nullptr, lnh, lnl,
                                  nl_g + (size_t)i*DIMC, nl_b + (size_t)i*DIMC, LROWS);
        gemm_tc<<<dim3(DIMC/128, LROWS/128), 256, GEMM_SMEM>>>(
            lnh, lnl, wqTh + (size_t)i*DIMC*DIMC, wqTl + (size_t)i*DIMC*DIMC,
            nullptr, qh, ql, LROWS, DIMC, DIMC, nullptr, nullptr, 0);
        gemm_tc<<<dim3(NKV/128, LROWS/128), 256, GEMM_SMEM>>>(
            lnh, lnl, wkvTh + (size_t)i*NKV*DIMC, wkvTl + (size_t)i*NKV*DIMC,
            nullptr, kvlh, kvll, LROWS, NKV, DIMC, nullptr, nullptr, 0);
        attn_tc<<<BTOT * HEADS, 256, ATT_SMEM>>>(qh, ql, kvmh, kvml, kvlh, kvll, ath, atl);
        gemm_tc<<<dim3(DIMC/128, LROWS/128), 256, GEMM_SMEM>>>(
            ath, atl, woTh + (size_t)i*DIMC*DIMC, woTl + (size_t)i*DIMC*DIMC,
            lat, nullptr, nullptr, LROWS, DIMC, DIMC, nullptr, lat, 0);
        ln_kernel<<<LROWS, 128>>>(lat, nullptr, lnh, lnl,
                                  ff_g + (size_t)i*DIMC, ff_b + (size_t)i*DIMC, LROWS);
        gemm_tc<<<dim3(FFD/128, LROWS/128), 256, GEMM_SMEM>>>(
            lnh, lnl, w1Th + (size_t)i*FFD*DIMC, w1Tl + (size_t)i*FFD*DIMC,
            nullptr, h1h, h1l, LROWS, FFD, DIMC, nullptr, nullptr, 1);
        gemm_tc<<<dim3(DIMC/128, LROWS/128), 256, GEMM_SMEM>>>(
            h1h, h1l, w2Th + (size_t)i*DIMC*FFD, w2Tl + (size_t)i*DIMC*FFD,
            lat, nullptr, nullptr, LROWS, DIMC, FFD, nullptr, lat, 0);
    }
    ln_kernel<<<LROWS, 128>>>(lat, out, nullptr, nullptr, fin_g, fin_b, LROWS);
}

// round 7
// speedup vs baseline: 3.3794x; 1.0471x over previous
#include <cuda_runtime.h>
#include <cuda_bf16.h>
#include <math.h>
#include <stdint.h>

// ---------------- problem constants ----------------
#define DIMC   1024
#define DEPTHL 6
#define HEADS  16
#define DHEAD  64
#define NKV    2048
#define NQKV   3072
#define FFD    4096
#define BTOT   32
#define MEDIA  1024
#define NMEDIA (BTOT*MEDIA)          // 32768
#define NLAT   64
#define LROWS  (BTOT*NLAT)           // 2048

typedef __nv_bfloat16 bf16;

// ---------------- scratch ----------------
__device__ __align__(1024) bf16  g_xh  [(size_t)NMEDIA*DIMC];
__device__ __align__(1024) bf16  g_xl  [(size_t)NMEDIA*DIMC];
__device__ __align__(1024) bf16  g_kvmh[(size_t)DEPTHL*NMEDIA*NKV];  // all layers
__device__ __align__(1024) bf16  g_kvml[(size_t)DEPTHL*NMEDIA*NKV];
__device__ float g_lat [LROWS*DIMC];
__device__ __align__(1024) bf16  g_lnh [LROWS*DIMC];
__device__ __align__(1024) bf16  g_lnl [LROWS*DIMC];
__device__ __align__(1024) bf16  g_qkvh[(size_t)LROWS*NQKV];         // fused q|k|v latent
__device__ __align__(1024) bf16  g_qkvl[(size_t)LROWS*NQKV];
__device__ __align__(1024) bf16  g_ath [LROWS*DIMC];
__device__ __align__(1024) bf16  g_atl [LROWS*DIMC];
__device__ __align__(1024) bf16  g_h1h [(size_t)LROWS*FFD];
__device__ __align__(1024) bf16  g_h1l [(size_t)LROWS*FFD];
__device__ float g_bias[DEPTHL*NKV];
__device__ float g_part[(size_t)4*LROWS*DIMC];                       // split-K partials

// weight planes, chunk-tiled [K/32][N][32]
__device__ __align__(1024) bf16 g_wqkvTh[(size_t)DEPTHL*NQKV*DIMC];  // wq rows 0..1023, wkv rows 1024..3071
__device__ __align__(1024) bf16 g_wqkvTl[(size_t)DEPTHL*NQKV*DIMC];
__device__ __align__(1024) bf16 g_wkvGh [(size_t)DEPTHL*NKV*DIMC];   // nm_g-folded
__device__ __align__(1024) bf16 g_wkvGl [(size_t)DEPTHL*NKV*DIMC];
__device__ __align__(1024) bf16 g_woTh  [(size_t)DEPTHL*DIMC*DIMC];
__device__ __align__(1024) bf16 g_woTl  [(size_t)DEPTHL*DIMC*DIMC];
__device__ __align__(1024) bf16 g_w1Th  [(size_t)DEPTHL*FFD*DIMC];
__device__ __align__(1024) bf16 g_w1Tl  [(size_t)DEPTHL*FFD*DIMC];
__device__ __align__(1024) bf16 g_w2Th  [(size_t)DEPTHL*DIMC*FFD];
__device__ __align__(1024) bf16 g_w2Tl  [(size_t)DEPTHL*DIMC*FFD];

// ---------------- helpers ----------------
__device__ __forceinline__ uint32_t smem_u32(const void* p) {
    return (uint32_t)__cvta_generic_to_shared(p);
}
__device__ __forceinline__ size_t tiled_idx(int row, int k, int nrows) {
    const int kc = k >> 5, kin = k & 31;
    const int q = kin >> 3, b = kin & 7;
    const int qs = q ^ ((row >> 1) & 3);
    return ((size_t)kc * nrows + row) * 32 + qs * 8 + b;
}
__device__ __forceinline__ void bulk_g2s(uint32_t dst, const void* src, uint32_t bytes, uint32_t mbar) {
    asm volatile("cp.async.bulk.shared::cluster.global.mbarrier::complete_tx::bytes [%0], [%1], %2, [%3];"
                 :: "r"(dst), "l"(src), "r"(bytes), "r"(mbar) : "memory");
}
#define MBARRIER_INIT(addr, cnt) \
    asm volatile("mbarrier.init.shared.b64 [%0], %1;" :: "r"(addr), "r"(cnt) : "memory")
#define MBARRIER_EXPECT_TX(addr, tx) \
    asm volatile("mbarrier.arrive.expect_tx.shared.b64 _, [%0], %1;" :: "r"(addr), "r"(tx) : "memory")
#define MBARRIER_WAIT_PARITY(addr, par) do { \
    uint32_t _m = (addr), _p = (par), _d; \
    asm volatile("{\n\t.reg .pred p;\n\t" \
        "mbarrier.try_wait.parity.acquire.cta.shared::cta.b64 p, [%1], %2;\n\t" \
        "selp.b32 %0, 1, 0, p;\n\t}" : "=r"(_d) : "r"(_m), "r"(_p) : "memory"); \
    if (!_d) { \
        asm volatile("{\n\t.reg .pred P1;\n\t" \
            "WL_%=:\n\t" \
            "mbarrier.try_wait.parity.acquire.cta.shared::cta.b64 P1, [%0], %1, 0x989680;\n\t" \
            "@P1 bra.uni WD_%=;\n\tbra.uni WL_%=;\n\tWD_%=:\n\t}" \
            :: "r"(_m), "r"(_p) : "memory"); \
    } } while (0)

__device__ __forceinline__ void ldmx4(uint32_t* r, uint32_t a) {
    asm volatile("ldmatrix.sync.aligned.m8n8.x4.shared.b16 {%0,%1,%2,%3}, [%4];"
                 : "=r"(r[0]), "=r"(r[1]), "=r"(r[2]), "=r"(r[3]) : "r"(a));
}
__device__ __forceinline__ void ldmx4t(uint32_t* r, uint32_t a) {
    asm volatile("ldmatrix.sync.aligned.m8n8.x4.trans.shared.b16 {%0,%1,%2,%3}, [%4];"
                 : "=r"(r[0]), "=r"(r[1]), "=r"(r[2]), "=r"(r[3]) : "r"(a));
}
__device__ __forceinline__ void mma16816(float* d, const uint32_t* a, const uint32_t* b) {
    asm volatile("mma.sync.aligned.m16n8k16.row.col.f32.bf16.bf16.f32 "
                 "{%0,%1,%2,%3},{%4,%5,%6,%7},{%8,%9},{%0,%1,%2,%3};"
                 : "+f"(d[0]), "+f"(d[1]), "+f"(d[2]), "+f"(d[3])
                 : "r"(a[0]), "r"(a[1]), "r"(a[2]), "r"(a[3]),
                   "r"(b[0]), "r"(b[1]));
}
__device__ __forceinline__ uint32_t bits(__nv_bfloat162 h) {
    return *reinterpret_cast<uint32_t*>(&h);
}

// ---------------- LayerNorm ----------------
__global__ void ln_kernel(const float* __restrict__ in,
                          float* __restrict__ outF,
                          bf16* __restrict__ outH, bf16* __restrict__ outL,
                          const float* __restrict__ g, const float* __restrict__ b,
                          int nrows)
{
    const int row = blockIdx.x;
    const float* x = in + (size_t)row * DIMC;
    float s = 0.f, sq = 0.f;
    for (int c = threadIdx.x; c < DIMC; c += blockDim.x) {
        float v = x[c]; s += v; sq += v * v;
    }
    __shared__ float sh[64];
    #pragma unroll
    for (int o = 16; o > 0; o >>= 1) {
        s  += __shfl_down_sync(0xffffffffu, s,  o);
        sq += __shfl_down_sync(0xffffffffu, sq, o);
    }
    const int wid = threadIdx.x >> 5, lid = threadIdx.x & 31;
    if (lid == 0) { sh[wid] = s; sh[wid + 32] = sq; }
    __syncthreads();
    if (threadIdx.x == 0) {
        float ts = 0.f, tsq = 0.f;
        const int nw = blockDim.x >> 5;
        for (int i = 0; i < nw; i++) { ts += sh[i]; tsq += sh[i + 32]; }
        const float mean = ts * (1.0f / DIMC);
        const float var  = tsq * (1.0f / DIMC) - mean * mean;
        sh[0] = mean; sh[1] = rsqrtf(var + 1e-5f);
    }
    __syncthreads();
    const float mean = sh[0], rstd = sh[1];

    for (int k0 = threadIdx.x * 8; k0 < DIMC; k0 += blockDim.x * 8) {
        float v[8];
        #pragma unroll
        for (int e = 0; e < 8; e++) {
            float t = (x[k0 + e] - mean) * rstd;
            if (g) t = t * g[k0 + e] + b[k0 + e];
            v[e] = t;
        }
        if (outF) {
            float* o = outF + (size_t)row * DIMC + k0;
            #pragma unroll
            for (int e = 0; e < 8; e++) o[e] = v[e];
        }
        if (outH) {
            uint32_t hq[4], lq[4];
            #pragma unroll
            for (int e = 0; e < 4; e++) {
                const __nv_bfloat162 h = __floats2bfloat162_rn(v[2*e], v[2*e+1]);
                const __nv_bfloat162 l = __floats2bfloat162_rn(v[2*e]   - __low2float(h),
                                                               v[2*e+1] - __high2float(h));
                hq[e] = bits(h); lq[e] = bits(l);
            }
            const size_t ti = tiled_idx(row, k0, nrows);
            *reinterpret_cast<uint4*>(&outH[ti]) = make_uint4(hq[0], hq[1], hq[2], hq[3]);
            *reinterpret_cast<uint4*>(&outL[ti]) = make_uint4(lq[0], lq[1], lq[2], lq[3]);
        }
    }
}

// ---------------- bias: all layers, k-parallel ----------------
__global__ void bias_kernel(const float* __restrict__ nm_b,
                            const float* __restrict__ wkv, float* __restrict__ out)
{
    const int layer = blockIdx.y;
    const int tid = threadIdx.x;
    const int n  = blockIdx.x * 32 + (tid & 31);
    const int ks = tid >> 5;
    const float* bv = nm_b + (size_t)layer * DIMC;
    const float* W  = wkv  + (size_t)layer * DIMC * NKV;
    float s = 0.f;
    #pragma unroll 4
    for (int k = ks * 128; k < ks * 128 + 128; k++)
        s += bv[k] * __ldg(&W[(size_t)k * NKV + n]);
    __shared__ float red[8][32];
    red[ks][tid & 31] = s;
    __syncthreads();
    if (ks == 0) {
        float t = 0.f;
        #pragma unroll
        for (int i = 0; i < 8; i++) t += red[i][tid & 31];
        out[(size_t)layer * NKV + n] = t;
    }
}

__global__ void init_lat_kernel(const float* __restrict__ latents, float* __restrict__ lat)
{
    const int idx = blockIdx.x * blockDim.x + threadIdx.x;
    lat[idx] = latents[idx & (NLAT * DIMC - 1)];
}

// ---------------- split-K reduce (+residual) ----------------
__global__ void redk_kernel(const float* __restrict__ part, int S,
                            const float* __restrict__ resid, float* __restrict__ outF)
{
    const size_t i = (size_t)blockIdx.x * blockDim.x + threadIdx.x;
    const size_t MN = (size_t)gridDim.x * blockDim.x;
    float v = resid ? resid[i] : 0.f;
    for (int s = 0; s < S; s++) v += part[(size_t)s * MN + i];
    outF[i] = v;
}

// ---------------- weight transpose + gamma + split (batched over depth) ----------------
__global__ void wsplit_kernel(const float* __restrict__ W0, const float* __restrict__ g0,
                              bf16* __restrict__ Th0, bf16* __restrict__ Tl0,
                              int K, int N, int nofs, int ntot)
{
    const int z = blockIdx.z;
    const float* W = W0 + (size_t)z * K * N;
    const float* g = g0 ? g0 + (size_t)z * K : nullptr;
    bf16* Th = Th0 + (size_t)z * ntot * K;
    bf16* Tl = Tl0 + (size_t)z * ntot * K;
    __shared__ float t[32][33];
    const int n0 = blockIdx.x * 32, k0 = blockIdx.y * 32;
    const int tx = threadIdx.x, ty = threadIdx.y;
    #pragma unroll
    for (int i = 0; i < 4; i++) {
        float v = W[(size_t)(k0 + ty + 8 * i) * N + n0 + tx];
        if (g) v *= g[k0 + ty + 8 * i];
        t[ty + 8 * i][tx] = v;
    }
    __syncthreads();
    #pragma unroll
    for (int i = 0; i < 4; i++) {
        const int n = n0 + ty + 8 * i, k = k0 + tx;
        const float v = t[tx][ty + 8 * i];
        const bf16 h = __float2bfloat16_rn(v);
        const size_t ti = tiled_idx(nofs + n, k, ntot);
        Th[ti] = h;
        Tl[ti] = __float2bfloat16_rn(v - __bfloat162float(h));
    }
}

// =====================================================================
// bf16x3 HMMA GEMM, software-pipelined at k16 granularity.
// grid.z = layers (lstr* strides) OR split-K partitions (splitk>1, Cpart).
// =====================================================================
#define NSTG 4
#define STG_BYTES 32768
#define TILEOFF 1024
#define GEMM_SMEM (TILEOFF + NSTG*STG_BYTES)

__global__ void __launch_bounds__(256, 1)
gemm_tc(const bf16* __restrict__ Ah, const bf16* __restrict__ Al,
        const bf16* __restrict__ Bh0, const bf16* __restrict__ Bl0,
        float* __restrict__ Cf, bf16* __restrict__ Ch0, bf16* __restrict__ Cl0,
        int M, int N, int K,
        const float* __restrict__ bias0, const float* __restrict__ resid, int dogelu,
        size_t lstrB, size_t lstrC, int lstrBias,
        int splitk, float* __restrict__ Cpart)
{
    extern __shared__ char smem[];
    const uint32_t sb = smem_u32(smem);
    const int tid  = threadIdx.x;
    const int lane = tid & 31;
    const int wid  = tid >> 5;
    const int wm   = wid & 1;
    const int wn   = wid >> 1;
    const int bm   = blockIdx.y * 128;
    const int bn   = blockIdx.x * 128;
    const int z    = blockIdx.z;

    const bf16* Bh = Bh0;
    const bf16* Bl = Bl0;
    bf16* Ch = Ch0;
    bf16* Cl = Cl0;
    const float* bias = bias0;
    const int nc = K >> 5;
    int ncl = nc, c0 = 0;
    if (splitk > 1) { ncl = nc / splitk; c0 = z * ncl; }
    else if (z) {
        Bh += (size_t)z * lstrB;  Bl += (size_t)z * lstrB;
        if (Ch0) { Ch += (size_t)z * lstrC; Cl += (size_t)z * lstrC; }
        if (bias0) bias += (size_t)z * lstrBias;
    }

    if (tid == 0) {
        #pragma unroll
        for (int s = 0; s < NSTG; s++) MBARRIER_INIT(sb + 8 * s, 1);
    }
    __syncthreads();

    float acc[4][4][4];
    #pragma unroll
    for (int i = 0; i < 4; i++)
        #pragma unroll
        for (int j = 0; j < 4; j++)
            #pragma unroll
            for (int q = 0; q < 4; q++) acc[i][j][q] = 0.f;

    auto issue = [&](int cl) {
        const int gc = c0 + cl;
        const uint32_t mb  = sb + 8 * (cl & 3);
        const uint32_t dst = sb + TILEOFF + (cl & 3) * STG_BYTES;
        MBARRIER_EXPECT_TX(mb, 32768u);
        bulk_g2s(dst,         Ah + ((size_t)gc * M + bm) * 32, 8192, mb);
        bulk_g2s(dst +  8192, Al + ((size_t)gc * M + bm) * 32, 8192, mb);
        bulk_g2s(dst + 16384, Bh + ((size_t)gc * N + bn) * 32, 8192, mb);
        bulk_g2s(dst + 24576, Bl + ((size_t)gc * N + bn) * 32, 8192, mb);
    };
    if (tid == 0) {
        const int pre = ncl < NSTG ? ncl : NSTG;
        for (int s = 0; s < pre; s++) issue(s);
    }

    // register fragment double buffers (k16 granularity)
    uint32_t a0H[16], a0L[16], b0H[8], b0L[8];
    uint32_t a1H[16], a1L[16], b1H[8], b1L[8];

    auto lds_step = [&](int u, uint32_t* aH, uint32_t* aL, uint32_t* bH, uint32_t* bL) {
        const uint32_t stA = sb + TILEOFF + ((u >> 1) & 3) * STG_BYTES;
        const uint32_t stB = stA + 16384;
        const int s16 = u & 1;
        #pragma unroll
        for (int mi = 0; mi < 4; mi++) {
            const int row = wm * 64 + mi * 16 + (lane & 15);
            const int q   = s16 * 2 + (lane >> 4);
            const uint32_t ad = stA + row * 64 + ((q ^ ((row >> 1) & 3)) << 4);
            ldmx4(aH + 4 * mi, ad);
            ldmx4(aL + 4 * mi, ad + 8192);
        }
        #pragma unroll
        for (int ni = 0; ni < 2; ni++) {
            const int row = wn * 32 + ni * 16 + (lane & 7) + ((lane >> 4) << 3);
            const int q   = s16 * 2 + ((lane >> 3) & 1);
            const uint32_t bd = stB + row * 64 + ((q ^ ((row >> 1) & 3)) << 4);
            uint32_t t[4];
            ldmx4(t, bd);
            bH[ni*4+0] = t[0]; bH[ni*4+1] = t[1]; bH[ni*4+2] = t[2]; bH[ni*4+3] = t[3];
            ldmx4(t, bd + 8192);
            bL[ni*4+0] = t[0]; bL[ni*4+1] = t[1]; bL[ni*4+2] = t[2]; bL[ni*4+3] = t[3];
        }
    };
    auto mma_step = [&](const uint32_t* aH, const uint32_t* aL,
                        const uint32_t* bH, const uint32_t* bL) {
        #pragma unroll
        for (int mi = 0; mi < 4; mi++)
            #pragma unroll
            for (int j = 0; j < 4; j++) {
                mma16816(acc[mi][j], aH + 4 * mi, bH + 2 * j);
                mma16816(acc[mi][j], aH + 4 * mi, bL + 2 * j);
                mma16816(acc[mi][j], aL + 4 * mi, bH + 2 * j);
            }
    };

    MBARRIER_WAIT_PARITY(sb, 0);
    lds_step(0, a0H, a0L, b0H, b0L);
    const int total = ncl * 2;
    for (int u = 0; u < total; u += 2) {
        lds_step(u + 1, a1H, a1L, b1H, b1L);      // same chunk/stage, already full
        __syncthreads();                           // all warps done reading stage (u>>1)&3
        const int cl = u >> 1;
        if (tid == 0 && cl + NSTG < ncl) issue(cl + NSTG);
        mma_step(a0H, a0L, b0H, b0L);
        if (u + 2 < total) {
            const int c2 = cl + 1;
            MBARRIER_WAIT_PARITY(sb + 8 * (c2 & 3), (c2 >> 2) & 1);
            lds_step(u + 2, a0H, a0L, b0H, b0L);
        }
        mma_step(a1H, a1L, b1H, b1L);
    }

    // ---- epilogue ----
    if (Cpart) {
        float* P = Cpart + (size_t)z * M * N;
        #pragma unroll
        for (int mi = 0; mi < 4; mi++)
            #pragma unroll
            for (int j = 0; j < 4; j++) {
                const int colb = bn + wn * 32 + j * 8 + (lane & 3) * 2;
                #pragma unroll
                for (int p = 0; p < 2; p++) {
                    const int row = bm + wm * 64 + mi * 16 + (lane >> 2) + 8 * p;
                    *reinterpret_cast<float2*>(&P[(size_t)row * N + colb]) =
                        make_float2(acc[mi][j][p * 2], acc[mi][j][p * 2 + 1]);
                }
            }
        return;
    }
    #pragma unroll
    for (int mi = 0; mi < 4; mi++) {
        #pragma unroll
        for (int j = 0; j < 4; j++) {
            const int colb = bn + wn * 32 + j * 8 + (lane & 3) * 2;
            #pragma unroll
            for (int p = 0; p < 2; p++) {
                const int row = bm + wm * 64 + mi * 16 + (lane >> 2) + 8 * p;
                float v0 = acc[mi][j][p * 2], v1 = acc[mi][j][p * 2 + 1];
                if (bias) { v0 += bias[colb]; v1 += bias[colb + 1]; }
                if (dogelu) {
                    v0 = 0.5f * v0 * (1.f + erff(v0 * 0.70710678118654752f));
                    v1 = 0.5f * v1 * (1.f + erff(v1 * 0.70710678118654752f));
                }
                if (resid) {
                    const float2 r = *reinterpret_cast<const float2*>(&resid[(size_t)row * N + colb]);
                    v0 += r.x; v1 += r.y;
                }
                if (Cf) *reinterpret_cast<float2*>(&Cf[(size_t)row * N + colb]) = make_float2(v0, v1);
                if (Ch) {
                    const __nv_bfloat162 h = __floats2bfloat162_rn(v0, v1);
                    const __nv_bfloat162 l = __floats2bfloat162_rn(v0 - __low2float(h),
                                                                   v1 - __high2float(h));
                    const size_t ti = tiled_idx(row, colb, M);
                    *reinterpret_cast<uint32_t*>(&Ch[ti]) = bits(h);
                    *reinterpret_cast<uint32_t*>(&Cl[ti]) = bits(l);
                }
            }
        }
    }
}

// =====================================================================
// Tensor-core flash attention (bf16x3), fused qkv latent buffer.
// =====================================================================
#define OFF_Q   1024
#define OFF_KV  (OFF_Q + 16384)
#define OFF_P   (OFF_KV + 65536)
#define OFF_SS  (OFF_P + 16384)
#define OFF_ST  (OFF_SS + 64*65*4)
#define ATT_SMEM (OFF_ST + 768)

__global__ void __launch_bounds__(256, 1)
attn_tc(const bf16* __restrict__ QKVh, const bf16* __restrict__ QKVl,
        const bf16* __restrict__ Kmh, const bf16* __restrict__ Kml,
        bf16* __restrict__ OH, bf16* __restrict__ OL)
{
    extern __shared__ char smem[];
    const uint32_t sb = smem_u32(smem);
    const int bt  = blockIdx.x >> 4;
    const int h   = blockIdx.x & 15;
    const int tid = threadIdx.x;
    const int lane = tid & 31;
    const int wid  = tid >> 5;
    const int wm   = wid & 1;
    const int wn   = wid >> 1;
    float* Ss    = reinterpret_cast<float*>(smem + OFF_SS);
    float* mrow  = reinterpret_cast<float*>(smem + OFF_ST);
    float* lrow  = mrow + 64;
    float* frow  = lrow + 64;

    if (tid == 0) { MBARRIER_INIT(sb, 1); MBARRIER_INIT(sb + 8, 1); }

    {
        #pragma unroll
        for (int seg = 0; seg < 4; seg++) {
            const bf16* src = (seg < 2 ? QKVh : QKVl) + ((size_t)(2 * h + (seg & 1)) * LROWS + bt * 64) * 32;
            const uint4 v = reinterpret_cast<const uint4*>(src)[tid];
            *reinterpret_cast<uint4*>(smem + OFF_Q + (seg >= 2 ? 8192 : 0) + (seg & 1) * 4096 + tid * 16) = v;
        }
    }
    if (tid < 64) { mrow[tid] = -INFINITY; lrow[tid] = 0.f; }
    __syncthreads();

    auto issueKV = [&](int t) {
        const int st = t & 1;
        const uint32_t mb = sb + 8 * st;
        const uint32_t dst = sb + OFF_KV + st * 32768;
        MBARRIER_EXPECT_TX(mb, 32768u);
        const bf16 *PH, *PL; size_t rbase, nr; int kcK, kcV;
        if (t < 16) { PH = Kmh;  PL = Kml;  rbase = (size_t)bt * 1024 + t * 64; nr = NMEDIA; kcK = 2*h;      kcV = 32 + 2*h; }
        else        { PH = QKVh; PL = QKVl; rbase = (size_t)bt * 64;            nr = LROWS;  kcK = 32 + 2*h; kcV = 64 + 2*h; }
        bulk_g2s(dst,          PH + ((size_t)kcK * nr + rbase) * 32,       4096, mb);
        bulk_g2s(dst +  4096,  PH + ((size_t)(kcK + 1) * nr + rbase) * 32, 4096, mb);
        bulk_g2s(dst +  8192,  PL + ((size_t)kcK * nr + rbase) * 32,       4096, mb);
        bulk_g2s(dst + 12288,  PL + ((size_t)(kcK + 1) * nr + rbase) * 32, 4096, mb);
        bulk_g2s(dst + 16384,  PH + ((size_t)kcV * nr + rbase) * 32,       4096, mb);
        bulk_g2s(dst + 20480,  PH + ((size_t)(kcV + 1) * nr + rbase) * 32, 4096, mb);
        bulk_g2s(dst + 24576,  PL + ((size_t)kcV * nr + rbase) * 32,       4096, mb);
        bulk_g2s(dst + 28672,  PL + ((size_t)(kcV + 1) * nr + rbase) * 32, 4096, mb);
    };
    if (tid == 0) issueKV(0);

    uint32_t qH[2][4][4], qL[2][4][4];
    #pragma unroll
    for (int mi = 0; mi < 2; mi++)
        #pragma unroll
        for (int s = 0; s < 4; s++) {
            const int row = wm * 32 + mi * 16 + (lane & 15);
            const int qq = (((s & 1) * 2 + (lane >> 4)) ^ ((row >> 1) & 3));
            const uint32_t ad = sb + OFF_Q + (s >> 1) * 4096 + row * 64 + (qq << 4);
            ldmx4(qH[mi][s], ad);
            ldmx4(qL[mi][s], ad + 8192);
        }

    float acc[2][2][4];
    #pragma unroll
    for (int i = 0; i < 2; i++)
        #pragma unroll
        for (int j = 0; j < 2; j++)
            #pragma unroll
            for (int q = 0; q < 4; q++) acc[i][j][q] = 0.f;

    for (int t = 0; t < 17; t++) {
        if (tid == 0 && t + 1 < 17) issueKV(t + 1);
        MBARRIER_WAIT_PARITY(sb + 8 * (t & 1), (t >> 1) & 1);
        const uint32_t kb = sb + OFF_KV + (t & 1) * 32768;

        float sc[2][2][4] = {};
        #pragma unroll
        for (int s = 0; s < 4; s++) {
            const int row = wn * 16 + (lane & 7) + ((lane >> 4) << 3);
            const int qq = (((s & 1) * 2 + ((lane >> 3) & 1)) ^ ((row >> 1) & 3));
            const uint32_t ad = kb + (s >> 1) * 4096 + row * 64 + (qq << 4);
            uint32_t tH[4], tL[4];
            ldmx4(tH, ad); ldmx4(tL, ad + 8192);
            uint32_t bh0[2] = {tH[0], tH[1]}, bh1[2] = {tH[2], tH[3]};
            uint32_t bl0[2] = {tL[0], tL[1]}, bl1[2] = {tL[2], tL[3]};
            #pragma unroll
            for (int mi = 0; mi < 2; mi++) {
                mma16816(sc[mi][0], qH[mi][s], bh0);
                mma16816(sc[mi][0], qH[mi][s], bl0);
                mma16816(sc[mi][0], qL[mi][s], bh0);
                mma16816(sc[mi][1], qH[mi][s], bh1);
                mma16816(sc[mi][1], qH[mi][s], bl1);
                mma16816(sc[mi][1], qL[mi][s], bh1);
            }
        }
        #pragma unroll
        for (int mi = 0; mi < 2; mi++)
            #pragma unroll
            for (int j = 0; j < 2; j++)
                #pragma unroll
                for (int p = 0; p < 2; p++) {
                    const int r = wm * 32 + mi * 16 + (lane >> 2) + 8 * p;
                    const int col = wn * 16 + j * 8 + (lane & 3) * 2;
                    Ss[r * 65 + col]     = sc[mi][j][p * 2]     * 0.125f;
                    Ss[r * 65 + col + 1] = sc[mi][j][p * 2 + 1] * 0.125f;
                }
        __syncthreads();

        {
            const int r = tid >> 2, qd = tid & 3;
            const int kb2 = qd * 16;
            float tmax = -INFINITY;
            #pragma unroll
            for (int k = 0; k < 16; k++) tmax = fmaxf(tmax, Ss[r * 65 + kb2 + k]);
            tmax = fmaxf(tmax, __shfl_xor_sync(0xffffffffu, tmax, 1));
            tmax = fmaxf(tmax, __shfl_xor_sync(0xffffffffu, tmax, 2));
            const float mold = mrow[r];
            const float mnew = fmaxf(mold, tmax);
            float s = 0.f;
            #pragma unroll
            for (int k = 0; k < 16; k++) {
                const float p = __expf(Ss[r * 65 + kb2 + k] - mnew);
                Ss[r * 65 + kb2 + k] = p;
                s += p;
            }
            s += __shfl_xor_sync(0xffffffffu, s, 1);
            s += __shfl_xor_sync(0xffffffffu, s, 2);
            if (qd == 0) {
                const float fac = __expf(mold - mnew);
                lrow[r] = lrow[r] * fac + s;
                mrow[r] = mnew;
                frow[r] = fac;
            }
        }
        __syncthreads();

        #pragma unroll
        for (int mi = 0; mi < 2; mi++)
            #pragma unroll
            for (int p = 0; p < 2; p++) {
                const float fac = frow[wm * 32 + mi * 16 + (lane >> 2) + 8 * p];
                #pragma unroll
                for (int j = 0; j < 2; j++) {
                    acc[mi][j][p * 2]     *= fac;
                    acc[mi][j][p * 2 + 1] *= fac;
                }
            }
        #pragma unroll
        for (int i = 0; i < 8; i++) {
            const int pi = tid * 8 + i;
            const int q = pi >> 5, kp = pi & 31, k = kp * 2;
            const int kc = k >> 5, kin = k & 31;
            const int qq = ((kin >> 3) ^ ((q >> 1) & 3));
            const int off = OFF_P + kc * 4096 + q * 64 + (qq << 4) + (kin & 7) * 2;
            const float v0 = Ss[q * 65 + k], v1 = Ss[q * 65 + k + 1];
            const __nv_bfloat162 hh = __floats2bfloat162_rn(v0, v1);
            const __nv_bfloat162 ll = __floats2bfloat162_rn(v0 - __low2float(hh),
                                                            v1 - __high2float(hh));
            *reinterpret_cast<uint32_t*>(smem + off)        = bits(hh);
            *reinterpret_cast<uint32_t*>(smem + off + 8192) = bits(ll);
        }
        __syncthreads();

        #pragma unroll
        for (int s = 0; s < 4; s++) {
            uint32_t pH[2][4], pL[2][4];
            #pragma unroll
            for (int mi = 0; mi < 2; mi++) {
                const int row = wm * 32 + mi * 16 + (lane & 15);
                const int qq = (((s & 1) * 2 + (lane >> 4)) ^ ((row >> 1) & 3));
                const uint32_t ad = sb + OFF_P + (s >> 1) * 4096 + row * 64 + (qq << 4);
                ldmx4(pH[mi], ad);
                ldmx4(pL[mi], ad + 8192);
            }
            const int key  = s * 16 + (lane & 15);
            const int dinb = wn * 16 + ((lane >> 4) << 3);
            const int kcv  = dinb >> 5, din = dinb & 31;
            const int qq   = ((din >> 3) ^ ((key >> 1) & 3));
            const uint32_t ad = kb + 16384 + kcv * 4096 + key * 64 + (qq << 4);
            uint32_t tH[4], tL[4];
            ldmx4t(tH, ad); ldmx4t(tL, ad + 8192);
            uint32_t vh0[2] = {tH[0], tH[1]}, vh1[2] = {tH[2], tH[3]};
            uint32_t vl0[2] = {tL[0], tL[1]}, vl1[2] = {tL[2], tL[3]};
            #pragma unroll
            for (int mi = 0; mi < 2; mi++) {
                mma16816(acc[mi][0], pH[mi], vh0);
                mma16816(acc[mi][0], pH[mi], vl0);
                mma16816(acc[mi][0], pL[mi], vh0);
                mma16816(acc[mi][1], pH[mi], vh1);
                mma16816(acc[mi][1], pH[mi], vl1);
                mma16816(acc[mi][1], pL[mi], vh1);
            }
        }
        __syncthreads();
    }

    #pragma unroll
    for (int mi = 0; mi < 2; mi++)
        #pragma unroll
        for (int p = 0; p < 2; p++) {
            const int r = wm * 32 + mi * 16 + (lane >> 2) + 8 * p;
            const float inv = 1.0f / lrow[r];
            #pragma unroll
            for (int j = 0; j < 2; j++) {
                const int col = h * 64 + wn * 16 + j * 8 + (lane & 3) * 2;
                const float v0 = acc[mi][j][p * 2] * inv;
                const float v1 = acc[mi][j][p * 2 + 1] * inv;
                const __nv_bfloat162 hh = __floats2bfloat162_rn(v0, v1);
                const __nv_bfloat162 ll = __floats2bfloat162_rn(v0 - __low2float(hh),
                                                                v1 - __high2float(hh));
                const size_t ti = tiled_idx(bt * 64 + r, col, LROWS);
                *reinterpret_cast<uint32_t*>(&OH[ti]) = bits(hh);
                *reinterpret_cast<uint32_t*>(&OL[ti]) = bits(ll);
            }
        }
}

// ---------------- orchestration ----------------
extern "C" void kernel_launch(void* const* d_in, const int* in_sizes, int n_in,
                              void* d_out, int out_size)
{
    (void)in_sizes; (void)n_in; (void)out_size;
    const float* x       = (const float*)d_in[0];
    const float* latents = (const float*)d_in[1];
    const float* nm_g    = (const float*)d_in[2];
    const float* nm_b    = (const float*)d_in[3];
    const float* nl_g    = (const float*)d_in[4];
    const float* nl_b    = (const float*)d_in[5];
    const float* wq      = (const float*)d_in[6];
    const float* wkv     = (const float*)d_in[7];
    const float* wo      = (const float*)d_in[8];
    const float* ff_g    = (const float*)d_in[9];
    const float* ff_b    = (const float*)d_in[10];
    const float* w1      = (const float*)d_in[11];
    const float* w2      = (const float*)d_in[12];
    const float* fin_g   = (const float*)d_in[13];
    const float* fin_b   = (const float*)d_in[14];
    float* out = (float*)d_out;

    bf16 *xh, *xl, *kvmh, *kvml, *lnh, *lnl, *qkvh, *qkvl, *ath, *atl, *h1h, *h1l;
    float *lat, *bias, *part;
    cudaGetSymbolAddress((void**)&xh,   g_xh);   cudaGetSymbolAddress((void**)&xl,   g_xl);
    cudaGetSymbolAddress((void**)&kvmh, g_kvmh); cudaGetSymbolAddress((void**)&kvml, g_kvml);
    cudaGetSymbolAddress((void**)&lat,  g_lat);
    cudaGetSymbolAddress((void**)&lnh,  g_lnh);  cudaGetSymbolAddress((void**)&lnl,  g_lnl);
    cudaGetSymbolAddress((void**)&qkvh, g_qkvh); cudaGetSymbolAddress((void**)&qkvl, g_qkvl);
    cudaGetSymbolAddress((void**)&ath,  g_ath);  cudaGetSymbolAddress((void**)&atl,  g_atl);
    cudaGetSymbolAddress((void**)&h1h,  g_h1h);  cudaGetSymbolAddress((void**)&h1l,  g_h1l);
    cudaGetSymbolAddress((void**)&bias, g_bias); cudaGetSymbolAddress((void**)&part, g_part);

    bf16 *wqkvTh, *wqkvTl, *wkvGh, *wkvGl, *woTh, *woTl, *w1Th, *w1Tl, *w2Th, *w2Tl;
    cudaGetSymbolAddress((void**)&wqkvTh, g_wqkvTh); cudaGetSymbolAddress((void**)&wqkvTl, g_wqkvTl);
    cudaGetSymbolAddress((void**)&wkvGh,  g_wkvGh);  cudaGetSymbolAddress((void**)&wkvGl,  g_wkvGl);
    cudaGetSymbolAddress((void**)&woTh,   g_woTh);   cudaGetSymbolAddress((void**)&woTl,   g_woTl);
    cudaGetSymbolAddress((void**)&w1Th,   g_w1Th);   cudaGetSymbolAddress((void**)&w1Tl,   g_w1Tl);
    cudaGetSymbolAddress((void**)&w2Th,   g_w2Th);   cudaGetSymbolAddress((void**)&w2Tl,   g_w2Tl);

    cudaFuncSetAttribute(gemm_tc, cudaFuncAttributeMaxDynamicSharedMemorySize, GEMM_SMEM);
    cudaFuncSetAttribute(attn_tc, cudaFuncAttributeMaxDynamicSharedMemorySize, ATT_SMEM);
    const dim3 tb(32, 8);

    // ---- weight prep (batched over depth) ----
    wsplit_kernel<<<dim3(DIMC/32, DIMC/32, DEPTHL), tb>>>(wq,  nullptr, wqkvTh, wqkvTl, DIMC, DIMC, 0,    NQKV);
    wsplit_kernel<<<dim3(NKV/32,  DIMC/32, DEPTHL), tb>>>(wkv, nullptr, wqkvTh, wqkvTl, DIMC, NKV,  DIMC, NQKV);
    wsplit_kernel<<<dim3(NKV/32,  DIMC/32, DEPTHL), tb>>>(wkv, nm_g,    wkvGh,  wkvGl,  DIMC, NKV,  0,    NKV);
    wsplit_kernel<<<dim3(DIMC/32, DIMC/32, DEPTHL), tb>>>(wo,  nullptr, woTh,   woTl,   DIMC, DIMC, 0,    DIMC);
    wsplit_kernel<<<dim3(FFD/32,  DIMC/32, DEPTHL), tb>>>(w1,  nullptr, w1Th,   w1Tl,   DIMC, FFD,  0,    FFD);
    wsplit_kernel<<<dim3(DIMC/32, FFD/32,  DEPTHL), tb>>>(w2,  nullptr, w2Th,   w2Tl,   FFD,  DIMC, 0,    DIMC);
    bias_kernel<<<dim3(NKV/32, DEPTHL), 256>>>(nm_b, wkv, bias);

    ln_kernel<<<NMEDIA, 128>>>(x, nullptr, xh, xl, nullptr, nullptr, NMEDIA);
    init_lat_kernel<<<(LROWS * DIMC) / 256, 256>>>(latents, lat);

    // ---- all-layer media KV (xhat is layer-invariant) ----
    gemm_tc<<<dim3(NKV/128, NMEDIA/128, DEPTHL), 256, GEMM_SMEM>>>(
        xh, xl, wkvGh, wkvGl, nullptr, kvmh, kvml, NMEDIA, NKV, DIMC,
        bias, nullptr, 0,
        (size_t)NKV*DIMC, (size_t)NMEDIA*NKV, NKV, 1, nullptr);

    for (int i = 0; i < DEPTHL; i++) {
        ln_kernel<<<LROWS, 128>>>(lat, nullptr, lnh, lnl,
                                  nl_g + (size_t)i*DIMC, nl_b + (size_t)i*DIMC, LROWS);
        // fused Q|K|V latent GEMM
        gemm_tc<<<dim3(NQKV/128, LROWS/128), 256, GEMM_SMEM>>>(
            lnh, lnl, wqkvTh + (size_t)i*NQKV*DIMC, wqkvTl + (size_t)i*NQKV*DIMC,
            nullptr, qkvh, qkvl, LROWS, NQKV, DIMC, nullptr, nullptr, 0,
            0, 0, 0, 1, nullptr);
        attn_tc<<<BTOT * HEADS, 256, ATT_SMEM>>>(
            qkvh, qkvl, kvmh + (size_t)i*NMEDIA*NKV, kvml + (size_t)i*NMEDIA*NKV, ath, atl);
        // lat += attn @ wo   (split-K 2)
        gemm_tc<<<dim3(DIMC/128, LROWS/128, 2), 256, GEMM_SMEM>>>(
            ath, atl, woTh + (size_t)i*DIMC*DIMC, woTl + (size_t)i*DIMC*DIMC,
            nullptr, nullptr, nullptr, LROWS, DIMC, DIMC, nullptr, nullptr, 0,
            0, 0, 0, 2, part);
        redk_kernel<<<(LROWS*DIMC)/256, 256>>>(part, 2, lat, lat);
        ln_kernel<<<LROWS, 128>>>(lat, nullptr, lnh, lnl,
                                  ff_g + (size_t)i*DIMC, ff_b + (size_t)i*DIMC, LROWS);
        gemm_tc<<<dim3(FFD/128, LROWS/128), 256, GEMM_SMEM>>>(
            lnh, lnl, w1Th + (size_t)i*FFD*DIMC, w1Tl + (size_t)i*FFD*DIMC,
            nullptr, h1h, h1l, LROWS, FFD, DIMC, nullptr, nullptr, 1,
            0, 0, 0, 1, nullptr);
        // lat += gelu(h1) @ w2   (split-K 4)
        gemm_tc<<<dim3(DIMC/128, LROWS/128, 4), 256, GEMM_SMEM>>>(
            h1h, h1l, w2Th + (size_t)i*DIMC*FFD, w2Tl + (size_t)i*DIMC*FFD,
            nullptr, nullptr, nullptr, LROWS, DIMC, FFD, nullptr, nullptr, 0,
            0, 0, 0, 4, part);
        redk_kernel<<<(LROWS*DIMC)/256, 256>>>(part, 4, lat, lat);
    }
    ln_kernel<<<LROWS, 128>>>(lat, out, nullptr, nullptr, fin_g, fin_b, LROWS);
}

// round 8
// speedup vs baseline: 4.3103x; 1.2755x over previous
#include <cuda_runtime.h>
#include <cuda_fp16.h>
#include <math.h>
#include <stdint.h>

// ---------------- problem constants ----------------
#define DIMC   1024
#define DEPTHL 6
#define HEADS  16
#define DHEAD  64
#define NKV    2048
#define NQKV   3072
#define FFD    4096
#define BTOT   32
#define MEDIA  1024
#define NMEDIA (BTOT*MEDIA)          // 32768
#define NLAT   64
#define LROWS  (BTOT*NLAT)           // 2048

typedef __half hf;

// ---------------- scratch ----------------
__device__ __align__(1024) hf    g_xh  [(size_t)NMEDIA*DIMC];
__device__ __align__(1024) hf    g_xl  [(size_t)NMEDIA*DIMC];
__device__ __align__(1024) hf    g_kvmh[(size_t)DEPTHL*NMEDIA*NKV];  // single plane (B-side)
__device__ float g_lat [LROWS*DIMC];
__device__ __align__(1024) hf    g_lnh [LROWS*DIMC];
__device__ __align__(1024) hf    g_lnl [LROWS*DIMC];
__device__ __align__(1024) hf    g_qkvh[(size_t)LROWS*NQKV];
__device__ __align__(1024) hf    g_qkvl[(size_t)LROWS*NQKV];
__device__ __align__(1024) hf    g_ath [LROWS*DIMC];
__device__ __align__(1024) hf    g_atl [LROWS*DIMC];
__device__ __align__(1024) hf    g_h1h [(size_t)LROWS*FFD];
__device__ __align__(1024) hf    g_h1l [(size_t)LROWS*FFD];
__device__ float g_bias[DEPTHL*NKV];
__device__ float g_part[(size_t)4*LROWS*DIMC];

// weight planes (single fp16, B-side), chunk-tiled [K/32][N][32]
__device__ __align__(1024) hf g_wqkvT[(size_t)DEPTHL*NQKV*DIMC];
__device__ __align__(1024) hf g_wkvG [(size_t)DEPTHL*NKV*DIMC];
__device__ __align__(1024) hf g_woT  [(size_t)DEPTHL*DIMC*DIMC];
__device__ __align__(1024) hf g_w1T  [(size_t)DEPTHL*FFD*DIMC];
__device__ __align__(1024) hf g_w2T  [(size_t)DEPTHL*DIMC*FFD];

// ---------------- helpers ----------------
__device__ __forceinline__ uint32_t smem_u32(const void* p) {
    return (uint32_t)__cvta_generic_to_shared(p);
}
__device__ __forceinline__ size_t tiled_idx(int row, int k, int nrows) {
    const int kc = k >> 5, kin = k & 31;
    const int q = kin >> 3, b = kin & 7;
    const int qs = q ^ ((row >> 1) & 3);
    return ((size_t)kc * nrows + row) * 32 + qs * 8 + b;
}
__device__ __forceinline__ void bulk_g2s(uint32_t dst, const void* src, uint32_t bytes, uint32_t mbar) {
    asm volatile("cp.async.bulk.shared::cluster.global.mbarrier::complete_tx::bytes [%0], [%1], %2, [%3];"
                 :: "r"(dst), "l"(src), "r"(bytes), "r"(mbar) : "memory");
}
#define MBARRIER_INIT(addr, cnt) \
    asm volatile("mbarrier.init.shared.b64 [%0], %1;" :: "r"(addr), "r"(cnt) : "memory")
#define MBARRIER_EXPECT_TX(addr, tx) \
    asm volatile("mbarrier.arrive.expect_tx.shared.b64 _, [%0], %1;" :: "r"(addr), "r"(tx) : "memory")
#define MBARRIER_WAIT_PARITY(addr, par) do { \
    uint32_t _m = (addr), _p = (par), _d; \
    asm volatile("{\n\t.reg .pred p;\n\t" \
        "mbarrier.try_wait.parity.acquire.cta.shared::cta.b64 p, [%1], %2;\n\t" \
        "selp.b32 %0, 1, 0, p;\n\t}" : "=r"(_d) : "r"(_m), "r"(_p) : "memory"); \
    if (!_d) { \
        asm volatile("{\n\t.reg .pred P1;\n\t" \
            "WL_%=:\n\t" \
            "mbarrier.try_wait.parity.acquire.cta.shared::cta.b64 P1, [%0], %1, 0x989680;\n\t" \
            "@P1 bra.uni WD_%=;\n\tbra.uni WL_%=;\n\tWD_%=:\n\t}" \
            :: "r"(_m), "r"(_p) : "memory"); \
    } } while (0)

__device__ __forceinline__ void ldmx4(uint32_t* r, uint32_t a) {
    asm volatile("ldmatrix.sync.aligned.m8n8.x4.shared.b16 {%0,%1,%2,%3}, [%4];"
                 : "=r"(r[0]), "=r"(r[1]), "=r"(r[2]), "=r"(r[3]) : "r"(a));
}
__device__ __forceinline__ void ldmx4t(uint32_t* r, uint32_t a) {
    asm volatile("ldmatrix.sync.aligned.m8n8.x4.trans.shared.b16 {%0,%1,%2,%3}, [%4];"
                 : "=r"(r[0]), "=r"(r[1]), "=r"(r[2]), "=r"(r[3]) : "r"(a));
}
__device__ __forceinline__ void mma16816(float* d, const uint32_t* a, const uint32_t* b) {
    asm volatile("mma.sync.aligned.m16n8k16.row.col.f32.f16.f16.f32 "
                 "{%0,%1,%2,%3},{%4,%5,%6,%7},{%8,%9},{%0,%1,%2,%3};"
                 : "+f"(d[0]), "+f"(d[1]), "+f"(d[2]), "+f"(d[3])
                 : "r"(a[0]), "r"(a[1]), "r"(a[2]), "r"(a[3]),
                   "r"(b[0]), "r"(b[1]));
}
__device__ __forceinline__ uint32_t bits2(__half2 h) {
    return *reinterpret_cast<uint32_t*>(&h);
}

// ---------------- LayerNorm: fp32 in -> fp32 out and/or tiled fp16 planes ----------
__global__ void ln_kernel(const float* __restrict__ in,
                          float* __restrict__ outF,
                          hf* __restrict__ outH, hf* __restrict__ outL,
                          const float* __restrict__ g, const float* __restrict__ b,
                          int nrows)
{
    const int row = blockIdx.x;
    const float* x = in + (size_t)row * DIMC;
    float s = 0.f, sq = 0.f;
    for (int c = threadIdx.x; c < DIMC; c += blockDim.x) {
        float v = x[c]; s += v; sq += v * v;
    }
    __shared__ float sh[64];
    #pragma unroll
    for (int o = 16; o > 0; o >>= 1) {
        s  += __shfl_down_sync(0xffffffffu, s,  o);
        sq += __shfl_down_sync(0xffffffffu, sq, o);
    }
    const int wid = threadIdx.x >> 5, lid = threadIdx.x & 31;
    if (lid == 0) { sh[wid] = s; sh[wid + 32] = sq; }
    __syncthreads();
    if (threadIdx.x == 0) {
        float ts = 0.f, tsq = 0.f;
        const int nw = blockDim.x >> 5;
        for (int i = 0; i < nw; i++) { ts += sh[i]; tsq += sh[i + 32]; }
        const float mean = ts * (1.0f / DIMC);
        const float var  = tsq * (1.0f / DIMC) - mean * mean;
        sh[0] = mean; sh[1] = rsqrtf(var + 1e-5f);
    }
    __syncthreads();
    const float mean = sh[0], rstd = sh[1];

    for (int k0 = threadIdx.x * 8; k0 < DIMC; k0 += blockDim.x * 8) {
        float v[8];
        #pragma unroll
        for (int e = 0; e < 8; e++) {
            float t = (x[k0 + e] - mean) * rstd;
            if (g) t = t * g[k0 + e] + b[k0 + e];
            v[e] = t;
        }
        if (outF) {
            float* o = outF + (size_t)row * DIMC + k0;
            #pragma unroll
            for (int e = 0; e < 8; e++) o[e] = v[e];
        }
        if (outH) {
            uint32_t hq[4], lq[4];
            #pragma unroll
            for (int e = 0; e < 4; e++) {
                const __half2 h = __floats2half2_rn(v[2*e], v[2*e+1]);
                const __half2 l = __floats2half2_rn(v[2*e]   - __low2float(h),
                                                    v[2*e+1] - __high2float(h));
                hq[e] = bits2(h); lq[e] = bits2(l);
            }
            const size_t ti = tiled_idx(row, k0, nrows);
            *reinterpret_cast<uint4*>(&outH[ti]) = make_uint4(hq[0], hq[1], hq[2], hq[3]);
            *reinterpret_cast<uint4*>(&outL[ti]) = make_uint4(lq[0], lq[1], lq[2], lq[3]);
        }
    }
}

// ---------------- bias: all layers, k-parallel ----------------
__global__ void bias_kernel(const float* __restrict__ nm_b,
                            const float* __restrict__ wkv, float* __restrict__ out)
{
    const int layer = blockIdx.y;
    const int tid = threadIdx.x;
    const int n  = blockIdx.x * 32 + (tid & 31);
    const int ks = tid >> 5;
    const float* bv = nm_b + (size_t)layer * DIMC;
    const float* W  = wkv  + (size_t)layer * DIMC * NKV;
    float s = 0.f;
    #pragma unroll 4
    for (int k = ks * 128; k < ks * 128 + 128; k++)
        s += bv[k] * __ldg(&W[(size_t)k * NKV + n]);
    __shared__ float red[8][32];
    red[ks][tid & 31] = s;
    __syncthreads();
    if (ks == 0) {
        float t = 0.f;
        #pragma unroll
        for (int i = 0; i < 8; i++) t += red[i][tid & 31];
        out[(size_t)layer * NKV + n] = t;
    }
}

__global__ void init_lat_kernel(const float* __restrict__ latents, float* __restrict__ lat)
{
    const int idx = blockIdx.x * blockDim.x + threadIdx.x;
    lat[idx] = latents[idx & (NLAT * DIMC - 1)];
}

// ---------------- split-K reduce (+residual) ----------------
__global__ void redk_kernel(const float* __restrict__ part, int S,
                            const float* __restrict__ resid, float* __restrict__ outF)
{
    const size_t i = (size_t)blockIdx.x * blockDim.x + threadIdx.x;
    const size_t MN = (size_t)gridDim.x * blockDim.x;
    float v = resid ? resid[i] : 0.f;
    for (int s = 0; s < S; s++) v += part[(size_t)s * MN + i];
    outF[i] = v;
}

// ---------------- weight transpose + gamma + fp16 quantize (batched over depth) ----
__global__ void wsplit_kernel(const float* __restrict__ W0, const float* __restrict__ g0,
                              hf* __restrict__ T0, int K, int N, int nofs, int ntot)
{
    const int z = blockIdx.z;
    const float* W = W0 + (size_t)z * K * N;
    const float* g = g0 ? g0 + (size_t)z * K : nullptr;
    hf* T = T0 + (size_t)z * ntot * K;
    __shared__ float t[32][33];
    const int n0 = blockIdx.x * 32, k0 = blockIdx.y * 32;
    const int tx = threadIdx.x, ty = threadIdx.y;
    #pragma unroll
    for (int i = 0; i < 4; i++) {
        float v = W[(size_t)(k0 + ty + 8 * i) * N + n0 + tx];
        if (g) v *= g[k0 + ty + 8 * i];
        t[ty + 8 * i][tx] = v;
    }
    __syncthreads();
    #pragma unroll
    for (int i = 0; i < 4; i++) {
        const int n = n0 + ty + 8 * i, k = k0 + tx;
        T[tiled_idx(nofs + n, k, ntot)] = __float2half_rn(t[tx][ty + 8 * i]);
    }
}

// =====================================================================
// fp16 2-term HMMA GEMM: C = epi((Ah+Al) @ B^T), B single fp16 plane.
// Software-pipelined at k16 granularity; cp.async.bulk staging.
// grid.z = layers (lstr*) OR split-K partitions (splitk>1, Cpart).
// =====================================================================
#define NSTG 4
#define STG_BYTES 24576              // Ah 8K | Al 8K | B 8K
#define TILEOFF 1024
#define GEMM_SMEM (TILEOFF + NSTG*STG_BYTES)   // 99328

__global__ void __launch_bounds__(256, 1)
gemm_tc(const hf* __restrict__ Ah, const hf* __restrict__ Al,
        const hf* __restrict__ B0,
        float* __restrict__ Cf, hf* __restrict__ Ch0, hf* __restrict__ Cl0,
        int M, int N, int K,
        const float* __restrict__ bias0, const float* __restrict__ resid, int dogelu,
        size_t lstrB, size_t lstrC, int lstrBias,
        int splitk, float* __restrict__ Cpart)
{
    extern __shared__ char smem[];
    const uint32_t sb = smem_u32(smem);
    const int tid  = threadIdx.x;
    const int lane = tid & 31;
    const int wid  = tid >> 5;
    const int wm   = wid & 1;
    const int wn   = wid >> 1;
    const int bm   = blockIdx.y * 128;
    const int bn   = blockIdx.x * 128;
    const int z    = blockIdx.z;

    const hf* B = B0;
    hf* Ch = Ch0;
    hf* Cl = Cl0;
    const float* bias = bias0;
    const int nc = K >> 5;
    int ncl = nc, c0 = 0;
    if (splitk > 1) { ncl = nc / splitk; c0 = z * ncl; }
    else if (z) {
        B += (size_t)z * lstrB;
        if (Ch0) { Ch += (size_t)z * lstrC; if (Cl0) Cl += (size_t)z * lstrC; }
        if (bias0) bias += (size_t)z * lstrBias;
    }

    if (tid == 0) {
        #pragma unroll
        for (int s = 0; s < NSTG; s++) MBARRIER_INIT(sb + 8 * s, 1);
    }
    __syncthreads();

    float acc[4][4][4];
    #pragma unroll
    for (int i = 0; i < 4; i++)
        #pragma unroll
        for (int j = 0; j < 4; j++)
            #pragma unroll
            for (int q = 0; q < 4; q++) acc[i][j][q] = 0.f;

    auto issue = [&](int cl) {
        const int gc = c0 + cl;
        const uint32_t mb  = sb + 8 * (cl & 3);
        const uint32_t dst = sb + TILEOFF + (cl & 3) * STG_BYTES;
        MBARRIER_EXPECT_TX(mb, 24576u);
        bulk_g2s(dst,         Ah + ((size_t)gc * M + bm) * 32, 8192, mb);
        bulk_g2s(dst +  8192, Al + ((size_t)gc * M + bm) * 32, 8192, mb);
        bulk_g2s(dst + 16384, B  + ((size_t)gc * N + bn) * 32, 8192, mb);
    };
    if (tid == 0) {
        const int pre = ncl < NSTG ? ncl : NSTG;
        for (int s = 0; s < pre; s++) issue(s);
    }

    uint32_t a0H[16], a0L[16], b0[8];
    uint32_t a1H[16], a1L[16], b1[8];

    auto lds_step = [&](int u, uint32_t* aH, uint32_t* aL, uint32_t* bf) {
        const uint32_t stA = sb + TILEOFF + ((u >> 1) & 3) * STG_BYTES;
        const uint32_t stB = stA + 16384;
        const int s16 = u & 1;
        #pragma unroll
        for (int mi = 0; mi < 4; mi++) {
            const int row = wm * 64 + mi * 16 + (lane & 15);
            const int q   = s16 * 2 + (lane >> 4);
            const uint32_t ad = stA + row * 64 + ((q ^ ((row >> 1) & 3)) << 4);
            ldmx4(aH + 4 * mi, ad);
            ldmx4(aL + 4 * mi, ad + 8192);
        }
        #pragma unroll
        for (int ni = 0; ni < 2; ni++) {
            const int row = wn * 32 + ni * 16 + (lane & 7) + ((lane >> 4) << 3);
            const int q   = s16 * 2 + ((lane >> 3) & 1);
            const uint32_t bd = stB + row * 64 + ((q ^ ((row >> 1) & 3)) << 4);
            uint32_t t[4];
            ldmx4(t, bd);
            bf[ni*4+0] = t[0]; bf[ni*4+1] = t[1]; bf[ni*4+2] = t[2]; bf[ni*4+3] = t[3];
        }
    };
    auto mma_step = [&](const uint32_t* aH, const uint32_t* aL, const uint32_t* bf) {
        #pragma unroll
        for (int mi = 0; mi < 4; mi++)
            #pragma unroll
            for (int j = 0; j < 4; j++) {
                mma16816(acc[mi][j], aH + 4 * mi, bf + 2 * j);
                mma16816(acc[mi][j], aL + 4 * mi, bf + 2 * j);
            }
    };

    MBARRIER_WAIT_PARITY(sb, 0);
    lds_step(0, a0H, a0L, b0);
    const int total = ncl * 2;
    for (int u = 0; u < total; u += 2) {
        lds_step(u + 1, a1H, a1L, b1);
        __syncthreads();
        const int cl = u >> 1;
        if (tid == 0 && cl + NSTG < ncl) issue(cl + NSTG);
        mma_step(a0H, a0L, b0);
        if (u + 2 < total) {
            const int c2 = cl + 1;
            MBARRIER_WAIT_PARITY(sb + 8 * (c2 & 3), (c2 >> 2) & 1);
            lds_step(u + 2, a0H, a0L, b0);
        }
        mma_step(a1H, a1L, b1);
    }

    // ---- epilogue ----
    if (Cpart) {
        float* P = Cpart + (size_t)z * M * N;
        #pragma unroll
        for (int mi = 0; mi < 4; mi++)
            #pragma unroll
            for (int j = 0; j < 4; j++) {
                const int colb = bn + wn * 32 + j * 8 + (lane & 3) * 2;
                #pragma unroll
                for (int p = 0; p < 2; p++) {
                    const int row = bm + wm * 64 + mi * 16 + (lane >> 2) + 8 * p;
                    *reinterpret_cast<float2*>(&P[(size_t)row * N + colb]) =
                        make_float2(acc[mi][j][p * 2], acc[mi][j][p * 2 + 1]);
                }
            }
        return;
    }
    #pragma unroll
    for (int mi = 0; mi < 4; mi++) {
        #pragma unroll
        for (int j = 0; j < 4; j++) {
            const int colb = bn + wn * 32 + j * 8 + (lane & 3) * 2;
            #pragma unroll
            for (int p = 0; p < 2; p++) {
                const int row = bm + wm * 64 + mi * 16 + (lane >> 2) + 8 * p;
                float v0 = acc[mi][j][p * 2], v1 = acc[mi][j][p * 2 + 1];
                if (bias) { v0 += bias[colb]; v1 += bias[colb + 1]; }
                if (dogelu) {
                    v0 = 0.5f * v0 * (1.f + erff(v0 * 0.70710678118654752f));
                    v1 = 0.5f * v1 * (1.f + erff(v1 * 0.70710678118654752f));
                }
                if (resid) {
                    const float2 r = *reinterpret_cast<const float2*>(&resid[(size_t)row * N + colb]);
                    v0 += r.x; v1 += r.y;
                }
                if (Cf) *reinterpret_cast<float2*>(&Cf[(size_t)row * N + colb]) = make_float2(v0, v1);
                if (Ch) {
                    const __half2 h = __floats2half2_rn(v0, v1);
                    const size_t ti = tiled_idx(row, colb, M);
                    *reinterpret_cast<uint32_t*>(&Ch[ti]) = bits2(h);
                    if (Cl) {
                        const __half2 l = __floats2half2_rn(v0 - __low2float(h),
                                                            v1 - __high2float(h));
                        *reinterpret_cast<uint32_t*>(&Cl[ti]) = bits2(l);
                    }
                }
            }
        }
    }
}

// =====================================================================
// Tensor-core flash attention (fp16 2-term): Q/P split, K/V single plane.
// =====================================================================
#define OFF_Q   1024
#define OFF_KV  (OFF_Q + 16384)          // 2 stages x 16384 (K 8K + V 8K)
#define OFF_P   (OFF_KV + 32768)
#define OFF_SS  (OFF_P + 16384)
#define OFF_ST  (OFF_SS + 64*65*4)
#define ATT_SMEM (OFF_ST + 768)          // 83968

__global__ void __launch_bounds__(256, 1)
attn_tc(const hf* __restrict__ QKVh, const hf* __restrict__ QKVl,
        const hf* __restrict__ Kmh,
        hf* __restrict__ OH, hf* __restrict__ OL)
{
    extern __shared__ char smem[];
    const uint32_t sb = smem_u32(smem);
    const int bt  = blockIdx.x >> 4;
    const int h   = blockIdx.x & 15;
    const int tid = threadIdx.x;
    const int lane = tid & 31;
    const int wid  = tid >> 5;
    const int wm   = wid & 1;
    const int wn   = wid >> 1;
    float* Ss    = reinterpret_cast<float*>(smem + OFF_SS);
    float* mrow  = reinterpret_cast<float*>(smem + OFF_ST);
    float* lrow  = mrow + 64;
    float* frow  = lrow + 64;

    if (tid == 0) { MBARRIER_INIT(sb, 1); MBARRIER_INIT(sb + 8, 1); }

    {
        #pragma unroll
        for (int seg = 0; seg < 4; seg++) {
            const hf* src = (seg < 2 ? QKVh : QKVl) + ((size_t)(2 * h + (seg & 1)) * LROWS + bt * 64) * 32;
            const uint4 v = reinterpret_cast<const uint4*>(src)[tid];
            *reinterpret_cast<uint4*>(smem + OFF_Q + (seg >= 2 ? 8192 : 0) + (seg & 1) * 4096 + tid * 16) = v;
        }
    }
    if (tid < 64) { mrow[tid] = -INFINITY; lrow[tid] = 0.f; }
    __syncthreads();

    auto issueKV = [&](int t) {
        const int st = t & 1;
        const uint32_t mb = sb + 8 * st;
        const uint32_t dst = sb + OFF_KV + st * 16384;
        MBARRIER_EXPECT_TX(mb, 16384u);
        const hf* PH; size_t rbase, nr; int kcK, kcV;
        if (t < 16) { PH = Kmh;  rbase = (size_t)bt * 1024 + t * 64; nr = NMEDIA; kcK = 2*h;      kcV = 32 + 2*h; }
        else        { PH = QKVh; rbase = (size_t)bt * 64;            nr = LROWS;  kcK = 32 + 2*h; kcV = 64 + 2*h; }
        bulk_g2s(dst,          PH + ((size_t)kcK * nr + rbase) * 32,       4096, mb);
        bulk_g2s(dst +  4096,  PH + ((size_t)(kcK + 1) * nr + rbase) * 32, 4096, mb);
        bulk_g2s(dst +  8192,  PH + ((size_t)kcV * nr + rbase) * 32,       4096, mb);
        bulk_g2s(dst + 12288,  PH + ((size_t)(kcV + 1) * nr + rbase) * 32, 4096, mb);
    };
    if (tid == 0) issueKV(0);

    uint32_t qH[2][4][4], qL[2][4][4];
    #pragma unroll
    for (int mi = 0; mi < 2; mi++)
        #pragma unroll
        for (int s = 0; s < 4; s++) {
            const int row = wm * 32 + mi * 16 + (lane & 15);
            const int qq = (((s & 1) * 2 + (lane >> 4)) ^ ((row >> 1) & 3));
            const uint32_t ad = sb + OFF_Q + (s >> 1) * 4096 + row * 64 + (qq << 4);
            ldmx4(qH[mi][s], ad);
            ldmx4(qL[mi][s], ad + 8192);
        }

    float acc[2][2][4];
    #pragma unroll
    for (int i = 0; i < 2; i++)
        #pragma unroll
        for (int j = 0; j < 2; j++)
            #pragma unroll
            for (int q = 0; q < 4; q++) acc[i][j][q] = 0.f;

    for (int t = 0; t < 17; t++) {
        if (tid == 0 && t + 1 < 17) issueKV(t + 1);
        MBARRIER_WAIT_PARITY(sb + 8 * (t & 1), (t >> 1) & 1);
        const uint32_t kb = sb + OFF_KV + (t & 1) * 16384;

        // ---- sim = Q @ K^T ----
        float sc[2][2][4] = {};
        #pragma unroll
        for (int s = 0; s < 4; s++) {
            const int row = wn * 16 + (lane & 7) + ((lane >> 4) << 3);
            const int qq = (((s & 1) * 2 + ((lane >> 3) & 1)) ^ ((row >> 1) & 3));
            const uint32_t ad = kb + (s >> 1) * 4096 + row * 64 + (qq << 4);
            uint32_t tH[4];
            ldmx4(tH, ad);
            uint32_t bh0[2] = {tH[0], tH[1]}, bh1[2] = {tH[2], tH[3]};
            #pragma unroll
            for (int mi = 0; mi < 2; mi++) {
                mma16816(sc[mi][0], qH[mi][s], bh0);
                mma16816(sc[mi][0], qL[mi][s], bh0);
                mma16816(sc[mi][1], qH[mi][s], bh1);
                mma16816(sc[mi][1], qL[mi][s], bh1);
            }
        }
        #pragma unroll
        for (int mi = 0; mi < 2; mi++)
            #pragma unroll
            for (int j = 0; j < 2; j++)
                #pragma unroll
                for (int p = 0; p < 2; p++) {
                    const int r = wm * 32 + mi * 16 + (lane >> 2) + 8 * p;
                    const int col = wn * 16 + j * 8 + (lane & 3) * 2;
                    Ss[r * 65 + col]     = sc[mi][j][p * 2]     * 0.125f;
                    Ss[r * 65 + col + 1] = sc[mi][j][p * 2 + 1] * 0.125f;
                }
        __syncthreads();

        // ---- online softmax ----
        {
            const int r = tid >> 2, qd = tid & 3;
            const int kb2 = qd * 16;
            float tmax = -INFINITY;
            #pragma unroll
            for (int k = 0; k < 16; k++) tmax = fmaxf(tmax, Ss[r * 65 + kb2 + k]);
            tmax = fmaxf(tmax, __shfl_xor_sync(0xffffffffu, tmax, 1));
            tmax = fmaxf(tmax, __shfl_xor_sync(0xffffffffu, tmax, 2));
            const float mold = mrow[r];
            const float mnew = fmaxf(mold, tmax);
            float s = 0.f;
            #pragma unroll
            for (int k = 0; k < 16; k++) {
                const float p = __expf(Ss[r * 65 + kb2 + k] - mnew);
                Ss[r * 65 + kb2 + k] = p;
                s += p;
            }
            s += __shfl_xor_sync(0xffffffffu, s, 1);
            s += __shfl_xor_sync(0xffffffffu, s, 2);
            if (qd == 0) {
                const float fac = __expf(mold - mnew);
                lrow[r] = lrow[r] * fac + s;
                mrow[r] = mnew;
                frow[r] = fac;
            }
        }
        __syncthreads();

        // ---- rescale acc, write P planes ----
        #pragma unroll
        for (int mi = 0; mi < 2; mi++)
            #pragma unroll
            for (int p = 0; p < 2; p++) {
                const float fac = frow[wm * 32 + mi * 16 + (lane >> 2) + 8 * p];
                #pragma unroll
                for (int j = 0; j < 2; j++) {
                    acc[mi][j][p * 2]     *= fac;
                    acc[mi][j][p * 2 + 1] *= fac;
                }
            }
        #pragma unroll
        for (int i = 0; i < 8; i++) {
            const int pi = tid * 8 + i;
            const int q = pi >> 5, kp = pi & 31, k = kp * 2;
            const int kc = k >> 5, kin = k & 31;
            const int qq = ((kin >> 3) ^ ((q >> 1) & 3));
            const int off = OFF_P + kc * 4096 + q * 64 + (qq << 4) + (kin & 7) * 2;
            const float v0 = Ss[q * 65 + k], v1 = Ss[q * 65 + k + 1];
            const __half2 hh = __floats2half2_rn(v0, v1);
            const __half2 ll = __floats2half2_rn(v0 - __low2float(hh),
                                                 v1 - __high2float(hh));
            *reinterpret_cast<uint32_t*>(smem + off)        = bits2(hh);
            *reinterpret_cast<uint32_t*>(smem + off + 8192) = bits2(ll);
        }
        __syncthreads();

        // ---- out += P @ V ----
        #pragma unroll
        for (int s = 0; s < 4; s++) {
            uint32_t pH[2][4], pL[2][4];
            #pragma unroll
            for (int mi = 0; mi < 2; mi++) {
                const int row = wm * 32 + mi * 16 + (lane & 15);
                const int qq = (((s & 1) * 2 + (lane >> 4)) ^ ((row >> 1) & 3));
                const uint32_t ad = sb + OFF_P + (s >> 1) * 4096 + row * 64 + (qq << 4);
                ldmx4(pH[mi], ad);
                ldmx4(pL[mi], ad + 8192);
            }
            const int key  = s * 16 + (lane & 15);
            const int dinb = wn * 16 + ((lane >> 4) << 3);
            const int kcv  = dinb >> 5, din = dinb & 31;
            const int qq   = ((din >> 3) ^ ((key >> 1) & 3));
            const uint32_t ad = kb + 8192 + kcv * 4096 + key * 64 + (qq << 4);
            uint32_t tH[4];
            ldmx4t(tH, ad);
            uint32_t vh0[2] = {tH[0], tH[1]}, vh1[2] = {tH[2], tH[3]};
            #pragma unroll
            for (int mi = 0; mi < 2; mi++) {
                mma16816(acc[mi][0], pH[mi], vh0);
                mma16816(acc[mi][0], pL[mi], vh0);
                mma16816(acc[mi][1], pH[mi], vh1);
                mma16816(acc[mi][1], pL[mi], vh1);
            }
        }
        __syncthreads();
    }

    #pragma unroll
    for (int mi = 0; mi < 2; mi++)
        #pragma unroll
        for (int p = 0; p < 2; p++) {
            const int r = wm * 32 + mi * 16 + (lane >> 2) + 8 * p;
            const float inv = 1.0f / lrow[r];
            #pragma unroll
            for (int j = 0; j < 2; j++) {
                const int col = h * 64 + wn * 16 + j * 8 + (lane & 3) * 2;
                const float v0 = acc[mi][j][p * 2] * inv;
                const float v1 = acc[mi][j][p * 2 + 1] * inv;
                const __half2 hh = __floats2half2_rn(v0, v1);
                const __half2 ll = __floats2half2_rn(v0 - __low2float(hh),
                                                     v1 - __high2float(hh));
                const size_t ti = tiled_idx(bt * 64 + r, col, LROWS);
                *reinterpret_cast<uint32_t*>(&OH[ti]) = bits2(hh);
                *reinterpret_cast<uint32_t*>(&OL[ti]) = bits2(ll);
            }
        }
}

// ---------------- orchestration ----------------
extern "C" void kernel_launch(void* const* d_in, const int* in_sizes, int n_in,
                              void* d_out, int out_size)
{
    (void)in_sizes; (void)n_in; (void)out_size;
    const float* x       = (const float*)d_in[0];
    const float* latents = (const float*)d_in[1];
    const float* nm_g    = (const float*)d_in[2];
    const float* nm_b    = (const float*)d_in[3];
    const float* nl_g    = (const float*)d_in[4];
    const float* nl_b    = (const float*)d_in[5];
    const float* wq      = (const float*)d_in[6];
    const float* wkv     = (const float*)d_in[7];
    const float* wo      = (const float*)d_in[8];
    const float* ff_g    = (const float*)d_in[9];
    const float* ff_b    = (const float*)d_in[10];
    const float* w1      = (const float*)d_in[11];
    const float* w2      = (const float*)d_in[12];
    const float* fin_g   = (const float*)d_in[13];
    const float* fin_b   = (const float*)d_in[14];
    float* out = (float*)d_out;

    hf *xh, *xl, *kvmh, *lnh, *lnl, *qkvh, *qkvl, *ath, *atl, *h1h, *h1l;
    float *lat, *bias, *part;
    cudaGetSymbolAddress((void**)&xh,   g_xh);   cudaGetSymbolAddress((void**)&xl,   g_xl);
    cudaGetSymbolAddress((void**)&kvmh, g_kvmh);
    cudaGetSymbolAddress((void**)&lat,  g_lat);
    cudaGetSymbolAddress((void**)&lnh,  g_lnh);  cudaGetSymbolAddress((void**)&lnl,  g_lnl);
    cudaGetSymbolAddress((void**)&qkvh, g_qkvh); cudaGetSymbolAddress((void**)&qkvl, g_qkvl);
    cudaGetSymbolAddress((void**)&ath,  g_ath);  cudaGetSymbolAddress((void**)&atl,  g_atl);
    cudaGetSymbolAddress((void**)&h1h,  g_h1h);  cudaGetSymbolAddress((void**)&h1l,  g_h1l);
    cudaGetSymbolAddress((void**)&bias, g_bias); cudaGetSymbolAddress((void**)&part, g_part);

    hf *wqkvT, *wkvG, *woT, *w1T, *w2T;
    cudaGetSymbolAddress((void**)&wqkvT, g_wqkvT);
    cudaGetSymbolAddress((void**)&wkvG,  g_wkvG);
    cudaGetSymbolAddress((void**)&woT,   g_woT);
    cudaGetSymbolAddress((void**)&w1T,   g_w1T);
    cudaGetSymbolAddress((void**)&w2T,   g_w2T);

    cudaFuncSetAttribute(gemm_tc, cudaFuncAttributeMaxDynamicSharedMemorySize, GEMM_SMEM);
    cudaFuncSetAttribute(attn_tc, cudaFuncAttributeMaxDynamicSharedMemorySize, ATT_SMEM);
    const dim3 tb(32, 8);

    // ---- weight prep (batched over depth; single fp16 plane) ----
    wsplit_kernel<<<dim3(DIMC/32, DIMC/32, DEPTHL), tb>>>(wq,  nullptr, wqkvT, DIMC, DIMC, 0,    NQKV);
    wsplit_kernel<<<dim3(NKV/32,  DIMC/32, DEPTHL), tb>>>(wkv, nullptr, wqkvT, DIMC, NKV,  DIMC, NQKV);
    wsplit_kernel<<<dim3(NKV/32,  DIMC/32, DEPTHL), tb>>>(wkv, nm_g,    wkvG,  DIMC, NKV,  0,    NKV);
    wsplit_kernel<<<dim3(DIMC/32, DIMC/32, DEPTHL), tb>>>(wo,  nullptr, woT,   DIMC, DIMC, 0,    DIMC);
    wsplit_kernel<<<dim3(FFD/32,  DIMC/32, DEPTHL), tb>>>(w1,  nullptr, w1T,   DIMC, FFD,  0,    FFD);
    wsplit_kernel<<<dim3(DIMC/32, FFD/32,  DEPTHL), tb>>>(w2,  nullptr, w2T,   FFD,  DIMC, 0,    DIMC);
    bias_kernel<<<dim3(NKV/32, DEPTHL), 256>>>(nm_b, wkv, bias);

    ln_kernel<<<NMEDIA, 128>>>(x, nullptr, xh, xl, nullptr, nullptr, NMEDIA);
    init_lat_kernel<<<(LROWS * DIMC) / 256, 256>>>(latents, lat);

    // ---- all-layer media KV (single fp16 plane out) ----
    gemm_tc<<<dim3(NKV/128, NMEDIA/128, DEPTHL), 256, GEMM_SMEM>>>(
        xh, xl, wkvG, nullptr, kvmh, nullptr, NMEDIA, NKV, DIMC,
        bias, nullptr, 0,
        (size_t)NKV*DIMC, (size_t)NMEDIA*NKV, NKV, 1, nullptr);

    for (int i = 0; i < DEPTHL; i++) {
        ln_kernel<<<LROWS, 128>>>(lat, nullptr, lnh, lnl,
                                  nl_g + (size_t)i*DIMC, nl_b + (size_t)i*DIMC, LROWS);
        // fused Q|K|V latent GEMM (hi+lo out; K/V parts use hi only)
        gemm_tc<<<dim3(NQKV/128, LROWS/128), 256, GEMM_SMEM>>>(
            lnh, lnl, wqkvT + (size_t)i*NQKV*DIMC,
            nullptr, qkvh, qkvl, LROWS, NQKV, DIMC, nullptr, nullptr, 0,
            0, 0, 0, 1, nullptr);
        attn_tc<<<BTOT * HEADS, 256, ATT_SMEM>>>(
            qkvh, qkvl, kvmh + (size_t)i*NMEDIA*NKV, ath, atl);
        // lat += attn @ wo (split-K 2)
        gemm_tc<<<dim3(DIMC/128, LROWS/128, 2), 256, GEMM_SMEM>>>(
            ath, atl, woT + (size_t)i*DIMC*DIMC,
            nullptr, nullptr, nullptr, LROWS, DIMC, DIMC, nullptr, nullptr, 0,
            0, 0, 0, 2, part);
        redk_kernel<<<(LROWS*DIMC)/256, 256>>>(part, 2, lat, lat);
        ln_kernel<<<LROWS, 128>>>(lat, nullptr, lnh, lnl,
                                  ff_g + (size_t)i*DIMC, ff_b + (size_t)i*DIMC, LROWS);
        gemm_tc<<<dim3(FFD/128, LROWS/128), 256, GEMM_SMEM>>>(
            lnh, lnl, w1T + (size_t)i*FFD*DIMC,
            nullptr, h1h, h1l, LROWS, FFD, DIMC, nullptr, nullptr, 1,
            0, 0, 0, 1, nullptr);
        // lat += gelu(h1) @ w2 (split-K 4)
        gemm_tc<<<dim3(DIMC/128, LROWS/128, 4), 256, GEMM_SMEM>>>(
            h1h, h1l, w2T + (size_t)i*DIMC*FFD,
            nullptr, nullptr, nullptr, LROWS, DIMC, FFD, nullptr, nullptr, 0,
            0, 0, 0, 4, part);
        redk_kernel<<<(LROWS*DIMC)/256, 256>>>(part, 4, lat, lat);
    }
    ln_kernel<<<LROWS, 128>>>(lat, out, nullptr, nullptr, fin_g, fin_b, LROWS);
}

// round 9
// speedup vs baseline: 5.4152x; 1.2563x over previous
#include <cuda_runtime.h>
#include <cuda_fp16.h>
#include <math.h>
#include <stdint.h>

// ---------------- problem constants ----------------
#define DIMC   1024
#define DEPTHL 6
#define HEADS  16
#define DHEAD  64
#define NKV    2048
#define NQKV   3072
#define FFD    4096
#define BTOT   32
#define MEDIA  1024
#define NMEDIA (BTOT*MEDIA)          // 32768
#define NLAT   64
#define LROWS  (BTOT*NLAT)           // 2048

typedef __half hf;

// ---------------- scratch ----------------
__device__ __align__(1024) hf    g_xh  [(size_t)NMEDIA*DIMC];
__device__ __align__(1024) hf    g_kvmh[(size_t)DEPTHL*NMEDIA*NKV];  // single plane
__device__ float g_lat [LROWS*DIMC];
__device__ __align__(1024) hf    g_lnh [LROWS*DIMC];
__device__ __align__(1024) hf    g_lnl [LROWS*DIMC];
__device__ __align__(1024) hf    g_qkvh[(size_t)LROWS*NQKV];
__device__ __align__(1024) hf    g_qkvl[(size_t)LROWS*NQKV];
__device__ __align__(1024) hf    g_ath [LROWS*DIMC];
__device__ __align__(1024) hf    g_atl [LROWS*DIMC];
__device__ __align__(1024) hf    g_h1h [(size_t)LROWS*FFD];
__device__ __align__(1024) hf    g_h1l [(size_t)LROWS*FFD];
__device__ float g_bias[DEPTHL*NKV];
__device__ float g_part[(size_t)4*LROWS*DIMC];

// weight planes (single fp16, B-side), chunk-tiled [K/32][N][32]
__device__ __align__(1024) hf g_wqkvT[(size_t)DEPTHL*NQKV*DIMC];
__device__ __align__(1024) hf g_wkvG [(size_t)DEPTHL*NKV*DIMC];
__device__ __align__(1024) hf g_woT  [(size_t)DEPTHL*DIMC*DIMC];
__device__ __align__(1024) hf g_w1T  [(size_t)DEPTHL*FFD*DIMC];
__device__ __align__(1024) hf g_w2T  [(size_t)DEPTHL*DIMC*FFD];

// ---------------- helpers ----------------
__device__ __forceinline__ uint32_t smem_u32(const void* p) {
    return (uint32_t)__cvta_generic_to_shared(p);
}
__device__ __forceinline__ size_t tiled_idx(int row, int k, int nrows) {
    const int kc = k >> 5, kin = k & 31;
    const int q = kin >> 3, b = kin & 7;
    const int qs = q ^ ((row >> 1) & 3);
    return ((size_t)kc * nrows + row) * 32 + qs * 8 + b;
}
__device__ __forceinline__ void bulk_g2s(uint32_t dst, const void* src, uint32_t bytes, uint32_t mbar) {
    asm volatile("cp.async.bulk.shared::cluster.global.mbarrier::complete_tx::bytes [%0], [%1], %2, [%3];"
                 :: "r"(dst), "l"(src), "r"(bytes), "r"(mbar) : "memory");
}
#define MBARRIER_INIT(addr, cnt) \
    asm volatile("mbarrier.init.shared.b64 [%0], %1;" :: "r"(addr), "r"(cnt) : "memory")
#define MBARRIER_EXPECT_TX(addr, tx) \
    asm volatile("mbarrier.arrive.expect_tx.shared.b64 _, [%0], %1;" :: "r"(addr), "r"(tx) : "memory")
#define MBARRIER_WAIT_PARITY(addr, par) do { \
    uint32_t _m = (addr), _p = (par), _d; \
    asm volatile("{\n\t.reg .pred p;\n\t" \
        "mbarrier.try_wait.parity.acquire.cta.shared::cta.b64 p, [%1], %2;\n\t" \
        "selp.b32 %0, 1, 0, p;\n\t}" : "=r"(_d) : "r"(_m), "r"(_p) : "memory"); \
    if (!_d) { \
        asm volatile("{\n\t.reg .pred P1;\n\t" \
            "WL_%=:\n\t" \
            "mbarrier.try_wait.parity.acquire.cta.shared::cta.b64 P1, [%0], %1, 0x989680;\n\t" \
            "@P1 bra.uni WD_%=;\n\tbra.uni WL_%=;\n\tWD_%=:\n\t}" \
            :: "r"(_m), "r"(_p) : "memory"); \
    } } while (0)

__device__ __forceinline__ void ldmx4(uint32_t* r, uint32_t a) {
    asm volatile("ldmatrix.sync.aligned.m8n8.x4.shared.b16 {%0,%1,%2,%3}, [%4];"
                 : "=r"(r[0]), "=r"(r[1]), "=r"(r[2]), "=r"(r[3]) : "r"(a));
}
__device__ __forceinline__ void ldmx4t(uint32_t* r, uint32_t a) {
    asm volatile("ldmatrix.sync.aligned.m8n8.x4.trans.shared.b16 {%0,%1,%2,%3}, [%4];"
                 : "=r"(r[0]), "=r"(r[1]), "=r"(r[2]), "=r"(r[3]) : "r"(a));
}
__device__ __forceinline__ void mma16816(float* d, const uint32_t* a, const uint32_t* b) {
    asm volatile("mma.sync.aligned.m16n8k16.row.col.f32.f16.f16.f32 "
                 "{%0,%1,%2,%3},{%4,%5,%6,%7},{%8,%9},{%0,%1,%2,%3};"
                 : "+f"(d[0]), "+f"(d[1]), "+f"(d[2]), "+f"(d[3])
                 : "r"(a[0]), "r"(a[1]), "r"(a[2]), "r"(a[3]),
                   "r"(b[0]), "r"(b[1]));
}
__device__ __forceinline__ uint32_t bits2(__half2 h) {
    return *reinterpret_cast<uint32_t*>(&h);
}

// ---------------- LayerNorm: fp32 in -> fp32 out and/or tiled fp16 planes ----------
__global__ void ln_kernel(const float* __restrict__ in,
                          float* __restrict__ outF,
                          hf* __restrict__ outH, hf* __restrict__ outL,
                          const float* __restrict__ g, const float* __restrict__ b,
                          int nrows)
{
    const int row = blockIdx.x;
    const float* x = in + (size_t)row * DIMC;
    float s = 0.f, sq = 0.f;
    for (int c = threadIdx.x; c < DIMC; c += blockDim.x) {
        float v = x[c]; s += v; sq += v * v;
    }
    __shared__ float sh[64];
    #pragma unroll
    for (int o = 16; o > 0; o >>= 1) {
        s  += __shfl_down_sync(0xffffffffu, s,  o);
        sq += __shfl_down_sync(0xffffffffu, sq, o);
    }
    const int wid = threadIdx.x >> 5, lid = threadIdx.x & 31;
    if (lid == 0) { sh[wid] = s; sh[wid + 32] = sq; }
    __syncthreads();
    if (threadIdx.x == 0) {
        float ts = 0.f, tsq = 0.f;
        const int nw = blockDim.x >> 5;
        for (int i = 0; i < nw; i++) { ts += sh[i]; tsq += sh[i + 32]; }
        const float mean = ts * (1.0f / DIMC);
        const float var  = tsq * (1.0f / DIMC) - mean * mean;
        sh[0] = mean; sh[1] = rsqrtf(var + 1e-5f);
    }
    __syncthreads();
    const float mean = sh[0], rstd = sh[1];

    for (int k0 = threadIdx.x * 8; k0 < DIMC; k0 += blockDim.x * 8) {
        float v[8];
        #pragma unroll
        for (int e = 0; e < 8; e++) {
            float t = (x[k0 + e] - mean) * rstd;
            if (g) t = t * g[k0 + e] + b[k0 + e];
            v[e] = t;
        }
        if (outF) {
            float* o = outF + (size_t)row * DIMC + k0;
            #pragma unroll
            for (int e = 0; e < 8; e++) o[e] = v[e];
        }
        if (outH) {
            uint32_t hq[4], lq[4];
            #pragma unroll
            for (int e = 0; e < 4; e++) {
                const __half2 h = __floats2half2_rn(v[2*e], v[2*e+1]);
                hq[e] = bits2(h);
                if (outL) {
                    const __half2 l = __floats2half2_rn(v[2*e]   - __low2float(h),
                                                        v[2*e+1] - __high2float(h));
                    lq[e] = bits2(l);
                }
            }
            const size_t ti = tiled_idx(row, k0, nrows);
            *reinterpret_cast<uint4*>(&outH[ti]) = make_uint4(hq[0], hq[1], hq[2], hq[3]);
            if (outL)
                *reinterpret_cast<uint4*>(&outL[ti]) = make_uint4(lq[0], lq[1], lq[2], lq[3]);
        }
    }
}

// ---------------- bias: all layers, k-parallel ----------------
__global__ void bias_kernel(const float* __restrict__ nm_b,
                            const float* __restrict__ wkv, float* __restrict__ out)
{
    const int layer = blockIdx.y;
    const int tid = threadIdx.x;
    const int n  = blockIdx.x * 32 + (tid & 31);
    const int ks = tid >> 5;
    const float* bv = nm_b + (size_t)layer * DIMC;
    const float* W  = wkv  + (size_t)layer * DIMC * NKV;
    float s = 0.f;
    #pragma unroll 4
    for (int k = ks * 128; k < ks * 128 + 128; k++)
        s += bv[k] * __ldg(&W[(size_t)k * NKV + n]);
    __shared__ float red[8][32];
    red[ks][tid & 31] = s;
    __syncthreads();
    if (ks == 0) {
        float t = 0.f;
        #pragma unroll
        for (int i = 0; i < 8; i++) t += red[i][tid & 31];
        out[(size_t)layer * NKV + n] = t;
    }
}

__global__ void init_lat_kernel(const float* __restrict__ latents, float* __restrict__ lat)
{
    const int idx = blockIdx.x * blockDim.x + threadIdx.x;
    lat[idx] = latents[idx & (NLAT * DIMC - 1)];
}

// ---------------- split-K reduce (+residual) ----------------
__global__ void redk_kernel(const float* __restrict__ part, int S,
                            const float* __restrict__ resid, float* __restrict__ outF)
{
    const size_t i = (size_t)blockIdx.x * blockDim.x + threadIdx.x;
    const size_t MN = (size_t)gridDim.x * blockDim.x;
    float v = resid ? resid[i] : 0.f;
    for (int s = 0; s < S; s++) v += part[(size_t)s * MN + i];
    outF[i] = v;
}

// ---------------- weight transpose + gamma + fp16 quantize (batched over depth) ----
__global__ void wsplit_kernel(const float* __restrict__ W0, const float* __restrict__ g0,
                              hf* __restrict__ T0, int K, int N, int nofs, int ntot)
{
    const int z = blockIdx.z;
    const float* W = W0 + (size_t)z * K * N;
    const float* g = g0 ? g0 + (size_t)z * K : nullptr;
    hf* T = T0 + (size_t)z * ntot * K;
    __shared__ float t[32][33];
    const int n0 = blockIdx.x * 32, k0 = blockIdx.y * 32;
    const int tx = threadIdx.x, ty = threadIdx.y;
    #pragma unroll
    for (int i = 0; i < 4; i++) {
        float v = W[(size_t)(k0 + ty + 8 * i) * N + n0 + tx];
        if (g) v *= g[k0 + ty + 8 * i];
        t[ty + 8 * i][tx] = v;
    }
    __syncthreads();
    #pragma unroll
    for (int i = 0; i < 4; i++) {
        const int n = n0 + ty + 8 * i, k = k0 + tx;
        T[tiled_idx(nofs + n, k, ntot)] = __float2half_rn(t[tx][ty + 8 * i]);
    }
}

// =====================================================================
// fp16 HMMA GEMM, AT = number of A-side terms (1 or 2).
// C = epi((Ah[+Al]) @ B^T), B single fp16 plane. k16-pipelined.
// grid.z = layers (lstr*) OR split-K partitions (splitk>1, Cpart).
// =====================================================================
#define NSTG 4
#define STG_BYTES 24576              // Ah 8K | Al 8K (unused if AT=1) | B 8K
#define TILEOFF 1024
#define GEMM_SMEM (TILEOFF + NSTG*STG_BYTES)   // 99328

template <int AT>
__global__ void __launch_bounds__(256, 1)
gemm_tc(const hf* __restrict__ Ah, const hf* __restrict__ Al,
        const hf* __restrict__ B0,
        float* __restrict__ Cf, hf* __restrict__ Ch0, hf* __restrict__ Cl0,
        int M, int N, int K,
        const float* __restrict__ bias0, const float* __restrict__ resid, int dogelu,
        size_t lstrB, size_t lstrC, int lstrBias,
        int splitk, float* __restrict__ Cpart)
{
    extern __shared__ char smem[];
    const uint32_t sb = smem_u32(smem);
    const int tid  = threadIdx.x;
    const int lane = tid & 31;
    const int wid  = tid >> 5;
    const int wm   = wid & 1;
    const int wn   = wid >> 1;
    const int bm   = blockIdx.y * 128;
    const int bn   = blockIdx.x * 128;
    const int z    = blockIdx.z;

    const hf* B = B0;
    hf* Ch = Ch0;
    hf* Cl = Cl0;
    const float* bias = bias0;
    const int nc = K >> 5;
    int ncl = nc, c0 = 0;
    if (splitk > 1) { ncl = nc / splitk; c0 = z * ncl; }
    else if (z) {
        B += (size_t)z * lstrB;
        if (Ch0) { Ch += (size_t)z * lstrC; if (Cl0) Cl += (size_t)z * lstrC; }
        if (bias0) bias += (size_t)z * lstrBias;
    }

    if (tid == 0) {
        #pragma unroll
        for (int s = 0; s < NSTG; s++) MBARRIER_INIT(sb + 8 * s, 1);
    }
    __syncthreads();

    float acc[4][4][4];
    #pragma unroll
    for (int i = 0; i < 4; i++)
        #pragma unroll
        for (int j = 0; j < 4; j++)
            #pragma unroll
            for (int q = 0; q < 4; q++) acc[i][j][q] = 0.f;

    auto issue = [&](int cl) {
        const int gc = c0 + cl;
        const uint32_t mb  = sb + 8 * (cl & 3);
        const uint32_t dst = sb + TILEOFF + (cl & 3) * STG_BYTES;
        MBARRIER_EXPECT_TX(mb, AT == 2 ? 24576u : 16384u);
        bulk_g2s(dst,         Ah + ((size_t)gc * M + bm) * 32, 8192, mb);
        if (AT == 2)
            bulk_g2s(dst + 8192, Al + ((size_t)gc * M + bm) * 32, 8192, mb);
        bulk_g2s(dst + 16384, B  + ((size_t)gc * N + bn) * 32, 8192, mb);
    };
    if (tid == 0) {
        const int pre = ncl < NSTG ? ncl : NSTG;
        for (int s = 0; s < pre; s++) issue(s);
    }

    uint32_t a0H[16], a0L[16], b0[8];
    uint32_t a1H[16], a1L[16], b1[8];

    auto lds_step = [&](int u, uint32_t* aH, uint32_t* aL, uint32_t* bf) {
        const uint32_t stA = sb + TILEOFF + ((u >> 1) & 3) * STG_BYTES;
        const uint32_t stB = stA + 16384;
        const int s16 = u & 1;
        #pragma unroll
        for (int mi = 0; mi < 4; mi++) {
            const int row = wm * 64 + mi * 16 + (lane & 15);
            const int q   = s16 * 2 + (lane >> 4);
            const uint32_t ad = stA + row * 64 + ((q ^ ((row >> 1) & 3)) << 4);
            ldmx4(aH + 4 * mi, ad);
            if (AT == 2) ldmx4(aL + 4 * mi, ad + 8192);
        }
        #pragma unroll
        for (int ni = 0; ni < 2; ni++) {
            const int row = wn * 32 + ni * 16 + (lane & 7) + ((lane >> 4) << 3);
            const int q   = s16 * 2 + ((lane >> 3) & 1);
            const uint32_t bd = stB + row * 64 + ((q ^ ((row >> 1) & 3)) << 4);
            uint32_t t[4];
            ldmx4(t, bd);
            bf[ni*4+0] = t[0]; bf[ni*4+1] = t[1]; bf[ni*4+2] = t[2]; bf[ni*4+3] = t[3];
        }
    };
    auto mma_step = [&](const uint32_t* aH, const uint32_t* aL, const uint32_t* bf) {
        #pragma unroll
        for (int mi = 0; mi < 4; mi++)
            #pragma unroll
            for (int j = 0; j < 4; j++) {
                mma16816(acc[mi][j], aH + 4 * mi, bf + 2 * j);
                if (AT == 2) mma16816(acc[mi][j], aL + 4 * mi, bf + 2 * j);
            }
    };

    MBARRIER_WAIT_PARITY(sb, 0);
    lds_step(0, a0H, a0L, b0);
    const int total = ncl * 2;
    for (int u = 0; u < total; u += 2) {
        lds_step(u + 1, a1H, a1L, b1);
        __syncthreads();
        const int cl = u >> 1;
        if (tid == 0 && cl + NSTG < ncl) issue(cl + NSTG);
        mma_step(a0H, a0L, b0);
        if (u + 2 < total) {
            const int c2 = cl + 1;
            MBARRIER_WAIT_PARITY(sb + 8 * (c2 & 3), (c2 >> 2) & 1);
            lds_step(u + 2, a0H, a0L, b0);
        }
        mma_step(a1H, a1L, b1);
    }

    // ---- epilogue ----
    if (Cpart) {
        float* P = Cpart + (size_t)z * M * N;
        #pragma unroll
        for (int mi = 0; mi < 4; mi++)
            #pragma unroll
            for (int j = 0; j < 4; j++) {
                const int colb = bn + wn * 32 + j * 8 + (lane & 3) * 2;
                #pragma unroll
                for (int p = 0; p < 2; p++) {
                    const int row = bm + wm * 64 + mi * 16 + (lane >> 2) + 8 * p;
                    *reinterpret_cast<float2*>(&P[(size_t)row * N + colb]) =
                        make_float2(acc[mi][j][p * 2], acc[mi][j][p * 2 + 1]);
                }
            }
        return;
    }
    #pragma unroll
    for (int mi = 0; mi < 4; mi++) {
        #pragma unroll
        for (int j = 0; j < 4; j++) {
            const int colb = bn + wn * 32 + j * 8 + (lane & 3) * 2;
            #pragma unroll
            for (int p = 0; p < 2; p++) {
                const int row = bm + wm * 64 + mi * 16 + (lane >> 2) + 8 * p;
                float v0 = acc[mi][j][p * 2], v1 = acc[mi][j][p * 2 + 1];
                if (bias) { v0 += bias[colb]; v1 += bias[colb + 1]; }
                if (dogelu) {
                    v0 = 0.5f * v0 * (1.f + erff(v0 * 0.70710678118654752f));
                    v1 = 0.5f * v1 * (1.f + erff(v1 * 0.70710678118654752f));
                }
                if (resid) {
                    const float2 r = *reinterpret_cast<const float2*>(&resid[(size_t)row * N + colb]);
                    v0 += r.x; v1 += r.y;
                }
                if (Cf) *reinterpret_cast<float2*>(&Cf[(size_t)row * N + colb]) = make_float2(v0, v1);
                if (Ch) {
                    const __half2 h = __floats2half2_rn(v0, v1);
                    const size_t ti = tiled_idx(row, colb, M);
                    *reinterpret_cast<uint32_t*>(&Ch[ti]) = bits2(h);
                    if (Cl) {
                        const __half2 l = __floats2half2_rn(v0 - __low2float(h),
                                                            v1 - __high2float(h));
                        *reinterpret_cast<uint32_t*>(&Cl[ti]) = bits2(l);
                    }
                }
            }
        }
    }
}

// =====================================================================
// Tensor-core flash attention (fp16 2-term Q/P, single-plane K/V).
// =====================================================================
#define OFF_Q   1024
#define OFF_KV  (OFF_Q + 16384)
#define OFF_P   (OFF_KV + 32768)
#define OFF_SS  (OFF_P + 16384)
#define OFF_ST  (OFF_SS + 64*65*4)
#define ATT_SMEM (OFF_ST + 768)

__global__ void __launch_bounds__(256, 1)
attn_tc(const hf* __restrict__ QKVh, const hf* __restrict__ QKVl,
        const hf* __restrict__ Kmh,
        hf* __restrict__ OH, hf* __restrict__ OL)
{
    extern __shared__ char smem[];
    const uint32_t sb = smem_u32(smem);
    const int bt  = blockIdx.x >> 4;
    const int h   = blockIdx.x & 15;
    const int tid = threadIdx.x;
    const int lane = tid & 31;
    const int wid  = tid >> 5;
    const int wm   = wid & 1;
    const int wn   = wid >> 1;
    float* Ss    = reinterpret_cast<float*>(smem + OFF_SS);
    float* mrow  = reinterpret_cast<float*>(smem + OFF_ST);
    float* lrow  = mrow + 64;
    float* frow  = lrow + 64;

    if (tid == 0) { MBARRIER_INIT(sb, 1); MBARRIER_INIT(sb + 8, 1); }

    {
        #pragma unroll
        for (int seg = 0; seg < 4; seg++) {
            const hf* src = (seg < 2 ? QKVh : QKVl) + ((size_t)(2 * h + (seg & 1)) * LROWS + bt * 64) * 32;
            const uint4 v = reinterpret_cast<const uint4*>(src)[tid];
            *reinterpret_cast<uint4*>(smem + OFF_Q + (seg >= 2 ? 8192 : 0) + (seg & 1) * 4096 + tid * 16) = v;
        }
    }
    if (tid < 64) { mrow[tid] = -INFINITY; lrow[tid] = 0.f; }
    __syncthreads();

    auto issueKV = [&](int t) {
        const int st = t & 1;
        const uint32_t mb = sb + 8 * st;
        const uint32_t dst = sb + OFF_KV + st * 16384;
        MBARRIER_EXPECT_TX(mb, 16384u);
        const hf* PH; size_t rbase, nr; int kcK, kcV;
        if (t < 16) { PH = Kmh;  rbase = (size_t)bt * 1024 + t * 64; nr = NMEDIA; kcK = 2*h;      kcV = 32 + 2*h; }
        else        { PH = QKVh; rbase = (size_t)bt * 64;            nr = LROWS;  kcK = 32 + 2*h; kcV = 64 + 2*h; }
        bulk_g2s(dst,          PH + ((size_t)kcK * nr + rbase) * 32,       4096, mb);
        bulk_g2s(dst +  4096,  PH + ((size_t)(kcK + 1) * nr + rbase) * 32, 4096, mb);
        bulk_g2s(dst +  8192,  PH + ((size_t)kcV * nr + rbase) * 32,       4096, mb);
        bulk_g2s(dst + 12288,  PH + ((size_t)(kcV + 1) * nr + rbase) * 32, 4096, mb);
    };
    if (tid == 0) issueKV(0);

    uint32_t qH[2][4][4], qL[2][4][4];
    #pragma unroll
    for (int mi = 0; mi < 2; mi++)
        #pragma unroll
        for (int s = 0; s < 4; s++) {
            const int row = wm * 32 + mi * 16 + (lane & 15);
            const int qq = (((s & 1) * 2 + (lane >> 4)) ^ ((row >> 1) & 3));
            const uint32_t ad = sb + OFF_Q + (s >> 1) * 4096 + row * 64 + (qq << 4);
            ldmx4(qH[mi][s], ad);
            ldmx4(qL[mi][s], ad + 8192);
        }

    float acc[2][2][4];
    #pragma unroll
    for (int i = 0; i < 2; i++)
        #pragma unroll
        for (int j = 0; j < 2; j++)
            #pragma unroll
            for (int q = 0; q < 4; q++) acc[i][j][q] = 0.f;

    for (int t = 0; t < 17; t++) {
        if (tid == 0 && t + 1 < 17) issueKV(t + 1);
        MBARRIER_WAIT_PARITY(sb + 8 * (t & 1), (t >> 1) & 1);
        const uint32_t kb = sb + OFF_KV + (t & 1) * 16384;

        float sc[2][2][4] = {};
        #pragma unroll
        for (int s = 0; s < 4; s++) {
            const int row = wn * 16 + (lane & 7) + ((lane >> 4) << 3);
            const int qq = (((s & 1) * 2 + ((lane >> 3) & 1)) ^ ((row >> 1) & 3));
            const uint32_t ad = kb + (s >> 1) * 4096 + row * 64 + (qq << 4);
            uint32_t tH[4];
            ldmx4(tH, ad);
            uint32_t bh0[2] = {tH[0], tH[1]}, bh1[2] = {tH[2], tH[3]};
            #pragma unroll
            for (int mi = 0; mi < 2; mi++) {
                mma16816(sc[mi][0], qH[mi][s], bh0);
                mma16816(sc[mi][0], qL[mi][s], bh0);
                mma16816(sc[mi][1], qH[mi][s], bh1);
                mma16816(sc[mi][1], qL[mi][s], bh1);
            }
        }
        #pragma unroll
        for (int mi = 0; mi < 2; mi++)
            #pragma unroll
            for (int j = 0; j < 2; j++)
                #pragma unroll
                for (int p = 0; p < 2; p++) {
                    const int r = wm * 32 + mi * 16 + (lane >> 2) + 8 * p;
                    const int col = wn * 16 + j * 8 + (lane & 3) * 2;
                    Ss[r * 65 + col]     = sc[mi][j][p * 2]     * 0.125f;
                    Ss[r * 65 + col + 1] = sc[mi][j][p * 2 + 1] * 0.125f;
                }
        __syncthreads();

        {
            const int r = tid >> 2, qd = tid & 3;
            const int kb2 = qd * 16;
            float tmax = -INFINITY;
            #pragma unroll
            for (int k = 0; k < 16; k++) tmax = fmaxf(tmax, Ss[r * 65 + kb2 + k]);
            tmax = fmaxf(tmax, __shfl_xor_sync(0xffffffffu, tmax, 1));
            tmax = fmaxf(tmax, __shfl_xor_sync(0xffffffffu, tmax, 2));
            const float mold = mrow[r];
            const float mnew = fmaxf(mold, tmax);
            float s = 0.f;
            #pragma unroll
            for (int k = 0; k < 16; k++) {
                const float p = __expf(Ss[r * 65 + kb2 + k] - mnew);
                Ss[r * 65 + kb2 + k] = p;
                s += p;
            }
            s += __shfl_xor_sync(0xffffffffu, s, 1);
            s += __shfl_xor_sync(0xffffffffu, s, 2);
            if (qd == 0) {
                const float fac = __expf(mold - mnew);
                lrow[r] = lrow[r] * fac + s;
                mrow[r] = mnew;
                frow[r] = fac;
            }
        }
        __syncthreads();

        #pragma unroll
        for (int mi = 0; mi < 2; mi++)
            #pragma unroll
            for (int p = 0; p < 2; p++) {
                const float fac = frow[wm * 32 + mi * 16 + (lane >> 2) + 8 * p];
                #pragma unroll
                for (int j = 0; j < 2; j++) {
                    acc[mi][j][p * 2]     *= fac;
                    acc[mi][j][p * 2 + 1] *= fac;
                }
            }
        #pragma unroll
        for (int i = 0; i < 8; i++) {
            const int pi = tid * 8 + i;
            const int q = pi >> 5, kp = pi & 31, k = kp * 2;
            const int kc = k >> 5, kin = k & 31;
            const int qq = ((kin >> 3) ^ ((q >> 1) & 3));
            const int off = OFF_P + kc * 4096 + q * 64 + (qq << 4) + (kin & 7) * 2;
            const float v0 = Ss[q * 65 + k], v1 = Ss[q * 65 + k + 1];
            const __half2 hh = __floats2half2_rn(v0, v1);
            const __half2 ll = __floats2half2_rn(v0 - __low2float(hh),
                                                 v1 - __high2float(hh));
            *reinterpret_cast<uint32_t*>(smem + off)        = bits2(hh);
            *reinterpret_cast<uint32_t*>(smem + off + 8192) = bits2(ll);
        }
        __syncthreads();

        #pragma unroll
        for (int s = 0; s < 4; s++) {
            uint32_t pH[2][4], pL[2][4];
            #pragma unroll
            for (int mi = 0; mi < 2; mi++) {
                const int row = wm * 32 + mi * 16 + (lane & 15);
                const int qq = (((s & 1) * 2 + (lane >> 4)) ^ ((row >> 1) & 3));
                const uint32_t ad = sb + OFF_P + (s >> 1) * 4096 + row * 64 + (qq << 4);
                ldmx4(pH[mi], ad);
                ldmx4(pL[mi], ad + 8192);
            }
            const int key  = s * 16 + (lane & 15);
            const int dinb = wn * 16 + ((lane >> 4) << 3);
            const int kcv  = dinb >> 5, din = dinb & 31;
            const int qq   = ((din >> 3) ^ ((key >> 1) & 3));
            const uint32_t ad = kb + 8192 + kcv * 4096 + key * 64 + (qq << 4);
            uint32_t tH[4];
            ldmx4t(tH, ad);
            uint32_t vh0[2] = {tH[0], tH[1]}, vh1[2] = {tH[2], tH[3]};
            #pragma unroll
            for (int mi = 0; mi < 2; mi++) {
                mma16816(acc[mi][0], pH[mi], vh0);
                mma16816(acc[mi][0], pL[mi], vh0);
                mma16816(acc[mi][1], pH[mi], vh1);
                mma16816(acc[mi][1], pL[mi], vh1);
            }
        }
        __syncthreads();
    }

    #pragma unroll
    for (int mi = 0; mi < 2; mi++)
        #pragma unroll
        for (int p = 0; p < 2; p++) {
            const int r = wm * 32 + mi * 16 + (lane >> 2) + 8 * p;
            const float inv = 1.0f / lrow[r];
            #pragma unroll
            for (int j = 0; j < 2; j++) {
                const int col = h * 64 + wn * 16 + j * 8 + (lane & 3) * 2;
                const float v0 = acc[mi][j][p * 2] * inv;
                const float v1 = acc[mi][j][p * 2 + 1] * inv;
                const __half2 hh = __floats2half2_rn(v0, v1);
                const __half2 ll = __floats2half2_rn(v0 - __low2float(hh),
                                                     v1 - __high2float(hh));
                const size_t ti = tiled_idx(bt * 64 + r, col, LROWS);
                *reinterpret_cast<uint32_t*>(&OH[ti]) = bits2(hh);
                *reinterpret_cast<uint32_t*>(&OL[ti]) = bits2(ll);
            }
        }
}

// ---------------- orchestration ----------------
extern "C" void kernel_launch(void* const* d_in, const int* in_sizes, int n_in,
                              void* d_out, int out_size)
{
    (void)in_sizes; (void)n_in; (void)out_size;
    const float* x       = (const float*)d_in[0];
    const float* latents = (const float*)d_in[1];
    const float* nm_g    = (const float*)d_in[2];
    const float* nm_b    = (const float*)d_in[3];
    const float* nl_g    = (const float*)d_in[4];
    const float* nl_b    = (const float*)d_in[5];
    const float* wq      = (const float*)d_in[6];
    const float* wkv     = (const float*)d_in[7];
    const float* wo      = (const float*)d_in[8];
    const float* ff_g    = (const float*)d_in[9];
    const float* ff_b    = (const float*)d_in[10];
    const float* w1      = (const float*)d_in[11];
    const float* w2      = (const float*)d_in[12];
    const float* fin_g   = (const float*)d_in[13];
    const float* fin_b   = (const float*)d_in[14];
    float* out = (float*)d_out;

    hf *xh, *kvmh, *lnh, *lnl, *qkvh, *qkvl, *ath, *atl, *h1h, *h1l;
    float *lat, *bias, *part;
    cudaGetSymbolAddress((void**)&xh,   g_xh);
    cudaGetSymbolAddress((void**)&kvmh, g_kvmh);
    cudaGetSymbolAddress((void**)&lat,  g_lat);
    cudaGetSymbolAddress((void**)&lnh,  g_lnh);  cudaGetSymbolAddress((void**)&lnl,  g_lnl);
    cudaGetSymbolAddress((void**)&qkvh, g_qkvh); cudaGetSymbolAddress((void**)&qkvl, g_qkvl);
    cudaGetSymbolAddress((void**)&ath,  g_ath);  cudaGetSymbolAddress((void**)&atl,  g_atl);
    cudaGetSymbolAddress((void**)&h1h,  g_h1h);  cudaGetSymbolAddress((void**)&h1l,  g_h1l);
    cudaGetSymbolAddress((void**)&bias, g_bias); cudaGetSymbolAddress((void**)&part, g_part);

    hf *wqkvT, *wkvG, *woT, *w1T, *w2T;
    cudaGetSymbolAddress((void**)&wqkvT, g_wqkvT);
    cudaGetSymbolAddress((void**)&wkvG,  g_wkvG);
    cudaGetSymbolAddress((void**)&woT,   g_woT);
    cudaGetSymbolAddress((void**)&w1T,   g_w1T);
    cudaGetSymbolAddress((void**)&w2T,   g_w2T);

    cudaFuncSetAttribute(gemm_tc<1>, cudaFuncAttributeMaxDynamicSharedMemorySize, GEMM_SMEM);
    cudaFuncSetAttribute(gemm_tc<2>, cudaFuncAttributeMaxDynamicSharedMemorySize, GEMM_SMEM);
    cudaFuncSetAttribute(attn_tc, cudaFuncAttributeMaxDynamicSharedMemorySize, ATT_SMEM);
    const dim3 tb(32, 8);

    // ---- weight prep (batched over depth; single fp16 plane) ----
    wsplit_kernel<<<dim3(DIMC/32, DIMC/32, DEPTHL), tb>>>(wq,  nullptr, wqkvT, DIMC, DIMC, 0,    NQKV);
    wsplit_kernel<<<dim3(NKV/32,  DIMC/32, DEPTHL), tb>>>(wkv, nullptr, wqkvT, DIMC, NKV,  DIMC, NQKV);
    wsplit_kernel<<<dim3(NKV/32,  DIMC/32, DEPTHL), tb>>>(wkv, nm_g,    wkvG,  DIMC, NKV,  0,    NKV);
    wsplit_kernel<<<dim3(DIMC/32, DIMC/32, DEPTHL), tb>>>(wo,  nullptr, woT,   DIMC, DIMC, 0,    DIMC);
    wsplit_kernel<<<dim3(FFD/32,  DIMC/32, DEPTHL), tb>>>(w1,  nullptr, w1T,   DIMC, FFD,  0,    FFD);
    wsplit_kernel<<<dim3(DIMC/32, FFD/32,  DEPTHL), tb>>>(w2,  nullptr, w2T,   FFD,  DIMC, 0,    DIMC);
    bias_kernel<<<dim3(NKV/32, DEPTHL), 256>>>(nm_b, wkv, bias);

    // media xhat: single fp16 plane only
    ln_kernel<<<NMEDIA, 128>>>(x, nullptr, xh, nullptr, nullptr, nullptr, NMEDIA);
    init_lat_kernel<<<(LROWS * DIMC) / 256, 256>>>(latents, lat);

    // ---- all-layer media KV: 1-term A ----
    gemm_tc<1><<<dim3(NKV/128, NMEDIA/128, DEPTHL), 256, GEMM_SMEM>>>(
        xh, nullptr, wkvG, nullptr, kvmh, nullptr, NMEDIA, NKV, DIMC,
        bias, nullptr, 0,
        (size_t)NKV*DIMC, (size_t)NMEDIA*NKV, NKV, 1, nullptr);

    for (int i = 0; i < DEPTHL; i++) {
        ln_kernel<<<LROWS, 128>>>(lat, nullptr, lnh, lnl,
                                  nl_g + (size_t)i*DIMC, nl_b + (size_t)i*DIMC, LROWS);
        gemm_tc<2><<<dim3(NQKV/128, LROWS/128), 256, GEMM_SMEM>>>(
            lnh, lnl, wqkvT + (size_t)i*NQKV*DIMC,
            nullptr, qkvh, qkvl, LROWS, NQKV, DIMC, nullptr, nullptr, 0,
            0, 0, 0, 1, nullptr);
        attn_tc<<<BTOT * HEADS, 256, ATT_SMEM>>>(
            qkvh, qkvl, kvmh + (size_t)i*NMEDIA*NKV, ath, atl);
        gemm_tc<2><<<dim3(DIMC/128, LROWS/128, 2), 256, GEMM_SMEM>>>(
            ath, atl, woT + (size_t)i*DIMC*DIMC,
            nullptr, nullptr, nullptr, LROWS, DIMC, DIMC, nullptr, nullptr, 0,
            0, 0, 0, 2, part);
        redk_kernel<<<(LROWS*DIMC)/256, 256>>>(part, 2, lat, lat);
        ln_kernel<<<LROWS, 128>>>(lat, nullptr, lnh, lnl,
                                  ff_g + (size_t)i*DIMC, ff_b + (size_t)i*DIMC, LROWS);
        gemm_tc<2><<<dim3(FFD/128, LROWS/128), 256, GEMM_SMEM>>>(
            lnh, lnl, w1T + (size_t)i*FFD*DIMC,
            nullptr, h1h, h1l, LROWS, FFD, DIMC, nullptr, nullptr, 1,
            0, 0, 0, 1, nullptr);
        gemm_tc<2><<<dim3(DIMC/128, LROWS/128, 4), 256, GEMM_SMEM>>>(
            h1h, h1l, w2T + (size_t)i*DIMC*FFD,
            nullptr, nullptr, nullptr, LROWS, DIMC, FFD, nullptr, nullptr, 0,
            0, 0, 0, 4, part);
        redk_kernel<<<(LROWS*DIMC)/256, 256>>>(part, 4, lat, lat);
    }
    ln_kernel<<<LROWS, 128>>>(lat, out, nullptr, nullptr, fin_g, fin_b, LROWS);
}

// round 10
// speedup vs baseline: 5.9399x; 1.0969x over previous
#include <cuda_runtime.h>
#include <cuda_fp16.h>
#include <math.h>
#include <stdint.h>

// ---------------- problem constants ----------------
#define DIMC   1024
#define DEPTHL 6
#define HEADS  16
#define DHEAD  64
#define NKV    2048
#define NQKV   3072
#define FFD    4096
#define BTOT   32
#define MEDIA  1024
#define NMEDIA (BTOT*MEDIA)          // 32768
#define NLAT   64
#define LROWS  (BTOT*NLAT)           // 2048

typedef __half hf;

// ---------------- scratch ----------------
__device__ __align__(1024) hf    g_xh  [(size_t)NMEDIA*DIMC];
__device__ __align__(1024) hf    g_kvmh[(size_t)DEPTHL*NMEDIA*NKV];  // single plane
__device__ float g_lat [LROWS*DIMC];
__device__ __align__(1024) hf    g_lnh [LROWS*DIMC];
__device__ __align__(1024) hf    g_lnl [LROWS*DIMC];
__device__ __align__(1024) hf    g_qkvh[(size_t)LROWS*NQKV];
__device__ __align__(1024) hf    g_qkvl[(size_t)LROWS*NQKV];
__device__ __align__(1024) hf    g_ath [LROWS*DIMC];                  // single plane
__device__ __align__(1024) hf    g_h1h [(size_t)LROWS*FFD];           // single plane
__device__ float g_bias[DEPTHL*NKV];
__device__ float g_part[(size_t)4*LROWS*DIMC];

// weight planes (single fp16, B-side), chunk-tiled [K/32][N][32]
__device__ __align__(1024) hf g_wqkvT[(size_t)DEPTHL*NQKV*DIMC];
__device__ __align__(1024) hf g_wkvG [(size_t)DEPTHL*NKV*DIMC];
__device__ __align__(1024) hf g_woT  [(size_t)DEPTHL*DIMC*DIMC];
__device__ __align__(1024) hf g_w1T  [(size_t)DEPTHL*FFD*DIMC];
__device__ __align__(1024) hf g_w2T  [(size_t)DEPTHL*DIMC*FFD];

// ---------------- helpers ----------------
__device__ __forceinline__ uint32_t smem_u32(const void* p) {
    return (uint32_t)__cvta_generic_to_shared(p);
}
__device__ __forceinline__ size_t tiled_idx(int row, int k, int nrows) {
    const int kc = k >> 5, kin = k & 31;
    const int q = kin >> 3, b = kin & 7;
    const int qs = q ^ ((row >> 1) & 3);
    return ((size_t)kc * nrows + row) * 32 + qs * 8 + b;
}
__device__ __forceinline__ void bulk_g2s(uint32_t dst, const void* src, uint32_t bytes, uint32_t mbar) {
    asm volatile("cp.async.bulk.shared::cluster.global.mbarrier::complete_tx::bytes [%0], [%1], %2, [%3];"
                 :: "r"(dst), "l"(src), "r"(bytes), "r"(mbar) : "memory");
}
#define MBARRIER_INIT(addr, cnt) \
    asm volatile("mbarrier.init.shared.b64 [%0], %1;" :: "r"(addr), "r"(cnt) : "memory")
#define MBARRIER_EXPECT_TX(addr, tx) \
    asm volatile("mbarrier.arrive.expect_tx.shared.b64 _, [%0], %1;" :: "r"(addr), "r"(tx) : "memory")
#define MBARRIER_WAIT_PARITY(addr, par) do { \
    uint32_t _m = (addr), _p = (par), _d; \
    asm volatile("{\n\t.reg .pred p;\n\t" \
        "mbarrier.try_wait.parity.acquire.cta.shared::cta.b64 p, [%1], %2;\n\t" \
        "selp.b32 %0, 1, 0, p;\n\t}" : "=r"(_d) : "r"(_m), "r"(_p) : "memory"); \
    if (!_d) { \
        asm volatile("{\n\t.reg .pred P1;\n\t" \
            "WL_%=:\n\t" \
            "mbarrier.try_wait.parity.acquire.cta.shared::cta.b64 P1, [%0], %1, 0x989680;\n\t" \
            "@P1 bra.uni WD_%=;\n\tbra.uni WL_%=;\n\tWD_%=:\n\t}" \
            :: "r"(_m), "r"(_p) : "memory"); \
    } } while (0)

__device__ __forceinline__ void ldmx4(uint32_t* r, uint32_t a) {
    asm volatile("ldmatrix.sync.aligned.m8n8.x4.shared.b16 {%0,%1,%2,%3}, [%4];"
                 : "=r"(r[0]), "=r"(r[1]), "=r"(r[2]), "=r"(r[3]) : "r"(a));
}
__device__ __forceinline__ void ldmx4t(uint32_t* r, uint32_t a) {
    asm volatile("ldmatrix.sync.aligned.m8n8.x4.trans.shared.b16 {%0,%1,%2,%3}, [%4];"
                 : "=r"(r[0]), "=r"(r[1]), "=r"(r[2]), "=r"(r[3]) : "r"(a));
}
__device__ __forceinline__ void mma16816(float* d, const uint32_t* a, const uint32_t* b) {
    asm volatile("mma.sync.aligned.m16n8k16.row.col.f32.f16.f16.f32 "
                 "{%0,%1,%2,%3},{%4,%5,%6,%7},{%8,%9},{%0,%1,%2,%3};"
                 : "+f"(d[0]), "+f"(d[1]), "+f"(d[2]), "+f"(d[3])
                 : "r"(a[0]), "r"(a[1]), "r"(a[2]), "r"(a[3]),
                   "r"(b[0]), "r"(b[1]));
}
__device__ __forceinline__ uint32_t bits2(__half2 h) {
    return *reinterpret_cast<uint32_t*>(&h);
}

// ---------------- LayerNorm: fp32 in -> fp32 out and/or tiled fp16 planes ----------
__global__ void ln_kernel(const float* __restrict__ in,
                          float* __restrict__ outF,
                          hf* __restrict__ outH, hf* __restrict__ outL,
                          const float* __restrict__ g, const float* __restrict__ b,
                          int nrows)
{
    const int row = blockIdx.x;
    const float* x = in + (size_t)row * DIMC;
    float s = 0.f, sq = 0.f;
    for (int c = threadIdx.x; c < DIMC; c += blockDim.x) {
        float v = x[c]; s += v; sq += v * v;
    }
    __shared__ float sh[64];
    #pragma unroll
    for (int o = 16; o > 0; o >>= 1) {
        s  += __shfl_down_sync(0xffffffffu, s,  o);
        sq += __shfl_down_sync(0xffffffffu, sq, o);
    }
    const int wid = threadIdx.x >> 5, lid = threadIdx.x & 31;
    if (lid == 0) { sh[wid] = s; sh[wid + 32] = sq; }
    __syncthreads();
    if (threadIdx.x == 0) {
        float ts = 0.f, tsq = 0.f;
        const int nw = blockDim.x >> 5;
        for (int i = 0; i < nw; i++) { ts += sh[i]; tsq += sh[i + 32]; }
        const float mean = ts * (1.0f / DIMC);
        const float var  = tsq * (1.0f / DIMC) - mean * mean;
        sh[0] = mean; sh[1] = rsqrtf(var + 1e-5f);
    }
    __syncthreads();
    const float mean = sh[0], rstd = sh[1];

    for (int k0 = threadIdx.x * 8; k0 < DIMC; k0 += blockDim.x * 8) {
        float v[8];
        #pragma unroll
        for (int e = 0; e < 8; e++) {
            float t = (x[k0 + e] - mean) * rstd;
            if (g) t = t * g[k0 + e] + b[k0 + e];
            v[e] = t;
        }
        if (outF) {
            float* o = outF + (size_t)row * DIMC + k0;
            #pragma unroll
            for (int e = 0; e < 8; e++) o[e] = v[e];
        }
        if (outH) {
            uint32_t hq[4], lq[4];
            #pragma unroll
            for (int e = 0; e < 4; e++) {
                const __half2 h = __floats2half2_rn(v[2*e], v[2*e+1]);
                hq[e] = bits2(h);
                if (outL) {
                    const __half2 l = __floats2half2_rn(v[2*e]   - __low2float(h),
                                                        v[2*e+1] - __high2float(h));
                    lq[e] = bits2(l);
                }
            }
            const size_t ti = tiled_idx(row, k0, nrows);
            *reinterpret_cast<uint4*>(&outH[ti]) = make_uint4(hq[0], hq[1], hq[2], hq[3]);
            if (outL)
                *reinterpret_cast<uint4*>(&outL[ti]) = make_uint4(lq[0], lq[1], lq[2], lq[3]);
        }
    }
}

// ---------------- fused split-K reduce + residual + LayerNorm ----------------
// v = latin + sum_s part[s]; optional latout=v; then LN(v) -> outF and/or planes.
__global__ void __launch_bounds__(128)
lnred_kernel(const float* __restrict__ part, int S,
             const float* __restrict__ latin,
             float* __restrict__ latout,
             float* __restrict__ outF,
             hf* __restrict__ outH, hf* __restrict__ outL,
             const float* __restrict__ g, const float* __restrict__ b)
{
    const int row = blockIdx.x;
    const int tid = threadIdx.x;           // 128 threads, 8 cols each
    const size_t base = (size_t)row * DIMC + tid * 8;
    float v[8];
    #pragma unroll
    for (int e = 0; e < 8; e++) v[e] = latin[base + e];
    for (int s = 0; s < S; s++) {
        const float* p = part + (size_t)s * LROWS * DIMC + base;
        #pragma unroll
        for (int e = 0; e < 8; e++) v[e] += p[e];
    }
    if (latout) {
        #pragma unroll
        for (int e = 0; e < 8; e++) latout[base + e] = v[e];
    }
    float s1 = 0.f, s2 = 0.f;
    #pragma unroll
    for (int e = 0; e < 8; e++) { s1 += v[e]; s2 += v[e] * v[e]; }
    __shared__ float sh[8];
    #pragma unroll
    for (int o = 16; o > 0; o >>= 1) {
        s1 += __shfl_down_sync(0xffffffffu, s1, o);
        s2 += __shfl_down_sync(0xffffffffu, s2, o);
    }
    const int wid = tid >> 5, lid = tid & 31;
    if (lid == 0) { sh[wid] = s1; sh[wid + 4] = s2; }
    __syncthreads();
    if (tid == 0) {
        float ts = sh[0] + sh[1] + sh[2] + sh[3];
        float tq = sh[4] + sh[5] + sh[6] + sh[7];
        const float mean = ts * (1.0f / DIMC);
        const float var  = tq * (1.0f / DIMC) - mean * mean;
        sh[0] = mean; sh[1] = rsqrtf(var + 1e-5f);
    }
    __syncthreads();
    const float mean = sh[0], rstd = sh[1];
    const int k0 = tid * 8;
    float t[8];
    #pragma unroll
    for (int e = 0; e < 8; e++)
        t[e] = (v[e] - mean) * rstd * g[k0 + e] + b[k0 + e];
    if (outF) {
        float* o = outF + base;
        #pragma unroll
        for (int e = 0; e < 8; e++) o[e] = t[e];
    }
    if (outH) {
        uint32_t hq[4], lq[4];
        #pragma unroll
        for (int e = 0; e < 4; e++) {
            const __half2 h = __floats2half2_rn(t[2*e], t[2*e+1]);
            hq[e] = bits2(h);
            if (outL) {
                const __half2 l = __floats2half2_rn(t[2*e]   - __low2float(h),
                                                    t[2*e+1] - __high2float(h));
                lq[e] = bits2(l);
            }
        }
        const size_t ti = tiled_idx(row, k0, LROWS);
        *reinterpret_cast<uint4*>(&outH[ti]) = make_uint4(hq[0], hq[1], hq[2], hq[3]);
        if (outL)
            *reinterpret_cast<uint4*>(&outL[ti]) = make_uint4(lq[0], lq[1], lq[2], lq[3]);
    }
}

// ---------------- bias: all layers, k-parallel ----------------
__global__ void bias_kernel(const float* __restrict__ nm_b,
                            const float* __restrict__ wkv, float* __restrict__ out)
{
    const int layer = blockIdx.y;
    const int tid = threadIdx.x;
    const int n  = blockIdx.x * 32 + (tid & 31);
    const int ks = tid >> 5;
    const float* bv = nm_b + (size_t)layer * DIMC;
    const float* W  = wkv  + (size_t)layer * DIMC * NKV;
    float s = 0.f;
    #pragma unroll 4
    for (int k = ks * 128; k < ks * 128 + 128; k++)
        s += bv[k] * __ldg(&W[(size_t)k * NKV + n]);
    __shared__ float red[8][32];
    red[ks][tid & 31] = s;
    __syncthreads();
    if (ks == 0) {
        float t = 0.f;
        #pragma unroll
        for (int i = 0; i < 8; i++) t += red[i][tid & 31];
        out[(size_t)layer * NKV + n] = t;
    }
}

__global__ void init_lat_kernel(const float* __restrict__ latents, float* __restrict__ lat)
{
    const int idx = blockIdx.x * blockDim.x + threadIdx.x;
    lat[idx] = latents[idx & (NLAT * DIMC - 1)];
}

// ---------------- weight transpose + gamma + fp16 quantize (batched over depth) ----
__global__ void wsplit_kernel(const float* __restrict__ W0, const float* __restrict__ g0,
                              hf* __restrict__ T0, int K, int N, int nofs, int ntot)
{
    const int z = blockIdx.z;
    const float* W = W0 + (size_t)z * K * N;
    const float* g = g0 ? g0 + (size_t)z * K : nullptr;
    hf* T = T0 + (size_t)z * ntot * K;
    __shared__ float t[32][33];
    const int n0 = blockIdx.x * 32, k0 = blockIdx.y * 32;
    const int tx = threadIdx.x, ty = threadIdx.y;
    #pragma unroll
    for (int i = 0; i < 4; i++) {
        float v = W[(size_t)(k0 + ty + 8 * i) * N + n0 + tx];
        if (g) v *= g[k0 + ty + 8 * i];
        t[ty + 8 * i][tx] = v;
    }
    __syncthreads();
    #pragma unroll
    for (int i = 0; i < 4; i++) {
        const int n = n0 + ty + 8 * i, k = k0 + tx;
        T[tiled_idx(nofs + n, k, ntot)] = __float2half_rn(t[tx][ty + 8 * i]);
    }
}

// =====================================================================
// fp16 HMMA GEMM, AT = A-side terms (1 or 2). k16-pipelined, bulk staged.
// =====================================================================
#define NSTG 4
#define STG_BYTES 24576
#define TILEOFF 1024
#define GEMM_SMEM (TILEOFF + NSTG*STG_BYTES)

template <int AT>
__global__ void __launch_bounds__(256, 1)
gemm_tc(const hf* __restrict__ Ah, const hf* __restrict__ Al,
        const hf* __restrict__ B0,
        float* __restrict__ Cf, hf* __restrict__ Ch0, hf* __restrict__ Cl0,
        int M, int N, int K,
        const float* __restrict__ bias0, const float* __restrict__ resid, int dogelu,
        size_t lstrB, size_t lstrC, int lstrBias,
        int splitk, float* __restrict__ Cpart)
{
    extern __shared__ char smem[];
    const uint32_t sb = smem_u32(smem);
    const int tid  = threadIdx.x;
    const int lane = tid & 31;
    const int wid  = tid >> 5;
    const int wm   = wid & 1;
    const int wn   = wid >> 1;
    const int bm   = blockIdx.y * 128;
    const int bn   = blockIdx.x * 128;
    const int z    = blockIdx.z;

    const hf* B = B0;
    hf* Ch = Ch0;
    hf* Cl = Cl0;
    const float* bias = bias0;
    const int nc = K >> 5;
    int ncl = nc, c0 = 0;
    if (splitk > 1) { ncl = nc / splitk; c0 = z * ncl; }
    else if (z) {
        B += (size_t)z * lstrB;
        if (Ch0) { Ch += (size_t)z * lstrC; if (Cl0) Cl += (size_t)z * lstrC; }
        if (bias0) bias += (size_t)z * lstrBias;
    }

    if (tid == 0) {
        #pragma unroll
        for (int s = 0; s < NSTG; s++) MBARRIER_INIT(sb + 8 * s, 1);
    }
    __syncthreads();

    float acc[4][4][4];
    #pragma unroll
    for (int i = 0; i < 4; i++)
        #pragma unroll
        for (int j = 0; j < 4; j++)
            #pragma unroll
            for (int q = 0; q < 4; q++) acc[i][j][q] = 0.f;

    auto issue = [&](int cl) {
        const int gc = c0 + cl;
        const uint32_t mb  = sb + 8 * (cl & 3);
        const uint32_t dst = sb + TILEOFF + (cl & 3) * STG_BYTES;
        MBARRIER_EXPECT_TX(mb, AT == 2 ? 24576u : 16384u);
        bulk_g2s(dst,         Ah + ((size_t)gc * M + bm) * 32, 8192, mb);
        if (AT == 2)
            bulk_g2s(dst + 8192, Al + ((size_t)gc * M + bm) * 32, 8192, mb);
        bulk_g2s(dst + 16384, B  + ((size_t)gc * N + bn) * 32, 8192, mb);
    };
    if (tid == 0) {
        const int pre = ncl < NSTG ? ncl : NSTG;
        for (int s = 0; s < pre; s++) issue(s);
    }

    uint32_t a0H[16], a0L[16], b0[8];
    uint32_t a1H[16], a1L[16], b1[8];

    auto lds_step = [&](int u, uint32_t* aH, uint32_t* aL, uint32_t* bf) {
        const uint32_t stA = sb + TILEOFF + ((u >> 1) & 3) * STG_BYTES;
        const uint32_t stB = stA + 16384;
        const int s16 = u & 1;
        #pragma unroll
        for (int mi = 0; mi < 4; mi++) {
            const int row = wm * 64 + mi * 16 + (lane & 15);
            const int q   = s16 * 2 + (lane >> 4);
            const uint32_t ad = stA + row * 64 + ((q ^ ((row >> 1) & 3)) << 4);
            ldmx4(aH + 4 * mi, ad);
            if (AT == 2) ldmx4(aL + 4 * mi, ad + 8192);
        }
        #pragma unroll
        for (int ni = 0; ni < 2; ni++) {
            const int row = wn * 32 + ni * 16 + (lane & 7) + ((lane >> 4) << 3);
            const int q   = s16 * 2 + ((lane >> 3) & 1);
            const uint32_t bd = stB + row * 64 + ((q ^ ((row >> 1) & 3)) << 4);
            uint32_t t[4];
            ldmx4(t, bd);
            bf[ni*4+0] = t[0]; bf[ni*4+1] = t[1]; bf[ni*4+2] = t[2]; bf[ni*4+3] = t[3];
        }
    };
    auto mma_step = [&](const uint32_t* aH, const uint32_t* aL, const uint32_t* bf) {
        #pragma unroll
        for (int mi = 0; mi < 4; mi++)
            #pragma unroll
            for (int j = 0; j < 4; j++) {
                mma16816(acc[mi][j], aH + 4 * mi, bf + 2 * j);
                if (AT == 2) mma16816(acc[mi][j], aL + 4 * mi, bf + 2 * j);
            }
    };

    MBARRIER_WAIT_PARITY(sb, 0);
    lds_step(0, a0H, a0L, b0);
    const int total = ncl * 2;
    for (int u = 0; u < total; u += 2) {
        lds_step(u + 1, a1H, a1L, b1);
        __syncthreads();
        const int cl = u >> 1;
        if (tid == 0 && cl + NSTG < ncl) issue(cl + NSTG);
        mma_step(a0H, a0L, b0);
        if (u + 2 < total) {
            const int c2 = cl + 1;
            MBARRIER_WAIT_PARITY(sb + 8 * (c2 & 3), (c2 >> 2) & 1);
            lds_step(u + 2, a0H, a0L, b0);
        }
        mma_step(a1H, a1L, b1);
    }

    // ---- epilogue ----
    if (Cpart) {
        float* P = Cpart + (size_t)z * M * N;
        #pragma unroll
        for (int mi = 0; mi < 4; mi++)
            #pragma unroll
            for (int j = 0; j < 4; j++) {
                const int colb = bn + wn * 32 + j * 8 + (lane & 3) * 2;
                #pragma unroll
                for (int p = 0; p < 2; p++) {
                    const int row = bm + wm * 64 + mi * 16 + (lane >> 2) + 8 * p;
                    *reinterpret_cast<float2*>(&P[(size_t)row * N + colb]) =
                        make_float2(acc[mi][j][p * 2], acc[mi][j][p * 2 + 1]);
                }
            }
        return;
    }
    #pragma unroll
    for (int mi = 0; mi < 4; mi++) {
        #pragma unroll
        for (int j = 0; j < 4; j++) {
            const int colb = bn + wn * 32 + j * 8 + (lane & 3) * 2;
            #pragma unroll
            for (int p = 0; p < 2; p++) {
                const int row = bm + wm * 64 + mi * 16 + (lane >> 2) + 8 * p;
                float v0 = acc[mi][j][p * 2], v1 = acc[mi][j][p * 2 + 1];
                if (bias) { v0 += bias[colb]; v1 += bias[colb + 1]; }
                if (dogelu) {
                    v0 = 0.5f * v0 * (1.f + erff(v0 * 0.70710678118654752f));
                    v1 = 0.5f * v1 * (1.f + erff(v1 * 0.70710678118654752f));
                }
                if (resid) {
                    const float2 r = *reinterpret_cast<const float2*>(&resid[(size_t)row * N + colb]);
                    v0 += r.x; v1 += r.y;
                }
                if (Cf) *reinterpret_cast<float2*>(&Cf[(size_t)row * N + colb]) = make_float2(v0, v1);
                if (Ch) {
                    const __half2 h = __floats2half2_rn(v0, v1);
                    const size_t ti = tiled_idx(row, colb, M);
                    *reinterpret_cast<uint32_t*>(&Ch[ti]) = bits2(h);
                    if (Cl) {
                        const __half2 l = __floats2half2_rn(v0 - __low2float(h),
                                                            v1 - __high2float(h));
                        *reinterpret_cast<uint32_t*>(&Cl[ti]) = bits2(l);
                    }
                }
            }
        }
    }
}

// =====================================================================
// Tensor-core flash attention (fp16 2-term Q/P, single-plane K/V/out).
// =====================================================================
#define OFF_Q   1024
#define OFF_KV  (OFF_Q + 16384)
#define OFF_P   (OFF_KV + 32768)
#define OFF_SS  (OFF_P + 16384)
#define OFF_ST  (OFF_SS + 64*65*4)
#define ATT_SMEM (OFF_ST + 768)

__global__ void __launch_bounds__(256, 1)
attn_tc(const hf* __restrict__ QKVh, const hf* __restrict__ QKVl,
        const hf* __restrict__ Kmh,
        hf* __restrict__ OH)
{
    extern __shared__ char smem[];
    const uint32_t sb = smem_u32(smem);
    const int bt  = blockIdx.x >> 4;
    const int h   = blockIdx.x & 15;
    const int tid = threadIdx.x;
    const int lane = tid & 31;
    const int wid  = tid >> 5;
    const int wm   = wid & 1;
    const int wn   = wid >> 1;
    float* Ss    = reinterpret_cast<float*>(smem + OFF_SS);
    float* mrow  = reinterpret_cast<float*>(smem + OFF_ST);
    float* lrow  = mrow + 64;
    float* frow  = lrow + 64;

    if (tid == 0) { MBARRIER_INIT(sb, 1); MBARRIER_INIT(sb + 8, 1); }

    {
        #pragma unroll
        for (int seg = 0; seg < 4; seg++) {
            const hf* src = (seg < 2 ? QKVh : QKVl) + ((size_t)(2 * h + (seg & 1)) * LROWS + bt * 64) * 32;
            const uint4 v = reinterpret_cast<const uint4*>(src)[tid];
            *reinterpret_cast<uint4*>(smem + OFF_Q + (seg >= 2 ? 8192 : 0) + (seg & 1) * 4096 + tid * 16) = v;
        }
    }
    if (tid < 64) { mrow[tid] = -INFINITY; lrow[tid] = 0.f; }
    __syncthreads();

    auto issueKV = [&](int t) {
        const int st = t & 1;
        const uint32_t mb = sb + 8 * st;
        const uint32_t dst = sb + OFF_KV + st * 16384;
        MBARRIER_EXPECT_TX(mb, 16384u);
        const hf* PH; size_t rbase, nr; int kcK, kcV;
        if (t < 16) { PH = Kmh;  rbase = (size_t)bt * 1024 + t * 64; nr = NMEDIA; kcK = 2*h;      kcV = 32 + 2*h; }
        else        { PH = QKVh; rbase = (size_t)bt * 64;            nr = LROWS;  kcK = 32 + 2*h; kcV = 64 + 2*h; }
        bulk_g2s(dst,          PH + ((size_t)kcK * nr + rbase) * 32,       4096, mb);
        bulk_g2s(dst +  4096,  PH + ((size_t)(kcK + 1) * nr + rbase) * 32, 4096, mb);
        bulk_g2s(dst +  8192,  PH + ((size_t)kcV * nr + rbase) * 32,       4096, mb);
        bulk_g2s(dst + 12288,  PH + ((size_t)(kcV + 1) * nr + rbase) * 32, 4096, mb);
    };
    if (tid == 0) issueKV(0);

    uint32_t qH[2][4][4], qL[2][4][4];
    #pragma unroll
    for (int mi = 0; mi < 2; mi++)
        #pragma unroll
        for (int s = 0; s < 4; s++) {
            const int row = wm * 32 + mi * 16 + (lane & 15);
            const int qq = (((s & 1) * 2 + (lane >> 4)) ^ ((row >> 1) & 3));
            const uint32_t ad = sb + OFF_Q + (s >> 1) * 4096 + row * 64 + (qq << 4);
            ldmx4(qH[mi][s], ad);
            ldmx4(qL[mi][s], ad + 8192);
        }

    float acc[2][2][4];
    #pragma unroll
    for (int i = 0; i < 2; i++)
        #pragma unroll
        for (int j = 0; j < 2; j++)
            #pragma unroll
            for (int q = 0; q < 4; q++) acc[i][j][q] = 0.f;

    for (int t = 0; t < 17; t++) {
        if (tid == 0 && t + 1 < 17) issueKV(t + 1);
        MBARRIER_WAIT_PARITY(sb + 8 * (t & 1), (t >> 1) & 1);
        const uint32_t kb = sb + OFF_KV + (t & 1) * 16384;

        float sc[2][2][4] = {};
        #pragma unroll
        for (int s = 0; s < 4; s++) {
            const int row = wn * 16 + (lane & 7) + ((lane >> 4) << 3);
            const int qq = (((s & 1) * 2 + ((lane >> 3) & 1)) ^ ((row >> 1) & 3));
            const uint32_t ad = kb + (s >> 1) * 4096 + row * 64 + (qq << 4);
            uint32_t tH[4];
            ldmx4(tH, ad);
            uint32_t bh0[2] = {tH[0], tH[1]}, bh1[2] = {tH[2], tH[3]};
            #pragma unroll
            for (int mi = 0; mi < 2; mi++) {
                mma16816(sc[mi][0], qH[mi][s], bh0);
                mma16816(sc[mi][0], qL[mi][s], bh0);
                mma16816(sc[mi][1], qH[mi][s], bh1);
                mma16816(sc[mi][1], qL[mi][s], bh1);
            }
        }
        #pragma unroll
        for (int mi = 0; mi < 2; mi++)
            #pragma unroll
            for (int j = 0; j < 2; j++)
                #pragma unroll
                for (int p = 0; p < 2; p++) {
                    const int r = wm * 32 + mi * 16 + (lane >> 2) + 8 * p;
                    const int col = wn * 16 + j * 8 + (lane & 3) * 2;
                    Ss[r * 65 + col]     = sc[mi][j][p * 2]     * 0.125f;
                    Ss[r * 65 + col + 1] = sc[mi][j][p * 2 + 1] * 0.125f;
                }
        __syncthreads();

        {
            const int r = tid >> 2, qd = tid & 3;
            const int kb2 = qd * 16;
            float tmax = -INFINITY;
            #pragma unroll
            for (int k = 0; k < 16; k++) tmax = fmaxf(tmax, Ss[r * 65 + kb2 + k]);
            tmax = fmaxf(tmax, __shfl_xor_sync(0xffffffffu, tmax, 1));
            tmax = fmaxf(tmax, __shfl_xor_sync(0xffffffffu, tmax, 2));
            const float mold = mrow[r];
            const float mnew = fmaxf(mold, tmax);
            float s = 0.f;
            #pragma unroll
            for (int k = 0; k < 16; k++) {
                const float p = __expf(Ss[r * 65 + kb2 + k] - mnew);
                Ss[r * 65 + kb2 + k] = p;
                s += p;
            }
            s += __shfl_xor_sync(0xffffffffu, s, 1);
            s += __shfl_xor_sync(0xffffffffu, s, 2);
            if (qd == 0) {
                const float fac = __expf(mold - mnew);
                lrow[r] = lrow[r] * fac + s;
                mrow[r] = mnew;
                frow[r] = fac;
            }
        }
        __syncthreads();

        #pragma unroll
        for (int mi = 0; mi < 2; mi++)
            #pragma unroll
            for (int p = 0; p < 2; p++) {
                const float fac = frow[wm * 32 + mi * 16 + (lane >> 2) + 8 * p];
                #pragma unroll
                for (int j = 0; j < 2; j++) {
                    acc[mi][j][p * 2]     *= fac;
                    acc[mi][j][p * 2 + 1] *= fac;
                }
            }
        #pragma unroll
        for (int i = 0; i < 8; i++) {
            const int pi = tid * 8 + i;
            const int q = pi >> 5, kp = pi & 31, k = kp * 2;
            const int kc = k >> 5, kin = k & 31;
            const int qq = ((kin >> 3) ^ ((q >> 1) & 3));
            const int off = OFF_P + kc * 4096 + q * 64 + (qq << 4) + (kin & 7) * 2;
            const float v0 = Ss[q * 65 + k], v1 = Ss[q * 65 + k + 1];
            const __half2 hh = __floats2half2_rn(v0, v1);
            const __half2 ll = __floats2half2_rn(v0 - __low2float(hh),
                                                 v1 - __high2float(hh));
            *reinterpret_cast<uint32_t*>(smem + off)        = bits2(hh);
            *reinterpret_cast<uint32_t*>(smem + off + 8192) = bits2(ll);
        }
        __syncthreads();

        #pragma unroll
        for (int s = 0; s < 4; s++) {
            uint32_t pH[2][4], pL[2][4];
            #pragma unroll
            for (int mi = 0; mi < 2; mi++) {
                const int row = wm * 32 + mi * 16 + (lane & 15);
                const int qq = (((s & 1) * 2 + (lane >> 4)) ^ ((row >> 1) & 3));
                const uint32_t ad = sb + OFF_P + (s >> 1) * 4096 + row * 64 + (qq << 4);
                ldmx4(pH[mi], ad);
                ldmx4(pL[mi], ad + 8192);
            }
            const int key  = s * 16 + (lane & 15);
            const int dinb = wn * 16 + ((lane >> 4) << 3);
            const int kcv  = dinb >> 5, din = dinb & 31;
            const int qq   = ((din >> 3) ^ ((key >> 1) & 3));
            const uint32_t ad = kb + 8192 + kcv * 4096 + key * 64 + (qq << 4);
            uint32_t tH[4];
            ldmx4t(tH, ad);
            uint32_t vh0[2] = {tH[0], tH[1]}, vh1[2] = {tH[2], tH[3]};
            #pragma unroll
            for (int mi = 0; mi < 2; mi++) {
                mma16816(acc[mi][0], pH[mi], vh0);
                mma16816(acc[mi][0], pL[mi], vh0);
                mma16816(acc[mi][1], pH[mi], vh1);
                mma16816(acc[mi][1], pL[mi], vh1);
            }
        }
        __syncthreads();
    }

    #pragma unroll
    for (int mi = 0; mi < 2; mi++)
        #pragma unroll
        for (int p = 0; p < 2; p++) {
            const int r = wm * 32 + mi * 16 + (lane >> 2) + 8 * p;
            const float inv = 1.0f / lrow[r];
            #pragma unroll
            for (int j = 0; j < 2; j++) {
                const int col = h * 64 + wn * 16 + j * 8 + (lane & 3) * 2;
                const float v0 = acc[mi][j][p * 2] * inv;
                const float v1 = acc[mi][j][p * 2 + 1] * inv;
                const __half2 hh = __floats2half2_rn(v0, v1);
                const size_t ti = tiled_idx(bt * 64 + r, col, LROWS);
                *reinterpret_cast<uint32_t*>(&OH[ti]) = bits2(hh);
            }
        }
}

// ---------------- orchestration ----------------
extern "C" void kernel_launch(void* const* d_in, const int* in_sizes, int n_in,
                              void* d_out, int out_size)
{
    (void)in_sizes; (void)n_in; (void)out_size;
    const float* x       = (const float*)d_in[0];
    const float* latents = (const float*)d_in[1];
    const float* nm_g    = (const float*)d_in[2];
    const float* nm_b    = (const float*)d_in[3];
    const float* nl_g    = (const float*)d_in[4];
    const float* nl_b    = (const float*)d_in[5];
    const float* wq      = (const float*)d_in[6];
    const float* wkv     = (const float*)d_in[7];
    const float* wo      = (const float*)d_in[8];
    const float* ff_g    = (const float*)d_in[9];
    const float* ff_b    = (const float*)d_in[10];
    const float* w1      = (const float*)d_in[11];
    const float* w2      = (const float*)d_in[12];
    const float* fin_g   = (const float*)d_in[13];
    const float* fin_b   = (const float*)d_in[14];
    float* out = (float*)d_out;

    hf *xh, *kvmh, *lnh, *lnl, *qkvh, *qkvl, *ath, *h1h;
    float *lat, *bias, *part;
    cudaGetSymbolAddress((void**)&xh,   g_xh);
    cudaGetSymbolAddress((void**)&kvmh, g_kvmh);
    cudaGetSymbolAddress((void**)&lat,  g_lat);
    cudaGetSymbolAddress((void**)&lnh,  g_lnh);  cudaGetSymbolAddress((void**)&lnl,  g_lnl);
    cudaGetSymbolAddress((void**)&qkvh, g_qkvh); cudaGetSymbolAddress((void**)&qkvl, g_qkvl);
    cudaGetSymbolAddress((void**)&ath,  g_ath);
    cudaGetSymbolAddress((void**)&h1h,  g_h1h);
    cudaGetSymbolAddress((void**)&bias, g_bias); cudaGetSymbolAddress((void**)&part, g_part);

    hf *wqkvT, *wkvG, *woT, *w1T, *w2T;
    cudaGetSymbolAddress((void**)&wqkvT, g_wqkvT);
    cudaGetSymbolAddress((void**)&wkvG,  g_wkvG);
    cudaGetSymbolAddress((void**)&woT,   g_woT);
    cudaGetSymbolAddress((void**)&w1T,   g_w1T);
    cudaGetSymbolAddress((void**)&w2T,   g_w2T);

    cudaFuncSetAttribute(gemm_tc<1>, cudaFuncAttributeMaxDynamicSharedMemorySize, GEMM_SMEM);
    cudaFuncSetAttribute(gemm_tc<2>, cudaFuncAttributeMaxDynamicSharedMemorySize, GEMM_SMEM);
    cudaFuncSetAttribute(attn_tc, cudaFuncAttributeMaxDynamicSharedMemorySize, ATT_SMEM);
    const dim3 tb(32, 8);

    // ---- weight prep ----
    wsplit_kernel<<<dim3(DIMC/32, DIMC/32, DEPTHL), tb>>>(wq,  nullptr, wqkvT, DIMC, DIMC, 0,    NQKV);
    wsplit_kernel<<<dim3(NKV/32,  DIMC/32, DEPTHL), tb>>>(wkv, nullptr, wqkvT, DIMC, NKV,  DIMC, NQKV);
    wsplit_kernel<<<dim3(NKV/32,  DIMC/32, DEPTHL), tb>>>(wkv, nm_g,    wkvG,  DIMC, NKV,  0,    NKV);
    wsplit_kernel<<<dim3(DIMC/32, DIMC/32, DEPTHL), tb>>>(wo,  nullptr, woT,   DIMC, DIMC, 0,    DIMC);
    wsplit_kernel<<<dim3(FFD/32,  DIMC/32, DEPTHL), tb>>>(w1,  nullptr, w1T,   DIMC, FFD,  0,    FFD);
    wsplit_kernel<<<dim3(DIMC/32, FFD/32,  DEPTHL), tb>>>(w2,  nullptr, w2T,   FFD,  DIMC, 0,    DIMC);
    bias_kernel<<<dim3(NKV/32, DEPTHL), 256>>>(nm_b, wkv, bias);

    ln_kernel<<<NMEDIA, 128>>>(x, nullptr, xh, nullptr, nullptr, nullptr, NMEDIA);
    init_lat_kernel<<<(LROWS * DIMC) / 256, 256>>>(latents, lat);

    // ---- all-layer media KV: 1-term A ----
    gemm_tc<1><<<dim3(NKV/128, NMEDIA/128, DEPTHL), 256, GEMM_SMEM>>>(
        xh, nullptr, wkvG, nullptr, kvmh, nullptr, NMEDIA, NKV, DIMC,
        bias, nullptr, 0,
        (size_t)NKV*DIMC, (size_t)NMEDIA*NKV, NKV, 1, nullptr);

    // layer 0 nl-LN (later layers produced by fused lnred)
    ln_kernel<<<LROWS, 128>>>(lat, nullptr, lnh, lnl, nl_g, nl_b, LROWS);

    for (int i = 0; i < DEPTHL; i++) {
        // fused Q|K|V latent GEMM (2-term A, hi+lo out)
        gemm_tc<2><<<dim3(NQKV/128, LROWS/128), 256, GEMM_SMEM>>>(
            lnh, lnl, wqkvT + (size_t)i*NQKV*DIMC,
            nullptr, qkvh, qkvl, LROWS, NQKV, DIMC, nullptr, nullptr, 0,
            0, 0, 0, 1, nullptr);
        attn_tc<<<BTOT * HEADS, 256, ATT_SMEM>>>(
            qkvh, qkvl, kvmh + (size_t)i*NMEDIA*NKV, ath);
        // wo (1-term A, split-K 2) -> part ; fused reduce+residual+ff-LN (hi only)
        gemm_tc<1><<<dim3(DIMC/128, LROWS/128, 2), 256, GEMM_SMEM>>>(
            ath, nullptr, woT + (size_t)i*DIMC*DIMC,
            nullptr, nullptr, nullptr, LROWS, DIMC, DIMC, nullptr, nullptr, 0,
            0, 0, 0, 2, part);
        lnred_kernel<<<LROWS, 128>>>(part, 2, lat, lat, nullptr, lnh, nullptr,
                                     ff_g + (size_t)i*DIMC, ff_b + (size_t)i*DIMC);
        // ff1 (1-term A) -> gelu -> h1h only
        gemm_tc<1><<<dim3(FFD/128, LROWS/128), 256, GEMM_SMEM>>>(
            lnh, nullptr, w1T + (size_t)i*FFD*DIMC,
            nullptr, h1h, nullptr, LROWS, FFD, DIMC, nullptr, nullptr, 1,
            0, 0, 0, 1, nullptr);
        // ff2 (1-term A, split-K 4) -> part ; fused reduce+residual+next-LN
        gemm_tc<1><<<dim3(DIMC/128, LROWS/128, 4), 256, GEMM_SMEM>>>(
            h1h, nullptr, w2T + (size_t)i*DIMC*FFD,
            nullptr, nullptr, nullptr, LROWS, DIMC, FFD, nullptr, nullptr, 0,
            0, 0, 0, 4, part);
        if (i + 1 < DEPTHL) {
            lnred_kernel<<<LROWS, 128>>>(part, 4, lat, lat, nullptr, lnh, lnl,
                                         nl_g + (size_t)(i+1)*DIMC, nl_b + (size_t)(i+1)*DIMC);
        } else {
            lnred_kernel<<<LROWS, 128>>>(part, 4, lat, nullptr, out, nullptr, nullptr,
                                         fin_g, fin_b);
        }
    }
}

// round 11
// speedup vs baseline: 6.9899x; 1.1768x over previous
#include <cuda_runtime.h>
#include <cuda_fp16.h>
#include <math.h>
#include <stdint.h>

// ---------------- problem constants ----------------
#define DIMC   1024
#define DEPTHL 6
#define HEADS  16
#define DHEAD  64
#define NKV    2048
#define NQKV   3072
#define FFD    4096
#define BTOT   32
#define MEDIA  1024
#define NMEDIA (BTOT*MEDIA)          // 32768
#define NLAT   64
#define LROWS  (BTOT*NLAT)           // 2048

typedef __half hf;

// ---------------- scratch ----------------
__device__ __align__(1024) hf    g_xh  [(size_t)NMEDIA*DIMC];
__device__ __align__(1024) hf    g_kvmh[(size_t)DEPTHL*NMEDIA*NKV];  // single plane
__device__ float g_lat [LROWS*DIMC];
__device__ __align__(1024) hf    g_lnh [LROWS*DIMC];
__device__ __align__(1024) hf    g_lnl [LROWS*DIMC];
__device__ __align__(1024) hf    g_qkvh[(size_t)LROWS*NQKV];
__device__ __align__(1024) hf    g_qkvl[(size_t)LROWS*NQKV];
__device__ __align__(1024) hf    g_ath [LROWS*DIMC];                  // single plane
__device__ __align__(1024) hf    g_h1h [(size_t)LROWS*FFD];           // single plane
__device__ float g_bias[DEPTHL*NKV];
__device__ float g_part[(size_t)4*LROWS*DIMC];

// weight planes (single fp16, B-side), chunk-tiled [K/32][N][32]
__device__ __align__(1024) hf g_wqkvT[(size_t)DEPTHL*NQKV*DIMC];
__device__ __align__(1024) hf g_wkvG [(size_t)DEPTHL*NKV*DIMC];
__device__ __align__(1024) hf g_woT  [(size_t)DEPTHL*DIMC*DIMC];
__device__ __align__(1024) hf g_w1T  [(size_t)DEPTHL*FFD*DIMC];
__device__ __align__(1024) hf g_w2T  [(size_t)DEPTHL*DIMC*FFD];

// ---------------- helpers ----------------
__device__ __forceinline__ uint32_t smem_u32(const void* p) {
    return (uint32_t)__cvta_generic_to_shared(p);
}
__device__ __forceinline__ size_t tiled_idx(int row, int k, int nrows) {
    const int kc = k >> 5, kin = k & 31;
    const int q = kin >> 3, b = kin & 7;
    const int qs = q ^ ((row >> 1) & 3);
    return ((size_t)kc * nrows + row) * 32 + qs * 8 + b;
}
__device__ __forceinline__ void bulk_g2s(uint32_t dst, const void* src, uint32_t bytes, uint32_t mbar) {
    asm volatile("cp.async.bulk.shared::cluster.global.mbarrier::complete_tx::bytes [%0], [%1], %2, [%3];"
                 :: "r"(dst), "l"(src), "r"(bytes), "r"(mbar) : "memory");
}
#define MBARRIER_INIT(addr, cnt) \
    asm volatile("mbarrier.init.shared.b64 [%0], %1;" :: "r"(addr), "r"(cnt) : "memory")
#define MBARRIER_EXPECT_TX(addr, tx) \
    asm volatile("mbarrier.arrive.expect_tx.shared.b64 _, [%0], %1;" :: "r"(addr), "r"(tx) : "memory")
#define MBARRIER_WAIT_PARITY(addr, par) do { \
    uint32_t _m = (addr), _p = (par), _d; \
    asm volatile("{\n\t.reg .pred p;\n\t" \
        "mbarrier.try_wait.parity.acquire.cta.shared::cta.b64 p, [%1], %2;\n\t" \
        "selp.b32 %0, 1, 0, p;\n\t}" : "=r"(_d) : "r"(_m), "r"(_p) : "memory"); \
    if (!_d) { \
        asm volatile("{\n\t.reg .pred P1;\n\t" \
            "WL_%=:\n\t" \
            "mbarrier.try_wait.parity.acquire.cta.shared::cta.b64 P1, [%0], %1, 0x989680;\n\t" \
            "@P1 bra.uni WD_%=;\n\tbra.uni WL_%=;\n\tWD_%=:\n\t}" \
            :: "r"(_m), "r"(_p) : "memory"); \
    } } while (0)

__device__ __forceinline__ void ldmx4(uint32_t* r, uint32_t a) {
    asm volatile("ldmatrix.sync.aligned.m8n8.x4.shared.b16 {%0,%1,%2,%3}, [%4];"
                 : "=r"(r[0]), "=r"(r[1]), "=r"(r[2]), "=r"(r[3]) : "r"(a));
}
__device__ __forceinline__ void ldmx4t(uint32_t* r, uint32_t a) {
    asm volatile("ldmatrix.sync.aligned.m8n8.x4.trans.shared.b16 {%0,%1,%2,%3}, [%4];"
                 : "=r"(r[0]), "=r"(r[1]), "=r"(r[2]), "=r"(r[3]) : "r"(a));
}
__device__ __forceinline__ void mma16816(float* d, const uint32_t* a, const uint32_t* b) {
    asm volatile("mma.sync.aligned.m16n8k16.row.col.f32.f16.f16.f32 "
                 "{%0,%1,%2,%3},{%4,%5,%6,%7},{%8,%9},{%0,%1,%2,%3};"
                 : "+f"(d[0]), "+f"(d[1]), "+f"(d[2]), "+f"(d[3])
                 : "r"(a[0]), "r"(a[1]), "r"(a[2]), "r"(a[3]),
                   "r"(b[0]), "r"(b[1]));
}
__device__ __forceinline__ uint32_t bits2(__half2 h) {
    return *reinterpret_cast<uint32_t*>(&h);
}

// ---------------- LayerNorm: fp32 in -> fp32 out and/or tiled fp16 planes ----------
__global__ void ln_kernel(const float* __restrict__ in,
                          float* __restrict__ outF,
                          hf* __restrict__ outH, hf* __restrict__ outL,
                          const float* __restrict__ g, const float* __restrict__ b,
                          int nrows)
{
    const int row = blockIdx.x;
    const float* x = in + (size_t)row * DIMC;
    float s = 0.f, sq = 0.f;
    for (int c = threadIdx.x; c < DIMC; c += blockDim.x) {
        float v = x[c]; s += v; sq += v * v;
    }
    __shared__ float sh[64];
    #pragma unroll
    for (int o = 16; o > 0; o >>= 1) {
        s  += __shfl_down_sync(0xffffffffu, s,  o);
        sq += __shfl_down_sync(0xffffffffu, sq, o);
    }
    const int wid = threadIdx.x >> 5, lid = threadIdx.x & 31;
    if (lid == 0) { sh[wid] = s; sh[wid + 32] = sq; }
    __syncthreads();
    if (threadIdx.x == 0) {
        float ts = 0.f, tsq = 0.f;
        const int nw = blockDim.x >> 5;
        for (int i = 0; i < nw; i++) { ts += sh[i]; tsq += sh[i + 32]; }
        const float mean = ts * (1.0f / DIMC);
        const float var  = tsq * (1.0f / DIMC) - mean * mean;
        sh[0] = mean; sh[1] = rsqrtf(var + 1e-5f);
    }
    __syncthreads();
    const float mean = sh[0], rstd = sh[1];

    for (int k0 = threadIdx.x * 8; k0 < DIMC; k0 += blockDim.x * 8) {
        float v[8];
        #pragma unroll
        for (int e = 0; e < 8; e++) {
            float t = (x[k0 + e] - mean) * rstd;
            if (g) t = t * g[k0 + e] + b[k0 + e];
            v[e] = t;
        }
        if (outF) {
            float* o = outF + (size_t)row * DIMC + k0;
            #pragma unroll
            for (int e = 0; e < 8; e++) o[e] = v[e];
        }
        if (outH) {
            uint32_t hq[4], lq[4];
            #pragma unroll
            for (int e = 0; e < 4; e++) {
                const __half2 h = __floats2half2_rn(v[2*e], v[2*e+1]);
                hq[e] = bits2(h);
                if (outL) {
                    const __half2 l = __floats2half2_rn(v[2*e]   - __low2float(h),
                                                        v[2*e+1] - __high2float(h));
                    lq[e] = bits2(l);
                }
            }
            const size_t ti = tiled_idx(row, k0, nrows);
            *reinterpret_cast<uint4*>(&outH[ti]) = make_uint4(hq[0], hq[1], hq[2], hq[3]);
            if (outL)
                *reinterpret_cast<uint4*>(&outL[ti]) = make_uint4(lq[0], lq[1], lq[2], lq[3]);
        }
    }
}

// ---------------- fused split-K reduce + residual + LayerNorm ----------------
__global__ void __launch_bounds__(128)
lnred_kernel(const float* __restrict__ part, int S,
             const float* __restrict__ latin,
             float* __restrict__ latout,
             float* __restrict__ outF,
             hf* __restrict__ outH, hf* __restrict__ outL,
             const float* __restrict__ g, const float* __restrict__ b)
{
    const int row = blockIdx.x;
    const int tid = threadIdx.x;
    const size_t base = (size_t)row * DIMC + tid * 8;
    float v[8];
    #pragma unroll
    for (int e = 0; e < 8; e++) v[e] = latin[base + e];
    for (int s = 0; s < S; s++) {
        const float* p = part + (size_t)s * LROWS * DIMC + base;
        #pragma unroll
        for (int e = 0; e < 8; e++) v[e] += p[e];
    }
    if (latout) {
        #pragma unroll
        for (int e = 0; e < 8; e++) latout[base + e] = v[e];
    }
    float s1 = 0.f, s2 = 0.f;
    #pragma unroll
    for (int e = 0; e < 8; e++) { s1 += v[e]; s2 += v[e] * v[e]; }
    __shared__ float sh[8];
    #pragma unroll
    for (int o = 16; o > 0; o >>= 1) {
        s1 += __shfl_down_sync(0xffffffffu, s1, o);
        s2 += __shfl_down_sync(0xffffffffu, s2, o);
    }
    const int wid = tid >> 5, lid = tid & 31;
    if (lid == 0) { sh[wid] = s1; sh[wid + 4] = s2; }
    __syncthreads();
    if (tid == 0) {
        float ts = sh[0] + sh[1] + sh[2] + sh[3];
        float tq = sh[4] + sh[5] + sh[6] + sh[7];
        const float mean = ts * (1.0f / DIMC);
        const float var  = tq * (1.0f / DIMC) - mean * mean;
        sh[0] = mean; sh[1] = rsqrtf(var + 1e-5f);
    }
    __syncthreads();
    const float mean = sh[0], rstd = sh[1];
    const int k0 = tid * 8;
    float t[8];
    #pragma unroll
    for (int e = 0; e < 8; e++)
        t[e] = (v[e] - mean) * rstd * g[k0 + e] + b[k0 + e];
    if (outF) {
        float* o = outF + base;
        #pragma unroll
        for (int e = 0; e < 8; e++) o[e] = t[e];
    }
    if (outH) {
        uint32_t hq[4], lq[4];
        #pragma unroll
        for (int e = 0; e < 4; e++) {
            const __half2 h = __floats2half2_rn(t[2*e], t[2*e+1]);
            hq[e] = bits2(h);
            if (outL) {
                const __half2 l = __floats2half2_rn(t[2*e]   - __low2float(h),
                                                    t[2*e+1] - __high2float(h));
                lq[e] = bits2(l);
            }
        }
        const size_t ti = tiled_idx(row, k0, LROWS);
        *reinterpret_cast<uint4*>(&outH[ti]) = make_uint4(hq[0], hq[1], hq[2], hq[3]);
        if (outL)
            *reinterpret_cast<uint4*>(&outL[ti]) = make_uint4(lq[0], lq[1], lq[2], lq[3]);
    }
}

// ---------------- bias: all layers, k-parallel ----------------
__global__ void bias_kernel(const float* __restrict__ nm_b,
                            const float* __restrict__ wkv, float* __restrict__ out)
{
    const int layer = blockIdx.y;
    const int tid = threadIdx.x;
    const int n  = blockIdx.x * 32 + (tid & 31);
    const int ks = tid >> 5;
    const float* bv = nm_b + (size_t)layer * DIMC;
    const float* W  = wkv  + (size_t)layer * DIMC * NKV;
    float s = 0.f;
    #pragma unroll 4
    for (int k = ks * 128; k < ks * 128 + 128; k++)
        s += bv[k] * __ldg(&W[(size_t)k * NKV + n]);
    __shared__ float red[8][32];
    red[ks][tid & 31] = s;
    __syncthreads();
    if (ks == 0) {
        float t = 0.f;
        #pragma unroll
        for (int i = 0; i < 8; i++) t += red[i][tid & 31];
        out[(size_t)layer * NKV + n] = t;
    }
}

__global__ void init_lat_kernel(const float* __restrict__ latents, float* __restrict__ lat)
{
    const int idx = blockIdx.x * blockDim.x + threadIdx.x;
    lat[idx] = latents[idx & (NLAT * DIMC - 1)];
}

// ---------------- weight transpose + gamma + fp16 quantize (batched over depth) ----
__global__ void wsplit_kernel(const float* __restrict__ W0, const float* __restrict__ g0,
                              hf* __restrict__ T0, int K, int N, int nofs, int ntot)
{
    const int z = blockIdx.z;
    const float* W = W0 + (size_t)z * K * N;
    const float* g = g0 ? g0 + (size_t)z * K : nullptr;
    hf* T = T0 + (size_t)z * ntot * K;
    __shared__ float t[32][33];
    const int n0 = blockIdx.x * 32, k0 = blockIdx.y * 32;
    const int tx = threadIdx.x, ty = threadIdx.y;
    #pragma unroll
    for (int i = 0; i < 4; i++) {
        float v = W[(size_t)(k0 + ty + 8 * i) * N + n0 + tx];
        if (g) v *= g[k0 + ty + 8 * i];
        t[ty + 8 * i][tx] = v;
    }
    __syncthreads();
    #pragma unroll
    for (int i = 0; i < 4; i++) {
        const int n = n0 + ty + 8 * i, k = k0 + tx;
        T[tiled_idx(nofs + n, k, ntot)] = __float2half_rn(t[tx][ty + 8 * i]);
    }
}

// =====================================================================
// 2-term fp16 HMMA GEMM (for qkv). k16-pipelined, occ 1.
// =====================================================================
#define NSTG 4
#define STG_BYTES 24576
#define TILEOFF 1024
#define GEMM_SMEM (TILEOFF + NSTG*STG_BYTES)

__global__ void __launch_bounds__(256, 1)
gemm_tc(const hf* __restrict__ Ah, const hf* __restrict__ Al,
        const hf* __restrict__ B0,
        hf* __restrict__ Ch, hf* __restrict__ Cl,
        int M, int N, int K)
{
    extern __shared__ char smem[];
    const uint32_t sb = smem_u32(smem);
    const int tid  = threadIdx.x;
    const int lane = tid & 31;
    const int wid  = tid >> 5;
    const int wm   = wid & 1;
    const int wn   = wid >> 1;
    const int bm   = blockIdx.y * 128;
    const int bn   = blockIdx.x * 128;
    const hf* B = B0;
    const int ncl = K >> 5;

    if (tid == 0) {
        #pragma unroll
        for (int s = 0; s < NSTG; s++) MBARRIER_INIT(sb + 8 * s, 1);
    }
    __syncthreads();

    float acc[4][4][4];
    #pragma unroll
    for (int i = 0; i < 4; i++)
        #pragma unroll
        for (int j = 0; j < 4; j++)
            #pragma unroll
            for (int q = 0; q < 4; q++) acc[i][j][q] = 0.f;

    auto issue = [&](int cl) {
        const uint32_t mb  = sb + 8 * (cl & 3);
        const uint32_t dst = sb + TILEOFF + (cl & 3) * STG_BYTES;
        MBARRIER_EXPECT_TX(mb, 24576u);
        bulk_g2s(dst,         Ah + ((size_t)cl * M + bm) * 32, 8192, mb);
        bulk_g2s(dst +  8192, Al + ((size_t)cl * M + bm) * 32, 8192, mb);
        bulk_g2s(dst + 16384, B  + ((size_t)cl * N + bn) * 32, 8192, mb);
    };
    if (tid == 0) {
        const int pre = ncl < NSTG ? ncl : NSTG;
        for (int s = 0; s < pre; s++) issue(s);
    }

    uint32_t a0H[16], a0L[16], b0[8];
    uint32_t a1H[16], a1L[16], b1[8];

    auto lds_step = [&](int u, uint32_t* aH, uint32_t* aL, uint32_t* bf) {
        const uint32_t stA = sb + TILEOFF + ((u >> 1) & 3) * STG_BYTES;
        const uint32_t stB = stA + 16384;
        const int s16 = u & 1;
        #pragma unroll
        for (int mi = 0; mi < 4; mi++) {
            const int row = wm * 64 + mi * 16 + (lane & 15);
            const int q   = s16 * 2 + (lane >> 4);
            const uint32_t ad = stA + row * 64 + ((q ^ ((row >> 1) & 3)) << 4);
            ldmx4(aH + 4 * mi, ad);
            ldmx4(aL + 4 * mi, ad + 8192);
        }
        #pragma unroll
        for (int ni = 0; ni < 2; ni++) {
            const int row = wn * 32 + ni * 16 + (lane & 7) + ((lane >> 4) << 3);
            const int q   = s16 * 2 + ((lane >> 3) & 1);
            const uint32_t bd = stB + row * 64 + ((q ^ ((row >> 1) & 3)) << 4);
            uint32_t t[4];
            ldmx4(t, bd);
            bf[ni*4+0] = t[0]; bf[ni*4+1] = t[1]; bf[ni*4+2] = t[2]; bf[ni*4+3] = t[3];
        }
    };
    auto mma_step = [&](const uint32_t* aH, const uint32_t* aL, const uint32_t* bf) {
        #pragma unroll
        for (int mi = 0; mi < 4; mi++)
            #pragma unroll
            for (int j = 0; j < 4; j++) {
                mma16816(acc[mi][j], aH + 4 * mi, bf + 2 * j);
                mma16816(acc[mi][j], aL + 4 * mi, bf + 2 * j);
            }
    };

    MBARRIER_WAIT_PARITY(sb, 0);
    lds_step(0, a0H, a0L, b0);
    const int total = ncl * 2;
    for (int u = 0; u < total; u += 2) {
        lds_step(u + 1, a1H, a1L, b1);
        __syncthreads();
        const int cl = u >> 1;
        if (tid == 0 && cl + NSTG < ncl) issue(cl + NSTG);
        mma_step(a0H, a0L, b0);
        if (u + 2 < total) {
            const int c2 = cl + 1;
            MBARRIER_WAIT_PARITY(sb + 8 * (c2 & 3), (c2 >> 2) & 1);
            lds_step(u + 2, a0H, a0L, b0);
        }
        mma_step(a1H, a1L, b1);
    }

    #pragma unroll
    for (int mi = 0; mi < 4; mi++) {
        #pragma unroll
        for (int j = 0; j < 4; j++) {
            const int colb = bn + wn * 32 + j * 8 + (lane & 3) * 2;
            #pragma unroll
            for (int p = 0; p < 2; p++) {
                const int row = bm + wm * 64 + mi * 16 + (lane >> 2) + 8 * p;
                const float v0 = acc[mi][j][p * 2], v1 = acc[mi][j][p * 2 + 1];
                const __half2 h = __floats2half2_rn(v0, v1);
                const __half2 l = __floats2half2_rn(v0 - __low2float(h),
                                                    v1 - __high2float(h));
                const size_t ti = tiled_idx(row, colb, M);
                *reinterpret_cast<uint32_t*>(&Ch[ti]) = bits2(h);
                *reinterpret_cast<uint32_t*>(&Cl[ti]) = bits2(l);
            }
        }
    }
}

// =====================================================================
// 1-term fp16 HMMA GEMM, occupancy 2 CTAs/SM (latency hidden by co-CTA).
// grid.z = layers (lstr*) OR split-K partitions (splitk>1, Cpart).
// =====================================================================
#define NSTG1 4
#define STG1  16384                   // A 8K | B 8K
#define G1_SMEM (1024 + NSTG1*STG1)   // 66560

__global__ void __launch_bounds__(256, 2)
gemm1_tc(const hf* __restrict__ Ah, const hf* __restrict__ B0,
         float* __restrict__ Cf, hf* __restrict__ Ch0,
         int M, int N, int K,
         const float* __restrict__ bias0, int dogelu,
         size_t lstrB, size_t lstrC, int lstrBias,
         int splitk, float* __restrict__ Cpart)
{
    extern __shared__ char smem[];
    const uint32_t sb = smem_u32(smem);
    const int tid  = threadIdx.x;
    const int lane = tid & 31;
    const int wid  = tid >> 5;
    const int wm   = wid & 1;
    const int wn   = wid >> 1;
    const int bm   = blockIdx.y * 128;
    const int bn   = blockIdx.x * 128;
    const int z    = blockIdx.z;

    const hf* B = B0;
    hf* Ch = Ch0;
    const float* bias = bias0;
    const int nc = K >> 5;
    int ncl = nc, c0 = 0;
    if (splitk > 1) { ncl = nc / splitk; c0 = z * ncl; }
    else if (z) {
        B += (size_t)z * lstrB;
        if (Ch0) Ch += (size_t)z * lstrC;
        if (bias0) bias += (size_t)z * lstrBias;
    }

    if (tid == 0) {
        #pragma unroll
        for (int s = 0; s < NSTG1; s++) MBARRIER_INIT(sb + 8 * s, 1);
    }
    __syncthreads();

    float acc[4][4][4];
    #pragma unroll
    for (int i = 0; i < 4; i++)
        #pragma unroll
        for (int j = 0; j < 4; j++)
            #pragma unroll
            for (int q = 0; q < 4; q++) acc[i][j][q] = 0.f;

    auto issue = [&](int cl) {
        const int gc = c0 + cl;
        const uint32_t mb  = sb + 8 * (cl & 3);
        const uint32_t dst = sb + 1024 + (cl & 3) * STG1;
        MBARRIER_EXPECT_TX(mb, 16384u);
        bulk_g2s(dst,        Ah + ((size_t)gc * M + bm) * 32, 8192, mb);
        bulk_g2s(dst + 8192, B  + ((size_t)gc * N + bn) * 32, 8192, mb);
    };
    if (tid == 0) {
        const int pre = ncl < NSTG1 ? ncl : NSTG1;
        for (int s = 0; s < pre; s++) issue(s);
    }

    for (int cl = 0; cl < ncl; cl++) {
        MBARRIER_WAIT_PARITY(sb + 8 * (cl & 3), (cl >> 2) & 1);
        const uint32_t stA = sb + 1024 + (cl & 3) * STG1;
        const uint32_t stB = stA + 8192;
        #pragma unroll
        for (int s16 = 0; s16 < 2; s16++) {
            uint32_t aH[16], bf[8];
            #pragma unroll
            for (int mi = 0; mi < 4; mi++) {
                const int row = wm * 64 + mi * 16 + (lane & 15);
                const int q   = s16 * 2 + (lane >> 4);
                ldmx4(aH + 4 * mi, stA + row * 64 + ((q ^ ((row >> 1) & 3)) << 4));
            }
            #pragma unroll
            for (int ni = 0; ni < 2; ni++) {
                const int row = wn * 32 + ni * 16 + (lane & 7) + ((lane >> 4) << 3);
                const int q   = s16 * 2 + ((lane >> 3) & 1);
                uint32_t t[4];
                ldmx4(t, stB + row * 64 + ((q ^ ((row >> 1) & 3)) << 4));
                bf[ni*4+0] = t[0]; bf[ni*4+1] = t[1]; bf[ni*4+2] = t[2]; bf[ni*4+3] = t[3];
            }
            #pragma unroll
            for (int mi = 0; mi < 4; mi++)
                #pragma unroll
                for (int j = 0; j < 4; j++)
                    mma16816(acc[mi][j], aH + 4 * mi, bf + 2 * j);
        }
        __syncthreads();
        if (tid == 0 && cl + NSTG1 < ncl) issue(cl + NSTG1);
    }

    // ---- epilogue ----
    if (Cpart) {
        float* P = Cpart + (size_t)z * M * N;
        #pragma unroll
        for (int mi = 0; mi < 4; mi++)
            #pragma unroll
            for (int j = 0; j < 4; j++) {
                const int colb = bn + wn * 32 + j * 8 + (lane & 3) * 2;
                #pragma unroll
                for (int p = 0; p < 2; p++) {
                    const int row = bm + wm * 64 + mi * 16 + (lane >> 2) + 8 * p;
                    *reinterpret_cast<float2*>(&P[(size_t)row * N + colb]) =
                        make_float2(acc[mi][j][p * 2], acc[mi][j][p * 2 + 1]);
                }
            }
        return;
    }
    #pragma unroll
    for (int mi = 0; mi < 4; mi++) {
        #pragma unroll
        for (int j = 0; j < 4; j++) {
            const int colb = bn + wn * 32 + j * 8 + (lane & 3) * 2;
            #pragma unroll
            for (int p = 0; p < 2; p++) {
                const int row = bm + wm * 64 + mi * 16 + (lane >> 2) + 8 * p;
                float v0 = acc[mi][j][p * 2], v1 = acc[mi][j][p * 2 + 1];
                if (bias) { v0 += bias[colb]; v1 += bias[colb + 1]; }
                if (dogelu) {
                    v0 = 0.5f * v0 * (1.f + erff(v0 * 0.70710678118654752f));
                    v1 = 0.5f * v1 * (1.f + erff(v1 * 0.70710678118654752f));
                }
                if (Cf) *reinterpret_cast<float2*>(&Cf[(size_t)row * N + colb]) = make_float2(v0, v1);
                if (Ch) {
                    const __half2 h = __floats2half2_rn(v0, v1);
                    *reinterpret_cast<uint32_t*>(&Ch[tiled_idx(row, colb, M)]) = bits2(h);
                }
            }
        }
    }
}

// =====================================================================
// Tensor-core flash attention (fp16 2-term Q/P, single-plane K/V/out).
// =====================================================================
#define OFF_Q   1024
#define OFF_KV  (OFF_Q + 16384)
#define OFF_P   (OFF_KV + 32768)
#define OFF_SS  (OFF_P + 16384)
#define OFF_ST  (OFF_SS + 64*65*4)
#define ATT_SMEM (OFF_ST + 768)

__global__ void __launch_bounds__(256, 1)
attn_tc(const hf* __restrict__ QKVh, const hf* __restrict__ QKVl,
        const hf* __restrict__ Kmh,
        hf* __restrict__ OH)
{
    extern __shared__ char smem[];
    const uint32_t sb = smem_u32(smem);
    const int bt  = blockIdx.x >> 4;
    const int h   = blockIdx.x & 15;
    const int tid = threadIdx.x;
    const int lane = tid & 31;
    const int wid  = tid >> 5;
    const int wm   = wid & 1;
    const int wn   = wid >> 1;
    float* Ss    = reinterpret_cast<float*>(smem + OFF_SS);
    float* mrow  = reinterpret_cast<float*>(smem + OFF_ST);
    float* lrow  = mrow + 64;
    float* frow  = lrow + 64;

    if (tid == 0) { MBARRIER_INIT(sb, 1); MBARRIER_INIT(sb + 8, 1); }

    {
        #pragma unroll
        for (int seg = 0; seg < 4; seg++) {
            const hf* src = (seg < 2 ? QKVh : QKVl) + ((size_t)(2 * h + (seg & 1)) * LROWS + bt * 64) * 32;
            const uint4 v = reinterpret_cast<const uint4*>(src)[tid];
            *reinterpret_cast<uint4*>(smem + OFF_Q + (seg >= 2 ? 8192 : 0) + (seg & 1) * 4096 + tid * 16) = v;
        }
    }
    if (tid < 64) { mrow[tid] = -INFINITY; lrow[tid] = 0.f; }
    __syncthreads();

    auto issueKV = [&](int t) {
        const int st = t & 1;
        const uint32_t mb = sb + 8 * st;
        const uint32_t dst = sb + OFF_KV + st * 16384;
        MBARRIER_EXPECT_TX(mb, 16384u);
        const hf* PH; size_t rbase, nr; int kcK, kcV;
        if (t < 16) { PH = Kmh;  rbase = (size_t)bt * 1024 + t * 64; nr = NMEDIA; kcK = 2*h;      kcV = 32 + 2*h; }
        else        { PH = QKVh; rbase = (size_t)bt * 64;            nr = LROWS;  kcK = 32 + 2*h; kcV = 64 + 2*h; }
        bulk_g2s(dst,          PH + ((size_t)kcK * nr + rbase) * 32,       4096, mb);
        bulk_g2s(dst +  4096,  PH + ((size_t)(kcK + 1) * nr + rbase) * 32, 4096, mb);
        bulk_g2s(dst +  8192,  PH + ((size_t)kcV * nr + rbase) * 32,       4096, mb);
        bulk_g2s(dst + 12288,  PH + ((size_t)(kcV + 1) * nr + rbase) * 32, 4096, mb);
    };
    if (tid == 0) issueKV(0);

    uint32_t qH[2][4][4], qL[2][4][4];
    #pragma unroll
    for (int mi = 0; mi < 2; mi++)
        #pragma unroll
        for (int s = 0; s < 4; s++) {
            const int row = wm * 32 + mi * 16 + (lane & 15);
            const int qq = (((s & 1) * 2 + (lane >> 4)) ^ ((row >> 1) & 3));
            const uint32_t ad = sb + OFF_Q + (s >> 1) * 4096 + row * 64 + (qq << 4);
            ldmx4(qH[mi][s], ad);
            ldmx4(qL[mi][s], ad + 8192);
        }

    float acc[2][2][4];
    #pragma unroll
    for (int i = 0; i < 2; i++)
        #pragma unroll
        for (int j = 0; j < 2; j++)
            #pragma unroll
            for (int q = 0; q < 4; q++) acc[i][j][q] = 0.f;

    for (int t = 0; t < 17; t++) {
        if (tid == 0 && t + 1 < 17) issueKV(t + 1);
        MBARRIER_WAIT_PARITY(sb + 8 * (t & 1), (t >> 1) & 1);
        const uint32_t kb = sb + OFF_KV + (t & 1) * 16384;

        float sc[2][2][4] = {};
        #pragma unroll
        for (int s = 0; s < 4; s++) {
            const int row = wn * 16 + (lane & 7) + ((lane >> 4) << 3);
            const int qq = (((s & 1) * 2 + ((lane >> 3) & 1)) ^ ((row >> 1) & 3));
            const uint32_t ad = kb + (s >> 1) * 4096 + row * 64 + (qq << 4);
            uint32_t tH[4];
            ldmx4(tH, ad);
            uint32_t bh0[2] = {tH[0], tH[1]}, bh1[2] = {tH[2], tH[3]};
            #pragma unroll
            for (int mi = 0; mi < 2; mi++) {
                mma16816(sc[mi][0], qH[mi][s], bh0);
                mma16816(sc[mi][0], qL[mi][s], bh0);
                mma16816(sc[mi][1], qH[mi][s], bh1);
                mma16816(sc[mi][1], qL[mi][s], bh1);
            }
        }
        #pragma unroll
        for (int mi = 0; mi < 2; mi++)
            #pragma unroll
            for (int j = 0; j < 2; j++)
                #pragma unroll
                for (int p = 0; p < 2; p++) {
                    const int r = wm * 32 + mi * 16 + (lane >> 2) + 8 * p;
                    const int col = wn * 16 + j * 8 + (lane & 3) * 2;
                    Ss[r * 65 + col]     = sc[mi][j][p * 2]     * 0.125f;
                    Ss[r * 65 + col + 1] = sc[mi][j][p * 2 + 1] * 0.125f;
                }
        __syncthreads();

        {
            const int r = tid >> 2, qd = tid & 3;
            const int kb2 = qd * 16;
            float tmax = -INFINITY;
            #pragma unroll
            for (int k = 0; k < 16; k++) tmax = fmaxf(tmax, Ss[r * 65 + kb2 + k]);
            tmax = fmaxf(tmax, __shfl_xor_sync(0xffffffffu, tmax, 1));
            tmax = fmaxf(tmax, __shfl_xor_sync(0xffffffffu, tmax, 2));
            const float mold = mrow[r];
            const float mnew = fmaxf(mold, tmax);
            float s = 0.f;
            #pragma unroll
            for (int k = 0; k < 16; k++) {
                const float p = __expf(Ss[r * 65 + kb2 + k] - mnew);
                Ss[r * 65 + kb2 + k] = p;
                s += p;
            }
            s += __shfl_xor_sync(0xffffffffu, s, 1);
            s += __shfl_xor_sync(0xffffffffu, s, 2);
            if (qd == 0) {
                const float fac = __expf(mold - mnew);
                lrow[r] = lrow[r] * fac + s;
                mrow[r] = mnew;
                frow[r] = fac;
            }
        }
        __syncthreads();

        #pragma unroll
        for (int mi = 0; mi < 2; mi++)
            #pragma unroll
            for (int p = 0; p < 2; p++) {
                const float fac = frow[wm * 32 + mi * 16 + (lane >> 2) + 8 * p];
                #pragma unroll
                for (int j = 0; j < 2; j++) {
                    acc[mi][j][p * 2]     *= fac;
                    acc[mi][j][p * 2 + 1] *= fac;
                }
            }
        #pragma unroll
        for (int i = 0; i < 8; i++) {
            const int pi = tid * 8 + i;
            const int q = pi >> 5, kp = pi & 31, k = kp * 2;
            const int kc = k >> 5, kin = k & 31;
            const int qq = ((kin >> 3) ^ ((q >> 1) & 3));
            const int off = OFF_P + kc * 4096 + q * 64 + (qq << 4) + (kin & 7) * 2;
            const float v0 = Ss[q * 65 + k], v1 = Ss[q * 65 + k + 1];
            const __half2 hh = __floats2half2_rn(v0, v1);
            const __half2 ll = __floats2half2_rn(v0 - __low2float(hh),
                                                 v1 - __high2float(hh));
            *reinterpret_cast<uint32_t*>(smem + off)        = bits2(hh);
            *reinterpret_cast<uint32_t*>(smem + off + 8192) = bits2(ll);
        }
        __syncthreads();

        #pragma unroll
        for (int s = 0; s < 4; s++) {
            uint32_t pH[2][4], pL[2][4];
            #pragma unroll
            for (int mi = 0; mi < 2; mi++) {
                const int row = wm * 32 + mi * 16 + (lane & 15);
                const int qq = (((s & 1) * 2 + (lane >> 4)) ^ ((row >> 1) & 3));
                const uint32_t ad = sb + OFF_P + (s >> 1) * 4096 + row * 64 + (qq << 4);
                ldmx4(pH[mi], ad);
                ldmx4(pL[mi], ad + 8192);
            }
            const int key  = s * 16 + (lane & 15);
            const int dinb = wn * 16 + ((lane >> 4) << 3);
            const int kcv  = dinb >> 5, din = dinb & 31;
            const int qq   = ((din >> 3) ^ ((key >> 1) & 3));
            const uint32_t ad = kb + 8192 + kcv * 4096 + key * 64 + (qq << 4);
            uint32_t tH[4];
            ldmx4t(tH, ad);
            uint32_t vh0[2] = {tH[0], tH[1]}, vh1[2] = {tH[2], tH[3]};
            #pragma unroll
            for (int mi = 0; mi < 2; mi++) {
                mma16816(acc[mi][0], pH[mi], vh0);
                mma16816(acc[mi][0], pL[mi], vh0);
                mma16816(acc[mi][1], pH[mi], vh1);
                mma16816(acc[mi][1], pL[mi], vh1);
            }
        }
        __syncthreads();
    }

    #pragma unroll
    for (int mi = 0; mi < 2; mi++)
        #pragma unroll
        for (int p = 0; p < 2; p++) {
            const int r = wm * 32 + mi * 16 + (lane >> 2) + 8 * p;
            const float inv = 1.0f / lrow[r];
            #pragma unroll
            for (int j = 0; j < 2; j++) {
                const int col = h * 64 + wn * 16 + j * 8 + (lane & 3) * 2;
                const float v0 = acc[mi][j][p * 2] * inv;
                const float v1 = acc[mi][j][p * 2 + 1] * inv;
                const __half2 hh = __floats2half2_rn(v0, v1);
                const size_t ti = tiled_idx(bt * 64 + r, col, LROWS);
                *reinterpret_cast<uint32_t*>(&OH[ti]) = bits2(hh);
            }
        }
}

// ---------------- orchestration ----------------
extern "C" void kernel_launch(void* const* d_in, const int* in_sizes, int n_in,
                              void* d_out, int out_size)
{
    (void)in_sizes; (void)n_in; (void)out_size;
    const float* x       = (const float*)d_in[0];
    const float* latents = (const float*)d_in[1];
    const float* nm_g    = (const float*)d_in[2];
    const float* nm_b    = (const float*)d_in[3];
    const float* nl_g    = (const float*)d_in[4];
    const float* nl_b    = (const float*)d_in[5];
    const float* wq      = (const float*)d_in[6];
    const float* wkv     = (const float*)d_in[7];
    const float* wo      = (const float*)d_in[8];
    const float* ff_g    = (const float*)d_in[9];
    const float* ff_b    = (const float*)d_in[10];
    const float* w1      = (const float*)d_in[11];
    const float* w2      = (const float*)d_in[12];
    const float* fin_g   = (const float*)d_in[13];
    const float* fin_b   = (const float*)d_in[14];
    float* out = (float*)d_out;

    hf *xh, *kvmh, *lnh, *lnl, *qkvh, *qkvl, *ath, *h1h;
    float *lat, *bias, *part;
    cudaGetSymbolAddress((void**)&xh,   g_xh);
    cudaGetSymbolAddress((void**)&kvmh, g_kvmh);
    cudaGetSymbolAddress((void**)&lat,  g_lat);
    cudaGetSymbolAddress((void**)&lnh,  g_lnh);  cudaGetSymbolAddress((void**)&lnl,  g_lnl);
    cudaGetSymbolAddress((void**)&qkvh, g_qkvh); cudaGetSymbolAddress((void**)&qkvl, g_qkvl);
    cudaGetSymbolAddress((void**)&ath,  g_ath);
    cudaGetSymbolAddress((void**)&h1h,  g_h1h);
    cudaGetSymbolAddress((void**)&bias, g_bias); cudaGetSymbolAddress((void**)&part, g_part);

    hf *wqkvT, *wkvG, *woT, *w1T, *w2T;
    cudaGetSymbolAddress((void**)&wqkvT, g_wqkvT);
    cudaGetSymbolAddress((void**)&wkvG,  g_wkvG);
    cudaGetSymbolAddress((void**)&woT,   g_woT);
    cudaGetSymbolAddress((void**)&w1T,   g_w1T);
    cudaGetSymbolAddress((void**)&w2T,   g_w2T);

    cudaFuncSetAttribute(gemm_tc,  cudaFuncAttributeMaxDynamicSharedMemorySize, GEMM_SMEM);
    cudaFuncSetAttribute(gemm1_tc, cudaFuncAttributeMaxDynamicSharedMemorySize, G1_SMEM);
    cudaFuncSetAttribute(attn_tc,  cudaFuncAttributeMaxDynamicSharedMemorySize, ATT_SMEM);
    const dim3 tb(32, 8);

    // ---- weight prep ----
    wsplit_kernel<<<dim3(DIMC/32, DIMC/32, DEPTHL), tb>>>(wq,  nullptr, wqkvT, DIMC, DIMC, 0,    NQKV);
    wsplit_kernel<<<dim3(NKV/32,  DIMC/32, DEPTHL), tb>>>(wkv, nullptr, wqkvT, DIMC, NKV,  DIMC, NQKV);
    wsplit_kernel<<<dim3(NKV/32,  DIMC/32, DEPTHL), tb>>>(wkv, nm_g,    wkvG,  DIMC, NKV,  0,    NKV);
    wsplit_kernel<<<dim3(DIMC/32, DIMC/32, DEPTHL), tb>>>(wo,  nullptr, woT,   DIMC, DIMC, 0,    DIMC);
    wsplit_kernel<<<dim3(FFD/32,  DIMC/32, DEPTHL), tb>>>(w1,  nullptr, w1T,   DIMC, FFD,  0,    FFD);
    wsplit_kernel<<<dim3(DIMC/32, FFD/32,  DEPTHL), tb>>>(w2,  nullptr, w2T,   FFD,  DIMC, 0,    DIMC);
    bias_kernel<<<dim3(NKV/32, DEPTHL), 256>>>(nm_b, wkv, bias);

    ln_kernel<<<NMEDIA, 128>>>(x, nullptr, xh, nullptr, nullptr, nullptr, NMEDIA);
    init_lat_kernel<<<(LROWS * DIMC) / 256, 256>>>(latents, lat);

    // ---- all-layer media KV: 1-term A, occ-2 kernel ----
    gemm1_tc<<<dim3(NKV/128, NMEDIA/128, DEPTHL), 256, G1_SMEM>>>(
        xh, wkvG, nullptr, kvmh, NMEDIA, NKV, DIMC,
        bias, 0,
        (size_t)NKV*DIMC, (size_t)NMEDIA*NKV, NKV, 1, nullptr);

    // layer 0 nl-LN
    ln_kernel<<<LROWS, 128>>>(lat, nullptr, lnh, lnl, nl_g, nl_b, LROWS);

    for (int i = 0; i < DEPTHL; i++) {
        // fused Q|K|V latent GEMM (2-term A, hi+lo out)
        gemm_tc<<<dim3(NQKV/128, LROWS/128), 256, GEMM_SMEM>>>(
            lnh, lnl, wqkvT + (size_t)i*NQKV*DIMC,
            qkvh, qkvl, LROWS, NQKV, DIMC);
        attn_tc<<<BTOT * HEADS, 256, ATT_SMEM>>>(
            qkvh, qkvl, kvmh + (size_t)i*NMEDIA*NKV, ath);
        // wo (1-term, split-K 2) -> part ; fused reduce+residual+ff-LN
        gemm1_tc<<<dim3(DIMC/128, LROWS/128, 2), 256, G1_SMEM>>>(
            ath, woT + (size_t)i*DIMC*DIMC,
            nullptr, nullptr, LROWS, DIMC, DIMC, nullptr, 0,
            0, 0, 0, 2, part);
        lnred_kernel<<<LROWS, 128>>>(part, 2, lat, lat, nullptr, lnh, nullptr,
                                     ff_g + (size_t)i*DIMC, ff_b + (size_t)i*DIMC);
        // ff1 (1-term) -> gelu -> h1h
        gemm1_tc<<<dim3(FFD/128, LROWS/128), 256, G1_SMEM>>>(
            lnh, w1T + (size_t)i*FFD*DIMC,
            nullptr, h1h, LROWS, FFD, DIMC, nullptr, 1,
            0, 0, 0, 1, nullptr);
        // ff2 (1-term, split-K 4) -> part ; fused reduce+residual+next-LN
        gemm1_tc<<<dim3(DIMC/128, LROWS/128, 4), 256, G1_SMEM>>>(
            h1h, w2T + (size_t)i*DIMC*FFD,
            nullptr, nullptr, LROWS, DIMC, FFD, nullptr, 0,
            0, 0, 0, 4, part);
        if (i + 1 < DEPTHL) {
            lnred_kernel<<<LROWS, 128>>>(part, 4, lat, lat, nullptr, lnh, lnl,
                                         nl_g + (size_t)(i+1)*DIMC, nl_b + (size_t)(i+1)*DIMC);
        } else {
            lnred_kernel<<<LROWS, 128>>>(part, 4, lat, nullptr, out, nullptr, nullptr,
                                         fin_g, fin_b);
        }
    }
}

// round 12
// speedup vs baseline: 8.2129x; 1.1750x over previous
#include <cuda_runtime.h>
#include <cuda_fp16.h>
#include <math.h>
#include <stdint.h>

// ---------------- problem constants ----------------
#define DIMC   1024
#define DEPTHL 6
#define HEADS  16
#define DHEAD  64
#define NKV    2048
#define NQKV   3072
#define FFD    4096
#define BTOT   32
#define MEDIA  1024
#define NMEDIA (BTOT*MEDIA)          // 32768
#define NLAT   64
#define LROWS  (BTOT*NLAT)           // 2048

typedef __half hf;

// ---------------- scratch ----------------
__device__ __align__(1024) hf    g_xh  [(size_t)NMEDIA*DIMC];
__device__ __align__(1024) hf    g_kvmh[(size_t)DEPTHL*NMEDIA*NKV];
__device__ float g_lat [LROWS*DIMC];
__device__ __align__(1024) hf    g_lnh [LROWS*DIMC];
__device__ __align__(1024) hf    g_lnl [LROWS*DIMC];
__device__ __align__(1024) hf    g_qkvh[(size_t)LROWS*NQKV];
__device__ __align__(1024) hf    g_qkvl[(size_t)LROWS*NQKV];
__device__ __align__(1024) hf    g_ath [LROWS*DIMC];
__device__ __align__(1024) hf    g_h1h [(size_t)LROWS*FFD];
__device__ float g_bias[DEPTHL*NKV];
__device__ float g_part[(size_t)4*LROWS*DIMC];

// weight planes (single fp16, B-side), chunk-tiled [K/32][N][32]
__device__ __align__(1024) hf g_wqkvT[(size_t)DEPTHL*NQKV*DIMC];
__device__ __align__(1024) hf g_wkvG [(size_t)DEPTHL*NKV*DIMC];
__device__ __align__(1024) hf g_woT  [(size_t)DEPTHL*DIMC*DIMC];
__device__ __align__(1024) hf g_w1T  [(size_t)DEPTHL*FFD*DIMC];
__device__ __align__(1024) hf g_w2T  [(size_t)DEPTHL*DIMC*FFD];

// ---------------- helpers ----------------
__device__ __forceinline__ uint32_t smem_u32(const void* p) {
    return (uint32_t)__cvta_generic_to_shared(p);
}
__device__ __forceinline__ size_t tiled_idx(int row, int k, int nrows) {
    const int kc = k >> 5, kin = k & 31;
    const int q = kin >> 3, b = kin & 7;
    const int qs = q ^ ((row >> 1) & 3);
    return ((size_t)kc * nrows + row) * 32 + qs * 8 + b;
}
__device__ __forceinline__ void bulk_g2s(uint32_t dst, const void* src, uint32_t bytes, uint32_t mbar) {
    asm volatile("cp.async.bulk.shared::cluster.global.mbarrier::complete_tx::bytes [%0], [%1], %2, [%3];"
                 :: "r"(dst), "l"(src), "r"(bytes), "r"(mbar) : "memory");
}
#define MBARRIER_INIT(addr, cnt) \
    asm volatile("mbarrier.init.shared.b64 [%0], %1;" :: "r"(addr), "r"(cnt) : "memory")
#define MBARRIER_EXPECT_TX(addr, tx) \
    asm volatile("mbarrier.arrive.expect_tx.shared.b64 _, [%0], %1;" :: "r"(addr), "r"(tx) : "memory")
#define MBARRIER_WAIT_PARITY(addr, par) do { \
    uint32_t _m = (addr), _p = (par), _d; \
    asm volatile("{\n\t.reg .pred p;\n\t" \
        "mbarrier.try_wait.parity.acquire.cta.shared::cta.b64 p, [%1], %2;\n\t" \
        "selp.b32 %0, 1, 0, p;\n\t}" : "=r"(_d) : "r"(_m), "r"(_p) : "memory"); \
    if (!_d) { \
        asm volatile("{\n\t.reg .pred P1;\n\t" \
            "WL_%=:\n\t" \
            "mbarrier.try_wait.parity.acquire.cta.shared::cta.b64 P1, [%0], %1, 0x989680;\n\t" \
            "@P1 bra.uni WD_%=;\n\tbra.uni WL_%=;\n\tWD_%=:\n\t}" \
            :: "r"(_m), "r"(_p) : "memory"); \
    } } while (0)

__device__ __forceinline__ void ldmx4(uint32_t* r, uint32_t a) {
    asm volatile("ldmatrix.sync.aligned.m8n8.x4.shared.b16 {%0,%1,%2,%3}, [%4];"
                 : "=r"(r[0]), "=r"(r[1]), "=r"(r[2]), "=r"(r[3]) : "r"(a));
}
__device__ __forceinline__ void ldmx4t(uint32_t* r, uint32_t a) {
    asm volatile("ldmatrix.sync.aligned.m8n8.x4.trans.shared.b16 {%0,%1,%2,%3}, [%4];"
                 : "=r"(r[0]), "=r"(r[1]), "=r"(r[2]), "=r"(r[3]) : "r"(a));
}
__device__ __forceinline__ void mma16816(float* d, const uint32_t* a, const uint32_t* b) {
    asm volatile("mma.sync.aligned.m16n8k16.row.col.f32.f16.f16.f32 "
                 "{%0,%1,%2,%3},{%4,%5,%6,%7},{%8,%9},{%0,%1,%2,%3};"
                 : "+f"(d[0]), "+f"(d[1]), "+f"(d[2]), "+f"(d[3])
                 : "r"(a[0]), "r"(a[1]), "r"(a[2]), "r"(a[3]),
                   "r"(b[0]), "r"(b[1]));
}
__device__ __forceinline__ uint32_t bits2(__half2 h) {
    return *reinterpret_cast<uint32_t*>(&h);
}

// ---------------- LayerNorm ----------------
__global__ void ln_kernel(const float* __restrict__ in,
                          float* __restrict__ outF,
                          hf* __restrict__ outH, hf* __restrict__ outL,
                          const float* __restrict__ g, const float* __restrict__ b,
                          int nrows)
{
    const int row = blockIdx.x;
    const float* x = in + (size_t)row * DIMC;
    float s = 0.f, sq = 0.f;
    for (int c = threadIdx.x; c < DIMC; c += blockDim.x) {
        float v = x[c]; s += v; sq += v * v;
    }
    __shared__ float sh[64];
    #pragma unroll
    for (int o = 16; o > 0; o >>= 1) {
        s  += __shfl_down_sync(0xffffffffu, s,  o);
        sq += __shfl_down_sync(0xffffffffu, sq, o);
    }
    const int wid = threadIdx.x >> 5, lid = threadIdx.x & 31;
    if (lid == 0) { sh[wid] = s; sh[wid + 32] = sq; }
    __syncthreads();
    if (threadIdx.x == 0) {
        float ts = 0.f, tsq = 0.f;
        const int nw = blockDim.x >> 5;
        for (int i = 0; i < nw; i++) { ts += sh[i]; tsq += sh[i + 32]; }
        const float mean = ts * (1.0f / DIMC);
        const float var  = tsq * (1.0f / DIMC) - mean * mean;
        sh[0] = mean; sh[1] = rsqrtf(var + 1e-5f);
    }
    __syncthreads();
    const float mean = sh[0], rstd = sh[1];

    for (int k0 = threadIdx.x * 8; k0 < DIMC; k0 += blockDim.x * 8) {
        float v[8];
        #pragma unroll
        for (int e = 0; e < 8; e++) {
            float t = (x[k0 + e] - mean) * rstd;
            if (g) t = t * g[k0 + e] + b[k0 + e];
            v[e] = t;
        }
        if (outF) {
            float* o = outF + (size_t)row * DIMC + k0;
            #pragma unroll
            for (int e = 0; e < 8; e++) o[e] = v[e];
        }
        if (outH) {
            uint32_t hq[4], lq[4];
            #pragma unroll
            for (int e = 0; e < 4; e++) {
                const __half2 h = __floats2half2_rn(v[2*e], v[2*e+1]);
                hq[e] = bits2(h);
                if (outL) {
                    const __half2 l = __floats2half2_rn(v[2*e]   - __low2float(h),
                                                        v[2*e+1] - __high2float(h));
                    lq[e] = bits2(l);
                }
            }
            const size_t ti = tiled_idx(row, k0, nrows);
            *reinterpret_cast<uint4*>(&outH[ti]) = make_uint4(hq[0], hq[1], hq[2], hq[3]);
            if (outL)
                *reinterpret_cast<uint4*>(&outL[ti]) = make_uint4(lq[0], lq[1], lq[2], lq[3]);
        }
    }
}

// ---------------- fused split-K reduce + residual + LayerNorm ----------------
__global__ void __launch_bounds__(128)
lnred_kernel(const float* __restrict__ part, int S,
             const float* __restrict__ latin,
             float* __restrict__ latout,
             float* __restrict__ outF,
             hf* __restrict__ outH, hf* __restrict__ outL,
             const float* __restrict__ g, const float* __restrict__ b)
{
    const int row = blockIdx.x;
    const int tid = threadIdx.x;
    const size_t base = (size_t)row * DIMC + tid * 8;
    float v[8];
    #pragma unroll
    for (int e = 0; e < 8; e++) v[e] = latin[base + e];
    for (int s = 0; s < S; s++) {
        const float* p = part + (size_t)s * LROWS * DIMC + base;
        #pragma unroll
        for (int e = 0; e < 8; e++) v[e] += p[e];
    }
    if (latout) {
        #pragma unroll
        for (int e = 0; e < 8; e++) latout[base + e] = v[e];
    }
    float s1 = 0.f, s2 = 0.f;
    #pragma unroll
    for (int e = 0; e < 8; e++) { s1 += v[e]; s2 += v[e] * v[e]; }
    __shared__ float sh[8];
    #pragma unroll
    for (int o = 16; o > 0; o >>= 1) {
        s1 += __shfl_down_sync(0xffffffffu, s1, o);
        s2 += __shfl_down_sync(0xffffffffu, s2, o);
    }
    const int wid = tid >> 5, lid = tid & 31;
    if (lid == 0) { sh[wid] = s1; sh[wid + 4] = s2; }
    __syncthreads();
    if (tid == 0) {
        float ts = sh[0] + sh[1] + sh[2] + sh[3];
        float tq = sh[4] + sh[5] + sh[6] + sh[7];
        const float mean = ts * (1.0f / DIMC);
        const float var  = tq * (1.0f / DIMC) - mean * mean;
        sh[0] = mean; sh[1] = rsqrtf(var + 1e-5f);
    }
    __syncthreads();
    const float mean = sh[0], rstd = sh[1];
    const int k0 = tid * 8;
    float t[8];
    #pragma unroll
    for (int e = 0; e < 8; e++)
        t[e] = (v[e] - mean) * rstd * g[k0 + e] + b[k0 + e];
    if (outF) {
        float* o = outF + base;
        #pragma unroll
        for (int e = 0; e < 8; e++) o[e] = t[e];
    }
    if (outH) {
        uint32_t hq[4], lq[4];
        #pragma unroll
        for (int e = 0; e < 4; e++) {
            const __half2 h = __floats2half2_rn(t[2*e], t[2*e+1]);
            hq[e] = bits2(h);
            if (outL) {
                const __half2 l = __floats2half2_rn(t[2*e]   - __low2float(h),
                                                    t[2*e+1] - __high2float(h));
                lq[e] = bits2(l);
            }
        }
        const size_t ti = tiled_idx(row, k0, LROWS);
        *reinterpret_cast<uint4*>(&outH[ti]) = make_uint4(hq[0], hq[1], hq[2], hq[3]);
        if (outL)
            *reinterpret_cast<uint4*>(&outL[ti]) = make_uint4(lq[0], lq[1], lq[2], lq[3]);
    }
}

// ---------------- bias: all layers, k-parallel ----------------
__global__ void bias_kernel(const float* __restrict__ nm_b,
                            const float* __restrict__ wkv, float* __restrict__ out)
{
    const int layer = blockIdx.y;
    const int tid = threadIdx.x;
    const int n  = blockIdx.x * 32 + (tid & 31);
    const int ks = tid >> 5;
    const float* bv = nm_b + (size_t)layer * DIMC;
    const float* W  = wkv  + (size_t)layer * DIMC * NKV;
    float s = 0.f;
    #pragma unroll 4
    for (int k = ks * 128; k < ks * 128 + 128; k++)
        s += bv[k] * __ldg(&W[(size_t)k * NKV + n]);
    __shared__ float red[8][32];
    red[ks][tid & 31] = s;
    __syncthreads();
    if (ks == 0) {
        float t = 0.f;
        #pragma unroll
        for (int i = 0; i < 8; i++) t += red[i][tid & 31];
        out[(size_t)layer * NKV + n] = t;
    }
}

__global__ void init_lat_kernel(const float* __restrict__ latents, float* __restrict__ lat)
{
    const int idx = blockIdx.x * blockDim.x + threadIdx.x;
    lat[idx] = latents[idx & (NLAT * DIMC - 1)];
}

// ---------------- weight transpose + gamma + fp16 quantize (batched over depth) ----
__global__ void wsplit_kernel(const float* __restrict__ W0, const float* __restrict__ g0,
                              hf* __restrict__ T0, int K, int N, int nofs, int ntot)
{
    const int z = blockIdx.z;
    const float* W = W0 + (size_t)z * K * N;
    const float* g = g0 ? g0 + (size_t)z * K : nullptr;
    hf* T = T0 + (size_t)z * ntot * K;
    __shared__ float t[32][33];
    const int n0 = blockIdx.x * 32, k0 = blockIdx.y * 32;
    const int tx = threadIdx.x, ty = threadIdx.y;
    #pragma unroll
    for (int i = 0; i < 4; i++) {
        float v = W[(size_t)(k0 + ty + 8 * i) * N + n0 + tx];
        if (g) v *= g[k0 + ty + 8 * i];
        t[ty + 8 * i][tx] = v;
    }
    __syncthreads();
    #pragma unroll
    for (int i = 0; i < 4; i++) {
        const int n = n0 + ty + 8 * i, k = k0 + tx;
        T[tiled_idx(nofs + n, k, ntot)] = __float2half_rn(t[tx][ty + 8 * i]);
    }
}

// =====================================================================
// 2-term fp16 HMMA GEMM, single reg buffer, occ 2 (for qkv).
// Writes hi plane always; lo plane only for columns < loN.
// =====================================================================
#define NSTG2 2
#define STG2  24576                   // Ah 8K | Al 8K | B 8K
#define G2_SMEM (1024 + NSTG2*STG2)   // 50176

__global__ void __launch_bounds__(256, 2)
gemm2b_tc(const hf* __restrict__ Ah, const hf* __restrict__ Al,
          const hf* __restrict__ B, hf* __restrict__ Ch, hf* __restrict__ Cl,
          int M, int N, int K, int loN)
{
    extern __shared__ char smem[];
    const uint32_t sb = smem_u32(smem);
    const int tid  = threadIdx.x;
    const int lane = tid & 31;
    const int wid  = tid >> 5;
    const int wm   = wid & 1;
    const int wn   = wid >> 1;
    const int bm   = blockIdx.y * 128;
    const int bn   = blockIdx.x * 128;
    const int ncl  = K >> 5;

    if (tid == 0) {
        #pragma unroll
        for (int s = 0; s < NSTG2; s++) MBARRIER_INIT(sb + 8 * s, 1);
    }
    __syncthreads();

    float acc[4][4][4];
    #pragma unroll
    for (int i = 0; i < 4; i++)
        #pragma unroll
        for (int j = 0; j < 4; j++)
            #pragma unroll
            for (int q = 0; q < 4; q++) acc[i][j][q] = 0.f;

    auto issue = [&](int cl) {
        const uint32_t mb  = sb + 8 * (cl & 1);
        const uint32_t dst = sb + 1024 + (cl & 1) * STG2;
        MBARRIER_EXPECT_TX(mb, 24576u);
        bulk_g2s(dst,         Ah + ((size_t)cl * M + bm) * 32, 8192, mb);
        bulk_g2s(dst +  8192, Al + ((size_t)cl * M + bm) * 32, 8192, mb);
        bulk_g2s(dst + 16384, B  + ((size_t)cl * N + bn) * 32, 8192, mb);
    };
    if (tid == 0) { issue(0); issue(1); }

    for (int cl = 0; cl < ncl; cl++) {
        MBARRIER_WAIT_PARITY(sb + 8 * (cl & 1), (cl >> 1) & 1);
        const uint32_t stA = sb + 1024 + (cl & 1) * STG2;
        const uint32_t stB = stA + 16384;
        #pragma unroll
        for (int s16 = 0; s16 < 2; s16++) {
            uint32_t aH[16], aL[16], bf[8];
            #pragma unroll
            for (int mi = 0; mi < 4; mi++) {
                const int row = wm * 64 + mi * 16 + (lane & 15);
                const int q   = s16 * 2 + (lane >> 4);
                const uint32_t ad = stA + row * 64 + ((q ^ ((row >> 1) & 3)) << 4);
                ldmx4(aH + 4 * mi, ad);
                ldmx4(aL + 4 * mi, ad + 8192);
            }
            #pragma unroll
            for (int ni = 0; ni < 2; ni++) {
                const int row = wn * 32 + ni * 16 + (lane & 7) + ((lane >> 4) << 3);
                const int q   = s16 * 2 + ((lane >> 3) & 1);
                uint32_t t[4];
                ldmx4(t, stB + row * 64 + ((q ^ ((row >> 1) & 3)) << 4));
                bf[ni*4+0] = t[0]; bf[ni*4+1] = t[1]; bf[ni*4+2] = t[2]; bf[ni*4+3] = t[3];
            }
            #pragma unroll
            for (int mi = 0; mi < 4; mi++)
                #pragma unroll
                for (int j = 0; j < 4; j++) {
                    mma16816(acc[mi][j], aH + 4 * mi, bf + 2 * j);
                    mma16816(acc[mi][j], aL + 4 * mi, bf + 2 * j);
                }
        }
        __syncthreads();
        if (tid == 0 && cl + NSTG2 < ncl) issue(cl + NSTG2);
    }

    const int wlo = (bn < loN);
    #pragma unroll
    for (int mi = 0; mi < 4; mi++) {
        #pragma unroll
        for (int j = 0; j < 4; j++) {
            const int colb = bn + wn * 32 + j * 8 + (lane & 3) * 2;
            #pragma unroll
            for (int p = 0; p < 2; p++) {
                const int row = bm + wm * 64 + mi * 16 + (lane >> 2) + 8 * p;
                const float v0 = acc[mi][j][p * 2], v1 = acc[mi][j][p * 2 + 1];
                const __half2 h = __floats2half2_rn(v0, v1);
                const size_t ti = tiled_idx(row, colb, M);
                *reinterpret_cast<uint32_t*>(&Ch[ti]) = bits2(h);
                if (wlo) {
                    const __half2 l = __floats2half2_rn(v0 - __low2float(h),
                                                        v1 - __high2float(h));
                    *reinterpret_cast<uint32_t*>(&Cl[ti]) = bits2(l);
                }
            }
        }
    }
}

// =====================================================================
// 1-term fp16 HMMA GEMM, occ 2 (unchanged from R11).
// =====================================================================
#define NSTG1 4
#define STG1  16384
#define G1_SMEM (1024 + NSTG1*STG1)

__global__ void __launch_bounds__(256, 2)
gemm1_tc(const hf* __restrict__ Ah, const hf* __restrict__ B0,
         float* __restrict__ Cf, hf* __restrict__ Ch0,
         int M, int N, int K,
         const float* __restrict__ bias0, int dogelu,
         size_t lstrB, size_t lstrC, int lstrBias,
         int splitk, float* __restrict__ Cpart)
{
    extern __shared__ char smem[];
    const uint32_t sb = smem_u32(smem);
    const int tid  = threadIdx.x;
    const int lane = tid & 31;
    const int wid  = tid >> 5;
    const int wm   = wid & 1;
    const int wn   = wid >> 1;
    const int bm   = blockIdx.y * 128;
    const int bn   = blockIdx.x * 128;
    const int z    = blockIdx.z;

    const hf* B = B0;
    hf* Ch = Ch0;
    const float* bias = bias0;
    const int nc = K >> 5;
    int ncl = nc, c0 = 0;
    if (splitk > 1) { ncl = nc / splitk; c0 = z * ncl; }
    else if (z) {
        B += (size_t)z * lstrB;
        if (Ch0) Ch += (size_t)z * lstrC;
        if (bias0) bias += (size_t)z * lstrBias;
    }

    if (tid == 0) {
        #pragma unroll
        for (int s = 0; s < NSTG1; s++) MBARRIER_INIT(sb + 8 * s, 1);
    }
    __syncthreads();

    float acc[4][4][4];
    #pragma unroll
    for (int i = 0; i < 4; i++)
        #pragma unroll
        for (int j = 0; j < 4; j++)
            #pragma unroll
            for (int q = 0; q < 4; q++) acc[i][j][q] = 0.f;

    auto issue = [&](int cl) {
        const int gc = c0 + cl;
        const uint32_t mb  = sb + 8 * (cl & 3);
        const uint32_t dst = sb + 1024 + (cl & 3) * STG1;
        MBARRIER_EXPECT_TX(mb, 16384u);
        bulk_g2s(dst,        Ah + ((size_t)gc * M + bm) * 32, 8192, mb);
        bulk_g2s(dst + 8192, B  + ((size_t)gc * N + bn) * 32, 8192, mb);
    };
    if (tid == 0) {
        const int pre = ncl < NSTG1 ? ncl : NSTG1;
        for (int s = 0; s < pre; s++) issue(s);
    }

    for (int cl = 0; cl < ncl; cl++) {
        MBARRIER_WAIT_PARITY(sb + 8 * (cl & 3), (cl >> 2) & 1);
        const uint32_t stA = sb + 1024 + (cl & 3) * STG1;
        const uint32_t stB = stA + 8192;
        #pragma unroll
        for (int s16 = 0; s16 < 2; s16++) {
            uint32_t aH[16], bf[8];
            #pragma unroll
            for (int mi = 0; mi < 4; mi++) {
                const int row = wm * 64 + mi * 16 + (lane & 15);
                const int q   = s16 * 2 + (lane >> 4);
                ldmx4(aH + 4 * mi, stA + row * 64 + ((q ^ ((row >> 1) & 3)) << 4));
            }
            #pragma unroll
            for (int ni = 0; ni < 2; ni++) {
                const int row = wn * 32 + ni * 16 + (lane & 7) + ((lane >> 4) << 3);
                const int q   = s16 * 2 + ((lane >> 3) & 1);
                uint32_t t[4];
                ldmx4(t, stB + row * 64 + ((q ^ ((row >> 1) & 3)) << 4));
                bf[ni*4+0] = t[0]; bf[ni*4+1] = t[1]; bf[ni*4+2] = t[2]; bf[ni*4+3] = t[3];
            }
            #pragma unroll
            for (int mi = 0; mi < 4; mi++)
                #pragma unroll
                for (int j = 0; j < 4; j++)
                    mma16816(acc[mi][j], aH + 4 * mi, bf + 2 * j);
        }
        __syncthreads();
        if (tid == 0 && cl + NSTG1 < ncl) issue(cl + NSTG1);
    }

    if (Cpart) {
        float* P = Cpart + (size_t)z * M * N;
        #pragma unroll
        for (int mi = 0; mi < 4; mi++)
            #pragma unroll
            for (int j = 0; j < 4; j++) {
                const int colb = bn + wn * 32 + j * 8 + (lane & 3) * 2;
                #pragma unroll
                for (int p = 0; p < 2; p++) {
                    const int row = bm + wm * 64 + mi * 16 + (lane >> 2) + 8 * p;
                    *reinterpret_cast<float2*>(&P[(size_t)row * N + colb]) =
                        make_float2(acc[mi][j][p * 2], acc[mi][j][p * 2 + 1]);
                }
            }
        return;
    }
    #pragma unroll
    for (int mi = 0; mi < 4; mi++) {
        #pragma unroll
        for (int j = 0; j < 4; j++) {
            const int colb = bn + wn * 32 + j * 8 + (lane & 3) * 2;
            #pragma unroll
            for (int p = 0; p < 2; p++) {
                const int row = bm + wm * 64 + mi * 16 + (lane >> 2) + 8 * p;
                float v0 = acc[mi][j][p * 2], v1 = acc[mi][j][p * 2 + 1];
                if (bias) { v0 += bias[colb]; v1 += bias[colb + 1]; }
                if (dogelu) {
                    v0 = 0.5f * v0 * (1.f + erff(v0 * 0.70710678118654752f));
                    v1 = 0.5f * v1 * (1.f + erff(v1 * 0.70710678118654752f));
                }
                if (Cf) *reinterpret_cast<float2*>(&Cf[(size_t)row * N + colb]) = make_float2(v0, v1);
                if (Ch) {
                    const __half2 h = __floats2half2_rn(v0, v1);
                    *reinterpret_cast<uint32_t*>(&Ch[tiled_idx(row, colb, M)]) = bits2(h);
                }
            }
        }
    }
}

// =====================================================================
// FA2 attention: 128 threads / 4 warps; warp = 16 queries x all keys.
// Register-resident scores, softmax stats, and P (C-frag == A-frag identity).
// smem: Q planes 16K + KV 2x16K. occ 3.
// =====================================================================
#define A_OFFQ  1024
#define A_OFFKV (A_OFFQ + 16384)
#define A_SMEM  (A_OFFKV + 32768)     // 50176

__global__ void __launch_bounds__(128, 3)
attn_tc(const hf* __restrict__ QKVh, const hf* __restrict__ QKVl,
        const hf* __restrict__ Kmh,
        hf* __restrict__ OH)
{
    extern __shared__ char smem[];
    const uint32_t sb = smem_u32(smem);
    const int bt  = blockIdx.x >> 4;
    const int h   = blockIdx.x & 15;
    const int tid = threadIdx.x;
    const int lane = tid & 31;
    const int wq   = tid >> 5;          // 4 warps, 16 query rows each

    if (tid == 0) { MBARRIER_INIT(sb, 1); MBARRIER_INIT(sb + 8, 1); }

    // Q planes copy: 4 segs x 4096B; 128 thr x 16B x 2 passes
    #pragma unroll
    for (int seg = 0; seg < 4; seg++) {
        const hf* src = (seg < 2 ? QKVh : QKVl) + ((size_t)(2 * h + (seg & 1)) * LROWS + bt * 64) * 32;
        #pragma unroll
        for (int it = 0; it < 2; it++) {
            const int idx = tid + it * 128;
            const uint4 v = reinterpret_cast<const uint4*>(src)[idx];
            *reinterpret_cast<uint4*>(smem + A_OFFQ + (seg >= 2 ? 8192 : 0) + (seg & 1) * 4096 + idx * 16) = v;
        }
    }
    __syncthreads();

    auto issueKV = [&](int t) {
        const int st = t & 1;
        const uint32_t mb = sb + 8 * st;
        const uint32_t dst = sb + A_OFFKV + st * 16384;
        MBARRIER_EXPECT_TX(mb, 16384u);
        const hf* PH; size_t rbase, nr; int kcK, kcV;
        if (t < 16) { PH = Kmh;  rbase = (size_t)bt * 1024 + t * 64; nr = NMEDIA; kcK = 2*h;      kcV = 32 + 2*h; }
        else        { PH = QKVh; rbase = (size_t)bt * 64;            nr = LROWS;  kcK = 32 + 2*h; kcV = 64 + 2*h; }
        bulk_g2s(dst,          PH + ((size_t)kcK * nr + rbase) * 32,       4096, mb);
        bulk_g2s(dst +  4096,  PH + ((size_t)(kcK + 1) * nr + rbase) * 32, 4096, mb);
        bulk_g2s(dst +  8192,  PH + ((size_t)kcV * nr + rbase) * 32,       4096, mb);
        bulk_g2s(dst + 12288,  PH + ((size_t)(kcV + 1) * nr + rbase) * 32, 4096, mb);
    };
    if (tid == 0) issueKV(0);

    // Q fragments (warp's 16 rows, k = dhead 64 in 4 k16 steps)
    uint32_t qH[4][4], qL[4][4];
    #pragma unroll
    for (int s = 0; s < 4; s++) {
        const int row = wq * 16 + (lane & 15);
        const int qq = (((s & 1) * 2 + (lane >> 4)) ^ ((row >> 1) & 3));
        const uint32_t ad = sb + A_OFFQ + (s >> 1) * 4096 + row * 64 + (qq << 4);
        ldmx4(qH[s], ad);
        ldmx4(qL[s], ad + 8192);
    }

    float mrow[2] = {-INFINITY, -INFINITY};
    float lrow[2] = {0.f, 0.f};
    float acc[4][2][4];                 // dg, j(n8), frag
    #pragma unroll
    for (int d = 0; d < 4; d++)
        #pragma unroll
        for (int j = 0; j < 2; j++)
            #pragma unroll
            for (int q = 0; q < 4; q++) acc[d][j][q] = 0.f;

    for (int t = 0; t < 17; t++) {
        if (tid == 0 && t + 1 < 17) issueKV(t + 1);
        MBARRIER_WAIT_PARITY(sb + 8 * (t & 1), (t >> 1) & 1);
        const uint32_t kb = sb + A_OFFKV + (t & 1) * 16384;

        // ---- scores: warp rows x 64 keys ----
        float sc[4][2][4];              // kg, j(n8), frag
        #pragma unroll
        for (int kg = 0; kg < 4; kg++)
            #pragma unroll
            for (int j = 0; j < 2; j++)
                #pragma unroll
                for (int q = 0; q < 4; q++) sc[kg][j][q] = 0.f;
        #pragma unroll
        for (int s = 0; s < 4; s++) {
            #pragma unroll
            for (int kg = 0; kg < 4; kg++) {
                const int row = kg * 16 + (lane & 7) + ((lane >> 4) << 3);
                const int qq = (((s & 1) * 2 + ((lane >> 3) & 1)) ^ ((row >> 1) & 3));
                uint32_t tB[4];
                ldmx4(tB, kb + (s >> 1) * 4096 + row * 64 + (qq << 4));
                uint32_t b0[2] = {tB[0], tB[1]}, b1[2] = {tB[2], tB[3]};
                mma16816(sc[kg][0], qH[s], b0);
                mma16816(sc[kg][0], qL[s], b0);
                mma16816(sc[kg][1], qH[s], b1);
                mma16816(sc[kg][1], qL[s], b1);
            }
        }
        #pragma unroll
        for (int kg = 0; kg < 4; kg++)
            #pragma unroll
            for (int j = 0; j < 2; j++)
                #pragma unroll
                for (int q = 0; q < 4; q++) sc[kg][j][q] *= 0.125f;

        // ---- register online softmax (per row-part p; 4 lanes per row) ----
        #pragma unroll
        for (int p = 0; p < 2; p++) {
            float m = -INFINITY;
            #pragma unroll
            for (int kg = 0; kg < 4; kg++)
                #pragma unroll
                for (int j = 0; j < 2; j++) {
                    m = fmaxf(m, sc[kg][j][p * 2]);
                    m = fmaxf(m, sc[kg][j][p * 2 + 1]);
                }
            m = fmaxf(m, __shfl_xor_sync(0xffffffffu, m, 1));
            m = fmaxf(m, __shfl_xor_sync(0xffffffffu, m, 2));
            const float mnew = fmaxf(mrow[p], m);
            const float fac = __expf(mrow[p] - mnew);
            float sum = 0.f;
            #pragma unroll
            for (int kg = 0; kg < 4; kg++)
                #pragma unroll
                for (int j = 0; j < 2; j++) {
                    const float e0 = __expf(sc[kg][j][p * 2]     - mnew);
                    const float e1 = __expf(sc[kg][j][p * 2 + 1] - mnew);
                    sc[kg][j][p * 2] = e0; sc[kg][j][p * 2 + 1] = e1;
                    sum += e0 + e1;
                }
            sum += __shfl_xor_sync(0xffffffffu, sum, 1);
            sum += __shfl_xor_sync(0xffffffffu, sum, 2);
            lrow[p] = lrow[p] * fac + sum;
            mrow[p] = mnew;
            #pragma unroll
            for (int d = 0; d < 4; d++)
                #pragma unroll
                for (int j = 0; j < 2; j++) {
                    acc[d][j][p * 2]     *= fac;
                    acc[d][j][p * 2 + 1] *= fac;
                }
        }

        // ---- PV: P from registers (C-frag == A-frag), V via ldmx4t ----
        #pragma unroll
        for (int kg = 0; kg < 4; kg++) {
            uint32_t pa[4];
            pa[0] = bits2(__floats2half2_rn(sc[kg][0][0], sc[kg][0][1]));
            pa[1] = bits2(__floats2half2_rn(sc[kg][0][2], sc[kg][0][3]));
            pa[2] = bits2(__floats2half2_rn(sc[kg][1][0], sc[kg][1][1]));
            pa[3] = bits2(__floats2half2_rn(sc[kg][1][2], sc[kg][1][3]));
            #pragma unroll
            for (int dg = 0; dg < 4; dg++) {
                const int key  = kg * 16 + (lane & 15);
                const int dinb = dg * 16 + ((lane >> 4) << 3);
                const int kcv  = dinb >> 5, din = dinb & 31;
                const int qq   = ((din >> 3) ^ ((key >> 1) & 3));
                uint32_t tV[4];
                ldmx4t(tV, kb + 8192 + kcv * 4096 + key * 64 + (qq << 4));
                uint32_t v0[2] = {tV[0], tV[1]}, v1[2] = {tV[2], tV[3]};
                mma16816(acc[dg][0], pa, v0);
                mma16816(acc[dg][1], pa, v1);
            }
        }
        __syncthreads();     // stage reuse guard before next issue
    }

    // ---- finalize ----
    #pragma unroll
    for (int p = 0; p < 2; p++) {
        const float inv = 1.0f / lrow[p];
        const int row = bt * 64 + wq * 16 + (lane >> 2) + 8 * p;
        #pragma unroll
        for (int dg = 0; dg < 4; dg++)
            #pragma unroll
            for (int j = 0; j < 2; j++) {
                const int col = h * 64 + dg * 16 + j * 8 + (lane & 3) * 2;
                const __half2 hh = __floats2half2_rn(acc[dg][j][p * 2] * inv,
                                                     acc[dg][j][p * 2 + 1] * inv);
                *reinterpret_cast<uint32_t*>(&OH[tiled_idx(row, col, LROWS)]) = bits2(hh);
            }
    }
}

// ---------------- orchestration ----------------
extern "C" void kernel_launch(void* const* d_in, const int* in_sizes, int n_in,
                              void* d_out, int out_size)
{
    (void)in_sizes; (void)n_in; (void)out_size;
    const float* x       = (const float*)d_in[0];
    const float* latents = (const float*)d_in[1];
    const float* nm_g    = (const float*)d_in[2];
    const float* nm_b    = (const float*)d_in[3];
    const float* nl_g    = (const float*)d_in[4];
    const float* nl_b    = (const float*)d_in[5];
    const float* wq      = (const float*)d_in[6];
    const float* wkv     = (const float*)d_in[7];
    const float* wo      = (const float*)d_in[8];
    const float* ff_g    = (const float*)d_in[9];
    const float* ff_b    = (const float*)d_in[10];
    const float* w1      = (const float*)d_in[11];
    const float* w2      = (const float*)d_in[12];
    const float* fin_g   = (const float*)d_in[13];
    const float* fin_b   = (const float*)d_in[14];
    float* out = (float*)d_out;

    hf *xh, *kvmh, *lnh, *lnl, *qkvh, *qkvl, *ath, *h1h;
    float *lat, *bias, *part;
    cudaGetSymbolAddress((void**)&xh,   g_xh);
    cudaGetSymbolAddress((void**)&kvmh, g_kvmh);
    cudaGetSymbolAddress((void**)&lat,  g_lat);
    cudaGetSymbolAddress((void**)&lnh,  g_lnh);  cudaGetSymbolAddress((void**)&lnl,  g_lnl);
    cudaGetSymbolAddress((void**)&qkvh, g_qkvh); cudaGetSymbolAddress((void**)&qkvl, g_qkvl);
    cudaGetSymbolAddress((void**)&ath,  g_ath);
    cudaGetSymbolAddress((void**)&h1h,  g_h1h);
    cudaGetSymbolAddress((void**)&bias, g_bias); cudaGetSymbolAddress((void**)&part, g_part);

    hf *wqkvT, *wkvG, *woT, *w1T, *w2T;
    cudaGetSymbolAddress((void**)&wqkvT, g_wqkvT);
    cudaGetSymbolAddress((void**)&wkvG,  g_wkvG);
    cudaGetSymbolAddress((void**)&woT,   g_woT);
    cudaGetSymbolAddress((void**)&w1T,   g_w1T);
    cudaGetSymbolAddress((void**)&w2T,   g_w2T);

    cudaFuncSetAttribute(gemm2b_tc, cudaFuncAttributeMaxDynamicSharedMemorySize, G2_SMEM);
    cudaFuncSetAttribute(gemm1_tc,  cudaFuncAttributeMaxDynamicSharedMemorySize, G1_SMEM);
    cudaFuncSetAttribute(attn_tc,   cudaFuncAttributeMaxDynamicSharedMemorySize, A_SMEM);
    const dim3 tb(32, 8);

    // ---- weight prep ----
    wsplit_kernel<<<dim3(DIMC/32, DIMC/32, DEPTHL), tb>>>(wq,  nullptr, wqkvT, DIMC, DIMC, 0,    NQKV);
    wsplit_kernel<<<dim3(NKV/32,  DIMC/32, DEPTHL), tb>>>(wkv, nullptr, wqkvT, DIMC, NKV,  DIMC, NQKV);
    wsplit_kernel<<<dim3(NKV/32,  DIMC/32, DEPTHL), tb>>>(wkv, nm_g,    wkvG,  DIMC, NKV,  0,    NKV);
    wsplit_kernel<<<dim3(DIMC/32, DIMC/32, DEPTHL), tb>>>(wo,  nullptr, woT,   DIMC, DIMC, 0,    DIMC);
    wsplit_kernel<<<dim3(FFD/32,  DIMC/32, DEPTHL), tb>>>(w1,  nullptr, w1T,   DIMC, FFD,  0,    FFD);
    wsplit_kernel<<<dim3(DIMC/32, FFD/32,  DEPTHL), tb>>>(w2,  nullptr, w2T,   FFD,  DIMC, 0,    DIMC);
    bias_kernel<<<dim3(NKV/32, DEPTHL), 256>>>(nm_b, wkv, bias);

    ln_kernel<<<NMEDIA, 128>>>(x, nullptr, xh, nullptr, nullptr, nullptr, NMEDIA);
    init_lat_kernel<<<(LROWS * DIMC) / 256, 256>>>(latents, lat);

    // ---- all-layer media KV: 1-term A, occ-2 ----
    gemm1_tc<<<dim3(NKV/128, NMEDIA/128, DEPTHL), 256, G1_SMEM>>>(
        xh, wkvG, nullptr, kvmh, NMEDIA, NKV, DIMC,
        bias, 0,
        (size_t)NKV*DIMC, (size_t)NMEDIA*NKV, NKV, 1, nullptr);

    // layer 0 nl-LN
    ln_kernel<<<LROWS, 128>>>(lat, nullptr, lnh, lnl, nl_g, nl_b, LROWS);

    for (int i = 0; i < DEPTHL; i++) {
        // fused Q|K|V latent GEMM (2-term A, occ-2; lo plane only for Q cols)
        gemm2b_tc<<<dim3(NQKV/128, LROWS/128), 256, G2_SMEM>>>(
            lnh, lnl, wqkvT + (size_t)i*NQKV*DIMC,
            qkvh, qkvl, LROWS, NQKV, DIMC, DIMC);
        attn_tc<<<BTOT * HEADS, 128, A_SMEM>>>(
            qkvh, qkvl, kvmh + (size_t)i*NMEDIA*NKV, ath);
        // wo (1-term, split-K 2) -> part ; fused reduce+residual+ff-LN
        gemm1_tc<<<dim3(DIMC/128, LROWS/128, 2), 256, G1_SMEM>>>(
            ath, woT + (size_t)i*DIMC*DIMC,
            nullptr, nullptr, LROWS, DIMC, DIMC, nullptr, 0,
            0, 0, 0, 2, part);
        lnred_kernel<<<LROWS, 128>>>(part, 2, lat, lat, nullptr, lnh, nullptr,
                                     ff_g + (size_t)i*DIMC, ff_b + (size_t)i*DIMC);
        // ff1 (1-term) -> gelu -> h1h
        gemm1_tc<<<dim3(FFD/128, LROWS/128), 256, G1_SMEM>>>(
            lnh, w1T + (size_t)i*FFD*DIMC,
            nullptr, h1h, LROWS, FFD, DIMC, nullptr, 1,
            0, 0, 0, 1, nullptr);
        // ff2 (1-term, split-K 4) -> part ; fused reduce+residual+next-LN
        gemm1_tc<<<dim3(DIMC/128, LROWS/128, 4), 256, G1_SMEM>>>(
            h1h, w2T + (size_t)i*DIMC*FFD,
            nullptr, nullptr, LROWS, DIMC, FFD, nullptr, 0,
            0, 0, 0, 4, part);
        if (i + 1 < DEPTHL) {
            lnred_kernel<<<LROWS, 128>>>(part, 4, lat, lat, nullptr, lnh, lnl,
                                         nl_g + (size_t)(i+1)*DIMC, nl_b + (size_t)(i+1)*DIMC);
        } else {
            lnred_kernel<<<LROWS, 128>>>(part, 4, lat, nullptr, out, nullptr, nullptr,
                                         fin_g, fin_b);
        }
    }
}

// round 13
// speedup vs baseline: 8.2339x; 1.0026x over previous
#include <cuda_runtime.h>
#include <cuda_fp16.h>
#include <math.h>
#include <stdint.h>

// ---------------- problem constants ----------------
#define DIMC   1024
#define DEPTHL 6
#define HEADS  16
#define DHEAD  64
#define NKV    2048
#define NQKV   3072
#define FFD    4096
#define BTOT   32
#define MEDIA  1024
#define NMEDIA (BTOT*MEDIA)          // 32768
#define NLAT   64
#define LROWS  (BTOT*NLAT)           // 2048

typedef __half hf;

// ---------------- scratch ----------------
__device__ __align__(1024) hf    g_xh  [(size_t)NMEDIA*DIMC];
__device__ __align__(1024) hf    g_kvmh[(size_t)DEPTHL*NMEDIA*NKV];
__device__ float g_lat [LROWS*DIMC];
__device__ __align__(1024) hf    g_lnh [LROWS*DIMC];
__device__ __align__(1024) hf    g_lnl [LROWS*DIMC];
__device__ __align__(1024) hf    g_qkvh[(size_t)LROWS*NQKV];
__device__ __align__(1024) hf    g_qkvl[(size_t)LROWS*NQKV];
__device__ __align__(1024) hf    g_ath [LROWS*DIMC];
__device__ __align__(1024) hf    g_h1h [(size_t)LROWS*FFD];
__device__ float g_bias[DEPTHL*NKV];
__device__ float g_part[(size_t)4*LROWS*DIMC];

// weight planes (single fp16, B-side), chunk-tiled [K/32][N][32]
__device__ __align__(1024) hf g_wqkvT[(size_t)DEPTHL*NQKV*DIMC];
__device__ __align__(1024) hf g_wkvG [(size_t)DEPTHL*NKV*DIMC];
__device__ __align__(1024) hf g_woT  [(size_t)DEPTHL*DIMC*DIMC];
__device__ __align__(1024) hf g_w1T  [(size_t)DEPTHL*FFD*DIMC];
__device__ __align__(1024) hf g_w2T  [(size_t)DEPTHL*DIMC*FFD];

// ---------------- helpers ----------------
__device__ __forceinline__ uint32_t smem_u32(const void* p) {
    return (uint32_t)__cvta_generic_to_shared(p);
}
__device__ __forceinline__ size_t tiled_idx(int row, int k, int nrows) {
    const int kc = k >> 5, kin = k & 31;
    const int q = kin >> 3, b = kin & 7;
    const int qs = q ^ ((row >> 1) & 3);
    return ((size_t)kc * nrows + row) * 32 + qs * 8 + b;
}
__device__ __forceinline__ void bulk_g2s(uint32_t dst, const void* src, uint32_t bytes, uint32_t mbar) {
    asm volatile("cp.async.bulk.shared::cluster.global.mbarrier::complete_tx::bytes [%0], [%1], %2, [%3];"
                 :: "r"(dst), "l"(src), "r"(bytes), "r"(mbar) : "memory");
}
#define MBARRIER_INIT(addr, cnt) \
    asm volatile("mbarrier.init.shared.b64 [%0], %1;" :: "r"(addr), "r"(cnt) : "memory")
#define MBARRIER_EXPECT_TX(addr, tx) \
    asm volatile("mbarrier.arrive.expect_tx.shared.b64 _, [%0], %1;" :: "r"(addr), "r"(tx) : "memory")
#define MBARRIER_WAIT_PARITY(addr, par) do { \
    uint32_t _m = (addr), _p = (par), _d; \
    asm volatile("{\n\t.reg .pred p;\n\t" \
        "mbarrier.try_wait.parity.acquire.cta.shared::cta.b64 p, [%1], %2;\n\t" \
        "selp.b32 %0, 1, 0, p;\n\t}" : "=r"(_d) : "r"(_m), "r"(_p) : "memory"); \
    if (!_d) { \
        asm volatile("{\n\t.reg .pred P1;\n\t" \
            "WL_%=:\n\t" \
            "mbarrier.try_wait.parity.acquire.cta.shared::cta.b64 P1, [%0], %1, 0x989680;\n\t" \
            "@P1 bra.uni WD_%=;\n\tbra.uni WL_%=;\n\tWD_%=:\n\t}" \
            :: "r"(_m), "r"(_p) : "memory"); \
    } } while (0)

__device__ __forceinline__ void ldmx4(uint32_t* r, uint32_t a) {
    asm volatile("ldmatrix.sync.aligned.m8n8.x4.shared.b16 {%0,%1,%2,%3}, [%4];"
                 : "=r"(r[0]), "=r"(r[1]), "=r"(r[2]), "=r"(r[3]) : "r"(a));
}
__device__ __forceinline__ void ldmx4t(uint32_t* r, uint32_t a) {
    asm volatile("ldmatrix.sync.aligned.m8n8.x4.trans.shared.b16 {%0,%1,%2,%3}, [%4];"
                 : "=r"(r[0]), "=r"(r[1]), "=r"(r[2]), "=r"(r[3]) : "r"(a));
}
__device__ __forceinline__ void mma16816(float* d, const uint32_t* a, const uint32_t* b) {
    asm volatile("mma.sync.aligned.m16n8k16.row.col.f32.f16.f16.f32 "
                 "{%0,%1,%2,%3},{%4,%5,%6,%7},{%8,%9},{%0,%1,%2,%3};"
                 : "+f"(d[0]), "+f"(d[1]), "+f"(d[2]), "+f"(d[3])
                 : "r"(a[0]), "r"(a[1]), "r"(a[2]), "r"(a[3]),
                   "r"(b[0]), "r"(b[1]));
}
__device__ __forceinline__ uint32_t bits2(__half2 h) {
    return *reinterpret_cast<uint32_t*>(&h);
}

// ---------------- LayerNorm ----------------
__global__ void ln_kernel(const float* __restrict__ in,
                          float* __restrict__ outF,
                          hf* __restrict__ outH, hf* __restrict__ outL,
                          const float* __restrict__ g, const float* __restrict__ b,
                          int nrows)
{
    const int row = blockIdx.x;
    const float* x = in + (size_t)row * DIMC;
    float s = 0.f, sq = 0.f;
    for (int c = threadIdx.x; c < DIMC; c += blockDim.x) {
        float v = x[c]; s += v; sq += v * v;
    }
    __shared__ float sh[64];
    #pragma unroll
    for (int o = 16; o > 0; o >>= 1) {
        s  += __shfl_down_sync(0xffffffffu, s,  o);
        sq += __shfl_down_sync(0xffffffffu, sq, o);
    }
    const int wid = threadIdx.x >> 5, lid = threadIdx.x & 31;
    if (lid == 0) { sh[wid] = s; sh[wid + 32] = sq; }
    __syncthreads();
    if (threadIdx.x == 0) {
        float ts = 0.f, tsq = 0.f;
        const int nw = blockDim.x >> 5;
        for (int i = 0; i < nw; i++) { ts += sh[i]; tsq += sh[i + 32]; }
        const float mean = ts * (1.0f / DIMC);
        const float var  = tsq * (1.0f / DIMC) - mean * mean;
        sh[0] = mean; sh[1] = rsqrtf(var + 1e-5f);
    }
    __syncthreads();
    const float mean = sh[0], rstd = sh[1];

    for (int k0 = threadIdx.x * 8; k0 < DIMC; k0 += blockDim.x * 8) {
        float v[8];
        #pragma unroll
        for (int e = 0; e < 8; e++) {
            float t = (x[k0 + e] - mean) * rstd;
            if (g) t = t * g[k0 + e] + b[k0 + e];
            v[e] = t;
        }
        if (outF) {
            float* o = outF + (size_t)row * DIMC + k0;
            #pragma unroll
            for (int e = 0; e < 8; e++) o[e] = v[e];
        }
        if (outH) {
            uint32_t hq[4], lq[4];
            #pragma unroll
            for (int e = 0; e < 4; e++) {
                const __half2 h = __floats2half2_rn(v[2*e], v[2*e+1]);
                hq[e] = bits2(h);
                if (outL) {
                    const __half2 l = __floats2half2_rn(v[2*e]   - __low2float(h),
                                                        v[2*e+1] - __high2float(h));
                    lq[e] = bits2(l);
                }
            }
            const size_t ti = tiled_idx(row, k0, nrows);
            *reinterpret_cast<uint4*>(&outH[ti]) = make_uint4(hq[0], hq[1], hq[2], hq[3]);
            if (outL)
                *reinterpret_cast<uint4*>(&outL[ti]) = make_uint4(lq[0], lq[1], lq[2], lq[3]);
        }
    }
}

// ---------------- fused split-K reduce + residual + LayerNorm ----------------
__global__ void __launch_bounds__(128)
lnred_kernel(const float* __restrict__ part, int S,
             const float* __restrict__ latin,
             float* __restrict__ latout,
             float* __restrict__ outF,
             hf* __restrict__ outH, hf* __restrict__ outL,
             const float* __restrict__ g, const float* __restrict__ b)
{
    const int row = blockIdx.x;
    const int tid = threadIdx.x;
    const size_t base = (size_t)row * DIMC + tid * 8;
    float v[8];
    #pragma unroll
    for (int e = 0; e < 8; e++) v[e] = latin[base + e];
    for (int s = 0; s < S; s++) {
        const float* p = part + (size_t)s * LROWS * DIMC + base;
        #pragma unroll
        for (int e = 0; e < 8; e++) v[e] += p[e];
    }
    if (latout) {
        #pragma unroll
        for (int e = 0; e < 8; e++) latout[base + e] = v[e];
    }
    float s1 = 0.f, s2 = 0.f;
    #pragma unroll
    for (int e = 0; e < 8; e++) { s1 += v[e]; s2 += v[e] * v[e]; }
    __shared__ float sh[8];
    #pragma unroll
    for (int o = 16; o > 0; o >>= 1) {
        s1 += __shfl_down_sync(0xffffffffu, s1, o);
        s2 += __shfl_down_sync(0xffffffffu, s2, o);
    }
    const int wid = tid >> 5, lid = tid & 31;
    if (lid == 0) { sh[wid] = s1; sh[wid + 4] = s2; }
    __syncthreads();
    if (tid == 0) {
        float ts = sh[0] + sh[1] + sh[2] + sh[3];
        float tq = sh[4] + sh[5] + sh[6] + sh[7];
        const float mean = ts * (1.0f / DIMC);
        const float var  = tq * (1.0f / DIMC) - mean * mean;
        sh[0] = mean; sh[1] = rsqrtf(var + 1e-5f);
    }
    __syncthreads();
    const float mean = sh[0], rstd = sh[1];
    const int k0 = tid * 8;
    float t[8];
    #pragma unroll
    for (int e = 0; e < 8; e++)
        t[e] = (v[e] - mean) * rstd * g[k0 + e] + b[k0 + e];
    if (outF) {
        float* o = outF + base;
        #pragma unroll
        for (int e = 0; e < 8; e++) o[e] = t[e];
    }
    if (outH) {
        uint32_t hq[4], lq[4];
        #pragma unroll
        for (int e = 0; e < 4; e++) {
            const __half2 h = __floats2half2_rn(t[2*e], t[2*e+1]);
            hq[e] = bits2(h);
            if (outL) {
                const __half2 l = __floats2half2_rn(t[2*e]   - __low2float(h),
                                                    t[2*e+1] - __high2float(h));
                lq[e] = bits2(l);
            }
        }
        const size_t ti = tiled_idx(row, k0, LROWS);
        *reinterpret_cast<uint4*>(&outH[ti]) = make_uint4(hq[0], hq[1], hq[2], hq[3]);
        if (outL)
            *reinterpret_cast<uint4*>(&outL[ti]) = make_uint4(lq[0], lq[1], lq[2], lq[3]);
    }
}

// ---------------- bias: all layers, k-parallel ----------------
__global__ void bias_kernel(const float* __restrict__ nm_b,
                            const float* __restrict__ wkv, float* __restrict__ out)
{
    const int layer = blockIdx.y;
    const int tid = threadIdx.x;
    const int n  = blockIdx.x * 32 + (tid & 31);
    const int ks = tid >> 5;
    const float* bv = nm_b + (size_t)layer * DIMC;
    const float* W  = wkv  + (size_t)layer * DIMC * NKV;
    float s = 0.f;
    #pragma unroll 4
    for (int k = ks * 128; k < ks * 128 + 128; k++)
        s += bv[k] * __ldg(&W[(size_t)k * NKV + n]);
    __shared__ float red[8][32];
    red[ks][tid & 31] = s;
    __syncthreads();
    if (ks == 0) {
        float t = 0.f;
        #pragma unroll
        for (int i = 0; i < 8; i++) t += red[i][tid & 31];
        out[(size_t)layer * NKV + n] = t;
    }
}

__global__ void init_lat_kernel(const float* __restrict__ latents, float* __restrict__ lat)
{
    const int idx = blockIdx.x * blockDim.x + threadIdx.x;
    lat[idx] = latents[idx & (NLAT * DIMC - 1)];
}

// ---------------- weight transpose + gamma + fp16 quantize (batched over depth) ----
__global__ void wsplit_kernel(const float* __restrict__ W0, const float* __restrict__ g0,
                              hf* __restrict__ T0, int K, int N, int nofs, int ntot)
{
    const int z = blockIdx.z;
    const float* W = W0 + (size_t)z * K * N;
    const float* g = g0 ? g0 + (size_t)z * K : nullptr;
    hf* T = T0 + (size_t)z * ntot * K;
    __shared__ float t[32][33];
    const int n0 = blockIdx.x * 32, k0 = blockIdx.y * 32;
    const int tx = threadIdx.x, ty = threadIdx.y;
    #pragma unroll
    for (int i = 0; i < 4; i++) {
        float v = W[(size_t)(k0 + ty + 8 * i) * N + n0 + tx];
        if (g) v *= g[k0 + ty + 8 * i];
        t[ty + 8 * i][tx] = v;
    }
    __syncthreads();
    #pragma unroll
    for (int i = 0; i < 4; i++) {
        const int n = n0 + ty + 8 * i, k = k0 + tx;
        T[tiled_idx(nofs + n, k, ntot)] = __float2half_rn(t[tx][ty + 8 * i]);
    }
}

// =====================================================================
// 2-term fp16 HMMA GEMM, single reg buffer, occ 2 (for qkv).
// =====================================================================
#define NSTG2 2
#define STG2  24576
#define G2_SMEM (1024 + NSTG2*STG2)

__global__ void __launch_bounds__(256, 2)
gemm2b_tc(const hf* __restrict__ Ah, const hf* __restrict__ Al,
          const hf* __restrict__ B, hf* __restrict__ Ch, hf* __restrict__ Cl,
          int M, int N, int K, int loN)
{
    extern __shared__ char smem[];
    const uint32_t sb = smem_u32(smem);
    const int tid  = threadIdx.x;
    const int lane = tid & 31;
    const int wid  = tid >> 5;
    const int wm   = wid & 1;
    const int wn   = wid >> 1;
    const int bm   = blockIdx.y * 128;
    const int bn   = blockIdx.x * 128;
    const int ncl  = K >> 5;

    if (tid == 0) {
        #pragma unroll
        for (int s = 0; s < NSTG2; s++) MBARRIER_INIT(sb + 8 * s, 1);
    }
    __syncthreads();

    float acc[4][4][4];
    #pragma unroll
    for (int i = 0; i < 4; i++)
        #pragma unroll
        for (int j = 0; j < 4; j++)
            #pragma unroll
            for (int q = 0; q < 4; q++) acc[i][j][q] = 0.f;

    auto issue = [&](int cl) {
        const uint32_t mb  = sb + 8 * (cl & 1);
        const uint32_t dst = sb + 1024 + (cl & 1) * STG2;
        MBARRIER_EXPECT_TX(mb, 24576u);
        bulk_g2s(dst,         Ah + ((size_t)cl * M + bm) * 32, 8192, mb);
        bulk_g2s(dst +  8192, Al + ((size_t)cl * M + bm) * 32, 8192, mb);
        bulk_g2s(dst + 16384, B  + ((size_t)cl * N + bn) * 32, 8192, mb);
    };
    if (tid == 0) { issue(0); issue(1); }

    for (int cl = 0; cl < ncl; cl++) {
        MBARRIER_WAIT_PARITY(sb + 8 * (cl & 1), (cl >> 1) & 1);
        const uint32_t stA = sb + 1024 + (cl & 1) * STG2;
        const uint32_t stB = stA + 16384;
        #pragma unroll
        for (int s16 = 0; s16 < 2; s16++) {
            uint32_t aH[16], aL[16], bf[8];
            #pragma unroll
            for (int mi = 0; mi < 4; mi++) {
                const int row = wm * 64 + mi * 16 + (lane & 15);
                const int q   = s16 * 2 + (lane >> 4);
                const uint32_t ad = stA + row * 64 + ((q ^ ((row >> 1) & 3)) << 4);
                ldmx4(aH + 4 * mi, ad);
                ldmx4(aL + 4 * mi, ad + 8192);
            }
            #pragma unroll
            for (int ni = 0; ni < 2; ni++) {
                const int row = wn * 32 + ni * 16 + (lane & 7) + ((lane >> 4) << 3);
                const int q   = s16 * 2 + ((lane >> 3) & 1);
                uint32_t t[4];
                ldmx4(t, stB + row * 64 + ((q ^ ((row >> 1) & 3)) << 4));
                bf[ni*4+0] = t[0]; bf[ni*4+1] = t[1]; bf[ni*4+2] = t[2]; bf[ni*4+3] = t[3];
            }
            #pragma unroll
            for (int mi = 0; mi < 4; mi++)
                #pragma unroll
                for (int j = 0; j < 4; j++) {
                    mma16816(acc[mi][j], aH + 4 * mi, bf + 2 * j);
                    mma16816(acc[mi][j], aL + 4 * mi, bf + 2 * j);
                }
        }
        __syncthreads();
        if (tid == 0 && cl + NSTG2 < ncl) issue(cl + NSTG2);
    }

    const int wlo = (bn < loN);
    #pragma unroll
    for (int mi = 0; mi < 4; mi++) {
        #pragma unroll
        for (int j = 0; j < 4; j++) {
            const int colb = bn + wn * 32 + j * 8 + (lane & 3) * 2;
            #pragma unroll
            for (int p = 0; p < 2; p++) {
                const int row = bm + wm * 64 + mi * 16 + (lane >> 2) + 8 * p;
                const float v0 = acc[mi][j][p * 2], v1 = acc[mi][j][p * 2 + 1];
                const __half2 h = __floats2half2_rn(v0, v1);
                const size_t ti = tiled_idx(row, colb, M);
                *reinterpret_cast<uint32_t*>(&Ch[ti]) = bits2(h);
                if (wlo) {
                    const __half2 l = __floats2half2_rn(v0 - __low2float(h),
                                                        v1 - __high2float(h));
                    *reinterpret_cast<uint32_t*>(&Cl[ti]) = bits2(l);
                }
            }
        }
    }
}

// =====================================================================
// 1-term fp16 HMMA GEMM, occ 2.
// =====================================================================
#define NSTG1 4
#define STG1  16384
#define G1_SMEM (1024 + NSTG1*STG1)

__global__ void __launch_bounds__(256, 2)
gemm1_tc(const hf* __restrict__ Ah, const hf* __restrict__ B0,
         float* __restrict__ Cf, hf* __restrict__ Ch0,
         int M, int N, int K,
         const float* __restrict__ bias0, int dogelu,
         size_t lstrB, size_t lstrC, int lstrBias,
         int splitk, float* __restrict__ Cpart)
{
    extern __shared__ char smem[];
    const uint32_t sb = smem_u32(smem);
    const int tid  = threadIdx.x;
    const int lane = tid & 31;
    const int wid  = tid >> 5;
    const int wm   = wid & 1;
    const int wn   = wid >> 1;
    const int bm   = blockIdx.y * 128;
    const int bn   = blockIdx.x * 128;
    const int z    = blockIdx.z;

    const hf* B = B0;
    hf* Ch = Ch0;
    const float* bias = bias0;
    const int nc = K >> 5;
    int ncl = nc, c0 = 0;
    if (splitk > 1) { ncl = nc / splitk; c0 = z * ncl; }
    else if (z) {
        B += (size_t)z * lstrB;
        if (Ch0) Ch += (size_t)z * lstrC;
        if (bias0) bias += (size_t)z * lstrBias;
    }

    if (tid == 0) {
        #pragma unroll
        for (int s = 0; s < NSTG1; s++) MBARRIER_INIT(sb + 8 * s, 1);
    }
    __syncthreads();

    float acc[4][4][4];
    #pragma unroll
    for (int i = 0; i < 4; i++)
        #pragma unroll
        for (int j = 0; j < 4; j++)
            #pragma unroll
            for (int q = 0; q < 4; q++) acc[i][j][q] = 0.f;

    auto issue = [&](int cl) {
        const int gc = c0 + cl;
        const uint32_t mb  = sb + 8 * (cl & 3);
        const uint32_t dst = sb + 1024 + (cl & 3) * STG1;
        MBARRIER_EXPECT_TX(mb, 16384u);
        bulk_g2s(dst,        Ah + ((size_t)gc * M + bm) * 32, 8192, mb);
        bulk_g2s(dst + 8192, B  + ((size_t)gc * N + bn) * 32, 8192, mb);
    };
    if (tid == 0) {
        const int pre = ncl < NSTG1 ? ncl : NSTG1;
        for (int s = 0; s < pre; s++) issue(s);
    }

    for (int cl = 0; cl < ncl; cl++) {
        MBARRIER_WAIT_PARITY(sb + 8 * (cl & 3), (cl >> 2) & 1);
        const uint32_t stA = sb + 1024 + (cl & 3) * STG1;
        const uint32_t stB = stA + 8192;
        #pragma unroll
        for (int s16 = 0; s16 < 2; s16++) {
            uint32_t aH[16], bf[8];
            #pragma unroll
            for (int mi = 0; mi < 4; mi++) {
                const int row = wm * 64 + mi * 16 + (lane & 15);
                const int q   = s16 * 2 + (lane >> 4);
                ldmx4(aH + 4 * mi, stA + row * 64 + ((q ^ ((row >> 1) & 3)) << 4));
            }
            #pragma unroll
            for (int ni = 0; ni < 2; ni++) {
                const int row = wn * 32 + ni * 16 + (lane & 7) + ((lane >> 4) << 3);
                const int q   = s16 * 2 + ((lane >> 3) & 1);
                uint32_t t[4];
                ldmx4(t, stB + row * 64 + ((q ^ ((row >> 1) & 3)) << 4));
                bf[ni*4+0] = t[0]; bf[ni*4+1] = t[1]; bf[ni*4+2] = t[2]; bf[ni*4+3] = t[3];
            }
            #pragma unroll
            for (int mi = 0; mi < 4; mi++)
                #pragma unroll
                for (int j = 0; j < 4; j++)
                    mma16816(acc[mi][j], aH + 4 * mi, bf + 2 * j);
        }
        __syncthreads();
        if (tid == 0 && cl + NSTG1 < ncl) issue(cl + NSTG1);
    }

    if (Cpart) {
        float* P = Cpart + (size_t)z * M * N;
        #pragma unroll
        for (int mi = 0; mi < 4; mi++)
            #pragma unroll
            for (int j = 0; j < 4; j++) {
                const int colb = bn + wn * 32 + j * 8 + (lane & 3) * 2;
                #pragma unroll
                for (int p = 0; p < 2; p++) {
                    const int row = bm + wm * 64 + mi * 16 + (lane >> 2) + 8 * p;
                    *reinterpret_cast<float2*>(&P[(size_t)row * N + colb]) =
                        make_float2(acc[mi][j][p * 2], acc[mi][j][p * 2 + 1]);
                }
            }
        return;
    }
    #pragma unroll
    for (int mi = 0; mi < 4; mi++) {
        #pragma unroll
        for (int j = 0; j < 4; j++) {
            const int colb = bn + wn * 32 + j * 8 + (lane & 3) * 2;
            #pragma unroll
            for (int p = 0; p < 2; p++) {
                const int row = bm + wm * 64 + mi * 16 + (lane >> 2) + 8 * p;
                float v0 = acc[mi][j][p * 2], v1 = acc[mi][j][p * 2 + 1];
                if (bias) { v0 += bias[colb]; v1 += bias[colb + 1]; }
                if (dogelu) {
                    v0 = 0.5f * v0 * (1.f + erff(v0 * 0.70710678118654752f));
                    v1 = 0.5f * v1 * (1.f + erff(v1 * 0.70710678118654752f));
                }
                if (Cf) *reinterpret_cast<float2*>(&Cf[(size_t)row * N + colb]) = make_float2(v0, v1);
                if (Ch) {
                    const __half2 h = __floats2half2_rn(v0, v1);
                    *reinterpret_cast<uint32_t*>(&Ch[tiled_idx(row, colb, M)]) = bits2(h);
                }
            }
        }
    }
}

// =====================================================================
// FA2 attention (register P, occ 3) — unchanged from R12.
// =====================================================================
#define A_OFFQ  1024
#define A_OFFKV (A_OFFQ + 16384)
#define A_SMEM  (A_OFFKV + 32768)

__global__ void __launch_bounds__(128, 3)
attn_tc(const hf* __restrict__ QKVh, const hf* __restrict__ QKVl,
        const hf* __restrict__ Kmh,
        hf* __restrict__ OH)
{
    extern __shared__ char smem[];
    const uint32_t sb = smem_u32(smem);
    const int bt  = blockIdx.x >> 4;
    const int h   = blockIdx.x & 15;
    const int tid = threadIdx.x;
    const int lane = tid & 31;
    const int wq   = tid >> 5;

    if (tid == 0) { MBARRIER_INIT(sb, 1); MBARRIER_INIT(sb + 8, 1); }

    #pragma unroll
    for (int seg = 0; seg < 4; seg++) {
        const hf* src = (seg < 2 ? QKVh : QKVl) + ((size_t)(2 * h + (seg & 1)) * LROWS + bt * 64) * 32;
        #pragma unroll
        for (int it = 0; it < 2; it++) {
            const int idx = tid + it * 128;
            const uint4 v = reinterpret_cast<const uint4*>(src)[idx];
            *reinterpret_cast<uint4*>(smem + A_OFFQ + (seg >= 2 ? 8192 : 0) + (seg & 1) * 4096 + idx * 16) = v;
        }
    }
    __syncthreads();

    auto issueKV = [&](int t) {
        const int st = t & 1;
        const uint32_t mb = sb + 8 * st;
        const uint32_t dst = sb + A_OFFKV + st * 16384;
        MBARRIER_EXPECT_TX(mb, 16384u);
        const hf* PH; size_t rbase, nr; int kcK, kcV;
        if (t < 16) { PH = Kmh;  rbase = (size_t)bt * 1024 + t * 64; nr = NMEDIA; kcK = 2*h;      kcV = 32 + 2*h; }
        else        { PH = QKVh; rbase = (size_t)bt * 64;            nr = LROWS;  kcK = 32 + 2*h; kcV = 64 + 2*h; }
        bulk_g2s(dst,          PH + ((size_t)kcK * nr + rbase) * 32,       4096, mb);
        bulk_g2s(dst +  4096,  PH + ((size_t)(kcK + 1) * nr + rbase) * 32, 4096, mb);
        bulk_g2s(dst +  8192,  PH + ((size_t)kcV * nr + rbase) * 32,       4096, mb);
        bulk_g2s(dst + 12288,  PH + ((size_t)(kcV + 1) * nr + rbase) * 32, 4096, mb);
    };
    if (tid == 0) issueKV(0);

    uint32_t qH[4][4], qL[4][4];
    #pragma unroll
    for (int s = 0; s < 4; s++) {
        const int row = wq * 16 + (lane & 15);
        const int qq = (((s & 1) * 2 + (lane >> 4)) ^ ((row >> 1) & 3));
        const uint32_t ad = sb + A_OFFQ + (s >> 1) * 4096 + row * 64 + (qq << 4);
        ldmx4(qH[s], ad);
        ldmx4(qL[s], ad + 8192);
    }

    float mrow[2] = {-INFINITY, -INFINITY};
    float lrow[2] = {0.f, 0.f};
    float acc[4][2][4];
    #pragma unroll
    for (int d = 0; d < 4; d++)
        #pragma unroll
        for (int j = 0; j < 2; j++)
            #pragma unroll
            for (int q = 0; q < 4; q++) acc[d][j][q] = 0.f;

    for (int t = 0; t < 17; t++) {
        if (tid == 0 && t + 1 < 17) issueKV(t + 1);
        MBARRIER_WAIT_PARITY(sb + 8 * (t & 1), (t >> 1) & 1);
        const uint32_t kb = sb + A_OFFKV + (t & 1) * 16384;

        float sc[4][2][4];
        #pragma unroll
        for (int kg = 0; kg < 4; kg++)
            #pragma unroll
            for (int j = 0; j < 2; j++)
                #pragma unroll
                for (int q = 0; q < 4; q++) sc[kg][j][q] = 0.f;
        #pragma unroll
        for (int s = 0; s < 4; s++) {
            #pragma unroll
            for (int kg = 0; kg < 4; kg++) {
                const int row = kg * 16 + (lane & 7) + ((lane >> 4) << 3);
                const int qq = (((s & 1) * 2 + ((lane >> 3) & 1)) ^ ((row >> 1) & 3));
                uint32_t tB[4];
                ldmx4(tB, kb + (s >> 1) * 4096 + row * 64 + (qq << 4));
                uint32_t b0[2] = {tB[0], tB[1]}, b1[2] = {tB[2], tB[3]};
                mma16816(sc[kg][0], qH[s], b0);
                mma16816(sc[kg][0], qL[s], b0);
                mma16816(sc[kg][1], qH[s], b1);
                mma16816(sc[kg][1], qL[s], b1);
            }
        }
        #pragma unroll
        for (int kg = 0; kg < 4; kg++)
            #pragma unroll
            for (int j = 0; j < 2; j++)
                #pragma unroll
                for (int q = 0; q < 4; q++) sc[kg][j][q] *= 0.125f;

        #pragma unroll
        for (int p = 0; p < 2; p++) {
            float m = -INFINITY;
            #pragma unroll
            for (int kg = 0; kg < 4; kg++)
                #pragma unroll
                for (int j = 0; j < 2; j++) {
                    m = fmaxf(m, sc[kg][j][p * 2]);
                    m = fmaxf(m, sc[kg][j][p * 2 + 1]);
                }
            m = fmaxf(m, __shfl_xor_sync(0xffffffffu, m, 1));
            m = fmaxf(m, __shfl_xor_sync(0xffffffffu, m, 2));
            const float mnew = fmaxf(mrow[p], m);
            const float fac = __expf(mrow[p] - mnew);
            float sum = 0.f;
            #pragma unroll
            for (int kg = 0; kg < 4; kg++)
                #pragma unroll
                for (int j = 0; j < 2; j++) {
                    const float e0 = __expf(sc[kg][j][p * 2]     - mnew);
                    const float e1 = __expf(sc[kg][j][p * 2 + 1] - mnew);
                    sc[kg][j][p * 2] = e0; sc[kg][j][p * 2 + 1] = e1;
                    sum += e0 + e1;
                }
            sum += __shfl_xor_sync(0xffffffffu, sum, 1);
            sum += __shfl_xor_sync(0xffffffffu, sum, 2);
            lrow[p] = lrow[p] * fac + sum;
            mrow[p] = mnew;
            #pragma unroll
            for (int d = 0; d < 4; d++)
                #pragma unroll
                for (int j = 0; j < 2; j++) {
                    acc[d][j][p * 2]     *= fac;
                    acc[d][j][p * 2 + 1] *= fac;
                }
        }

        #pragma unroll
        for (int kg = 0; kg < 4; kg++) {
            uint32_t pa[4];
            pa[0] = bits2(__floats2half2_rn(sc[kg][0][0], sc[kg][0][1]));
            pa[1] = bits2(__floats2half2_rn(sc[kg][0][2], sc[kg][0][3]));
            pa[2] = bits2(__floats2half2_rn(sc[kg][1][0], sc[kg][1][1]));
            pa[3] = bits2(__floats2half2_rn(sc[kg][1][2], sc[kg][1][3]));
            #pragma unroll
            for (int dg = 0; dg < 4; dg++) {
                const int key  = kg * 16 + (lane & 15);
                const int dinb = dg * 16 + ((lane >> 4) << 3);
                const int kcv  = dinb >> 5, din = dinb & 31;
                const int qq   = ((din >> 3) ^ ((key >> 1) & 3));
                uint32_t tV[4];
                ldmx4t(tV, kb + 8192 + kcv * 4096 + key * 64 + (qq << 4));
                uint32_t v0[2] = {tV[0], tV[1]}, v1[2] = {tV[2], tV[3]};
                mma16816(acc[dg][0], pa, v0);
                mma16816(acc[dg][1], pa, v1);
            }
        }
        __syncthreads();
    }

    #pragma unroll
    for (int p = 0; p < 2; p++) {
        const float inv = 1.0f / lrow[p];
        const int row = bt * 64 + wq * 16 + (lane >> 2) + 8 * p;
        #pragma unroll
        for (int dg = 0; dg < 4; dg++)
            #pragma unroll
            for (int j = 0; j < 2; j++) {
                const int col = h * 64 + dg * 16 + j * 8 + (lane & 3) * 2;
                const __half2 hh = __floats2half2_rn(acc[dg][j][p * 2] * inv,
                                                     acc[dg][j][p * 2 + 1] * inv);
                *reinterpret_cast<uint32_t*>(&OH[tiled_idx(row, col, LROWS)]) = bits2(hh);
            }
    }
}

// ---------------- orchestration (dual-stream graph fork) ----------------
extern "C" void kernel_launch(void* const* d_in, const int* in_sizes, int n_in,
                              void* d_out, int out_size)
{
    (void)in_sizes; (void)n_in; (void)out_size;
    const float* x       = (const float*)d_in[0];
    const float* latents = (const float*)d_in[1];
    const float* nm_g    = (const float*)d_in[2];
    const float* nm_b    = (const float*)d_in[3];
    const float* nl_g    = (const float*)d_in[4];
    const float* nl_b    = (const float*)d_in[5];
    const float* wq      = (const float*)d_in[6];
    const float* wkv     = (const float*)d_in[7];
    const float* wo      = (const float*)d_in[8];
    const float* ff_g    = (const float*)d_in[9];
    const float* ff_b    = (const float*)d_in[10];
    const float* w1      = (const float*)d_in[11];
    const float* w2      = (const float*)d_in[12];
    const float* fin_g   = (const float*)d_in[13];
    const float* fin_b   = (const float*)d_in[14];
    float* out = (float*)d_out;

    hf *xh, *kvmh, *lnh, *lnl, *qkvh, *qkvl, *ath, *h1h;
    float *lat, *bias, *part;
    cudaGetSymbolAddress((void**)&xh,   g_xh);
    cudaGetSymbolAddress((void**)&kvmh, g_kvmh);
    cudaGetSymbolAddress((void**)&lat,  g_lat);
    cudaGetSymbolAddress((void**)&lnh,  g_lnh);  cudaGetSymbolAddress((void**)&lnl,  g_lnl);
    cudaGetSymbolAddress((void**)&qkvh, g_qkvh); cudaGetSymbolAddress((void**)&qkvl, g_qkvl);
    cudaGetSymbolAddress((void**)&ath,  g_ath);
    cudaGetSymbolAddress((void**)&h1h,  g_h1h);
    cudaGetSymbolAddress((void**)&bias, g_bias); cudaGetSymbolAddress((void**)&part, g_part);

    hf *wqkvT, *wkvG, *woT, *w1T, *w2T;
    cudaGetSymbolAddress((void**)&wqkvT, g_wqkvT);
    cudaGetSymbolAddress((void**)&wkvG,  g_wkvG);
    cudaGetSymbolAddress((void**)&woT,   g_woT);
    cudaGetSymbolAddress((void**)&w1T,   g_w1T);
    cudaGetSymbolAddress((void**)&w2T,   g_w2T);

    cudaFuncSetAttribute(gemm2b_tc, cudaFuncAttributeMaxDynamicSharedMemorySize, G2_SMEM);
    cudaFuncSetAttribute(gemm1_tc,  cudaFuncAttributeMaxDynamicSharedMemorySize, G1_SMEM);
    cudaFuncSetAttribute(attn_tc,   cudaFuncAttributeMaxDynamicSharedMemorySize, A_SMEM);
    const dim3 tb(32, 8);

    // second stream + fork/join events (host-side handles; no device allocs;
    // under graph capture these become pure graph dependencies)
    cudaStream_t s2;
    cudaStreamCreate(&s2);
    cudaEvent_t eFork, eKv[DEPTHL];
    cudaEventCreateWithFlags(&eFork, cudaEventDisableTiming);
    for (int i = 0; i < DEPTHL; i++) cudaEventCreateWithFlags(&eKv[i], cudaEventDisableTiming);

    // ---- kv-path prerequisites on main stream ----
    wsplit_kernel<<<dim3(NKV/32, DIMC/32, DEPTHL), tb>>>(wkv, nm_g, wkvG, DIMC, NKV, 0, NKV);
    bias_kernel<<<dim3(NKV/32, DEPTHL), 256>>>(nm_b, wkv, bias);
    ln_kernel<<<NMEDIA, 128>>>(x, nullptr, xh, nullptr, nullptr, nullptr, NMEDIA);
    cudaEventRecord(eFork, 0);
    cudaStreamWaitEvent(s2, eFork, 0);

    // ---- kv_media per layer on stream 2 (overlaps the latent path) ----
    for (int i = 0; i < DEPTHL; i++) {
        gemm1_tc<<<dim3(NKV/128, NMEDIA/128), 256, G1_SMEM, s2>>>(
            xh, wkvG + (size_t)i*NKV*DIMC, nullptr, kvmh + (size_t)i*NMEDIA*NKV,
            NMEDIA, NKV, DIMC, bias + (size_t)i*NKV, 0,
            0, 0, 0, 1, nullptr);
        cudaEventRecord(eKv[i], s2);
    }

    // ---- latent-path prep on main stream ----
    wsplit_kernel<<<dim3(DIMC/32, DIMC/32, DEPTHL), tb>>>(wq,  nullptr, wqkvT, DIMC, DIMC, 0,    NQKV);
    wsplit_kernel<<<dim3(NKV/32,  DIMC/32, DEPTHL), tb>>>(wkv, nullptr, wqkvT, DIMC, NKV,  DIMC, NQKV);
    wsplit_kernel<<<dim3(DIMC/32, DIMC/32, DEPTHL), tb>>>(wo,  nullptr, woT,   DIMC, DIMC, 0,    DIMC);
    wsplit_kernel<<<dim3(FFD/32,  DIMC/32, DEPTHL), tb>>>(w1,  nullptr, w1T,   DIMC, FFD,  0,    FFD);
    wsplit_kernel<<<dim3(DIMC/32, FFD/32,  DEPTHL), tb>>>(w2,  nullptr, w2T,   FFD,  DIMC, 0,    DIMC);
    init_lat_kernel<<<(LROWS * DIMC) / 256, 256>>>(latents, lat);
    ln_kernel<<<LROWS, 128>>>(lat, nullptr, lnh, lnl, nl_g, nl_b, LROWS);

    for (int i = 0; i < DEPTHL; i++) {
        gemm2b_tc<<<dim3(NQKV/128, LROWS/128), 256, G2_SMEM>>>(
            lnh, lnl, wqkvT + (size_t)i*NQKV*DIMC,
            qkvh, qkvl, LROWS, NQKV, DIMC, DIMC);
        cudaStreamWaitEvent(0, eKv[i], 0);         // attn needs kvm[i]
        attn_tc<<<BTOT * HEADS, 128, A_SMEM>>>(
            qkvh, qkvl, kvmh + (size_t)i*NMEDIA*NKV, ath);
        gemm1_tc<<<dim3(DIMC/128, LROWS/128, 2), 256, G1_SMEM>>>(
            ath, woT + (size_t)i*DIMC*DIMC,
            nullptr, nullptr, LROWS, DIMC, DIMC, nullptr, 0,
            0, 0, 0, 2, part);
        lnred_kernel<<<LROWS, 128>>>(part, 2, lat, lat, nullptr, lnh, nullptr,
                                     ff_g + (size_t)i*DIMC, ff_b + (size_t)i*DIMC);
        gemm1_tc<<<dim3(FFD/128, LROWS/128), 256, G1_SMEM>>>(
            lnh, w1T + (size_t)i*FFD*DIMC,
            nullptr, h1h, LROWS, FFD, DIMC, nullptr, 1,
            0, 0, 0, 1, nullptr);
        gemm1_tc<<<dim3(DIMC/128, LROWS/128, 4), 256, G1_SMEM>>>(
            h1h, w2T + (size_t)i*DIMC*FFD,
            nullptr, nullptr, LROWS, DIMC, FFD, nullptr, 0,
            0, 0, 0, 4, part);
        if (i + 1 < DEPTHL) {
            lnred_kernel<<<LROWS, 128>>>(part, 4, lat, lat, nullptr, lnh, lnl,
                                         nl_g + (size_t)(i+1)*DIMC, nl_b + (size_t)(i+1)*DIMC);
        } else {
            lnred_kernel<<<LROWS, 128>>>(part, 4, lat, nullptr, out, nullptr, nullptr,
                                         fin_g, fin_b);
        }
    }
}

// round 14
// speedup vs baseline: 9.0859x; 1.1035x over previous
#include <cuda_runtime.h>
#include <cuda_fp16.h>
#include <math.h>
#include <stdint.h>

// ---------------- problem constants ----------------
#define DIMC   1024
#define DEPTHL 6
#define HEADS  16
#define DHEAD  64
#define NKV    2048
#define NQKV   3072
#define FFD    4096
#define BTOT   32
#define MEDIA  1024
#define NMEDIA (BTOT*MEDIA)          // 32768
#define NLAT   64
#define LROWS  (BTOT*NLAT)           // 2048

typedef __half hf;

// ---------------- scratch ----------------
__device__ __align__(1024) hf    g_xh  [(size_t)NMEDIA*DIMC];
__device__ __align__(1024) hf    g_kvmh[(size_t)DEPTHL*NMEDIA*NKV];
__device__ float g_lat [LROWS*DIMC];
__device__ __align__(1024) hf    g_lnh [LROWS*DIMC];
__device__ __align__(1024) hf    g_qkvh[(size_t)LROWS*NQKV];
__device__ __align__(1024) hf    g_ath [LROWS*DIMC];
__device__ __align__(1024) hf    g_h1h [(size_t)LROWS*FFD];
__device__ float g_bias[DEPTHL*NKV];
__device__ float g_part[(size_t)4*LROWS*DIMC];

// weight planes (single fp16, B-side), chunk-tiled [K/32][N][32]
__device__ __align__(1024) hf g_wqkvT[(size_t)DEPTHL*NQKV*DIMC];
__device__ __align__(1024) hf g_wkvG [(size_t)DEPTHL*NKV*DIMC];
__device__ __align__(1024) hf g_woT  [(size_t)DEPTHL*DIMC*DIMC];
__device__ __align__(1024) hf g_w1T  [(size_t)DEPTHL*FFD*DIMC];
__device__ __align__(1024) hf g_w2T  [(size_t)DEPTHL*DIMC*FFD];

// ---------------- helpers ----------------
__device__ __forceinline__ uint32_t smem_u32(const void* p) {
    return (uint32_t)__cvta_generic_to_shared(p);
}
__device__ __forceinline__ size_t tiled_idx(int row, int k, int nrows) {
    const int kc = k >> 5, kin = k & 31;
    const int q = kin >> 3, b = kin & 7;
    const int qs = q ^ ((row >> 1) & 3);
    return ((size_t)kc * nrows + row) * 32 + qs * 8 + b;
}
__device__ __forceinline__ void bulk_g2s(uint32_t dst, const void* src, uint32_t bytes, uint32_t mbar) {
    asm volatile("cp.async.bulk.shared::cluster.global.mbarrier::complete_tx::bytes [%0], [%1], %2, [%3];"
                 :: "r"(dst), "l"(src), "r"(bytes), "r"(mbar) : "memory");
}
#define MBARRIER_INIT(addr, cnt) \
    asm volatile("mbarrier.init.shared.b64 [%0], %1;" :: "r"(addr), "r"(cnt) : "memory")
#define MBARRIER_EXPECT_TX(addr, tx) \
    asm volatile("mbarrier.arrive.expect_tx.shared.b64 _, [%0], %1;" :: "r"(addr), "r"(tx) : "memory")
#define MBARRIER_WAIT_PARITY(addr, par) do { \
    uint32_t _m = (addr), _p = (par), _d; \
    asm volatile("{\n\t.reg .pred p;\n\t" \
        "mbarrier.try_wait.parity.acquire.cta.shared::cta.b64 p, [%1], %2;\n\t" \
        "selp.b32 %0, 1, 0, p;\n\t}" : "=r"(_d) : "r"(_m), "r"(_p) : "memory"); \
    if (!_d) { \
        asm volatile("{\n\t.reg .pred P1;\n\t" \
            "WL_%=:\n\t" \
            "mbarrier.try_wait.parity.acquire.cta.shared::cta.b64 P1, [%0], %1, 0x989680;\n\t" \
            "@P1 bra.uni WD_%=;\n\tbra.uni WL_%=;\n\tWD_%=:\n\t}" \
            :: "r"(_m), "r"(_p) : "memory"); \
    } } while (0)

__device__ __forceinline__ void ldmx4(uint32_t* r, uint32_t a) {
    asm volatile("ldmatrix.sync.aligned.m8n8.x4.shared.b16 {%0,%1,%2,%3}, [%4];"
                 : "=r"(r[0]), "=r"(r[1]), "=r"(r[2]), "=r"(r[3]) : "r"(a));
}
__device__ __forceinline__ void ldmx4t(uint32_t* r, uint32_t a) {
    asm volatile("ldmatrix.sync.aligned.m8n8.x4.trans.shared.b16 {%0,%1,%2,%3}, [%4];"
                 : "=r"(r[0]), "=r"(r[1]), "=r"(r[2]), "=r"(r[3]) : "r"(a));
}
__device__ __forceinline__ void mma16816(float* d, const uint32_t* a, const uint32_t* b) {
    asm volatile("mma.sync.aligned.m16n8k16.row.col.f32.f16.f16.f32 "
                 "{%0,%1,%2,%3},{%4,%5,%6,%7},{%8,%9},{%0,%1,%2,%3};"
                 : "+f"(d[0]), "+f"(d[1]), "+f"(d[2]), "+f"(d[3])
                 : "r"(a[0]), "r"(a[1]), "r"(a[2]), "r"(a[3]),
                   "r"(b[0]), "r"(b[1]));
}
__device__ __forceinline__ uint32_t bits2(__half2 h) {
    return *reinterpret_cast<uint32_t*>(&h);
}

// ---------------- LayerNorm: fp32 in -> fp32 out and/or tiled fp16 hi plane ----
__global__ void ln_kernel(const float* __restrict__ in,
                          float* __restrict__ outF,
                          hf* __restrict__ outH,
                          const float* __restrict__ g, const float* __restrict__ b,
                          int nrows)
{
    const int row = blockIdx.x;
    const float* x = in + (size_t)row * DIMC;
    float s = 0.f, sq = 0.f;
    for (int c = threadIdx.x; c < DIMC; c += blockDim.x) {
        float v = x[c]; s += v; sq += v * v;
    }
    __shared__ float sh[64];
    #pragma unroll
    for (int o = 16; o > 0; o >>= 1) {
        s  += __shfl_down_sync(0xffffffffu, s,  o);
        sq += __shfl_down_sync(0xffffffffu, sq, o);
    }
    const int wid = threadIdx.x >> 5, lid = threadIdx.x & 31;
    if (lid == 0) { sh[wid] = s; sh[wid + 32] = sq; }
    __syncthreads();
    if (threadIdx.x == 0) {
        float ts = 0.f, tsq = 0.f;
        const int nw = blockDim.x >> 5;
        for (int i = 0; i < nw; i++) { ts += sh[i]; tsq += sh[i + 32]; }
        const float mean = ts * (1.0f / DIMC);
        const float var  = tsq * (1.0f / DIMC) - mean * mean;
        sh[0] = mean; sh[1] = rsqrtf(var + 1e-5f);
    }
    __syncthreads();
    const float mean = sh[0], rstd = sh[1];

    for (int k0 = threadIdx.x * 8; k0 < DIMC; k0 += blockDim.x * 8) {
        float v[8];
        #pragma unroll
        for (int e = 0; e < 8; e++) {
            float t = (x[k0 + e] - mean) * rstd;
            if (g) t = t * g[k0 + e] + b[k0 + e];
            v[e] = t;
        }
        if (outF) {
            float* o = outF + (size_t)row * DIMC + k0;
            #pragma unroll
            for (int e = 0; e < 8; e++) o[e] = v[e];
        }
        if (outH) {
            uint32_t hq[4];
            #pragma unroll
            for (int e = 0; e < 4; e++)
                hq[e] = bits2(__floats2half2_rn(v[2*e], v[2*e+1]));
            *reinterpret_cast<uint4*>(&outH[tiled_idx(row, k0, nrows)]) =
                make_uint4(hq[0], hq[1], hq[2], hq[3]);
        }
    }
}

// ---------------- fused split-K reduce + residual + LayerNorm ----------------
__global__ void __launch_bounds__(128)
lnred_kernel(const float* __restrict__ part, int S,
             const float* __restrict__ latin,
             float* __restrict__ latout,
             float* __restrict__ outF,
             hf* __restrict__ outH,
             const float* __restrict__ g, const float* __restrict__ b)
{
    const int row = blockIdx.x;
    const int tid = threadIdx.x;
    const size_t base = (size_t)row * DIMC + tid * 8;
    float v[8];
    #pragma unroll
    for (int e = 0; e < 8; e++) v[e] = latin[base + e];
    for (int s = 0; s < S; s++) {
        const float* p = part + (size_t)s * LROWS * DIMC + base;
        #pragma unroll
        for (int e = 0; e < 8; e++) v[e] += p[e];
    }
    if (latout) {
        #pragma unroll
        for (int e = 0; e < 8; e++) latout[base + e] = v[e];
    }
    float s1 = 0.f, s2 = 0.f;
    #pragma unroll
    for (int e = 0; e < 8; e++) { s1 += v[e]; s2 += v[e] * v[e]; }
    __shared__ float sh[8];
    #pragma unroll
    for (int o = 16; o > 0; o >>= 1) {
        s1 += __shfl_down_sync(0xffffffffu, s1, o);
        s2 += __shfl_down_sync(0xffffffffu, s2, o);
    }
    const int wid = tid >> 5, lid = tid & 31;
    if (lid == 0) { sh[wid] = s1; sh[wid + 4] = s2; }
    __syncthreads();
    if (tid == 0) {
        float ts = sh[0] + sh[1] + sh[2] + sh[3];
        float tq = sh[4] + sh[5] + sh[6] + sh[7];
        const float mean = ts * (1.0f / DIMC);
        const float var  = tq * (1.0f / DIMC) - mean * mean;
        sh[0] = mean; sh[1] = rsqrtf(var + 1e-5f);
    }
    __syncthreads();
    const float mean = sh[0], rstd = sh[1];
    const int k0 = tid * 8;
    float t[8];
    #pragma unroll
    for (int e = 0; e < 8; e++)
        t[e] = (v[e] - mean) * rstd * g[k0 + e] + b[k0 + e];
    if (outF) {
        float* o = outF + base;
        #pragma unroll
        for (int e = 0; e < 8; e++) o[e] = t[e];
    }
    if (outH) {
        uint32_t hq[4];
        #pragma unroll
        for (int e = 0; e < 4; e++)
            hq[e] = bits2(__floats2half2_rn(t[2*e], t[2*e+1]));
        *reinterpret_cast<uint4*>(&outH[tiled_idx(row, k0, LROWS)]) =
            make_uint4(hq[0], hq[1], hq[2], hq[3]);
    }
}

// ---------------- bias: all layers, k-parallel ----------------
__global__ void bias_kernel(const float* __restrict__ nm_b,
                            const float* __restrict__ wkv, float* __restrict__ out)
{
    const int layer = blockIdx.y;
    const int tid = threadIdx.x;
    const int n  = blockIdx.x * 32 + (tid & 31);
    const int ks = tid >> 5;
    const float* bv = nm_b + (size_t)layer * DIMC;
    const float* W  = wkv  + (size_t)layer * DIMC * NKV;
    float s = 0.f;
    #pragma unroll 4
    for (int k = ks * 128; k < ks * 128 + 128; k++)
        s += bv[k] * __ldg(&W[(size_t)k * NKV + n]);
    __shared__ float red[8][32];
    red[ks][tid & 31] = s;
    __syncthreads();
    if (ks == 0) {
        float t = 0.f;
        #pragma unroll
        for (int i = 0; i < 8; i++) t += red[i][tid & 31];
        out[(size_t)layer * NKV + n] = t;
    }
}

__global__ void init_lat_kernel(const float* __restrict__ latents, float* __restrict__ lat)
{
    const int idx = blockIdx.x * blockDim.x + threadIdx.x;
    lat[idx] = latents[idx & (NLAT * DIMC - 1)];
}

// ---------------- weight transpose + gamma + fp16 quantize (batched over depth) ----
__global__ void wsplit_kernel(const float* __restrict__ W0, const float* __restrict__ g0,
                              hf* __restrict__ T0, int K, int N, int nofs, int ntot)
{
    const int z = blockIdx.z;
    const float* W = W0 + (size_t)z * K * N;
    const float* g = g0 ? g0 + (size_t)z * K : nullptr;
    hf* T = T0 + (size_t)z * ntot * K;
    __shared__ float t[32][33];
    const int n0 = blockIdx.x * 32, k0 = blockIdx.y * 32;
    const int tx = threadIdx.x, ty = threadIdx.y;
    #pragma unroll
    for (int i = 0; i < 4; i++) {
        float v = W[(size_t)(k0 + ty + 8 * i) * N + n0 + tx];
        if (g) v *= g[k0 + ty + 8 * i];
        t[ty + 8 * i][tx] = v;
    }
    __syncthreads();
    #pragma unroll
    for (int i = 0; i < 4; i++) {
        const int n = n0 + ty + 8 * i, k = k0 + tx;
        T[tiled_idx(nofs + n, k, ntot)] = __float2half_rn(t[tx][ty + 8 * i]);
    }
}

// =====================================================================
// 1-term fp16 HMMA GEMM, occ 2, K64 stages (2 chunks per barrier).
// grid.z = layers (lstr*) OR split-K partitions (splitk>1, Cpart).
// =====================================================================
#define NSTG1 2
#define STG1  32768                   // [A c0 8K | A c1 8K | B c0 8K | B c1 8K]
#define G1_SMEM (1024 + NSTG1*STG1)   // 66560

__global__ void __launch_bounds__(256, 2)
gemm1_tc(const hf* __restrict__ Ah, const hf* __restrict__ B0,
         float* __restrict__ Cf, hf* __restrict__ Ch0,
         int M, int N, int K,
         const float* __restrict__ bias0, int dogelu,
         size_t lstrB, size_t lstrC, int lstrBias,
         int splitk, float* __restrict__ Cpart)
{
    extern __shared__ char smem[];
    const uint32_t sb = smem_u32(smem);
    const int tid  = threadIdx.x;
    const int lane = tid & 31;
    const int wid  = tid >> 5;
    const int wm   = wid & 1;
    const int wn   = wid >> 1;
    const int bm   = blockIdx.y * 128;
    const int bn   = blockIdx.x * 128;
    const int z    = blockIdx.z;

    const hf* B = B0;
    hf* Ch = Ch0;
    const float* bias = bias0;
    const int nc = K >> 5;
    int ncl = nc, c0 = 0;
    if (splitk > 1) { ncl = nc / splitk; c0 = z * ncl; }
    else if (z) {
        B += (size_t)z * lstrB;
        if (Ch0) Ch += (size_t)z * lstrC;
        if (bias0) bias += (size_t)z * lstrBias;
    }
    const int nst = ncl >> 1;          // K64 stages (ncl always even here)

    if (tid == 0) {
        #pragma unroll
        for (int s = 0; s < NSTG1; s++) MBARRIER_INIT(sb + 8 * s, 1);
    }
    __syncthreads();

    float acc[4][4][4];
    #pragma unroll
    for (int i = 0; i < 4; i++)
        #pragma unroll
        for (int j = 0; j < 4; j++)
            #pragma unroll
            for (int q = 0; q < 4; q++) acc[i][j][q] = 0.f;

    auto issue = [&](int st) {
        const uint32_t mb  = sb + 8 * (st & 1);
        const uint32_t dst = sb + 1024 + (st & 1) * STG1;
        MBARRIER_EXPECT_TX(mb, 32768u);
        #pragma unroll
        for (int half = 0; half < 2; half++) {
            const int gc = c0 + 2 * st + half;
            bulk_g2s(dst + half * 8192,         Ah + ((size_t)gc * M + bm) * 32, 8192, mb);
            bulk_g2s(dst + 16384 + half * 8192, B  + ((size_t)gc * N + bn) * 32, 8192, mb);
        }
    };
    if (tid == 0) {
        issue(0);
        if (nst > 1) issue(1);
    }

    for (int st = 0; st < nst; st++) {
        MBARRIER_WAIT_PARITY(sb + 8 * (st & 1), (st >> 1) & 1);
        const uint32_t base = sb + 1024 + (st & 1) * STG1;
        #pragma unroll
        for (int u = 0; u < 4; u++) {
            const int half = u >> 1, s16 = u & 1;
            const uint32_t stA = base + half * 8192;
            const uint32_t stB = base + 16384 + half * 8192;
            uint32_t aH[16], bf[8];
            #pragma unroll
            for (int mi = 0; mi < 4; mi++) {
                const int row = wm * 64 + mi * 16 + (lane & 15);
                const int q   = s16 * 2 + (lane >> 4);
                ldmx4(aH + 4 * mi, stA + row * 64 + ((q ^ ((row >> 1) & 3)) << 4));
            }
            #pragma unroll
            for (int ni = 0; ni < 2; ni++) {
                const int row = wn * 32 + ni * 16 + (lane & 7) + ((lane >> 4) << 3);
                const int q   = s16 * 2 + ((lane >> 3) & 1);
                uint32_t t[4];
                ldmx4(t, stB + row * 64 + ((q ^ ((row >> 1) & 3)) << 4));
                bf[ni*4+0] = t[0]; bf[ni*4+1] = t[1]; bf[ni*4+2] = t[2]; bf[ni*4+3] = t[3];
            }
            #pragma unroll
            for (int mi = 0; mi < 4; mi++)
                #pragma unroll
                for (int j = 0; j < 4; j++)
                    mma16816(acc[mi][j], aH + 4 * mi, bf + 2 * j);
        }
        __syncthreads();
        if (tid == 0 && st + NSTG1 < nst) issue(st + NSTG1);
    }

    if (Cpart) {
        float* P = Cpart + (size_t)z * M * N;
        #pragma unroll
        for (int mi = 0; mi < 4; mi++)
            #pragma unroll
            for (int j = 0; j < 4; j++) {
                const int colb = bn + wn * 32 + j * 8 + (lane & 3) * 2;
                #pragma unroll
                for (int p = 0; p < 2; p++) {
                    const int row = bm + wm * 64 + mi * 16 + (lane >> 2) + 8 * p;
                    *reinterpret_cast<float2*>(&P[(size_t)row * N + colb]) =
                        make_float2(acc[mi][j][p * 2], acc[mi][j][p * 2 + 1]);
                }
            }
        return;
    }
    #pragma unroll
    for (int mi = 0; mi < 4; mi++) {
        #pragma unroll
        for (int j = 0; j < 4; j++) {
            const int colb = bn + wn * 32 + j * 8 + (lane & 3) * 2;
            #pragma unroll
            for (int p = 0; p < 2; p++) {
                const int row = bm + wm * 64 + mi * 16 + (lane >> 2) + 8 * p;
                float v0 = acc[mi][j][p * 2], v1 = acc[mi][j][p * 2 + 1];
                if (bias) { v0 += bias[colb]; v1 += bias[colb + 1]; }
                if (dogelu) {
                    v0 = 0.5f * v0 * (1.f + erff(v0 * 0.70710678118654752f));
                    v1 = 0.5f * v1 * (1.f + erff(v1 * 0.70710678118654752f));
                }
                if (Cf) *reinterpret_cast<float2*>(&Cf[(size_t)row * N + colb]) = make_float2(v0, v1);
                if (Ch) {
                    const __half2 h = __floats2half2_rn(v0, v1);
                    *reinterpret_cast<uint32_t*>(&Ch[tiled_idx(row, colb, M)]) = bits2(h);
                }
            }
        }
    }
}

// =====================================================================
// FA2 attention — single-plane Q (register P, occ 3).
// =====================================================================
#define A_OFFQ  1024
#define A_OFFKV (A_OFFQ + 8192)
#define A_SMEM  (A_OFFKV + 32768)     // 41984

__global__ void __launch_bounds__(128, 3)
attn_tc(const hf* __restrict__ QKVh,
        const hf* __restrict__ Kmh,
        hf* __restrict__ OH)
{
    extern __shared__ char smem[];
    const uint32_t sb = smem_u32(smem);
    const int bt  = blockIdx.x >> 4;
    const int h   = blockIdx.x & 15;
    const int tid = threadIdx.x;
    const int lane = tid & 31;
    const int wq   = tid >> 5;

    if (tid == 0) { MBARRIER_INIT(sb, 1); MBARRIER_INIT(sb + 8, 1); }

    // Q hi plane copy: 2 segs x 4096B
    #pragma unroll
    for (int seg = 0; seg < 2; seg++) {
        const hf* src = QKVh + ((size_t)(2 * h + seg) * LROWS + bt * 64) * 32;
        #pragma unroll
        for (int it = 0; it < 2; it++) {
            const int idx = tid + it * 128;
            const uint4 v = reinterpret_cast<const uint4*>(src)[idx];
            *reinterpret_cast<uint4*>(smem + A_OFFQ + seg * 4096 + idx * 16) = v;
        }
    }
    __syncthreads();

    auto issueKV = [&](int t) {
        const int st = t & 1;
        const uint32_t mb = sb + 8 * st;
        const uint32_t dst = sb + A_OFFKV + st * 16384;
        MBARRIER_EXPECT_TX(mb, 16384u);
        const hf* PH; size_t rbase, nr; int kcK, kcV;
        if (t < 16) { PH = Kmh;  rbase = (size_t)bt * 1024 + t * 64; nr = NMEDIA; kcK = 2*h;      kcV = 32 + 2*h; }
        else        { PH = QKVh; rbase = (size_t)bt * 64;            nr = LROWS;  kcK = 32 + 2*h; kcV = 64 + 2*h; }
        bulk_g2s(dst,          PH + ((size_t)kcK * nr + rbase) * 32,       4096, mb);
        bulk_g2s(dst +  4096,  PH + ((size_t)(kcK + 1) * nr + rbase) * 32, 4096, mb);
        bulk_g2s(dst +  8192,  PH + ((size_t)kcV * nr + rbase) * 32,       4096, mb);
        bulk_g2s(dst + 12288,  PH + ((size_t)(kcV + 1) * nr + rbase) * 32, 4096, mb);
    };
    if (tid == 0) issueKV(0);

    uint32_t qH[4][4];
    #pragma unroll
    for (int s = 0; s < 4; s++) {
        const int row = wq * 16 + (lane & 15);
        const int qq = (((s & 1) * 2 + (lane >> 4)) ^ ((row >> 1) & 3));
        ldmx4(qH[s], sb + A_OFFQ + (s >> 1) * 4096 + row * 64 + (qq << 4));
    }

    float mrow[2] = {-INFINITY, -INFINITY};
    float lrow[2] = {0.f, 0.f};
    float acc[4][2][4];
    #pragma unroll
    for (int d = 0; d < 4; d++)
        #pragma unroll
        for (int j = 0; j < 2; j++)
            #pragma unroll
            for (int q = 0; q < 4; q++) acc[d][j][q] = 0.f;

    for (int t = 0; t < 17; t++) {
        if (tid == 0 && t + 1 < 17) issueKV(t + 1);
        MBARRIER_WAIT_PARITY(sb + 8 * (t & 1), (t >> 1) & 1);
        const uint32_t kb = sb + A_OFFKV + (t & 1) * 16384;

        float sc[4][2][4];
        #pragma unroll
        for (int kg = 0; kg < 4; kg++)
            #pragma unroll
            for (int j = 0; j < 2; j++)
                #pragma unroll
                for (int q = 0; q < 4; q++) sc[kg][j][q] = 0.f;
        #pragma unroll
        for (int s = 0; s < 4; s++) {
            #pragma unroll
            for (int kg = 0; kg < 4; kg++) {
                const int row = kg * 16 + (lane & 7) + ((lane >> 4) << 3);
                const int qq = (((s & 1) * 2 + ((lane >> 3) & 1)) ^ ((row >> 1) & 3));
                uint32_t tB[4];
                ldmx4(tB, kb + (s >> 1) * 4096 + row * 64 + (qq << 4));
                uint32_t b0[2] = {tB[0], tB[1]}, b1[2] = {tB[2], tB[3]};
                mma16816(sc[kg][0], qH[s], b0);
                mma16816(sc[kg][1], qH[s], b1);
            }
        }
        #pragma unroll
        for (int kg = 0; kg < 4; kg++)
            #pragma unroll
            for (int j = 0; j < 2; j++)
                #pragma unroll
                for (int q = 0; q < 4; q++) sc[kg][j][q] *= 0.125f;

        #pragma unroll
        for (int p = 0; p < 2; p++) {
            float m = -INFINITY;
            #pragma unroll
            for (int kg = 0; kg < 4; kg++)
                #pragma unroll
                for (int j = 0; j < 2; j++) {
                    m = fmaxf(m, sc[kg][j][p * 2]);
                    m = fmaxf(m, sc[kg][j][p * 2 + 1]);
                }
            m = fmaxf(m, __shfl_xor_sync(0xffffffffu, m, 1));
            m = fmaxf(m, __shfl_xor_sync(0xffffffffu, m, 2));
            const float mnew = fmaxf(mrow[p], m);
            const float fac = __expf(mrow[p] - mnew);
            float sum = 0.f;
            #pragma unroll
            for (int kg = 0; kg < 4; kg++)
                #pragma unroll
                for (int j = 0; j < 2; j++) {
                    const float e0 = __expf(sc[kg][j][p * 2]     - mnew);
                    const float e1 = __expf(sc[kg][j][p * 2 + 1] - mnew);
                    sc[kg][j][p * 2] = e0; sc[kg][j][p * 2 + 1] = e1;
                    sum += e0 + e1;
                }
            sum += __shfl_xor_sync(0xffffffffu, sum, 1);
            sum += __shfl_xor_sync(0xffffffffu, sum, 2);
            lrow[p] = lrow[p] * fac + sum;
            mrow[p] = mnew;
            #pragma unroll
            for (int d = 0; d < 4; d++)
                #pragma unroll
                for (int j = 0; j < 2; j++) {
                    acc[d][j][p * 2]     *= fac;
                    acc[d][j][p * 2 + 1] *= fac;
                }
        }

        #pragma unroll
        for (int kg = 0; kg < 4; kg++) {
            uint32_t pa[4];
            pa[0] = bits2(__floats2half2_rn(sc[kg][0][0], sc[kg][0][1]));
            pa[1] = bits2(__floats2half2_rn(sc[kg][0][2], sc[kg][0][3]));
            pa[2] = bits2(__floats2half2_rn(sc[kg][1][0], sc[kg][1][1]));
            pa[3] = bits2(__floats2half2_rn(sc[kg][1][2], sc[kg][1][3]));
            #pragma unroll
            for (int dg = 0; dg < 4; dg++) {
                const int key  = kg * 16 + (lane & 15);
                const int dinb = dg * 16 + ((lane >> 4) << 3);
                const int kcv  = dinb >> 5, din = dinb & 31;
                const int qq   = ((din >> 3) ^ ((key >> 1) & 3));
                uint32_t tV[4];
                ldmx4t(tV, kb + 8192 + kcv * 4096 + key * 64 + (qq << 4));
                uint32_t v0[2] = {tV[0], tV[1]}, v1[2] = {tV[2], tV[3]};
                mma16816(acc[dg][0], pa, v0);
                mma16816(acc[dg][1], pa, v1);
            }
        }
        __syncthreads();
    }

    #pragma unroll
    for (int p = 0; p < 2; p++) {
        const float inv = 1.0f / lrow[p];
        const int row = bt * 64 + wq * 16 + (lane >> 2) + 8 * p;
        #pragma unroll
        for (int dg = 0; dg < 4; dg++)
            #pragma unroll
            for (int j = 0; j < 2; j++) {
                const int col = h * 64 + dg * 16 + j * 8 + (lane & 3) * 2;
                const __half2 hh = __floats2half2_rn(acc[dg][j][p * 2] * inv,
                                                     acc[dg][j][p * 2 + 1] * inv);
                *reinterpret_cast<uint32_t*>(&OH[tiled_idx(row, col, LROWS)]) = bits2(hh);
            }
    }
}

// ---------------- orchestration (dual-stream graph fork) ----------------
extern "C" void kernel_launch(void* const* d_in, const int* in_sizes, int n_in,
                              void* d_out, int out_size)
{
    (void)in_sizes; (void)n_in; (void)out_size;
    const float* x       = (const float*)d_in[0];
    const float* latents = (const float*)d_in[1];
    const float* nm_g    = (const float*)d_in[2];
    const float* nm_b    = (const float*)d_in[3];
    const float* nl_g    = (const float*)d_in[4];
    const float* nl_b    = (const float*)d_in[5];
    const float* wq      = (const float*)d_in[6];
    const float* wkv     = (const float*)d_in[7];
    const float* wo      = (const float*)d_in[8];
    const float* ff_g    = (const float*)d_in[9];
    const float* ff_b    = (const float*)d_in[10];
    const float* w1      = (const float*)d_in[11];
    const float* w2      = (const float*)d_in[12];
    const float* fin_g   = (const float*)d_in[13];
    const float* fin_b   = (const float*)d_in[14];
    float* out = (float*)d_out;

    hf *xh, *kvmh, *lnh, *qkvh, *ath, *h1h;
    float *lat, *bias, *part;
    cudaGetSymbolAddress((void**)&xh,   g_xh);
    cudaGetSymbolAddress((void**)&kvmh, g_kvmh);
    cudaGetSymbolAddress((void**)&lat,  g_lat);
    cudaGetSymbolAddress((void**)&lnh,  g_lnh);
    cudaGetSymbolAddress((void**)&qkvh, g_qkvh);
    cudaGetSymbolAddress((void**)&ath,  g_ath);
    cudaGetSymbolAddress((void**)&h1h,  g_h1h);
    cudaGetSymbolAddress((void**)&bias, g_bias); cudaGetSymbolAddress((void**)&part, g_part);

    hf *wqkvT, *wkvG, *woT, *w1T, *w2T;
    cudaGetSymbolAddress((void**)&wqkvT, g_wqkvT);
    cudaGetSymbolAddress((void**)&wkvG,  g_wkvG);
    cudaGetSymbolAddress((void**)&woT,   g_woT);
    cudaGetSymbolAddress((void**)&w1T,   g_w1T);
    cudaGetSymbolAddress((void**)&w2T,   g_w2T);

    cudaFuncSetAttribute(gemm1_tc, cudaFuncAttributeMaxDynamicSharedMemorySize, G1_SMEM);
    cudaFuncSetAttribute(attn_tc,  cudaFuncAttributeMaxDynamicSharedMemorySize, A_SMEM);
    const dim3 tb(32, 8);

    cudaStream_t s2;
    cudaStreamCreate(&s2);
    cudaEvent_t eFork, eKv[DEPTHL];
    cudaEventCreateWithFlags(&eFork, cudaEventDisableTiming);
    for (int i = 0; i < DEPTHL; i++) cudaEventCreateWithFlags(&eKv[i], cudaEventDisableTiming);

    // ---- kv-path prerequisites on main stream ----
    wsplit_kernel<<<dim3(NKV/32, DIMC/32, DEPTHL), tb>>>(wkv, nm_g, wkvG, DIMC, NKV, 0, NKV);
    bias_kernel<<<dim3(NKV/32, DEPTHL), 256>>>(nm_b, wkv, bias);
    ln_kernel<<<NMEDIA, 128>>>(x, nullptr, xh, nullptr, nullptr, NMEDIA);
    cudaEventRecord(eFork, 0);
    cudaStreamWaitEvent(s2, eFork, 0);

    // ---- kv_media per layer on stream 2 ----
    for (int i = 0; i < DEPTHL; i++) {
        gemm1_tc<<<dim3(NKV/128, NMEDIA/128), 256, G1_SMEM, s2>>>(
            xh, wkvG + (size_t)i*NKV*DIMC, nullptr, kvmh + (size_t)i*NMEDIA*NKV,
            NMEDIA, NKV, DIMC, bias + (size_t)i*NKV, 0,
            0, 0, 0, 1, nullptr);
        cudaEventRecord(eKv[i], s2);
    }

    // ---- latent-path prep on main stream ----
    wsplit_kernel<<<dim3(DIMC/32, DIMC/32, DEPTHL), tb>>>(wq,  nullptr, wqkvT, DIMC, DIMC, 0,    NQKV);
    wsplit_kernel<<<dim3(NKV/32,  DIMC/32, DEPTHL), tb>>>(wkv, nullptr, wqkvT, DIMC, NKV,  DIMC, NQKV);
    wsplit_kernel<<<dim3(DIMC/32, DIMC/32, DEPTHL), tb>>>(wo,  nullptr, woT,   DIMC, DIMC, 0,    DIMC);
    wsplit_kernel<<<dim3(FFD/32,  DIMC/32, DEPTHL), tb>>>(w1,  nullptr, w1T,   DIMC, FFD,  0,    FFD);
    wsplit_kernel<<<dim3(DIMC/32, FFD/32,  DEPTHL), tb>>>(w2,  nullptr, w2T,   FFD,  DIMC, 0,    DIMC);
    init_lat_kernel<<<(LROWS * DIMC) / 256, 256>>>(latents, lat);
    ln_kernel<<<LROWS, 128>>>(lat, nullptr, lnh, nl_g, nl_b, LROWS);

    for (int i = 0; i < DEPTHL; i++) {
        // fused Q|K|V latent GEMM — 1-term A now
        gemm1_tc<<<dim3(NQKV/128, LROWS/128), 256, G1_SMEM>>>(
            lnh, wqkvT + (size_t)i*NQKV*DIMC,
            nullptr, qkvh, LROWS, NQKV, DIMC, nullptr, 0,
            0, 0, 0, 1, nullptr);
        cudaStreamWaitEvent(0, eKv[i], 0);
        attn_tc<<<BTOT * HEADS, 128, A_SMEM>>>(
            qkvh, kvmh + (size_t)i*NMEDIA*NKV, ath);
        gemm1_tc<<<dim3(DIMC/128, LROWS/128, 2), 256, G1_SMEM>>>(
            ath, woT + (size_t)i*DIMC*DIMC,
            nullptr, nullptr, LROWS, DIMC, DIMC, nullptr, 0,
            0, 0, 0, 2, part);
        lnred_kernel<<<LROWS, 128>>>(part, 2, lat, lat, nullptr, lnh,
                                     ff_g + (size_t)i*DIMC, ff_b + (size_t)i*DIMC);
        gemm1_tc<<<dim3(FFD/128, LROWS/128), 256, G1_SMEM>>>(
            lnh, w1T + (size_t)i*FFD*DIMC,
            nullptr, h1h, LROWS, FFD, DIMC, nullptr, 1,
            0, 0, 0, 1, nullptr);
        gemm1_tc<<<dim3(DIMC/128, LROWS/128, 4), 256, G1_SMEM>>>(
            h1h, w2T + (size_t)i*DIMC*FFD,
            nullptr, nullptr, LROWS, DIMC, FFD, nullptr, 0,
            0, 0, 0, 4, part);
        if (i + 1 < DEPTHL) {
            lnred_kernel<<<LROWS, 128>>>(part, 4, lat, lat, nullptr, lnh,
                                         nl_g + (size_t)(i+1)*DIMC, nl_b + (size_t)(i+1)*DIMC);
        } else {
            lnred_kernel<<<LROWS, 128>>>(part, 4, lat, nullptr, out, nullptr,
                                         fin_g, fin_b);
        }
    }
}